// round 2
// baseline (speedup 1.0000x reference)
#include <cuda_runtime.h>

// ---------------------------------------------------------------------------
// Problem constants (fixed shapes)
//   B=1, S=8192, QC=4096, H=64, KC=64, OC=64, H*KC=4096
// ---------------------------------------------------------------------------
#define S_LEN 8192
#define D4096 4096

// Scratch (allocation-guard-safe __device__ globals)
__device__ float g_q[(size_t)S_LEN * D4096];     // q projection  (S, 4096)
__device__ float g_k[(size_t)S_LEN * D4096];     // k projection  (S, 4096)
__device__ float g_v[(size_t)S_LEN * D4096];     // v projection  (S, 4096)
__device__ float g_attn[(size_t)S_LEN * D4096];  // attn output   (S, 4096)

// ---------------------------------------------------------------------------
// Kernel 1: big SGEMM  C = A(MxK) @ B(KxN) + bias,  128x128 tile, TK=8,
// 256 threads, 8x8 register tile per thread.
// ---------------------------------------------------------------------------
__global__ __launch_bounds__(256) void sgemm128(
    const float* __restrict__ A, const float* __restrict__ Bm,
    const float* __restrict__ bias, float* __restrict__ C,
    int M, int N, int K)
{
    __shared__ float As[8][128];
    __shared__ float Bs[8][128];

    const int tid = threadIdx.x;
    const int bm = blockIdx.y * 128;
    const int bn = blockIdx.x * 128;
    const int tr = tid >> 4;    // 0..15
    const int tc = tid & 15;    // 0..15

    float acc[8][8];
#pragma unroll
    for (int i = 0; i < 8; i++)
#pragma unroll
        for (int j = 0; j < 8; j++) acc[i][j] = 0.0f;

    // A tile load mapping: 128 rows x 8 k  = 256 float4; thread -> (row, 4k)
    const int am = tid >> 1;
    const int ak = (tid & 1) * 4;
    // B tile load mapping: 8 rows x 128 n  = 256 float4; thread -> (k, 4n)
    const int bk = tid >> 5;
    const int bn4 = (tid & 31) * 4;

    const float* Aptr = A + (size_t)(bm + am) * K + ak;
    const float* Bptr = Bm + (size_t)bk * N + bn + bn4;

    for (int k0 = 0; k0 < K; k0 += 8) {
        float4 av = *reinterpret_cast<const float4*>(Aptr + k0);
        As[ak + 0][am] = av.x;
        As[ak + 1][am] = av.y;
        As[ak + 2][am] = av.z;
        As[ak + 3][am] = av.w;
        float4 bv = *reinterpret_cast<const float4*>(Bptr + (size_t)k0 * N);
        *reinterpret_cast<float4*>(&Bs[bk][bn4]) = bv;
        __syncthreads();

#pragma unroll
        for (int k = 0; k < 8; k++) {
            float a[8], b[8];
            *reinterpret_cast<float4*>(&a[0]) = *reinterpret_cast<float4*>(&As[k][tr * 8]);
            *reinterpret_cast<float4*>(&a[4]) = *reinterpret_cast<float4*>(&As[k][tr * 8 + 4]);
            *reinterpret_cast<float4*>(&b[0]) = *reinterpret_cast<float4*>(&Bs[k][tc * 8]);
            *reinterpret_cast<float4*>(&b[4]) = *reinterpret_cast<float4*>(&Bs[k][tc * 8 + 4]);
#pragma unroll
            for (int i = 0; i < 8; i++)
#pragma unroll
                for (int j = 0; j < 8; j++) acc[i][j] += a[i] * b[j];
        }
        __syncthreads();
    }

#pragma unroll
    for (int i = 0; i < 8; i++) {
        const size_t row = (size_t)(bm + tr * 8 + i);
        float* crow = C + row * N + bn + tc * 8;
#pragma unroll
        for (int j = 0; j < 8; j++)
            crow[j] = acc[i][j] + bias[bn + tc * 8 + j];
    }
}

// ---------------------------------------------------------------------------
// Kernel 2: small projection  out(S,4096) = in(S,64) @ W(64,4096) + bias.
// Each block: 8 tokens x 256 output columns (8x weight register reuse).
// ---------------------------------------------------------------------------
__global__ __launch_bounds__(256) void proj_small(
    const float* __restrict__ in, const float* __restrict__ W,
    const float* __restrict__ bias, float* __restrict__ out)
{
    __shared__ float ins[8][64];
    const int n = blockIdx.x * 256 + threadIdx.x;
    const int s0 = blockIdx.y * 8;

    for (int t = threadIdx.x; t < 512; t += 256)
        ins[t >> 6][t & 63] = in[(size_t)(s0 + (t >> 6)) * 64 + (t & 63)];
    __syncthreads();

    const float bv = bias[n];
    float acc[8];
#pragma unroll
    for (int g = 0; g < 8; g++) acc[g] = bv;

#pragma unroll
    for (int c = 0; c < 64; c++) {
        const float w = W[(size_t)c * 4096 + n];
#pragma unroll
        for (int g = 0; g < 8; g++) acc[g] += ins[g][c] * w;
    }
#pragma unroll
    for (int g = 0; g < 8; g++)
        out[(size_t)(s0 + g) * 4096 + n] = acc[g];
}

// ---------------------------------------------------------------------------
// Kernel 3: per-token attention. One block per token s.
//   logits[i,j] = sum_h q[s,h,i] * k[s,j,h]
//   attn = log_softmax(logits, axis=j) * keep(mask_u)
//   out[i,j]    = sum_m attn[i,m] * v[s,j,m]   -> g_attn[s, i*64+j]
// Thread layout: 256 threads = 64 rows (i) x 4 lanes (seg).
// Each thread owns j/m set {seg + 4*t} (bank-conflict-free both phases).
// ---------------------------------------------------------------------------
__global__ __launch_bounds__(256) void attn_kernel(const float* __restrict__ mask_u)
{
    __shared__ float sm1[4096];       // holds q (logits phase), then v (PV phase)
    __shared__ float ksm[64 * 65];    // k, padded stride 65

    const int s = blockIdx.x;
    const int tid = threadIdx.x;
    const float* qrow = g_q + (size_t)s * 4096;
    const float* krow = g_k + (size_t)s * 4096;
    const float* vrow = g_v + (size_t)s * 4096;

    // load q (vectorized) and k (padded scatter)
    for (int t = tid; t < 1024; t += 256)
        reinterpret_cast<float4*>(sm1)[t] = reinterpret_cast<const float4*>(qrow)[t];
    for (int t = tid; t < 4096; t += 256)
        ksm[(t >> 6) * 65 + (t & 63)] = krow[t];
    __syncthreads();

    const int i = tid >> 2;      // row 0..63
    const int seg = tid & 3;     // lane-within-row group

    // ---- logits ----
    float lg[16];
#pragma unroll
    for (int jj = 0; jj < 16; jj++) lg[jj] = 0.0f;
#pragma unroll
    for (int h = 0; h < 64; h++) {
        const float qv = sm1[h * 64 + i];           // broadcast across seg
#pragma unroll
        for (int jj = 0; jj < 16; jj++) {
            const int j = seg + jj * 4;
            lg[jj] += qv * ksm[j * 65 + h];         // lanes differ by 1..3 banks
        }
    }

    // ---- log-softmax over row (64 values across 4 lanes) ----
    float mx = lg[0];
#pragma unroll
    for (int jj = 1; jj < 16; jj++) mx = fmaxf(mx, lg[jj]);
    mx = fmaxf(mx, __shfl_xor_sync(0xffffffffu, mx, 1));
    mx = fmaxf(mx, __shfl_xor_sync(0xffffffffu, mx, 2));
    float se = 0.0f;
#pragma unroll
    for (int jj = 0; jj < 16; jj++) se += expf(lg[jj] - mx);
    se += __shfl_xor_sync(0xffffffffu, se, 1);
    se += __shfl_xor_sync(0xffffffffu, se, 2);
    const float lse = mx + logf(se);

    // ---- dropout mask scale ----
    const float* mrow = mask_u + ((size_t)s * 64 + i) * 64;
    float at[16];
#pragma unroll
    for (int jj = 0; jj < 16; jj++) {
        const int j = seg + jj * 4;
        const float keep = (mrow[j] > 0.25f) ? (1.0f / 0.75f) : 0.0f;
        at[jj] = (lg[jj] - lse) * keep;
    }

    // ---- load v over q's smem ----
    __syncthreads();
    for (int t = tid; t < 1024; t += 256)
        reinterpret_cast<float4*>(sm1)[t] = reinterpret_cast<const float4*>(vrow)[t];
    __syncthreads();

    // ---- out[i,j] = sum_m at[i,m] * v[j,m]; partial over this lane's m set ----
    float acc[64];
#pragma unroll
    for (int j = 0; j < 64; j++) acc[j] = 0.0f;
#pragma unroll
    for (int mm = 0; mm < 16; mm++) {
        const float a = at[mm];
        const int m = seg + mm * 4;
#pragma unroll
        for (int j = 0; j < 64; j++)
            acc[j] += a * sm1[j * 64 + m];          // lanes differ by 1..3 banks
    }
    // reduce across the 4 lanes of this row
#pragma unroll
    for (int j = 0; j < 64; j++) {
        acc[j] += __shfl_xor_sync(0xffffffffu, acc[j], 1);
        acc[j] += __shfl_xor_sync(0xffffffffu, acc[j], 2);
    }
    // each lane writes a contiguous 16-column chunk
    float* orow = g_attn + (size_t)s * 4096 + i * 64;
#pragma unroll
    for (int jj = 0; jj < 16; jj++)
        orow[seg * 16 + jj] = acc[seg * 16 + jj];
}

// ---------------------------------------------------------------------------
// Kernel 4: final GEMM  out(S,64) = g_attn(S,4096) @ Wo(4096,64) + bo.
// 64x64 tile per block, TK=16, 256 threads, 4x4 per thread.
// ---------------------------------------------------------------------------
__global__ __launch_bounds__(256) void gemm_out(
    const float* __restrict__ A, const float* __restrict__ W,
    const float* __restrict__ bias, float* __restrict__ C)
{
    __shared__ float As[16][64];
    __shared__ float Bs[16][64];

    const int tid = threadIdx.x;
    const int bm = blockIdx.x * 64;
    const int tr = tid >> 4;    // 0..15
    const int tc = tid & 15;    // 0..15

    float acc[4][4];
#pragma unroll
    for (int i = 0; i < 4; i++)
#pragma unroll
        for (int j = 0; j < 4; j++) acc[i][j] = 0.0f;

    const int am = tid >> 2;          // 0..63
    const int ak = (tid & 3) * 4;     // 0..12
    const int bk = tid >> 4;          // 0..15
    const int bn4 = (tid & 15) * 4;   // 0..60

    for (int k0 = 0; k0 < 4096; k0 += 16) {
        float4 av = *reinterpret_cast<const float4*>(&A[(size_t)(bm + am) * 4096 + k0 + ak]);
        As[ak + 0][am] = av.x;
        As[ak + 1][am] = av.y;
        As[ak + 2][am] = av.z;
        As[ak + 3][am] = av.w;
        float4 bv = *reinterpret_cast<const float4*>(&W[(size_t)(k0 + bk) * 64 + bn4]);
        *reinterpret_cast<float4*>(&Bs[bk][bn4]) = bv;
        __syncthreads();

#pragma unroll
        for (int k = 0; k < 16; k++) {
            float a[4], b[4];
            *reinterpret_cast<float4*>(a) = *reinterpret_cast<float4*>(&As[k][tr * 4]);
            *reinterpret_cast<float4*>(b) = *reinterpret_cast<float4*>(&Bs[k][tc * 4]);
#pragma unroll
            for (int i = 0; i < 4; i++)
#pragma unroll
                for (int j = 0; j < 4; j++) acc[i][j] += a[i] * b[j];
        }
        __syncthreads();
    }

#pragma unroll
    for (int i = 0; i < 4; i++) {
        float* crow = C + (size_t)(bm + tr * 4 + i) * 64 + tc * 4;
#pragma unroll
        for (int j = 0; j < 4; j++)
            crow[j] = acc[i][j] + bias[tc * 4 + j];
    }
}

// ---------------------------------------------------------------------------
// Launch
// ---------------------------------------------------------------------------
extern "C" void kernel_launch(void* const* d_in, const int* in_sizes, int n_in,
                              void* d_out, int out_size)
{
    const float* query  = (const float*)d_in[0];
    const float* key_in = (const float*)d_in[1];
    const float* value  = (const float*)d_in[2];
    const float* mask_u = (const float*)d_in[3];
    const float* Wq = (const float*)d_in[4];
    const float* bq = (const float*)d_in[5];
    const float* Wk = (const float*)d_in[6];
    const float* bk = (const float*)d_in[7];
    const float* Wv = (const float*)d_in[8];
    const float* bv = (const float*)d_in[9];
    const float* Wo = (const float*)d_in[10];
    const float* bo = (const float*)d_in[11];
    float* out = (float*)d_out;

    float *gq, *gk, *gv, *ga;
    cudaGetSymbolAddress((void**)&gq, g_q);
    cudaGetSymbolAddress((void**)&gk, g_k);
    cudaGetSymbolAddress((void**)&gv, g_v);
    cudaGetSymbolAddress((void**)&ga, g_attn);

    // 1) q = query @ Wq + bq          (8192x4096) @ (4096x4096)
    sgemm128<<<dim3(D4096 / 128, S_LEN / 128), 256>>>(query, Wq, bq, gq,
                                                      S_LEN, D4096, D4096);
    // 2) k, v projections             (8192x64) @ (64x4096)
    proj_small<<<dim3(D4096 / 256, S_LEN / 8), 256>>>(key_in, Wk, bk, gk);
    proj_small<<<dim3(D4096 / 256, S_LEN / 8), 256>>>(value, Wv, bv, gv);
    // 3) per-token attention
    attn_kernel<<<S_LEN, 256>>>(mask_u);
    // 4) out = attn @ Wo + bo         (8192x4096) @ (4096x64)
    gemm_out<<<S_LEN / 64, 256>>>(ga, Wo, bo, out);
}

// round 4
// speedup vs baseline: 1.8723x; 1.8723x over previous
#include <cuda_runtime.h>
#include <cuda_bf16.h>
#include <cstdint>

// ---------------------------------------------------------------------------
// Fixed shapes: B=1, S=8192, QC=4096, H=64, KC=64, OC=64, H*KC=4096
// ---------------------------------------------------------------------------
#define S_LEN 8192
#define D4096 4096

// Scratch (__device__ globals: allocation-guard-safe)
__device__ float g_q[(size_t)S_LEN * D4096];
__device__ float g_k[(size_t)S_LEN * D4096];
__device__ float g_v[(size_t)S_LEN * D4096];
__device__ float g_attn[(size_t)S_LEN * D4096];
__device__ __nv_bfloat16 g_Ah[(size_t)S_LEN * D4096];   // query hi
__device__ __nv_bfloat16 g_Al[(size_t)S_LEN * D4096];   // query lo
__device__ __nv_bfloat16 g_Bh[(size_t)D4096 * D4096];   // Wq^T hi  [n][k]
__device__ __nv_bfloat16 g_Bl[(size_t)D4096 * D4096];   // Wq^T lo  [n][k]

__device__ __forceinline__ uint32_t smem_u32(const void* p) {
    uint32_t a;
    asm("{ .reg .u64 t; cvta.to.shared.u64 t, %1; cvt.u32.u64 %0, t; }"
        : "=r"(a) : "l"(p));
    return a;
}

#define CP_ASYNC16(saddr, gptr) \
    asm volatile("cp.async.cg.shared.global [%0], [%1], 16;" \
                 :: "r"(saddr), "l"(gptr) : "memory")
#define CP_COMMIT() asm volatile("cp.async.commit_group;" ::: "memory")
#define CP_WAIT(n)  asm volatile("cp.async.wait_group %0;" :: "n"(n) : "memory")

#define LDSM_X4(r0, r1, r2, r3, addr) \
    asm volatile("ldmatrix.sync.aligned.m8n8.x4.shared.b16 {%0,%1,%2,%3}, [%4];" \
                 : "=r"(r0), "=r"(r1), "=r"(r2), "=r"(r3) : "r"(addr))

#define MMA_BF16(c, a, b0, b1) \
    asm volatile( \
        "mma.sync.aligned.m16n8k16.row.col.f32.bf16.bf16.f32 " \
        "{%0,%1,%2,%3}, {%4,%5,%6,%7}, {%8,%9}, {%0,%1,%2,%3};" \
        : "+f"((c)[0]), "+f"((c)[1]), "+f"((c)[2]), "+f"((c)[3]) \
        : "r"((a)[0]), "r"((a)[1]), "r"((a)[2]), "r"((a)[3]), "r"(b0), "r"(b1))

// ---------------------------------------------------------------------------
// Kernel A: fp32 -> (bf16 hi, bf16 lo), 8 elems per thread
// ---------------------------------------------------------------------------
__global__ __launch_bounds__(256) void convert_split(
    const float* __restrict__ in, __nv_bfloat16* __restrict__ hi,
    __nv_bfloat16* __restrict__ lo)
{
    const size_t base = ((size_t)blockIdx.x * 256 + threadIdx.x) * 8;
    float4 a = *reinterpret_cast<const float4*>(in + base);
    float4 b = *reinterpret_cast<const float4*>(in + base + 4);
    float f[8] = {a.x, a.y, a.z, a.w, b.x, b.y, b.z, b.w};
    __nv_bfloat16 h[8], l[8];
#pragma unroll
    for (int i = 0; i < 8; i++) {
        h[i] = __float2bfloat16(f[i]);
        l[i] = __float2bfloat16(f[i] - __bfloat162float(h[i]));
    }
    *reinterpret_cast<uint4*>(hi + base) = *reinterpret_cast<uint4*>(h);
    *reinterpret_cast<uint4*>(lo + base) = *reinterpret_cast<uint4*>(l);
}

// ---------------------------------------------------------------------------
// Kernel B: Wq (K,N) fp32 -> Wq^T (N,K) bf16 hi/lo.  64x64 tiles.
// ---------------------------------------------------------------------------
__global__ __launch_bounds__(256) void transpose_split(
    const float* __restrict__ W, __nv_bfloat16* __restrict__ hi,
    __nv_bfloat16* __restrict__ lo)
{
    __shared__ float ts[64][65];
    const int n0 = blockIdx.x * 64;
    const int k0 = blockIdx.y * 64;
    const int tid = threadIdx.x;
#pragma unroll
    for (int i = 0; i < 16; i++) {
        int idx = tid + i * 256;
        int r = idx >> 6, c = idx & 63;
        ts[r][c] = W[(size_t)(k0 + r) * D4096 + n0 + c];
    }
    __syncthreads();
#pragma unroll
    for (int i = 0; i < 8; i++) {
        int idx = tid + i * 256;
        int nl = idx >> 5, kl = (idx & 31) * 2;
        float f0 = ts[kl][nl], f1 = ts[kl + 1][nl];
        __nv_bfloat162 ph, pl;
        ph.x = __float2bfloat16(f0);
        ph.y = __float2bfloat16(f1);
        pl.x = __float2bfloat16(f0 - __bfloat162float(ph.x));
        pl.y = __float2bfloat16(f1 - __bfloat162float(ph.y));
        size_t o = (size_t)(n0 + nl) * D4096 + k0 + kl;
        *reinterpret_cast<__nv_bfloat162*>(hi + o) = ph;
        *reinterpret_cast<__nv_bfloat162*>(lo + o) = pl;
    }
}

// ---------------------------------------------------------------------------
// Kernel C: HMMA GEMM  C(8192,4096) = A @ B^T + bias (bf16 split, 3 products)
// CTA tile 128x128, K-chunk 32, double-buffered cp.async.
// 8 warps = 4(m) x 2(n); warp tile 32x64; m16n8k16 fragments via ldmatrix.
// SMEM per buffer: Ah, Al, Bh, Bl tiles, each 128 rows x 40 halves (80 B/row).
// ---------------------------------------------------------------------------
#define SA_BYTES 80          // padded row stride (40 halves)
#define TILE_B   10240       // 128 * 80
#define BUF_B    40960       // 4 tiles
#define GQ_SMEM  81920       // 2 buffers

__global__ __launch_bounds__(256) void mma_gemm_q(
    const __nv_bfloat16* __restrict__ Ah, const __nv_bfloat16* __restrict__ Al,
    const __nv_bfloat16* __restrict__ Bh, const __nv_bfloat16* __restrict__ Bl,
    const float* __restrict__ bias, float* __restrict__ C)
{
    extern __shared__ char smem[];
    const uint32_t sb = smem_u32(smem);
    const int tid = threadIdx.x;
    const int warp = tid >> 5, lane = tid & 31;
    const int m0 = blockIdx.y * 128;
    const int n0 = blockIdx.x * 128;
    const int wm = (warp & 3) * 32;   // warp m offset in CTA tile
    const int wn = (warp >> 2) * 64;  // warp n offset in CTA tile

    float c[2][8][4];
#pragma unroll
    for (int mt = 0; mt < 2; mt++)
#pragma unroll
        for (int nt = 0; nt < 8; nt++)
#pragma unroll
            for (int r = 0; r < 4; r++) c[mt][nt][r] = 0.0f;

    // staging mapping: idx in [0,512) per tile: row = idx>>2, kv = idx&3
    const int srow = tid >> 2;        // rows tid/4, +64
    const int skv = (tid & 3) * 16;   // 16B unit within 64B of k-chunk

    // ldmatrix per-lane address offsets (bytes within a tile)
    const int g = lane >> 3, r8 = lane & 7;
    // A: matrices (m0,k0),(m8,k0),(m0,k8),(m8,k8)
    const uint32_t a_off = (uint32_t)(wm + (g & 1) * 8 + r8) * SA_BYTES + (g >> 1) * 16;
    // B: matrices (n0,k0),(n0,k8),(n8,k0),(n8,k8)
    const uint32_t b_off = (uint32_t)(wn + (g >> 1) * 8 + r8) * SA_BYTES + (g & 1) * 16;

    auto stage = [&](int chunk, int buf) {
        const int k0 = chunk * 32;
        const uint32_t sbase = sb + buf * BUF_B;
#pragma unroll
        for (int i = 0; i < 2; i++) {
            const int row = srow + i * 64;
            const uint32_t sa = sbase + (uint32_t)row * SA_BYTES + skv;
            const size_t ga = (size_t)(m0 + row) * D4096 + k0 + skv / 2;
            const size_t gb = (size_t)(n0 + row) * D4096 + k0 + skv / 2;
            CP_ASYNC16(sa, Ah + ga);
            CP_ASYNC16(sa + TILE_B, Al + ga);
            CP_ASYNC16(sa + 2 * TILE_B, Bh + gb);
            CP_ASYNC16(sa + 3 * TILE_B, Bl + gb);
        }
        CP_COMMIT();
    };

    stage(0, 0);

    const int NIT = D4096 / 32;  // 128
    for (int it = 0; it < NIT; ++it) {
        if (it + 1 < NIT) {
            stage(it + 1, (it + 1) & 1);
            CP_WAIT(1);
        } else {
            CP_WAIT(0);
        }
        __syncthreads();

        const uint32_t buf = sb + (it & 1) * BUF_B;
#pragma unroll
        for (int ks = 0; ks < 2; ++ks) {
            const uint32_t koff = ks * 32;  // 16 halves = 32 bytes
            uint32_t ah[2][4], al[2][4];
#pragma unroll
            for (int mt = 0; mt < 2; mt++) {
                const uint32_t aa = buf + a_off + koff + (uint32_t)mt * 16 * SA_BYTES;
                LDSM_X4(ah[mt][0], ah[mt][1], ah[mt][2], ah[mt][3], aa);
                LDSM_X4(al[mt][0], al[mt][1], al[mt][2], al[mt][3], aa + TILE_B);
            }
            uint32_t bh[4][4], bl[4][4];
#pragma unroll
            for (int g4 = 0; g4 < 4; g4++) {
                const uint32_t ba = buf + 2 * TILE_B + b_off + koff +
                                    (uint32_t)g4 * 16 * SA_BYTES;
                LDSM_X4(bh[g4][0], bh[g4][1], bh[g4][2], bh[g4][3], ba);
                LDSM_X4(bl[g4][0], bl[g4][1], bl[g4][2], bl[g4][3], ba + TILE_B);
            }
#pragma unroll
            for (int mt = 0; mt < 2; mt++) {
#pragma unroll
                for (int nt = 0; nt < 8; nt++) {
                    const int q = nt >> 1, h = (nt & 1) * 2;
                    MMA_BF16(c[mt][nt], ah[mt], bh[q][h], bh[q][h + 1]);
                    MMA_BF16(c[mt][nt], ah[mt], bl[q][h], bl[q][h + 1]);
                    MMA_BF16(c[mt][nt], al[mt], bh[q][h], bh[q][h + 1]);
                }
            }
        }
        __syncthreads();
    }

    // epilogue: d0,d1 -> (row, col..col+1), d2,d3 -> (row+8, ...)
    const int rbase = m0 + wm + (lane >> 2);
    const int cbase = n0 + wn + (lane & 3) * 2;
#pragma unroll
    for (int mt = 0; mt < 2; mt++) {
#pragma unroll
        for (int nt = 0; nt < 8; nt++) {
            const int col = cbase + nt * 8;
            const float b0 = bias[col], b1 = bias[col + 1];
            float* p0 = C + (size_t)(rbase + mt * 16) * D4096 + col;
            float* p1 = C + (size_t)(rbase + mt * 16 + 8) * D4096 + col;
            p0[0] = c[mt][nt][0] + b0;
            p0[1] = c[mt][nt][1] + b1;
            p1[0] = c[mt][nt][2] + b0;
            p1[1] = c[mt][nt][3] + b1;
        }
    }
}

// ---------------------------------------------------------------------------
// Kernel 2: small projection  out(S,4096) = in(S,64) @ W(64,4096) + bias.
// ---------------------------------------------------------------------------
__global__ __launch_bounds__(256) void proj_small(
    const float* __restrict__ in, const float* __restrict__ W,
    const float* __restrict__ bias, float* __restrict__ out)
{
    __shared__ float ins[8][64];
    const int n = blockIdx.x * 256 + threadIdx.x;
    const int s0 = blockIdx.y * 8;

    for (int t = threadIdx.x; t < 512; t += 256)
        ins[t >> 6][t & 63] = in[(size_t)(s0 + (t >> 6)) * 64 + (t & 63)];
    __syncthreads();

    const float bv = bias[n];
    float acc[8];
#pragma unroll
    for (int g = 0; g < 8; g++) acc[g] = bv;
#pragma unroll
    for (int c = 0; c < 64; c++) {
        const float w = W[(size_t)c * 4096 + n];
#pragma unroll
        for (int g = 0; g < 8; g++) acc[g] += ins[g][c] * w;
    }
#pragma unroll
    for (int g = 0; g < 8; g++)
        out[(size_t)(s0 + g) * 4096 + n] = acc[g];
}

// ---------------------------------------------------------------------------
// Kernel 3: per-token attention (as R1/R2)
// ---------------------------------------------------------------------------
__global__ __launch_bounds__(256) void attn_kernel(const float* __restrict__ mask_u)
{
    __shared__ float sm1[4096];
    __shared__ float ksm[64 * 65];

    const int s = blockIdx.x;
    const int tid = threadIdx.x;
    const float* qrow = g_q + (size_t)s * 4096;
    const float* krow = g_k + (size_t)s * 4096;
    const float* vrow = g_v + (size_t)s * 4096;

    for (int t = tid; t < 1024; t += 256)
        reinterpret_cast<float4*>(sm1)[t] = reinterpret_cast<const float4*>(qrow)[t];
    for (int t = tid; t < 4096; t += 256)
        ksm[(t >> 6) * 65 + (t & 63)] = krow[t];
    __syncthreads();

    const int i = tid >> 2;
    const int seg = tid & 3;

    float lg[16];
#pragma unroll
    for (int jj = 0; jj < 16; jj++) lg[jj] = 0.0f;
#pragma unroll
    for (int h = 0; h < 64; h++) {
        const float qv = sm1[h * 64 + i];
#pragma unroll
        for (int jj = 0; jj < 16; jj++)
            lg[jj] += qv * ksm[(seg + jj * 4) * 65 + h];
    }

    float mx = lg[0];
#pragma unroll
    for (int jj = 1; jj < 16; jj++) mx = fmaxf(mx, lg[jj]);
    mx = fmaxf(mx, __shfl_xor_sync(0xffffffffu, mx, 1));
    mx = fmaxf(mx, __shfl_xor_sync(0xffffffffu, mx, 2));
    float se = 0.0f;
#pragma unroll
    for (int jj = 0; jj < 16; jj++) se += expf(lg[jj] - mx);
    se += __shfl_xor_sync(0xffffffffu, se, 1);
    se += __shfl_xor_sync(0xffffffffu, se, 2);
    const float lse = mx + logf(se);

    const float* mrow = mask_u + ((size_t)s * 64 + i) * 64;
    float at[16];
#pragma unroll
    for (int jj = 0; jj < 16; jj++) {
        const int j = seg + jj * 4;
        const float keep = (mrow[j] > 0.25f) ? (1.0f / 0.75f) : 0.0f;
        at[jj] = (lg[jj] - lse) * keep;
    }

    __syncthreads();
    for (int t = tid; t < 1024; t += 256)
        reinterpret_cast<float4*>(sm1)[t] = reinterpret_cast<const float4*>(vrow)[t];
    __syncthreads();

    float acc[64];
#pragma unroll
    for (int j = 0; j < 64; j++) acc[j] = 0.0f;
#pragma unroll
    for (int mm = 0; mm < 16; mm++) {
        const float a = at[mm];
        const int m = seg + mm * 4;
#pragma unroll
        for (int j = 0; j < 64; j++)
            acc[j] += a * sm1[j * 64 + m];
    }
#pragma unroll
    for (int j = 0; j < 64; j++) {
        acc[j] += __shfl_xor_sync(0xffffffffu, acc[j], 1);
        acc[j] += __shfl_xor_sync(0xffffffffu, acc[j], 2);
    }
    float* orow = g_attn + (size_t)s * 4096 + i * 64;
#pragma unroll
    for (int jj = 0; jj < 16; jj++)
        orow[seg * 16 + jj] = acc[seg * 16 + jj];
}

// ---------------------------------------------------------------------------
// Kernel 4: out(S,64) = g_attn(S,4096) @ Wo(4096,64) + bo
// ---------------------------------------------------------------------------
__global__ __launch_bounds__(256) void gemm_out(
    const float* __restrict__ A, const float* __restrict__ W,
    const float* __restrict__ bias, float* __restrict__ C)
{
    __shared__ float As[16][64];
    __shared__ float Bs[16][64];

    const int tid = threadIdx.x;
    const int bm = blockIdx.x * 64;
    const int tr = tid >> 4;
    const int tc = tid & 15;

    float acc[4][4];
#pragma unroll
    for (int i = 0; i < 4; i++)
#pragma unroll
        for (int j = 0; j < 4; j++) acc[i][j] = 0.0f;

    const int am = tid >> 2;
    const int ak = (tid & 3) * 4;
    const int bk = tid >> 4;
    const int bn4 = (tid & 15) * 4;

    for (int k0 = 0; k0 < 4096; k0 += 16) {
        float4 av = *reinterpret_cast<const float4*>(&A[(size_t)(bm + am) * 4096 + k0 + ak]);
        As[ak + 0][am] = av.x;
        As[ak + 1][am] = av.y;
        As[ak + 2][am] = av.z;
        As[ak + 3][am] = av.w;
        float4 bv = *reinterpret_cast<const float4*>(&W[(size_t)(k0 + bk) * 64 + bn4]);
        *reinterpret_cast<float4*>(&Bs[bk][bn4]) = bv;
        __syncthreads();

#pragma unroll
        for (int k = 0; k < 16; k++) {
            float a[4], b[4];
            *reinterpret_cast<float4*>(a) = *reinterpret_cast<float4*>(&As[k][tr * 4]);
            *reinterpret_cast<float4*>(b) = *reinterpret_cast<float4*>(&Bs[k][tc * 4]);
#pragma unroll
            for (int i = 0; i < 4; i++)
#pragma unroll
                for (int j = 0; j < 4; j++) acc[i][j] += a[i] * b[j];
        }
        __syncthreads();
    }

#pragma unroll
    for (int i = 0; i < 4; i++) {
        float* crow = C + (size_t)(bm + tr * 4 + i) * 64 + tc * 4;
#pragma unroll
        for (int j = 0; j < 4; j++)
            crow[j] = acc[i][j] + bias[tc * 4 + j];
    }
}

// ---------------------------------------------------------------------------
// Launch
// ---------------------------------------------------------------------------
extern "C" void kernel_launch(void* const* d_in, const int* in_sizes, int n_in,
                              void* d_out, int out_size)
{
    const float* query  = (const float*)d_in[0];
    const float* key_in = (const float*)d_in[1];
    const float* value  = (const float*)d_in[2];
    const float* mask_u = (const float*)d_in[3];
    const float* Wq = (const float*)d_in[4];
    const float* bq = (const float*)d_in[5];
    const float* Wk = (const float*)d_in[6];
    const float* bk = (const float*)d_in[7];
    const float* Wv = (const float*)d_in[8];
    const float* bv = (const float*)d_in[9];
    const float* Wo = (const float*)d_in[10];
    const float* bo = (const float*)d_in[11];
    float* out = (float*)d_out;

    float *gq, *gk, *gv, *ga;
    __nv_bfloat16 *ah, *al, *bh, *bl;
    cudaGetSymbolAddress((void**)&gq, g_q);
    cudaGetSymbolAddress((void**)&gk, g_k);
    cudaGetSymbolAddress((void**)&gv, g_v);
    cudaGetSymbolAddress((void**)&ga, g_attn);
    cudaGetSymbolAddress((void**)&ah, g_Ah);
    cudaGetSymbolAddress((void**)&al, g_Al);
    cudaGetSymbolAddress((void**)&bh, g_Bh);
    cudaGetSymbolAddress((void**)&bl, g_Bl);

    cudaFuncSetAttribute(mma_gemm_q, cudaFuncAttributeMaxDynamicSharedMemorySize, GQ_SMEM);

    // 0) split inputs to bf16 hi/lo
    convert_split<<<(S_LEN * (size_t)D4096) / (256 * 8), 256>>>(query, ah, al);
    transpose_split<<<dim3(64, 64), 256>>>(Wq, bh, bl);
    // 1) q = query @ Wq + bq  via HMMA (3-product bf16 split)
    mma_gemm_q<<<dim3(D4096 / 128, S_LEN / 128), 256, GQ_SMEM>>>(ah, al, bh, bl, bq, gq);
    // 2) k, v projections
    proj_small<<<dim3(D4096 / 256, S_LEN / 8), 256>>>(key_in, Wk, bk, gk);
    proj_small<<<dim3(D4096 / 256, S_LEN / 8), 256>>>(value, Wv, bv, gv);
    // 3) per-token attention
    attn_kernel<<<S_LEN, 256>>>(mask_u);
    // 4) out = attn @ Wo + bo
    gemm_out<<<S_LEN / 64, 256>>>(ga, Wo, bo, out);
}

// round 5
// speedup vs baseline: 1.9514x; 1.0423x over previous
#include <cuda_runtime.h>
#include <cuda_bf16.h>
#include <cstdint>

// ---------------------------------------------------------------------------
// Fixed shapes: B=1, S=8192, QC=4096, H=64, KC=64, OC=64, H*KC=4096
// ---------------------------------------------------------------------------
#define S_LEN 8192
#define D4096 4096

// Scratch (__device__ globals: allocation-guard-safe)
__device__ float g_q[(size_t)S_LEN * D4096];
__device__ float g_k[(size_t)S_LEN * D4096];
__device__ float g_v[(size_t)S_LEN * D4096];
__device__ float g_attn[(size_t)S_LEN * D4096];
__device__ __nv_bfloat16 g_Ah[(size_t)S_LEN * D4096];   // query hi
__device__ __nv_bfloat16 g_Al[(size_t)S_LEN * D4096];   // query lo
__device__ __nv_bfloat16 g_Bh[(size_t)D4096 * D4096];   // Wq^T hi  [n][k]
__device__ __nv_bfloat16 g_Bl[(size_t)D4096 * D4096];   // Wq^T lo  [n][k]

__device__ __forceinline__ uint32_t smem_u32(const void* p) {
    uint32_t a;
    asm("{ .reg .u64 t; cvta.to.shared.u64 t, %1; cvt.u32.u64 %0, t; }"
        : "=r"(a) : "l"(p));
    return a;
}

#define CP_ASYNC16(saddr, gptr) \
    asm volatile("cp.async.cg.shared.global [%0], [%1], 16;" \
                 :: "r"(saddr), "l"(gptr) : "memory")
#define CP_COMMIT() asm volatile("cp.async.commit_group;" ::: "memory")
#define CP_WAIT(n)  asm volatile("cp.async.wait_group %0;" :: "n"(n) : "memory")

#define LDSM_X4(r0, r1, r2, r3, addr) \
    asm volatile("ldmatrix.sync.aligned.m8n8.x4.shared.b16 {%0,%1,%2,%3}, [%4];" \
                 : "=r"(r0), "=r"(r1), "=r"(r2), "=r"(r3) : "r"(addr))

#define MMA_BF16(c, a, b0, b1) \
    asm volatile( \
        "mma.sync.aligned.m16n8k16.row.col.f32.bf16.bf16.f32 " \
        "{%0,%1,%2,%3}, {%4,%5,%6,%7}, {%8,%9}, {%0,%1,%2,%3};" \
        : "+f"((c)[0]), "+f"((c)[1]), "+f"((c)[2]), "+f"((c)[3]) \
        : "r"((a)[0]), "r"((a)[1]), "r"((a)[2]), "r"((a)[3]), "r"(b0), "r"(b1))

// ---------------------------------------------------------------------------
// Kernel A: fp32 -> (bf16 hi, bf16 lo), 8 elems per thread
// ---------------------------------------------------------------------------
__global__ __launch_bounds__(256) void convert_split(
    const float* __restrict__ in, __nv_bfloat16* __restrict__ hi,
    __nv_bfloat16* __restrict__ lo)
{
    const size_t base = ((size_t)blockIdx.x * 256 + threadIdx.x) * 8;
    float4 a = *reinterpret_cast<const float4*>(in + base);
    float4 b = *reinterpret_cast<const float4*>(in + base + 4);
    float f[8] = {a.x, a.y, a.z, a.w, b.x, b.y, b.z, b.w};
    __nv_bfloat16 h[8], l[8];
#pragma unroll
    for (int i = 0; i < 8; i++) {
        h[i] = __float2bfloat16(f[i]);
        l[i] = __float2bfloat16(f[i] - __bfloat162float(h[i]));
    }
    *reinterpret_cast<uint4*>(hi + base) = *reinterpret_cast<uint4*>(h);
    *reinterpret_cast<uint4*>(lo + base) = *reinterpret_cast<uint4*>(l);
}

// ---------------------------------------------------------------------------
// Kernel B: Wq (K,N) fp32 -> Wq^T (N,K) bf16 hi/lo.  64x64 tiles.
// ---------------------------------------------------------------------------
__global__ __launch_bounds__(256) void transpose_split(
    const float* __restrict__ W, __nv_bfloat16* __restrict__ hi,
    __nv_bfloat16* __restrict__ lo)
{
    __shared__ float ts[64][65];
    const int n0 = blockIdx.x * 64;
    const int k0 = blockIdx.y * 64;
    const int tid = threadIdx.x;
#pragma unroll
    for (int i = 0; i < 16; i++) {
        int idx = tid + i * 256;
        int r = idx >> 6, c = idx & 63;
        ts[r][c] = W[(size_t)(k0 + r) * D4096 + n0 + c];
    }
    __syncthreads();
#pragma unroll
    for (int i = 0; i < 8; i++) {
        int idx = tid + i * 256;
        int nl = idx >> 5, kl = (idx & 31) * 2;
        float f0 = ts[kl][nl], f1 = ts[kl + 1][nl];
        __nv_bfloat162 ph, pl;
        ph.x = __float2bfloat16(f0);
        ph.y = __float2bfloat16(f1);
        pl.x = __float2bfloat16(f0 - __bfloat162float(ph.x));
        pl.y = __float2bfloat16(f1 - __bfloat162float(ph.y));
        size_t o = (size_t)(n0 + nl) * D4096 + k0 + kl;
        *reinterpret_cast<__nv_bfloat162*>(hi + o) = ph;
        *reinterpret_cast<__nv_bfloat162*>(lo + o) = pl;
    }
}

// ---------------------------------------------------------------------------
// Kernel C: HMMA GEMM  C(8192,4096) = A @ B^T + bias (bf16 split, 3 products)
// CTA tile 128x128, K-chunk 32, 3-stage cp.async pipeline, CTA swizzle.
// ---------------------------------------------------------------------------
#define SA_BYTES 80          // padded row stride (40 halves)
#define TILE_B   10240       // 128 * 80
#define BUF_B    40960       // 4 tiles
#define GQ_SMEM  122880      // 3 buffers

__global__ __launch_bounds__(256) void mma_gemm_q(
    const __nv_bfloat16* __restrict__ Ah, const __nv_bfloat16* __restrict__ Al,
    const __nv_bfloat16* __restrict__ Bh, const __nv_bfloat16* __restrict__ Bl,
    const float* __restrict__ bias, float* __restrict__ C)
{
    extern __shared__ char smem[];
    const uint32_t sb = smem_u32(smem);
    const int tid = threadIdx.x;
    const int warp = tid >> 5, lane = tid & 31;

    // CTA swizzle: panels of 16 m-tiles x 32 n-tiles (wave ~16x9 tile block)
    const int bid = blockIdx.x;
    const int panel = bid >> 9;
    const int idx = bid & 511;
    const int m0 = (((panel << 4) | (idx & 15))) * 128;
    const int n0 = (idx >> 4) * 128;

    const int wm = (warp & 3) * 32;   // warp m offset
    const int wn = (warp >> 2) * 64;  // warp n offset

    float c[2][8][4];
#pragma unroll
    for (int mt = 0; mt < 2; mt++)
#pragma unroll
        for (int nt = 0; nt < 8; nt++)
#pragma unroll
            for (int r = 0; r < 4; r++) c[mt][nt][r] = 0.0f;

    const int srow = tid >> 2;
    const int skv = (tid & 3) * 16;

    const int g = lane >> 3, r8 = lane & 7;
    const uint32_t a_off = (uint32_t)(wm + (g & 1) * 8 + r8) * SA_BYTES + (g >> 1) * 16;
    const uint32_t b_off = (uint32_t)(wn + (g >> 1) * 8 + r8) * SA_BYTES + (g & 1) * 16;

    auto stage = [&](int chunk, int buf) {
        const int k0 = chunk * 32;
        const uint32_t sbase = sb + buf * BUF_B;
#pragma unroll
        for (int i = 0; i < 2; i++) {
            const int row = srow + i * 64;
            const uint32_t sa = sbase + (uint32_t)row * SA_BYTES + skv;
            const size_t ga = (size_t)(m0 + row) * D4096 + k0 + skv / 2;
            const size_t gb = (size_t)(n0 + row) * D4096 + k0 + skv / 2;
            CP_ASYNC16(sa, Ah + ga);
            CP_ASYNC16(sa + TILE_B, Al + ga);
            CP_ASYNC16(sa + 2 * TILE_B, Bh + gb);
            CP_ASYNC16(sa + 3 * TILE_B, Bl + gb);
        }
        CP_COMMIT();
    };

    stage(0, 0);
    stage(1, 1);

    const int NIT = D4096 / 32;  // 128
    for (int it = 0; it < NIT; ++it) {
        if (it == NIT - 1) { CP_WAIT(0); } else { CP_WAIT(1); }
        __syncthreads();

        const uint32_t buf = sb + (it % 3) * BUF_B;
#pragma unroll
        for (int ks = 0; ks < 2; ++ks) {
            const uint32_t koff = ks * 32;
            uint32_t ah[2][4], al[2][4];
#pragma unroll
            for (int mt = 0; mt < 2; mt++) {
                const uint32_t aa = buf + a_off + koff + (uint32_t)mt * 16 * SA_BYTES;
                LDSM_X4(ah[mt][0], ah[mt][1], ah[mt][2], ah[mt][3], aa);
                LDSM_X4(al[mt][0], al[mt][1], al[mt][2], al[mt][3], aa + TILE_B);
            }
            uint32_t bh[4][4], bl[4][4];
#pragma unroll
            for (int g4 = 0; g4 < 4; g4++) {
                const uint32_t ba = buf + 2 * TILE_B + b_off + koff +
                                    (uint32_t)g4 * 16 * SA_BYTES;
                LDSM_X4(bh[g4][0], bh[g4][1], bh[g4][2], bh[g4][3], ba);
                LDSM_X4(bl[g4][0], bl[g4][1], bl[g4][2], bl[g4][3], ba + TILE_B);
            }
#pragma unroll
            for (int mt = 0; mt < 2; mt++) {
#pragma unroll
                for (int nt = 0; nt < 8; nt++) {
                    const int q = nt >> 1, h = (nt & 1) * 2;
                    MMA_BF16(c[mt][nt], ah[mt], bh[q][h], bh[q][h + 1]);
                    MMA_BF16(c[mt][nt], ah[mt], bl[q][h], bl[q][h + 1]);
                    MMA_BF16(c[mt][nt], al[mt], bh[q][h], bh[q][h + 1]);
                }
            }
        }
        __syncthreads();
        if (it + 2 < NIT) stage(it + 2, (it + 2) % 3);
    }

    const int rbase = m0 + wm + (lane >> 2);
    const int cbase = n0 + wn + (lane & 3) * 2;
#pragma unroll
    for (int mt = 0; mt < 2; mt++) {
#pragma unroll
        for (int nt = 0; nt < 8; nt++) {
            const int col = cbase + nt * 8;
            const float b0 = bias[col], b1 = bias[col + 1];
            float* p0 = C + (size_t)(rbase + mt * 16) * D4096 + col;
            float* p1 = C + (size_t)(rbase + mt * 16 + 8) * D4096 + col;
            p0[0] = c[mt][nt][0] + b0;
            p0[1] = c[mt][nt][1] + b1;
            p1[0] = c[mt][nt][2] + b0;
            p1[1] = c[mt][nt][3] + b1;
        }
    }
}

// ---------------------------------------------------------------------------
// Kernel 2: small projection, 32 tokens per CTA (4x more W reuse than R4)
// ---------------------------------------------------------------------------
__global__ __launch_bounds__(256) void proj_small(
    const float* __restrict__ in, const float* __restrict__ W,
    const float* __restrict__ bias, float* __restrict__ out)
{
    __shared__ float ins[32][64];
    const int n = blockIdx.x * 256 + threadIdx.x;
    const int s0 = blockIdx.y * 32;

    for (int t = threadIdx.x; t < 2048; t += 256)
        ins[t >> 6][t & 63] = in[(size_t)(s0 + (t >> 6)) * 64 + (t & 63)];
    __syncthreads();

    const float bv = bias[n];
    float acc[32];
#pragma unroll
    for (int g = 0; g < 32; g++) acc[g] = bv;
#pragma unroll
    for (int c = 0; c < 64; c++) {
        const float w = W[(size_t)c * 4096 + n];
#pragma unroll
        for (int g = 0; g < 32; g++) acc[g] += ins[g][c] * w;
    }
#pragma unroll
    for (int g = 0; g < 32; g++)
        out[(size_t)(s0 + g) * 4096 + n] = acc[g];
}

// ---------------------------------------------------------------------------
// Kernel 3: per-token attention — register-blocked 4x4 tiles, two 64^3 GEMMs.
// 256 threads = 16(row groups) x 16(col groups); thread tile 4x4.
//   smA: q (linear 4096) then vT (vs[m*68+j])
//   smB: kT (kt[h*68+j])  then at (at[i*68+j])
// ---------------------------------------------------------------------------
__global__ __launch_bounds__(256, 4) void attn_kernel(const float* __restrict__ mask_u)
{
    __shared__ float smA[4352];
    __shared__ float smB[4352];

    const int s = blockIdx.x;
    const int tid = threadIdx.x;
    const int tr = tid >> 4;   // 0..15
    const int tc = tid & 15;   // 0..15
    const float* qrow = g_q + (size_t)s * 4096;
    const float* krow = g_k + (size_t)s * 4096;
    const float* vrow = g_v + (size_t)s * 4096;

    // stage q linear, k transposed (kt[h*68+j] = k[j][h])
    for (int t = tid; t < 1024; t += 256)
        reinterpret_cast<float4*>(smA)[t] = reinterpret_cast<const float4*>(qrow)[t];
    for (int t = tid; t < 4096; t += 256)
        smB[(t & 63) * 68 + (t >> 6)] = krow[t];
    __syncthreads();

    // logits[i][j] = sum_h q[h][i] * k[j][h];  i = tr*4+a, j = tc*4+b
    float lg[4][4];
#pragma unroll
    for (int a = 0; a < 4; a++)
#pragma unroll
        for (int b = 0; b < 4; b++) lg[a][b] = 0.0f;
#pragma unroll 8
    for (int h = 0; h < 64; h++) {
        const float4 qv = *reinterpret_cast<const float4*>(smA + h * 64 + tr * 4);
        const float4 kv = *reinterpret_cast<const float4*>(smB + h * 68 + tc * 4);
        const float qa[4] = {qv.x, qv.y, qv.z, qv.w};
        const float kb[4] = {kv.x, kv.y, kv.z, kv.w};
#pragma unroll
        for (int a = 0; a < 4; a++)
#pragma unroll
            for (int b = 0; b < 4; b++) lg[a][b] += qa[a] * kb[b];
    }

    // log-softmax over j: reduce across 16 tc lanes (within 16-lane half-warps)
    float lse[4];
#pragma unroll
    for (int a = 0; a < 4; a++) {
        float mx = fmaxf(fmaxf(lg[a][0], lg[a][1]), fmaxf(lg[a][2], lg[a][3]));
        mx = fmaxf(mx, __shfl_xor_sync(0xffffffffu, mx, 1));
        mx = fmaxf(mx, __shfl_xor_sync(0xffffffffu, mx, 2));
        mx = fmaxf(mx, __shfl_xor_sync(0xffffffffu, mx, 4));
        mx = fmaxf(mx, __shfl_xor_sync(0xffffffffu, mx, 8));
        float se = expf(lg[a][0] - mx) + expf(lg[a][1] - mx) +
                   expf(lg[a][2] - mx) + expf(lg[a][3] - mx);
        se += __shfl_xor_sync(0xffffffffu, se, 1);
        se += __shfl_xor_sync(0xffffffffu, se, 2);
        se += __shfl_xor_sync(0xffffffffu, se, 4);
        se += __shfl_xor_sync(0xffffffffu, se, 8);
        lse[a] = mx + logf(se);
    }

    // dropout-scaled at[i][j] (in place over lg)
#pragma unroll
    for (int a = 0; a < 4; a++) {
        const float4 mv = *reinterpret_cast<const float4*>(
            mask_u + ((size_t)s * 64 + tr * 4 + a) * 64 + tc * 4);
        const float mm[4] = {mv.x, mv.y, mv.z, mv.w};
#pragma unroll
        for (int b = 0; b < 4; b++) {
            const float keep = (mm[b] > 0.25f) ? (1.0f / 0.75f) : 0.0f;
            lg[a][b] = (lg[a][b] - lse[a]) * keep;
        }
    }

    __syncthreads();  // all reads of q/kt done

    // store at[i*68+j]; stage v transposed (vs[m*68+j] = v[j][m])
#pragma unroll
    for (int a = 0; a < 4; a++) {
        float4 w;
        w.x = lg[a][0]; w.y = lg[a][1]; w.z = lg[a][2]; w.w = lg[a][3];
        *reinterpret_cast<float4*>(smB + (tr * 4 + a) * 68 + tc * 4) = w;
    }
    for (int t = tid; t < 4096; t += 256)
        smA[(t & 63) * 68 + (t >> 6)] = vrow[t];
    __syncthreads();

    // out[i][j] = sum_m at[i][m] * v[j][m]
    float acc[4][4];
#pragma unroll
    for (int a = 0; a < 4; a++)
#pragma unroll
        for (int b = 0; b < 4; b++) acc[a][b] = 0.0f;
#pragma unroll 8
    for (int m = 0; m < 64; m++) {
        const float4 vv = *reinterpret_cast<const float4*>(smA + m * 68 + tc * 4);
        const float vb[4] = {vv.x, vv.y, vv.z, vv.w};
#pragma unroll
        for (int a = 0; a < 4; a++) {
            const float av = smB[(tr * 4 + a) * 68 + m];
#pragma unroll
            for (int b = 0; b < 4; b++) acc[a][b] += av * vb[b];
        }
    }

    float* orow = g_attn + (size_t)s * 4096;
#pragma unroll
    for (int a = 0; a < 4; a++) {
        float4 w;
        w.x = acc[a][0]; w.y = acc[a][1]; w.z = acc[a][2]; w.w = acc[a][3];
        *reinterpret_cast<float4*>(orow + (tr * 4 + a) * 64 + tc * 4) = w;
    }
}

// ---------------------------------------------------------------------------
// Kernel 4: out(S,64) = g_attn(S,4096) @ Wo(4096,64) + bo
// ---------------------------------------------------------------------------
__global__ __launch_bounds__(256) void gemm_out(
    const float* __restrict__ A, const float* __restrict__ W,
    const float* __restrict__ bias, float* __restrict__ C)
{
    __shared__ float As[16][64];
    __shared__ float Bs[16][64];

    const int tid = threadIdx.x;
    const int bm = blockIdx.x * 64;
    const int tr = tid >> 4;
    const int tc = tid & 15;

    float acc[4][4];
#pragma unroll
    for (int i = 0; i < 4; i++)
#pragma unroll
        for (int j = 0; j < 4; j++) acc[i][j] = 0.0f;

    const int am = tid >> 2;
    const int ak = (tid & 3) * 4;
    const int bk = tid >> 4;
    const int bn4 = (tid & 15) * 4;

    for (int k0 = 0; k0 < 4096; k0 += 16) {
        float4 av = *reinterpret_cast<const float4*>(&A[(size_t)(bm + am) * 4096 + k0 + ak]);
        As[ak + 0][am] = av.x;
        As[ak + 1][am] = av.y;
        As[ak + 2][am] = av.z;
        As[ak + 3][am] = av.w;
        float4 bv = *reinterpret_cast<const float4*>(&W[(size_t)(k0 + bk) * 64 + bn4]);
        *reinterpret_cast<float4*>(&Bs[bk][bn4]) = bv;
        __syncthreads();

#pragma unroll
        for (int k = 0; k < 16; k++) {
            float a[4], b[4];
            *reinterpret_cast<float4*>(a) = *reinterpret_cast<float4*>(&As[k][tr * 4]);
            *reinterpret_cast<float4*>(b) = *reinterpret_cast<float4*>(&Bs[k][tc * 4]);
#pragma unroll
            for (int i = 0; i < 4; i++)
#pragma unroll
                for (int j = 0; j < 4; j++) acc[i][j] += a[i] * b[j];
        }
        __syncthreads();
    }

#pragma unroll
    for (int i = 0; i < 4; i++) {
        float* crow = C + (size_t)(bm + tr * 4 + i) * 64 + tc * 4;
#pragma unroll
        for (int j = 0; j < 4; j++)
            crow[j] = acc[i][j] + bias[tc * 4 + j];
    }
}

// ---------------------------------------------------------------------------
// Launch
// ---------------------------------------------------------------------------
extern "C" void kernel_launch(void* const* d_in, const int* in_sizes, int n_in,
                              void* d_out, int out_size)
{
    const float* query  = (const float*)d_in[0];
    const float* key_in = (const float*)d_in[1];
    const float* value  = (const float*)d_in[2];
    const float* mask_u = (const float*)d_in[3];
    const float* Wq = (const float*)d_in[4];
    const float* bq = (const float*)d_in[5];
    const float* Wk = (const float*)d_in[6];
    const float* bk = (const float*)d_in[7];
    const float* Wv = (const float*)d_in[8];
    const float* bv = (const float*)d_in[9];
    const float* Wo = (const float*)d_in[10];
    const float* bo = (const float*)d_in[11];
    float* out = (float*)d_out;

    float *gq, *gk, *gv, *ga;
    __nv_bfloat16 *ah, *al, *bh, *bl;
    cudaGetSymbolAddress((void**)&gq, g_q);
    cudaGetSymbolAddress((void**)&gk, g_k);
    cudaGetSymbolAddress((void**)&gv, g_v);
    cudaGetSymbolAddress((void**)&ga, g_attn);
    cudaGetSymbolAddress((void**)&ah, g_Ah);
    cudaGetSymbolAddress((void**)&al, g_Al);
    cudaGetSymbolAddress((void**)&bh, g_Bh);
    cudaGetSymbolAddress((void**)&bl, g_Bl);

    cudaFuncSetAttribute(mma_gemm_q, cudaFuncAttributeMaxDynamicSharedMemorySize, GQ_SMEM);

    convert_split<<<(S_LEN * (size_t)D4096) / (256 * 8), 256>>>(query, ah, al);
    transpose_split<<<dim3(64, 64), 256>>>(Wq, bh, bl);
    mma_gemm_q<<<2048, 256, GQ_SMEM>>>(ah, al, bh, bl, bq, gq);
    proj_small<<<dim3(D4096 / 256, S_LEN / 32), 256>>>(key_in, Wk, bk, gk);
    proj_small<<<dim3(D4096 / 256, S_LEN / 32), 256>>>(value, Wv, bv, gv);
    attn_kernel<<<S_LEN, 256>>>(mask_u);
    gemm_out<<<S_LEN / 64, 256>>>(ga, Wo, bo, out);
}

// round 6
// speedup vs baseline: 2.3170x; 1.1873x over previous
#include <cuda_runtime.h>
#include <cuda_bf16.h>
#include <cstdint>

#define S_LEN 8192
#define D4096 4096

__device__ float g_q[(size_t)S_LEN * D4096];
__device__ float g_k[(size_t)S_LEN * D4096];
__device__ float g_v[(size_t)S_LEN * D4096];
__device__ float g_attn[(size_t)S_LEN * D4096];
__device__ __nv_bfloat16 g_Ah[(size_t)S_LEN * D4096];   // query hi; reused as fp32 split-K scratch later
__device__ __nv_bfloat16 g_Al[(size_t)S_LEN * D4096];
__device__ __nv_bfloat16 g_Bh[(size_t)D4096 * D4096];
__device__ __nv_bfloat16 g_Bl[(size_t)D4096 * D4096];

__device__ __forceinline__ uint32_t smem_u32(const void* p) {
    uint32_t a;
    asm("{ .reg .u64 t; cvta.to.shared.u64 t, %1; cvt.u32.u64 %0, t; }"
        : "=r"(a) : "l"(p));
    return a;
}

#define CP_ASYNC16(saddr, gptr) \
    asm volatile("cp.async.cg.shared.global [%0], [%1], 16;" \
                 :: "r"(saddr), "l"(gptr) : "memory")
#define CP_COMMIT() asm volatile("cp.async.commit_group;" ::: "memory")
#define CP_WAIT(n)  asm volatile("cp.async.wait_group %0;" :: "n"(n) : "memory")

#define LDSM_X4(r0, r1, r2, r3, addr) \
    asm volatile("ldmatrix.sync.aligned.m8n8.x4.shared.b16 {%0,%1,%2,%3}, [%4];" \
                 : "=r"(r0), "=r"(r1), "=r"(r2), "=r"(r3) : "r"(addr))

#define MMA_BF16(c, a, b0, b1) \
    asm volatile( \
        "mma.sync.aligned.m16n8k16.row.col.f32.bf16.bf16.f32 " \
        "{%0,%1,%2,%3}, {%4,%5,%6,%7}, {%8,%9}, {%0,%1,%2,%3};" \
        : "+f"((c)[0]), "+f"((c)[1]), "+f"((c)[2]), "+f"((c)[3]) \
        : "r"((a)[0]), "r"((a)[1]), "r"((a)[2]), "r"((a)[3]), "r"(b0), "r"(b1))

// ---------------------------------------------------------------------------
// fp32 -> bf16 hi/lo split
// ---------------------------------------------------------------------------
__global__ __launch_bounds__(256) void convert_split(
    const float* __restrict__ in, __nv_bfloat16* __restrict__ hi,
    __nv_bfloat16* __restrict__ lo)
{
    const size_t base = ((size_t)blockIdx.x * 256 + threadIdx.x) * 8;
    float4 a = *reinterpret_cast<const float4*>(in + base);
    float4 b = *reinterpret_cast<const float4*>(in + base + 4);
    float f[8] = {a.x, a.y, a.z, a.w, b.x, b.y, b.z, b.w};
    __nv_bfloat16 h[8], l[8];
#pragma unroll
    for (int i = 0; i < 8; i++) {
        h[i] = __float2bfloat16(f[i]);
        l[i] = __float2bfloat16(f[i] - __bfloat162float(h[i]));
    }
    *reinterpret_cast<uint4*>(hi + base) = *reinterpret_cast<uint4*>(h);
    *reinterpret_cast<uint4*>(lo + base) = *reinterpret_cast<uint4*>(l);
}

// ---------------------------------------------------------------------------
// Wq (K,N) fp32 -> Wq^T (N,K) bf16 hi/lo
// ---------------------------------------------------------------------------
__global__ __launch_bounds__(256) void transpose_split(
    const float* __restrict__ W, __nv_bfloat16* __restrict__ hi,
    __nv_bfloat16* __restrict__ lo)
{
    __shared__ float ts[64][65];
    const int n0 = blockIdx.x * 64;
    const int k0 = blockIdx.y * 64;
    const int tid = threadIdx.x;
#pragma unroll
    for (int i = 0; i < 16; i++) {
        int idx = tid + i * 256;
        int r = idx >> 6, c = idx & 63;
        ts[r][c] = W[(size_t)(k0 + r) * D4096 + n0 + c];
    }
    __syncthreads();
#pragma unroll
    for (int i = 0; i < 8; i++) {
        int idx = tid + i * 256;
        int nl = idx >> 5, kl = (idx & 31) * 2;
        float f0 = ts[kl][nl], f1 = ts[kl + 1][nl];
        __nv_bfloat162 ph, pl;
        ph.x = __float2bfloat16(f0);
        ph.y = __float2bfloat16(f1);
        pl.x = __float2bfloat16(f0 - __bfloat162float(ph.x));
        pl.y = __float2bfloat16(f1 - __bfloat162float(ph.y));
        size_t o = (size_t)(n0 + nl) * D4096 + k0 + kl;
        *reinterpret_cast<__nv_bfloat162*>(hi + o) = ph;
        *reinterpret_cast<__nv_bfloat162*>(lo + o) = pl;
    }
}

// ---------------------------------------------------------------------------
// HMMA GEMM: 512 threads, 16 warps (4m x 4n), warp tile 32x32, CTA 128x128,
// K-chunk 32, 3-stage cp.async, early-stage placement, single barrier/iter.
// ---------------------------------------------------------------------------
#define SA_BYTES 80
#define TILE_B   10240
#define BUF_B    40960
#define GQ_SMEM  122880

__global__ __launch_bounds__(512) void mma_gemm_q(
    const __nv_bfloat16* __restrict__ Ah, const __nv_bfloat16* __restrict__ Al,
    const __nv_bfloat16* __restrict__ Bh, const __nv_bfloat16* __restrict__ Bl,
    const float* __restrict__ bias, float* __restrict__ C)
{
    extern __shared__ char smem[];
    const uint32_t sb = smem_u32(smem);
    const int tid = threadIdx.x;
    const int warp = tid >> 5, lane = tid & 31;

    // CTA swizzle: panels of 16 m-tiles x 32 n-tiles
    const int bid = blockIdx.x;
    const int panel = bid >> 9;
    const int idx = bid & 511;
    const int m0 = (((panel << 4) | (idx & 15))) * 128;
    const int n0 = (idx >> 4) * 128;

    const int wm = (warp & 3) * 32;
    const int wn = (warp >> 2) * 32;

    float c[2][4][4];
#pragma unroll
    for (int mt = 0; mt < 2; mt++)
#pragma unroll
        for (int nt = 0; nt < 4; nt++)
#pragma unroll
            for (int r = 0; r < 4; r++) c[mt][nt][r] = 0.0f;

    const int srow = tid >> 2;        // 0..127
    const int skv = (tid & 3) * 16;

    const int g = lane >> 3, r8 = lane & 7;
    const uint32_t a_off = (uint32_t)(wm + (g & 1) * 8 + r8) * SA_BYTES + (g >> 1) * 16;
    const uint32_t b_off = (uint32_t)(wn + (g >> 1) * 8 + r8) * SA_BYTES + (g & 1) * 16;

    auto stage = [&](int chunk, int buf) {
        const int k0 = chunk * 32;
        const uint32_t sa = sb + buf * BUF_B + (uint32_t)srow * SA_BYTES + skv;
        const size_t ga = (size_t)(m0 + srow) * D4096 + k0 + skv / 2;
        const size_t gb = (size_t)(n0 + srow) * D4096 + k0 + skv / 2;
        CP_ASYNC16(sa, Ah + ga);
        CP_ASYNC16(sa + TILE_B, Al + ga);
        CP_ASYNC16(sa + 2 * TILE_B, Bh + gb);
        CP_ASYNC16(sa + 3 * TILE_B, Bl + gb);
        CP_COMMIT();
    };

    stage(0, 0);
    stage(1, 1);

    const int NIT = D4096 / 32;  // 128
    for (int it = 0; it < NIT; ++it) {
        if (it == NIT - 1) { CP_WAIT(0); } else { CP_WAIT(1); }
        __syncthreads();
        if (it + 2 < NIT) stage(it + 2, (it + 2) % 3);

        const uint32_t buf = sb + (it % 3) * BUF_B;
#pragma unroll
        for (int ks = 0; ks < 2; ++ks) {
            const uint32_t koff = ks * 32;
            uint32_t ah[2][4], al[2][4];
#pragma unroll
            for (int mt = 0; mt < 2; mt++) {
                const uint32_t aa = buf + a_off + koff + (uint32_t)mt * 16 * SA_BYTES;
                LDSM_X4(ah[mt][0], ah[mt][1], ah[mt][2], ah[mt][3], aa);
                LDSM_X4(al[mt][0], al[mt][1], al[mt][2], al[mt][3], aa + TILE_B);
            }
            uint32_t bh[2][4], bl[2][4];
#pragma unroll
            for (int g4 = 0; g4 < 2; g4++) {
                const uint32_t ba = buf + 2 * TILE_B + b_off + koff +
                                    (uint32_t)g4 * 16 * SA_BYTES;
                LDSM_X4(bh[g4][0], bh[g4][1], bh[g4][2], bh[g4][3], ba);
                LDSM_X4(bl[g4][0], bl[g4][1], bl[g4][2], bl[g4][3], ba + TILE_B);
            }
#pragma unroll
            for (int mt = 0; mt < 2; mt++) {
#pragma unroll
                for (int nt = 0; nt < 4; nt++) {
                    const int q = nt >> 1, h = (nt & 1) * 2;
                    MMA_BF16(c[mt][nt], ah[mt], bh[q][h], bh[q][h + 1]);
                    MMA_BF16(c[mt][nt], ah[mt], bl[q][h], bl[q][h + 1]);
                    MMA_BF16(c[mt][nt], al[mt], bh[q][h], bh[q][h + 1]);
                }
            }
        }
        // no trailing barrier: 3-buffer rotation + top barrier order reuse
    }

    const int rbase = m0 + wm + (lane >> 2);
    const int cbase = n0 + wn + (lane & 3) * 2;
#pragma unroll
    for (int mt = 0; mt < 2; mt++) {
#pragma unroll
        for (int nt = 0; nt < 4; nt++) {
            const int col = cbase + nt * 8;
            const float b0 = bias[col], b1 = bias[col + 1];
            float* p0 = C + (size_t)(rbase + mt * 16) * D4096 + col;
            float* p1 = C + (size_t)(rbase + mt * 16 + 8) * D4096 + col;
            p0[0] = c[mt][nt][0] + b0;
            p0[1] = c[mt][nt][1] + b1;
            p1[0] = c[mt][nt][2] + b0;
            p1[1] = c[mt][nt][3] + b1;
        }
    }
}

// ---------------------------------------------------------------------------
// small projection: 16 tokens per CTA
// ---------------------------------------------------------------------------
__global__ __launch_bounds__(256) void proj_small(
    const float* __restrict__ in, const float* __restrict__ W,
    const float* __restrict__ bias, float* __restrict__ out)
{
    __shared__ float ins[16][64];
    const int n = blockIdx.x * 256 + threadIdx.x;
    const int s0 = blockIdx.y * 16;

    for (int t = threadIdx.x; t < 1024; t += 256)
        ins[t >> 6][t & 63] = in[(size_t)(s0 + (t >> 6)) * 64 + (t & 63)];
    __syncthreads();

    const float bv = bias[n];
    float acc[16];
#pragma unroll
    for (int g = 0; g < 16; g++) acc[g] = bv;
#pragma unroll
    for (int c = 0; c < 64; c++) {
        const float w = W[(size_t)c * 4096 + n];
#pragma unroll
        for (int g = 0; g < 16; g++) acc[g] += ins[g][c] * w;
    }
#pragma unroll
    for (int g = 0; g < 16; g++)
        out[(size_t)(s0 + g) * 4096 + n] = acc[g];
}

// ---------------------------------------------------------------------------
// per-token attention (register-blocked 4x4, as R5)
// ---------------------------------------------------------------------------
__global__ __launch_bounds__(256, 4) void attn_kernel(const float* __restrict__ mask_u)
{
    __shared__ float smA[4352];
    __shared__ float smB[4352];

    const int s = blockIdx.x;
    const int tid = threadIdx.x;
    const int tr = tid >> 4;
    const int tc = tid & 15;
    const float* qrow = g_q + (size_t)s * 4096;
    const float* krow = g_k + (size_t)s * 4096;
    const float* vrow = g_v + (size_t)s * 4096;

    for (int t = tid; t < 1024; t += 256)
        reinterpret_cast<float4*>(smA)[t] = reinterpret_cast<const float4*>(qrow)[t];
    for (int t = tid; t < 4096; t += 256)
        smB[(t & 63) * 68 + (t >> 6)] = krow[t];
    __syncthreads();

    float lg[4][4];
#pragma unroll
    for (int a = 0; a < 4; a++)
#pragma unroll
        for (int b = 0; b < 4; b++) lg[a][b] = 0.0f;
#pragma unroll 8
    for (int h = 0; h < 64; h++) {
        const float4 qv = *reinterpret_cast<const float4*>(smA + h * 64 + tr * 4);
        const float4 kv = *reinterpret_cast<const float4*>(smB + h * 68 + tc * 4);
        const float qa[4] = {qv.x, qv.y, qv.z, qv.w};
        const float kb[4] = {kv.x, kv.y, kv.z, kv.w};
#pragma unroll
        for (int a = 0; a < 4; a++)
#pragma unroll
            for (int b = 0; b < 4; b++) lg[a][b] += qa[a] * kb[b];
    }

    float lse[4];
#pragma unroll
    for (int a = 0; a < 4; a++) {
        float mx = fmaxf(fmaxf(lg[a][0], lg[a][1]), fmaxf(lg[a][2], lg[a][3]));
        mx = fmaxf(mx, __shfl_xor_sync(0xffffffffu, mx, 1));
        mx = fmaxf(mx, __shfl_xor_sync(0xffffffffu, mx, 2));
        mx = fmaxf(mx, __shfl_xor_sync(0xffffffffu, mx, 4));
        mx = fmaxf(mx, __shfl_xor_sync(0xffffffffu, mx, 8));
        float se = expf(lg[a][0] - mx) + expf(lg[a][1] - mx) +
                   expf(lg[a][2] - mx) + expf(lg[a][3] - mx);
        se += __shfl_xor_sync(0xffffffffu, se, 1);
        se += __shfl_xor_sync(0xffffffffu, se, 2);
        se += __shfl_xor_sync(0xffffffffu, se, 4);
        se += __shfl_xor_sync(0xffffffffu, se, 8);
        lse[a] = mx + logf(se);
    }

#pragma unroll
    for (int a = 0; a < 4; a++) {
        const float4 mv = *reinterpret_cast<const float4*>(
            mask_u + ((size_t)s * 64 + tr * 4 + a) * 64 + tc * 4);
        const float mm[4] = {mv.x, mv.y, mv.z, mv.w};
#pragma unroll
        for (int b = 0; b < 4; b++) {
            const float keep = (mm[b] > 0.25f) ? (1.0f / 0.75f) : 0.0f;
            lg[a][b] = (lg[a][b] - lse[a]) * keep;
        }
    }

    __syncthreads();

#pragma unroll
    for (int a = 0; a < 4; a++) {
        float4 w;
        w.x = lg[a][0]; w.y = lg[a][1]; w.z = lg[a][2]; w.w = lg[a][3];
        *reinterpret_cast<float4*>(smB + (tr * 4 + a) * 68 + tc * 4) = w;
    }
    for (int t = tid; t < 4096; t += 256)
        smA[(t & 63) * 68 + (t >> 6)] = vrow[t];
    __syncthreads();

    float acc[4][4];
#pragma unroll
    for (int a = 0; a < 4; a++)
#pragma unroll
        for (int b = 0; b < 4; b++) acc[a][b] = 0.0f;
#pragma unroll 8
    for (int m = 0; m < 64; m++) {
        const float4 vv = *reinterpret_cast<const float4*>(smA + m * 68 + tc * 4);
        const float vb[4] = {vv.x, vv.y, vv.z, vv.w};
#pragma unroll
        for (int a = 0; a < 4; a++) {
            const float av = smB[(tr * 4 + a) * 68 + m];
#pragma unroll
            for (int b = 0; b < 4; b++) acc[a][b] += av * vb[b];
        }
    }

    float* orow = g_attn + (size_t)s * 4096;
#pragma unroll
    for (int a = 0; a < 4; a++) {
        float4 w;
        w.x = acc[a][0]; w.y = acc[a][1]; w.z = acc[a][2]; w.w = acc[a][3];
        *reinterpret_cast<float4*>(orow + (tr * 4 + a) * 64 + tc * 4) = w;
    }
}

// ---------------------------------------------------------------------------
// final GEMM, split-K=4: partials then reduce
// ---------------------------------------------------------------------------
__global__ __launch_bounds__(256) void gemm_out_part(
    const float* __restrict__ A, const float* __restrict__ W,
    float* __restrict__ part)
{
    __shared__ float As[16][64];
    __shared__ float Bs[16][64];

    const int tid = threadIdx.x;
    const int bm = blockIdx.x * 64;
    const int ks = blockIdx.y;          // 0..3
    const int tr = tid >> 4;
    const int tc = tid & 15;

    float acc[4][4];
#pragma unroll
    for (int i = 0; i < 4; i++)
#pragma unroll
        for (int j = 0; j < 4; j++) acc[i][j] = 0.0f;

    const int am = tid >> 2;
    const int ak = (tid & 3) * 4;
    const int bk = tid >> 4;
    const int bn4 = (tid & 15) * 4;

    const int kbeg = ks * 1024, kend = kbeg + 1024;
    for (int k0 = kbeg; k0 < kend; k0 += 16) {
        float4 av = *reinterpret_cast<const float4*>(&A[(size_t)(bm + am) * 4096 + k0 + ak]);
        As[ak + 0][am] = av.x;
        As[ak + 1][am] = av.y;
        As[ak + 2][am] = av.z;
        As[ak + 3][am] = av.w;
        float4 bv = *reinterpret_cast<const float4*>(&W[(size_t)(k0 + bk) * 64 + bn4]);
        *reinterpret_cast<float4*>(&Bs[bk][bn4]) = bv;
        __syncthreads();

#pragma unroll
        for (int k = 0; k < 16; k++) {
            float a[4], b[4];
            *reinterpret_cast<float4*>(a) = *reinterpret_cast<float4*>(&As[k][tr * 4]);
            *reinterpret_cast<float4*>(b) = *reinterpret_cast<float4*>(&Bs[k][tc * 4]);
#pragma unroll
            for (int i = 0; i < 4; i++)
#pragma unroll
                for (int j = 0; j < 4; j++) acc[i][j] += a[i] * b[j];
        }
        __syncthreads();
    }

    float* pbase = part + (size_t)ks * S_LEN * 64;
#pragma unroll
    for (int i = 0; i < 4; i++) {
        float* crow = pbase + (size_t)(bm + tr * 4 + i) * 64 + tc * 4;
#pragma unroll
        for (int j = 0; j < 4; j++) crow[j] = acc[i][j];
    }
}

__global__ __launch_bounds__(256) void gemm_out_reduce(
    const float* __restrict__ part, const float* __restrict__ bias,
    float* __restrict__ out)
{
    const size_t i = (size_t)blockIdx.x * 256 + threadIdx.x;
    const float b = bias[i & 63];
    out[i] = part[i] + part[i + (size_t)S_LEN * 64] +
             part[i + (size_t)2 * S_LEN * 64] + part[i + (size_t)3 * S_LEN * 64] + b;
}

// ---------------------------------------------------------------------------
// Launch
// ---------------------------------------------------------------------------
extern "C" void kernel_launch(void* const* d_in, const int* in_sizes, int n_in,
                              void* d_out, int out_size)
{
    const float* query  = (const float*)d_in[0];
    const float* key_in = (const float*)d_in[1];
    const float* value  = (const float*)d_in[2];
    const float* mask_u = (const float*)d_in[3];
    const float* Wq = (const float*)d_in[4];
    const float* bq = (const float*)d_in[5];
    const float* Wk = (const float*)d_in[6];
    const float* bk = (const float*)d_in[7];
    const float* Wv = (const float*)d_in[8];
    const float* bv = (const float*)d_in[9];
    const float* Wo = (const float*)d_in[10];
    const float* bo = (const float*)d_in[11];
    float* out = (float*)d_out;

    float *gq, *gk, *gv, *ga;
    __nv_bfloat16 *ah, *al, *bh, *bl;
    cudaGetSymbolAddress((void**)&gq, g_q);
    cudaGetSymbolAddress((void**)&gk, g_k);
    cudaGetSymbolAddress((void**)&gv, g_v);
    cudaGetSymbolAddress((void**)&ga, g_attn);
    cudaGetSymbolAddress((void**)&ah, g_Ah);
    cudaGetSymbolAddress((void**)&al, g_Al);
    cudaGetSymbolAddress((void**)&bh, g_Bh);
    cudaGetSymbolAddress((void**)&bl, g_Bl);

    cudaFuncSetAttribute(mma_gemm_q, cudaFuncAttributeMaxDynamicSharedMemorySize, GQ_SMEM);

    convert_split<<<(S_LEN * (size_t)D4096) / (256 * 8), 256>>>(query, ah, al);
    transpose_split<<<dim3(64, 64), 256>>>(Wq, bh, bl);
    mma_gemm_q<<<2048, 512, GQ_SMEM>>>(ah, al, bh, bl, bq, gq);
    proj_small<<<dim3(D4096 / 256, S_LEN / 16), 256>>>(key_in, Wk, bk, gk);
    proj_small<<<dim3(D4096 / 256, S_LEN / 16), 256>>>(value, Wv, bv, gv);
    attn_kernel<<<S_LEN, 256>>>(mask_u);
    // g_Ah (64MB bf16) reused as fp32 split-K scratch (needs 8MB)
    float* part = (float*)ah;
    gemm_out_part<<<dim3(S_LEN / 64, 4), 256>>>(ga, Wo, part);
    gemm_out_reduce<<<(S_LEN * 64) / 256, 256>>>(part, bo, out);
}

// round 7
// speedup vs baseline: 2.5322x; 1.0929x over previous
#include <cuda_runtime.h>
#include <cuda_bf16.h>
#include <cstdint>

#define S_LEN 8192
#define D4096 4096

__device__ float g_q[(size_t)S_LEN * D4096];
__device__ float g_k[(size_t)S_LEN * D4096];
__device__ float g_v[(size_t)S_LEN * D4096];
__device__ float g_attn[(size_t)S_LEN * D4096];
__device__ __nv_bfloat16 g_Ah[(size_t)S_LEN * D4096];   // query hi; later fp32 split-K scratch
__device__ __nv_bfloat16 g_Al[(size_t)S_LEN * D4096];
__device__ __nv_bfloat16 g_Bh[(size_t)D4096 * D4096];
__device__ __nv_bfloat16 g_Bl[(size_t)D4096 * D4096];
// small proj operands (reused for k then v)
__device__ __nv_bfloat16 g_xh[(size_t)S_LEN * 64];
__device__ __nv_bfloat16 g_xl[(size_t)S_LEN * 64];
__device__ __nv_bfloat16 g_wh[(size_t)D4096 * 64];
__device__ __nv_bfloat16 g_wl[(size_t)D4096 * 64];

__device__ __forceinline__ uint32_t smem_u32(const void* p) {
    uint32_t a;
    asm("{ .reg .u64 t; cvta.to.shared.u64 t, %1; cvt.u32.u64 %0, t; }"
        : "=r"(a) : "l"(p));
    return a;
}

#define CP_ASYNC16(saddr, gptr) \
    asm volatile("cp.async.cg.shared.global [%0], [%1], 16;" \
                 :: "r"(saddr), "l"(gptr) : "memory")
#define CP_COMMIT() asm volatile("cp.async.commit_group;" ::: "memory")
#define CP_WAIT(n)  asm volatile("cp.async.wait_group %0;" :: "n"(n) : "memory")

#define LDSM_X4(r0, r1, r2, r3, addr) \
    asm volatile("ldmatrix.sync.aligned.m8n8.x4.shared.b16 {%0,%1,%2,%3}, [%4];" \
                 : "=r"(r0), "=r"(r1), "=r"(r2), "=r"(r3) : "r"(addr))

#define MMA_BF16(c, a, b0, b1) \
    asm volatile( \
        "mma.sync.aligned.m16n8k16.row.col.f32.bf16.bf16.f32 " \
        "{%0,%1,%2,%3}, {%4,%5,%6,%7}, {%8,%9}, {%0,%1,%2,%3};" \
        : "+f"((c)[0]), "+f"((c)[1]), "+f"((c)[2]), "+f"((c)[3]) \
        : "r"((a)[0]), "r"((a)[1]), "r"((a)[2]), "r"((a)[3]), "r"(b0), "r"(b1))

// ---------------------------------------------------------------------------
// fp32 -> bf16 hi/lo split (count must be multiple of 2048)
// ---------------------------------------------------------------------------
__global__ __launch_bounds__(256) void convert_split(
    const float* __restrict__ in, __nv_bfloat16* __restrict__ hi,
    __nv_bfloat16* __restrict__ lo)
{
    const size_t base = ((size_t)blockIdx.x * 256 + threadIdx.x) * 8;
    float4 a = *reinterpret_cast<const float4*>(in + base);
    float4 b = *reinterpret_cast<const float4*>(in + base + 4);
    float f[8] = {a.x, a.y, a.z, a.w, b.x, b.y, b.z, b.w};
    __nv_bfloat16 h[8], l[8];
#pragma unroll
    for (int i = 0; i < 8; i++) {
        h[i] = __float2bfloat16(f[i]);
        l[i] = __float2bfloat16(f[i] - __bfloat162float(h[i]));
    }
    *reinterpret_cast<uint4*>(hi + base) = *reinterpret_cast<uint4*>(h);
    *reinterpret_cast<uint4*>(lo + base) = *reinterpret_cast<uint4*>(l);
}

// ---------------------------------------------------------------------------
// Wq (4096,4096) -> Wq^T bf16 hi/lo
// ---------------------------------------------------------------------------
__global__ __launch_bounds__(256) void transpose_split(
    const float* __restrict__ W, __nv_bfloat16* __restrict__ hi,
    __nv_bfloat16* __restrict__ lo)
{
    __shared__ float ts[64][65];
    const int n0 = blockIdx.x * 64;
    const int k0 = blockIdx.y * 64;
    const int tid = threadIdx.x;
#pragma unroll
    for (int i = 0; i < 16; i++) {
        int idx = tid + i * 256;
        int r = idx >> 6, c = idx & 63;
        ts[r][c] = W[(size_t)(k0 + r) * D4096 + n0 + c];
    }
    __syncthreads();
#pragma unroll
    for (int i = 0; i < 8; i++) {
        int idx = tid + i * 256;
        int nl = idx >> 5, kl = (idx & 31) * 2;
        float f0 = ts[kl][nl], f1 = ts[kl + 1][nl];
        __nv_bfloat162 ph, pl;
        ph.x = __float2bfloat16(f0);
        ph.y = __float2bfloat16(f1);
        pl.x = __float2bfloat16(f0 - __bfloat162float(ph.x));
        pl.y = __float2bfloat16(f1 - __bfloat162float(ph.y));
        size_t o = (size_t)(n0 + nl) * D4096 + k0 + kl;
        *reinterpret_cast<__nv_bfloat162*>(hi + o) = ph;
        *reinterpret_cast<__nv_bfloat162*>(lo + o) = pl;
    }
}

// ---------------------------------------------------------------------------
// W (64,4096) -> W^T (4096,64) bf16 hi/lo
// ---------------------------------------------------------------------------
__global__ __launch_bounds__(256) void transpose_w64(
    const float* __restrict__ W, __nv_bfloat16* __restrict__ hi,
    __nv_bfloat16* __restrict__ lo)
{
    __shared__ float ts[64][65];
    const int n0 = blockIdx.x * 64;
    const int tid = threadIdx.x;
    for (int t = tid; t < 4096; t += 256)
        ts[t >> 6][t & 63] = W[(size_t)(t >> 6) * D4096 + n0 + (t & 63)];
    __syncthreads();
    for (int t = tid; t < 4096; t += 256) {
        int nl = t >> 6, kl = t & 63;
        float f = ts[kl][nl];
        __nv_bfloat16 h = __float2bfloat16(f);
        hi[(size_t)(n0 + nl) * 64 + kl] = h;
        lo[(size_t)(n0 + nl) * 64 + kl] = __float2bfloat16(f - __bfloat162float(h));
    }
}

// ---------------------------------------------------------------------------
// Main HMMA GEMM: CTA 128x256, 512 thr (16 warps, 4m x 4n, warp tile 32x64),
// K-chunk 32, 3-stage cp.async, single barrier per iter.
// Buffer: Ah(10240) Al(10240) Bh(20480) Bl(20480) = 61440; x3 = 184320.
// ---------------------------------------------------------------------------
#define SA 80
#define A_TB 10240
#define B_TB 20480
#define BUF_B 61440
#define GQ_SMEM 184320

__global__ __launch_bounds__(512) void mma_gemm_q(
    const __nv_bfloat16* __restrict__ Ah, const __nv_bfloat16* __restrict__ Al,
    const __nv_bfloat16* __restrict__ Bh, const __nv_bfloat16* __restrict__ Bl,
    const float* __restrict__ bias, float* __restrict__ C)
{
    extern __shared__ char smem[];
    const uint32_t sb = smem_u32(smem);
    const int tid = threadIdx.x;
    const int warp = tid >> 5, lane = tid & 31;

    // n fastest (16 n-tiles): wave keeps full B panel in L2
    const int m0 = (blockIdx.x >> 4) * 128;
    const int n0 = (blockIdx.x & 15) * 256;

    const int wm = (warp & 3) * 32;
    const int wn = (warp >> 2) * 64;

    float c[2][8][4];
#pragma unroll
    for (int mt = 0; mt < 2; mt++)
#pragma unroll
        for (int nt = 0; nt < 8; nt++)
#pragma unroll
            for (int r = 0; r < 4; r++) c[mt][nt][r] = 0.0f;

    const int srow = tid >> 2;        // 0..127
    const int skv = (tid & 3) * 16;   // byte offset in 64B k-chunk payload

    const int g = lane >> 3, r8 = lane & 7;
    const uint32_t a_off = (uint32_t)(wm + (g & 1) * 8 + r8) * SA + (g >> 1) * 16;
    const uint32_t b_off = 2 * A_TB + (uint32_t)(wn + (g >> 1) * 8 + r8) * SA + (g & 1) * 16;

    auto stage = [&](int chunk, int buf) {
        const int k0 = chunk * 32;
        const uint32_t base = sb + buf * BUF_B;
        // A: 1 chunk per tile per thread
        {
            const uint32_t sa = base + (uint32_t)srow * SA + skv;
            const size_t ga = (size_t)(m0 + srow) * D4096 + k0 + skv / 2;
            CP_ASYNC16(sa, Ah + ga);
            CP_ASYNC16(sa + A_TB, Al + ga);
        }
        // B: 2 rows per thread
#pragma unroll
        for (int i = 0; i < 2; i++) {
            const int row = srow + i * 128;
            const uint32_t sa = base + 2 * A_TB + (uint32_t)row * SA + skv;
            const size_t gb = (size_t)(n0 + row) * D4096 + k0 + skv / 2;
            CP_ASYNC16(sa, Bh + gb);
            CP_ASYNC16(sa + B_TB, Bl + gb);
        }
        CP_COMMIT();
    };

    stage(0, 0);
    stage(1, 1);

    const int NIT = D4096 / 32;  // 128
    for (int it = 0; it < NIT; ++it) {
        if (it == NIT - 1) { CP_WAIT(0); } else { CP_WAIT(1); }
        __syncthreads();
        if (it + 2 < NIT) stage(it + 2, (it + 2) % 3);

        const uint32_t buf = sb + (it % 3) * BUF_B;
#pragma unroll
        for (int ks = 0; ks < 2; ++ks) {
            const uint32_t koff = ks * 32;
            uint32_t ah[2][4], al[2][4];
#pragma unroll
            for (int mt = 0; mt < 2; mt++) {
                const uint32_t aa = buf + a_off + koff + (uint32_t)mt * 16 * SA;
                LDSM_X4(ah[mt][0], ah[mt][1], ah[mt][2], ah[mt][3], aa);
                LDSM_X4(al[mt][0], al[mt][1], al[mt][2], al[mt][3], aa + A_TB);
            }
#pragma unroll
            for (int g4 = 0; g4 < 4; g4++) {
                uint32_t bh4[4], bl4[4];
                const uint32_t ba = buf + b_off + koff + (uint32_t)g4 * 16 * SA;
                LDSM_X4(bh4[0], bh4[1], bh4[2], bh4[3], ba);
                LDSM_X4(bl4[0], bl4[1], bl4[2], bl4[3], ba + B_TB);
#pragma unroll
                for (int mt = 0; mt < 2; mt++) {
#pragma unroll
                    for (int sub = 0; sub < 2; sub++) {
                        const int nt = g4 * 2 + sub, h = sub * 2;
                        MMA_BF16(c[mt][nt], ah[mt], bh4[h], bh4[h + 1]);
                        MMA_BF16(c[mt][nt], ah[mt], bl4[h], bl4[h + 1]);
                        MMA_BF16(c[mt][nt], al[mt], bh4[h], bh4[h + 1]);
                    }
                }
            }
        }
    }

    const int rbase = m0 + wm + (lane >> 2);
    const int cbase = n0 + wn + (lane & 3) * 2;
#pragma unroll
    for (int mt = 0; mt < 2; mt++) {
#pragma unroll
        for (int nt = 0; nt < 8; nt++) {
            const int col = cbase + nt * 8;
            const float b0 = bias[col], b1 = bias[col + 1];
            float* p0 = C + (size_t)(rbase + mt * 16) * D4096 + col;
            float* p1 = C + (size_t)(rbase + mt * 16 + 8) * D4096 + col;
            p0[0] = c[mt][nt][0] + b0;
            p0[1] = c[mt][nt][1] + b1;
            p1[0] = c[mt][nt][2] + b0;
            p1[1] = c[mt][nt][3] + b1;
        }
    }
}

// ---------------------------------------------------------------------------
// HMMA projection: out(8192,4096) = X(8192,64) @ W^T + bias (split-bf16).
// CTA 128x128, 256 thr (8 warps: 4m x 2n, warp 32x64), K=64 single stage.
// SMEM: Ah Al Bh Bl, each 128 rows x 144B stride (128B payload) = 18432.
// ---------------------------------------------------------------------------
#define PSA 144
#define P_TB 18432
#define PROJ_SMEM 73728

__global__ __launch_bounds__(256) void mma_proj(
    const __nv_bfloat16* __restrict__ Xh, const __nv_bfloat16* __restrict__ Xl,
    const __nv_bfloat16* __restrict__ Wh, const __nv_bfloat16* __restrict__ Wl,
    const float* __restrict__ bias, float* __restrict__ out)
{
    extern __shared__ char smem[];
    const uint32_t sb = smem_u32(smem);
    const int tid = threadIdx.x;
    const int warp = tid >> 5, lane = tid & 31;
    const int m0 = blockIdx.y * 128;
    const int n0 = blockIdx.x * 128;
    const int wm = (warp & 3) * 32;
    const int wn = (warp >> 2) * 64;

    // stage all four tiles (K=64: 8 x 16B chunks per row)
#pragma unroll
    for (int j = 0; j < 4; j++) {
        const int idx = tid + j * 256;
        const int row = idx >> 3, kc = (idx & 7) * 16;
        const uint32_t sa = sb + (uint32_t)row * PSA + kc;
        const size_t gx = (size_t)(m0 + row) * 64 + kc / 2;
        const size_t gw = (size_t)(n0 + row) * 64 + kc / 2;
        CP_ASYNC16(sa, Xh + gx);
        CP_ASYNC16(sa + P_TB, Xl + gx);
        CP_ASYNC16(sa + 2 * P_TB, Wh + gw);
        CP_ASYNC16(sa + 3 * P_TB, Wl + gw);
    }
    CP_COMMIT();

    float c[2][8][4];
#pragma unroll
    for (int mt = 0; mt < 2; mt++)
#pragma unroll
        for (int nt = 0; nt < 8; nt++)
#pragma unroll
            for (int r = 0; r < 4; r++) c[mt][nt][r] = 0.0f;

    const int g = lane >> 3, r8 = lane & 7;
    const uint32_t a_off = (uint32_t)(wm + (g & 1) * 8 + r8) * PSA + (g >> 1) * 16;
    const uint32_t b_off = 2 * P_TB + (uint32_t)(wn + (g >> 1) * 8 + r8) * PSA + (g & 1) * 16;

    CP_WAIT(0);
    __syncthreads();

#pragma unroll
    for (int ks = 0; ks < 4; ++ks) {
        const uint32_t koff = ks * 32;
        uint32_t ah[2][4], al[2][4];
#pragma unroll
        for (int mt = 0; mt < 2; mt++) {
            const uint32_t aa = sb + a_off + koff + (uint32_t)mt * 16 * PSA;
            LDSM_X4(ah[mt][0], ah[mt][1], ah[mt][2], ah[mt][3], aa);
            LDSM_X4(al[mt][0], al[mt][1], al[mt][2], al[mt][3], aa + P_TB);
        }
#pragma unroll
        for (int g4 = 0; g4 < 4; g4++) {
            uint32_t bh4[4], bl4[4];
            const uint32_t ba = sb + b_off + koff + (uint32_t)g4 * 16 * PSA;
            LDSM_X4(bh4[0], bh4[1], bh4[2], bh4[3], ba);
            LDSM_X4(bl4[0], bl4[1], bl4[2], bl4[3], ba + P_TB);
#pragma unroll
            for (int mt = 0; mt < 2; mt++) {
#pragma unroll
                for (int sub = 0; sub < 2; sub++) {
                    const int nt = g4 * 2 + sub, h = sub * 2;
                    MMA_BF16(c[mt][nt], ah[mt], bh4[h], bh4[h + 1]);
                    MMA_BF16(c[mt][nt], ah[mt], bl4[h], bl4[h + 1]);
                    MMA_BF16(c[mt][nt], al[mt], bh4[h], bh4[h + 1]);
                }
            }
        }
    }

    const int rbase = m0 + wm + (lane >> 2);
    const int cbase = n0 + wn + (lane & 3) * 2;
#pragma unroll
    for (int mt = 0; mt < 2; mt++) {
#pragma unroll
        for (int nt = 0; nt < 8; nt++) {
            const int col = cbase + nt * 8;
            const float b0 = bias[col], b1 = bias[col + 1];
            float* p0 = out + (size_t)(rbase + mt * 16) * D4096 + col;
            float* p1 = out + (size_t)(rbase + mt * 16 + 8) * D4096 + col;
            p0[0] = c[mt][nt][0] + b0;
            p0[1] = c[mt][nt][1] + b1;
            p1[0] = c[mt][nt][2] + b0;
            p1[1] = c[mt][nt][3] + b1;
        }
    }
}

// ---------------------------------------------------------------------------
// per-token attention (register-blocked 4x4)
// ---------------------------------------------------------------------------
__global__ __launch_bounds__(256, 4) void attn_kernel(const float* __restrict__ mask_u)
{
    __shared__ float smA[4352];
    __shared__ float smB[4352];

    const int s = blockIdx.x;
    const int tid = threadIdx.x;
    const int tr = tid >> 4;
    const int tc = tid & 15;
    const float* qrow = g_q + (size_t)s * 4096;
    const float* krow = g_k + (size_t)s * 4096;
    const float* vrow = g_v + (size_t)s * 4096;

    for (int t = tid; t < 1024; t += 256)
        reinterpret_cast<float4*>(smA)[t] = reinterpret_cast<const float4*>(qrow)[t];
    for (int t = tid; t < 4096; t += 256)
        smB[(t & 63) * 68 + (t >> 6)] = krow[t];
    __syncthreads();

    float lg[4][4];
#pragma unroll
    for (int a = 0; a < 4; a++)
#pragma unroll
        for (int b = 0; b < 4; b++) lg[a][b] = 0.0f;
#pragma unroll 8
    for (int h = 0; h < 64; h++) {
        const float4 qv = *reinterpret_cast<const float4*>(smA + h * 64 + tr * 4);
        const float4 kv = *reinterpret_cast<const float4*>(smB + h * 68 + tc * 4);
        const float qa[4] = {qv.x, qv.y, qv.z, qv.w};
        const float kb[4] = {kv.x, kv.y, kv.z, kv.w};
#pragma unroll
        for (int a = 0; a < 4; a++)
#pragma unroll
            for (int b = 0; b < 4; b++) lg[a][b] += qa[a] * kb[b];
    }

    float lse[4];
#pragma unroll
    for (int a = 0; a < 4; a++) {
        float mx = fmaxf(fmaxf(lg[a][0], lg[a][1]), fmaxf(lg[a][2], lg[a][3]));
        mx = fmaxf(mx, __shfl_xor_sync(0xffffffffu, mx, 1));
        mx = fmaxf(mx, __shfl_xor_sync(0xffffffffu, mx, 2));
        mx = fmaxf(mx, __shfl_xor_sync(0xffffffffu, mx, 4));
        mx = fmaxf(mx, __shfl_xor_sync(0xffffffffu, mx, 8));
        float se = expf(lg[a][0] - mx) + expf(lg[a][1] - mx) +
                   expf(lg[a][2] - mx) + expf(lg[a][3] - mx);
        se += __shfl_xor_sync(0xffffffffu, se, 1);
        se += __shfl_xor_sync(0xffffffffu, se, 2);
        se += __shfl_xor_sync(0xffffffffu, se, 4);
        se += __shfl_xor_sync(0xffffffffu, se, 8);
        lse[a] = mx + logf(se);
    }

#pragma unroll
    for (int a = 0; a < 4; a++) {
        const float4 mv = *reinterpret_cast<const float4*>(
            mask_u + ((size_t)s * 64 + tr * 4 + a) * 64 + tc * 4);
        const float mm[4] = {mv.x, mv.y, mv.z, mv.w};
#pragma unroll
        for (int b = 0; b < 4; b++) {
            const float keep = (mm[b] > 0.25f) ? (1.0f / 0.75f) : 0.0f;
            lg[a][b] = (lg[a][b] - lse[a]) * keep;
        }
    }

    __syncthreads();

#pragma unroll
    for (int a = 0; a < 4; a++) {
        float4 w;
        w.x = lg[a][0]; w.y = lg[a][1]; w.z = lg[a][2]; w.w = lg[a][3];
        *reinterpret_cast<float4*>(smB + (tr * 4 + a) * 68 + tc * 4) = w;
    }
    for (int t = tid; t < 4096; t += 256)
        smA[(t & 63) * 68 + (t >> 6)] = vrow[t];
    __syncthreads();

    float acc[4][4];
#pragma unroll
    for (int a = 0; a < 4; a++)
#pragma unroll
        for (int b = 0; b < 4; b++) acc[a][b] = 0.0f;
#pragma unroll 8
    for (int m = 0; m < 64; m++) {
        const float4 vv = *reinterpret_cast<const float4*>(smA + m * 68 + tc * 4);
        const float vb[4] = {vv.x, vv.y, vv.z, vv.w};
#pragma unroll
        for (int a = 0; a < 4; a++) {
            const float av = smB[(tr * 4 + a) * 68 + m];
#pragma unroll
            for (int b = 0; b < 4; b++) acc[a][b] += av * vb[b];
        }
    }

    float* orow = g_attn + (size_t)s * 4096;
#pragma unroll
    for (int a = 0; a < 4; a++) {
        float4 w;
        w.x = acc[a][0]; w.y = acc[a][1]; w.z = acc[a][2]; w.w = acc[a][3];
        *reinterpret_cast<float4*>(orow + (tr * 4 + a) * 64 + tc * 4) = w;
    }
}

// ---------------------------------------------------------------------------
// final GEMM, split-K=4
// ---------------------------------------------------------------------------
__global__ __launch_bounds__(256) void gemm_out_part(
    const float* __restrict__ A, const float* __restrict__ W,
    float* __restrict__ part)
{
    __shared__ float As[16][64];
    __shared__ float Bs[16][64];

    const int tid = threadIdx.x;
    const int bm = blockIdx.x * 64;
    const int ks = blockIdx.y;
    const int tr = tid >> 4;
    const int tc = tid & 15;

    float acc[4][4];
#pragma unroll
    for (int i = 0; i < 4; i++)
#pragma unroll
        for (int j = 0; j < 4; j++) acc[i][j] = 0.0f;

    const int am = tid >> 2;
    const int ak = (tid & 3) * 4;
    const int bk = tid >> 4;
    const int bn4 = (tid & 15) * 4;

    const int kbeg = ks * 1024, kend = kbeg + 1024;
    for (int k0 = kbeg; k0 < kend; k0 += 16) {
        float4 av = *reinterpret_cast<const float4*>(&A[(size_t)(bm + am) * 4096 + k0 + ak]);
        As[ak + 0][am] = av.x;
        As[ak + 1][am] = av.y;
        As[ak + 2][am] = av.z;
        As[ak + 3][am] = av.w;
        float4 bv = *reinterpret_cast<const float4*>(&W[(size_t)(k0 + bk) * 64 + bn4]);
        *reinterpret_cast<float4*>(&Bs[bk][bn4]) = bv;
        __syncthreads();

#pragma unroll
        for (int k = 0; k < 16; k++) {
            float a[4], b[4];
            *reinterpret_cast<float4*>(a) = *reinterpret_cast<float4*>(&As[k][tr * 4]);
            *reinterpret_cast<float4*>(b) = *reinterpret_cast<float4*>(&Bs[k][tc * 4]);
#pragma unroll
            for (int i = 0; i < 4; i++)
#pragma unroll
                for (int j = 0; j < 4; j++) acc[i][j] += a[i] * b[j];
        }
        __syncthreads();
    }

    float* pbase = part + (size_t)ks * S_LEN * 64;
#pragma unroll
    for (int i = 0; i < 4; i++) {
        float* crow = pbase + (size_t)(bm + tr * 4 + i) * 64 + tc * 4;
#pragma unroll
        for (int j = 0; j < 4; j++) crow[j] = acc[i][j];
    }
}

__global__ __launch_bounds__(256) void gemm_out_reduce(
    const float* __restrict__ part, const float* __restrict__ bias,
    float* __restrict__ out)
{
    const size_t i = (size_t)blockIdx.x * 256 + threadIdx.x;
    const float b = bias[i & 63];
    out[i] = part[i] + part[i + (size_t)S_LEN * 64] +
             part[i + (size_t)2 * S_LEN * 64] + part[i + (size_t)3 * S_LEN * 64] + b;
}

// ---------------------------------------------------------------------------
// Launch
// ---------------------------------------------------------------------------
extern "C" void kernel_launch(void* const* d_in, const int* in_sizes, int n_in,
                              void* d_out, int out_size)
{
    const float* query  = (const float*)d_in[0];
    const float* key_in = (const float*)d_in[1];
    const float* value  = (const float*)d_in[2];
    const float* mask_u = (const float*)d_in[3];
    const float* Wq = (const float*)d_in[4];
    const float* bq = (const float*)d_in[5];
    const float* Wk = (const float*)d_in[6];
    const float* bk = (const float*)d_in[7];
    const float* Wv = (const float*)d_in[8];
    const float* bv = (const float*)d_in[9];
    const float* Wo = (const float*)d_in[10];
    const float* bo = (const float*)d_in[11];
    float* out = (float*)d_out;

    float *gq, *gk, *gv, *ga;
    __nv_bfloat16 *ah, *al, *bh, *bl, *xh, *xl, *wh, *wl;
    cudaGetSymbolAddress((void**)&gq, g_q);
    cudaGetSymbolAddress((void**)&gk, g_k);
    cudaGetSymbolAddress((void**)&gv, g_v);
    cudaGetSymbolAddress((void**)&ga, g_attn);
    cudaGetSymbolAddress((void**)&ah, g_Ah);
    cudaGetSymbolAddress((void**)&al, g_Al);
    cudaGetSymbolAddress((void**)&bh, g_Bh);
    cudaGetSymbolAddress((void**)&bl, g_Bl);
    cudaGetSymbolAddress((void**)&xh, g_xh);
    cudaGetSymbolAddress((void**)&xl, g_xl);
    cudaGetSymbolAddress((void**)&wh, g_wh);
    cudaGetSymbolAddress((void**)&wl, g_wl);

    cudaFuncSetAttribute(mma_gemm_q, cudaFuncAttributeMaxDynamicSharedMemorySize, GQ_SMEM);
    cudaFuncSetAttribute(mma_proj, cudaFuncAttributeMaxDynamicSharedMemorySize, PROJ_SMEM);

    // Q projection path
    convert_split<<<(S_LEN * (size_t)D4096) / 2048, 256>>>(query, ah, al);
    transpose_split<<<dim3(64, 64), 256>>>(Wq, bh, bl);
    mma_gemm_q<<<1024, 512, GQ_SMEM>>>(ah, al, bh, bl, bq, gq);

    // K projection (HMMA)
    convert_split<<<(S_LEN * 64) / 2048, 256>>>(key_in, xh, xl);
    transpose_w64<<<64, 256>>>(Wk, wh, wl);
    mma_proj<<<dim3(D4096 / 128, S_LEN / 128), 256, PROJ_SMEM>>>(xh, xl, wh, wl, bk, gk);

    // V projection (HMMA, reuses x/w buffers)
    convert_split<<<(S_LEN * 64) / 2048, 256>>>(value, xh, xl);
    transpose_w64<<<64, 256>>>(Wv, wh, wl);
    mma_proj<<<dim3(D4096 / 128, S_LEN / 128), 256, PROJ_SMEM>>>(xh, xl, wh, wl, bv, gv);

    // attention
    attn_kernel<<<S_LEN, 256>>>(mask_u);

    // output GEMM (split-K into g_Ah scratch)
    float* part = (float*)ah;
    gemm_out_part<<<dim3(S_LEN / 64, 4), 256>>>(ga, Wo, part);
    gemm_out_reduce<<<(S_LEN * 64) / 256, 256>>>(part, bo, out);
}

// round 8
// speedup vs baseline: 2.6619x; 1.0512x over previous
#include <cuda_runtime.h>
#include <cuda_bf16.h>
#include <cstdint>

#define S_LEN 8192
#define D4096 4096

__device__ float g_q[(size_t)S_LEN * D4096];
__device__ float g_k[(size_t)S_LEN * D4096];
__device__ float g_v[(size_t)S_LEN * D4096];
__device__ __nv_bfloat16 g_Ah[(size_t)S_LEN * D4096];   // query hi; later attn-out hi
__device__ __nv_bfloat16 g_Al[(size_t)S_LEN * D4096];   // query lo; later attn-out lo
__device__ __nv_bfloat16 g_Bh[(size_t)D4096 * D4096];   // Wq^T hi; later fp32 split-K partials
__device__ __nv_bfloat16 g_Bl[(size_t)D4096 * D4096];   // Wq^T lo
__device__ __nv_bfloat16 g_xh[(size_t)S_LEN * 64];
__device__ __nv_bfloat16 g_xl[(size_t)S_LEN * 64];
__device__ __nv_bfloat16 g_wh[(size_t)D4096 * 64];
__device__ __nv_bfloat16 g_wl[(size_t)D4096 * 64];
__device__ __nv_bfloat16 g_woh[(size_t)64 * D4096];     // Wo^T hi  [n][k]
__device__ __nv_bfloat16 g_wol[(size_t)64 * D4096];     // Wo^T lo

__device__ __forceinline__ uint32_t smem_u32(const void* p) {
    uint32_t a;
    asm("{ .reg .u64 t; cvta.to.shared.u64 t, %1; cvt.u32.u64 %0, t; }"
        : "=r"(a) : "l"(p));
    return a;
}

#define CP_ASYNC16(saddr, gptr) \
    asm volatile("cp.async.cg.shared.global [%0], [%1], 16;" \
                 :: "r"(saddr), "l"(gptr) : "memory")
#define CP_COMMIT() asm volatile("cp.async.commit_group;" ::: "memory")
#define CP_WAIT(n)  asm volatile("cp.async.wait_group %0;" :: "n"(n) : "memory")

#define LDSM_X4(r0, r1, r2, r3, addr) \
    asm volatile("ldmatrix.sync.aligned.m8n8.x4.shared.b16 {%0,%1,%2,%3}, [%4];" \
                 : "=r"(r0), "=r"(r1), "=r"(r2), "=r"(r3) : "r"(addr))

#define MMA_BF16(c, a, b0, b1) \
    asm volatile( \
        "mma.sync.aligned.m16n8k16.row.col.f32.bf16.bf16.f32 " \
        "{%0,%1,%2,%3}, {%4,%5,%6,%7}, {%8,%9}, {%0,%1,%2,%3};" \
        : "+f"((c)[0]), "+f"((c)[1]), "+f"((c)[2]), "+f"((c)[3]) \
        : "r"((a)[0]), "r"((a)[1]), "r"((a)[2]), "r"((a)[3]), "r"(b0), "r"(b1))

// ---------------------------------------------------------------------------
// fp32 -> bf16 hi/lo split
// ---------------------------------------------------------------------------
__global__ __launch_bounds__(256) void convert_split(
    const float* __restrict__ in, __nv_bfloat16* __restrict__ hi,
    __nv_bfloat16* __restrict__ lo)
{
    const size_t base = ((size_t)blockIdx.x * 256 + threadIdx.x) * 8;
    float4 a = *reinterpret_cast<const float4*>(in + base);
    float4 b = *reinterpret_cast<const float4*>(in + base + 4);
    float f[8] = {a.x, a.y, a.z, a.w, b.x, b.y, b.z, b.w};
    __nv_bfloat16 h[8], l[8];
#pragma unroll
    for (int i = 0; i < 8; i++) {
        h[i] = __float2bfloat16(f[i]);
        l[i] = __float2bfloat16(f[i] - __bfloat162float(h[i]));
    }
    *reinterpret_cast<uint4*>(hi + base) = *reinterpret_cast<uint4*>(h);
    *reinterpret_cast<uint4*>(lo + base) = *reinterpret_cast<uint4*>(l);
}

// ---------------------------------------------------------------------------
// Wq (4096,4096) -> Wq^T bf16 hi/lo
// ---------------------------------------------------------------------------
__global__ __launch_bounds__(256) void transpose_split(
    const float* __restrict__ W, __nv_bfloat16* __restrict__ hi,
    __nv_bfloat16* __restrict__ lo)
{
    __shared__ float ts[64][65];
    const int n0 = blockIdx.x * 64;
    const int k0 = blockIdx.y * 64;
    const int tid = threadIdx.x;
#pragma unroll
    for (int i = 0; i < 16; i++) {
        int idx = tid + i * 256;
        int r = idx >> 6, c = idx & 63;
        ts[r][c] = W[(size_t)(k0 + r) * D4096 + n0 + c];
    }
    __syncthreads();
#pragma unroll
    for (int i = 0; i < 8; i++) {
        int idx = tid + i * 256;
        int nl = idx >> 5, kl = (idx & 31) * 2;
        float f0 = ts[kl][nl], f1 = ts[kl + 1][nl];
        __nv_bfloat162 ph, pl;
        ph.x = __float2bfloat16(f0);
        ph.y = __float2bfloat16(f1);
        pl.x = __float2bfloat16(f0 - __bfloat162float(ph.x));
        pl.y = __float2bfloat16(f1 - __bfloat162float(ph.y));
        size_t o = (size_t)(n0 + nl) * D4096 + k0 + kl;
        *reinterpret_cast<__nv_bfloat162*>(hi + o) = ph;
        *reinterpret_cast<__nv_bfloat162*>(lo + o) = pl;
    }
}

// ---------------------------------------------------------------------------
// W (64,4096) -> W^T (4096,64) bf16 hi/lo
// ---------------------------------------------------------------------------
__global__ __launch_bounds__(256) void transpose_w64(
    const float* __restrict__ W, __nv_bfloat16* __restrict__ hi,
    __nv_bfloat16* __restrict__ lo)
{
    __shared__ float ts[64][65];
    const int n0 = blockIdx.x * 64;
    const int tid = threadIdx.x;
    for (int t = tid; t < 4096; t += 256)
        ts[t >> 6][t & 63] = W[(size_t)(t >> 6) * D4096 + n0 + (t & 63)];
    __syncthreads();
    for (int t = tid; t < 4096; t += 256) {
        int nl = t >> 6, kl = t & 63;
        float f = ts[kl][nl];
        __nv_bfloat16 h = __float2bfloat16(f);
        hi[(size_t)(n0 + nl) * 64 + kl] = h;
        lo[(size_t)(n0 + nl) * 64 + kl] = __float2bfloat16(f - __bfloat162float(h));
    }
}

// ---------------------------------------------------------------------------
// Wo (4096,64) -> Wo^T (64,4096) bf16 hi/lo
// ---------------------------------------------------------------------------
__global__ __launch_bounds__(256) void transpose_wo(
    const float* __restrict__ W, __nv_bfloat16* __restrict__ hi,
    __nv_bfloat16* __restrict__ lo)
{
    __shared__ float ts[64][65];
    const int k0 = blockIdx.x * 64;
    const int tid = threadIdx.x;
    for (int t = tid; t < 4096; t += 256)
        ts[t >> 6][t & 63] = W[(size_t)(k0 + (t >> 6)) * 64 + (t & 63)];
    __syncthreads();
    for (int t = tid; t < 4096; t += 256) {
        int n = t >> 6, k = t & 63;
        float f = ts[k][n];
        __nv_bfloat16 h = __float2bfloat16(f);
        hi[(size_t)n * D4096 + k0 + k] = h;
        lo[(size_t)n * D4096 + k0 + k] = __float2bfloat16(f - __bfloat162float(h));
    }
}

// ---------------------------------------------------------------------------
// Main HMMA GEMM: CTA 128x256, 256 thr (8 warps = 2m x 4n, warp tile 64x64),
// K-chunk 32, 3-stage cp.async. Fragment reuse ratio 0.167 (vs 0.25 @32x64).
// ---------------------------------------------------------------------------
#define SA 80
#define A_TB 10240
#define B_TB 20480
#define BUF_B 61440
#define GQ_SMEM 184320

__global__ __launch_bounds__(256) void mma_gemm_q(
    const __nv_bfloat16* __restrict__ Ah, const __nv_bfloat16* __restrict__ Al,
    const __nv_bfloat16* __restrict__ Bh, const __nv_bfloat16* __restrict__ Bl,
    const float* __restrict__ bias, float* __restrict__ C)
{
    extern __shared__ char smem[];
    const uint32_t sb = smem_u32(smem);
    const int tid = threadIdx.x;
    const int warp = tid >> 5, lane = tid & 31;

    const int m0 = (blockIdx.x >> 4) * 128;
    const int n0 = (blockIdx.x & 15) * 256;

    const int wm = (warp & 1) * 64;
    const int wn = (warp >> 1) * 64;

    float c[4][8][4];
#pragma unroll
    for (int mt = 0; mt < 4; mt++)
#pragma unroll
        for (int nt = 0; nt < 8; nt++)
#pragma unroll
            for (int r = 0; r < 4; r++) c[mt][nt][r] = 0.0f;

    const int g = lane >> 3, r8 = lane & 7;
    const uint32_t a_off = (uint32_t)(wm + (g & 1) * 8 + r8) * SA + (g >> 1) * 16;
    const uint32_t b_off = 2 * A_TB + (uint32_t)(wn + (g >> 1) * 8 + r8) * SA + (g & 1) * 16;

    auto stage = [&](int chunk, int buf) {
        const int k0 = chunk * 32;
        const uint32_t base = sb + buf * BUF_B;
#pragma unroll
        for (int j = 0; j < 2; j++) {           // A: 128 rows x 4 chunks
            const int idx = tid + j * 256;
            const int row = idx >> 2, kc = (idx & 3) * 16;
            const uint32_t sa = base + (uint32_t)row * SA + kc;
            const size_t ga = (size_t)(m0 + row) * D4096 + k0 + kc / 2;
            CP_ASYNC16(sa, Ah + ga);
            CP_ASYNC16(sa + A_TB, Al + ga);
        }
#pragma unroll
        for (int j = 0; j < 4; j++) {           // B: 256 rows x 4 chunks
            const int idx = tid + j * 256;
            const int row = idx >> 2, kc = (idx & 3) * 16;
            const uint32_t sa = base + 2 * A_TB + (uint32_t)row * SA + kc;
            const size_t gb = (size_t)(n0 + row) * D4096 + k0 + kc / 2;
            CP_ASYNC16(sa, Bh + gb);
            CP_ASYNC16(sa + B_TB, Bl + gb);
        }
        CP_COMMIT();
    };

    stage(0, 0);
    stage(1, 1);

    const int NIT = D4096 / 32;  // 128
    for (int it = 0; it < NIT; ++it) {
        if (it == NIT - 1) { CP_WAIT(0); } else { CP_WAIT(1); }
        __syncthreads();
        if (it + 2 < NIT) stage(it + 2, (it + 2) % 3);

        const uint32_t buf = sb + (it % 3) * BUF_B;
#pragma unroll
        for (int ks = 0; ks < 2; ++ks) {
            const uint32_t koff = ks * 32;
            uint32_t ah[4][4], al[4][4];
#pragma unroll
            for (int mt = 0; mt < 4; mt++) {
                const uint32_t aa = buf + a_off + koff + (uint32_t)mt * 16 * SA;
                LDSM_X4(ah[mt][0], ah[mt][1], ah[mt][2], ah[mt][3], aa);
                LDSM_X4(al[mt][0], al[mt][1], al[mt][2], al[mt][3], aa + A_TB);
            }
#pragma unroll
            for (int g4 = 0; g4 < 4; g4++) {
                uint32_t bh4[4], bl4[4];
                const uint32_t ba = buf + b_off + koff + (uint32_t)g4 * 16 * SA;
                LDSM_X4(bh4[0], bh4[1], bh4[2], bh4[3], ba);
                LDSM_X4(bl4[0], bl4[1], bl4[2], bl4[3], ba + B_TB);
#pragma unroll
                for (int mt = 0; mt < 4; mt++) {
#pragma unroll
                    for (int sub = 0; sub < 2; sub++) {
                        const int nt = g4 * 2 + sub, h = sub * 2;
                        MMA_BF16(c[mt][nt], ah[mt], bh4[h], bh4[h + 1]);
                        MMA_BF16(c[mt][nt], ah[mt], bl4[h], bl4[h + 1]);
                        MMA_BF16(c[mt][nt], al[mt], bh4[h], bh4[h + 1]);
                    }
                }
            }
        }
    }

    const int rbase = m0 + wm + (lane >> 2);
    const int cbase = n0 + wn + (lane & 3) * 2;
#pragma unroll
    for (int mt = 0; mt < 4; mt++) {
#pragma unroll
        for (int nt = 0; nt < 8; nt++) {
            const int col = cbase + nt * 8;
            const float b0 = bias[col], b1 = bias[col + 1];
            float* p0 = C + (size_t)(rbase + mt * 16) * D4096 + col;
            float* p1 = C + (size_t)(rbase + mt * 16 + 8) * D4096 + col;
            p0[0] = c[mt][nt][0] + b0;
            p0[1] = c[mt][nt][1] + b1;
            p1[0] = c[mt][nt][2] + b0;
            p1[1] = c[mt][nt][3] + b1;
        }
    }
}

// ---------------------------------------------------------------------------
// HMMA projection (K=64) — unchanged from R7
// ---------------------------------------------------------------------------
#define PSA 144
#define P_TB 18432
#define PROJ_SMEM 73728

__global__ __launch_bounds__(256) void mma_proj(
    const __nv_bfloat16* __restrict__ Xh, const __nv_bfloat16* __restrict__ Xl,
    const __nv_bfloat16* __restrict__ Wh, const __nv_bfloat16* __restrict__ Wl,
    const float* __restrict__ bias, float* __restrict__ out)
{
    extern __shared__ char smem[];
    const uint32_t sb = smem_u32(smem);
    const int tid = threadIdx.x;
    const int warp = tid >> 5, lane = tid & 31;
    const int m0 = blockIdx.y * 128;
    const int n0 = blockIdx.x * 128;
    const int wm = (warp & 3) * 32;
    const int wn = (warp >> 2) * 64;

#pragma unroll
    for (int j = 0; j < 4; j++) {
        const int idx = tid + j * 256;
        const int row = idx >> 3, kc = (idx & 7) * 16;
        const uint32_t sa = sb + (uint32_t)row * PSA + kc;
        const size_t gx = (size_t)(m0 + row) * 64 + kc / 2;
        const size_t gw = (size_t)(n0 + row) * 64 + kc / 2;
        CP_ASYNC16(sa, Xh + gx);
        CP_ASYNC16(sa + P_TB, Xl + gx);
        CP_ASYNC16(sa + 2 * P_TB, Wh + gw);
        CP_ASYNC16(sa + 3 * P_TB, Wl + gw);
    }
    CP_COMMIT();

    float c[2][8][4];
#pragma unroll
    for (int mt = 0; mt < 2; mt++)
#pragma unroll
        for (int nt = 0; nt < 8; nt++)
#pragma unroll
            for (int r = 0; r < 4; r++) c[mt][nt][r] = 0.0f;

    const int g = lane >> 3, r8 = lane & 7;
    const uint32_t a_off = (uint32_t)(wm + (g & 1) * 8 + r8) * PSA + (g >> 1) * 16;
    const uint32_t b_off = 2 * P_TB + (uint32_t)(wn + (g >> 1) * 8 + r8) * PSA + (g & 1) * 16;

    CP_WAIT(0);
    __syncthreads();

#pragma unroll
    for (int ks = 0; ks < 4; ++ks) {
        const uint32_t koff = ks * 32;
        uint32_t ah[2][4], al[2][4];
#pragma unroll
        for (int mt = 0; mt < 2; mt++) {
            const uint32_t aa = sb + a_off + koff + (uint32_t)mt * 16 * PSA;
            LDSM_X4(ah[mt][0], ah[mt][1], ah[mt][2], ah[mt][3], aa);
            LDSM_X4(al[mt][0], al[mt][1], al[mt][2], al[mt][3], aa + P_TB);
        }
#pragma unroll
        for (int g4 = 0; g4 < 4; g4++) {
            uint32_t bh4[4], bl4[4];
            const uint32_t ba = sb + b_off + koff + (uint32_t)g4 * 16 * PSA;
            LDSM_X4(bh4[0], bh4[1], bh4[2], bh4[3], ba);
            LDSM_X4(bl4[0], bl4[1], bl4[2], bl4[3], ba + P_TB);
#pragma unroll
            for (int mt = 0; mt < 2; mt++) {
#pragma unroll
                for (int sub = 0; sub < 2; sub++) {
                    const int nt = g4 * 2 + sub, h = sub * 2;
                    MMA_BF16(c[mt][nt], ah[mt], bh4[h], bh4[h + 1]);
                    MMA_BF16(c[mt][nt], ah[mt], bl4[h], bl4[h + 1]);
                    MMA_BF16(c[mt][nt], al[mt], bh4[h], bh4[h + 1]);
                }
            }
        }
    }

    const int rbase = m0 + wm + (lane >> 2);
    const int cbase = n0 + wn + (lane & 3) * 2;
#pragma unroll
    for (int mt = 0; mt < 2; mt++) {
#pragma unroll
        for (int nt = 0; nt < 8; nt++) {
            const int col = cbase + nt * 8;
            const float b0 = bias[col], b1 = bias[col + 1];
            float* p0 = out + (size_t)(rbase + mt * 16) * D4096 + col;
            float* p1 = out + (size_t)(rbase + mt * 16 + 8) * D4096 + col;
            p0[0] = c[mt][nt][0] + b0;
            p0[1] = c[mt][nt][1] + b1;
            p1[0] = c[mt][nt][2] + b0;
            p1[1] = c[mt][nt][3] + b1;
        }
    }
}

// ---------------------------------------------------------------------------
// per-token attention; emits bf16 hi/lo for the HMMA output GEMM
// ---------------------------------------------------------------------------
__global__ __launch_bounds__(256, 4) void attn_kernel(
    const float* __restrict__ mask_u,
    __nv_bfloat16* __restrict__ oh, __nv_bfloat16* __restrict__ ol)
{
    __shared__ float smA[4352];
    __shared__ float smB[4352];

    const int s = blockIdx.x;
    const int tid = threadIdx.x;
    const int tr = tid >> 4;
    const int tc = tid & 15;
    const float* qrow = g_q + (size_t)s * 4096;
    const float* krow = g_k + (size_t)s * 4096;
    const float* vrow = g_v + (size_t)s * 4096;

    for (int t = tid; t < 1024; t += 256)
        reinterpret_cast<float4*>(smA)[t] = reinterpret_cast<const float4*>(qrow)[t];
    for (int t = tid; t < 4096; t += 256)
        smB[(t & 63) * 68 + (t >> 6)] = krow[t];
    __syncthreads();

    float lg[4][4];
#pragma unroll
    for (int a = 0; a < 4; a++)
#pragma unroll
        for (int b = 0; b < 4; b++) lg[a][b] = 0.0f;
#pragma unroll 8
    for (int h = 0; h < 64; h++) {
        const float4 qv = *reinterpret_cast<const float4*>(smA + h * 64 + tr * 4);
        const float4 kv = *reinterpret_cast<const float4*>(smB + h * 68 + tc * 4);
        const float qa[4] = {qv.x, qv.y, qv.z, qv.w};
        const float kb[4] = {kv.x, kv.y, kv.z, kv.w};
#pragma unroll
        for (int a = 0; a < 4; a++)
#pragma unroll
            for (int b = 0; b < 4; b++) lg[a][b] += qa[a] * kb[b];
    }

    float lse[4];
#pragma unroll
    for (int a = 0; a < 4; a++) {
        float mx = fmaxf(fmaxf(lg[a][0], lg[a][1]), fmaxf(lg[a][2], lg[a][3]));
        mx = fmaxf(mx, __shfl_xor_sync(0xffffffffu, mx, 1));
        mx = fmaxf(mx, __shfl_xor_sync(0xffffffffu, mx, 2));
        mx = fmaxf(mx, __shfl_xor_sync(0xffffffffu, mx, 4));
        mx = fmaxf(mx, __shfl_xor_sync(0xffffffffu, mx, 8));
        float se = __expf(lg[a][0] - mx) + __expf(lg[a][1] - mx) +
                   __expf(lg[a][2] - mx) + __expf(lg[a][3] - mx);
        se += __shfl_xor_sync(0xffffffffu, se, 1);
        se += __shfl_xor_sync(0xffffffffu, se, 2);
        se += __shfl_xor_sync(0xffffffffu, se, 4);
        se += __shfl_xor_sync(0xffffffffu, se, 8);
        lse[a] = mx + __logf(se);
    }

#pragma unroll
    for (int a = 0; a < 4; a++) {
        const float4 mv = *reinterpret_cast<const float4*>(
            mask_u + ((size_t)s * 64 + tr * 4 + a) * 64 + tc * 4);
        const float mm[4] = {mv.x, mv.y, mv.z, mv.w};
#pragma unroll
        for (int b = 0; b < 4; b++) {
            const float keep = (mm[b] > 0.25f) ? (1.0f / 0.75f) : 0.0f;
            lg[a][b] = (lg[a][b] - lse[a]) * keep;
        }
    }

    __syncthreads();

#pragma unroll
    for (int a = 0; a < 4; a++) {
        float4 w;
        w.x = lg[a][0]; w.y = lg[a][1]; w.z = lg[a][2]; w.w = lg[a][3];
        *reinterpret_cast<float4*>(smB + (tr * 4 + a) * 68 + tc * 4) = w;
    }
    for (int t = tid; t < 4096; t += 256)
        smA[(t & 63) * 68 + (t >> 6)] = vrow[t];
    __syncthreads();

    float acc[4][4];
#pragma unroll
    for (int a = 0; a < 4; a++)
#pragma unroll
        for (int b = 0; b < 4; b++) acc[a][b] = 0.0f;
#pragma unroll 8
    for (int m = 0; m < 64; m++) {
        const float4 vv = *reinterpret_cast<const float4*>(smA + m * 68 + tc * 4);
        const float vb[4] = {vv.x, vv.y, vv.z, vv.w};
#pragma unroll
        for (int a = 0; a < 4; a++) {
            const float av = smB[(tr * 4 + a) * 68 + m];
#pragma unroll
            for (int b = 0; b < 4; b++) acc[a][b] += av * vb[b];
        }
    }

    // emit bf16 hi/lo: column index = i*64 + j in the (8192 x 4096) matrix
#pragma unroll
    for (int a = 0; a < 4; a++) {
        const size_t o = (size_t)s * 4096 + (tr * 4 + a) * 64 + tc * 4;
        __nv_bfloat16 h[4], l[4];
#pragma unroll
        for (int b = 0; b < 4; b++) {
            h[b] = __float2bfloat16(acc[a][b]);
            l[b] = __float2bfloat16(acc[a][b] - __bfloat162float(h[b]));
        }
        *reinterpret_cast<uint2*>(oh + o) = *reinterpret_cast<uint2*>(h);
        *reinterpret_cast<uint2*>(ol + o) = *reinterpret_cast<uint2*>(l);
    }
}

// ---------------------------------------------------------------------------
// output GEMM via HMMA, split-K=8: out(8192,64) = AT(8192,4096) @ Wo^T
// CTA 128x64, 256 thr (8 warps = 4m x 2n, warp 32x32), k32 double-buffered.
// ---------------------------------------------------------------------------
#define OSA 80
#define OA_TB 10240
#define OB_TB 5120
#define OBUF 30720
#define GO_SMEM 61440

__global__ __launch_bounds__(256) void gemm_out_mma(
    const __nv_bfloat16* __restrict__ Ahp, const __nv_bfloat16* __restrict__ Alp,
    const __nv_bfloat16* __restrict__ Wh, const __nv_bfloat16* __restrict__ Wl,
    float* __restrict__ part)
{
    extern __shared__ char smem[];
    const uint32_t sb = smem_u32(smem);
    const int tid = threadIdx.x;
    const int warp = tid >> 5, lane = tid & 31;
    const int m0 = blockIdx.x * 128;
    const int ksp = blockIdx.y;          // 0..7
    const int kbase = ksp * 512;
    const int wm = (warp & 3) * 32;
    const int wn = (warp >> 2) * 32;

    float c[2][4][4];
#pragma unroll
    for (int mt = 0; mt < 2; mt++)
#pragma unroll
        for (int nt = 0; nt < 4; nt++)
#pragma unroll
            for (int r = 0; r < 4; r++) c[mt][nt][r] = 0.0f;

    const int g = lane >> 3, r8 = lane & 7;
    const uint32_t a_off = (uint32_t)(wm + (g & 1) * 8 + r8) * OSA + (g >> 1) * 16;
    const uint32_t b_off = 2 * OA_TB + (uint32_t)(wn + (g >> 1) * 8 + r8) * OSA + (g & 1) * 16;

    auto stage = [&](int chunk, int buf) {
        const int k0 = kbase + chunk * 32;
        const uint32_t base = sb + buf * OBUF;
#pragma unroll
        for (int j = 0; j < 2; j++) {       // A: 128 rows x 4 chunks
            const int idx = tid + j * 256;
            const int row = idx >> 2, kc = (idx & 3) * 16;
            const uint32_t sa = base + (uint32_t)row * OSA + kc;
            const size_t ga = (size_t)(m0 + row) * D4096 + k0 + kc / 2;
            CP_ASYNC16(sa, Ahp + ga);
            CP_ASYNC16(sa + OA_TB, Alp + ga);
        }
        {                                    // B: 64 rows x 4 chunks
            const int row = tid >> 2, kc = (tid & 3) * 16;
            const uint32_t sa = base + 2 * OA_TB + (uint32_t)row * OSA + kc;
            const size_t gb = (size_t)row * D4096 + k0 + kc / 2;
            CP_ASYNC16(sa, Wh + gb);
            CP_ASYNC16(sa + OB_TB, Wl + gb);
        }
        CP_COMMIT();
    };

    stage(0, 0);

    for (int it = 0; it < 16; ++it) {
        if (it + 1 < 16) {
            stage(it + 1, (it + 1) & 1);
            CP_WAIT(1);
        } else {
            CP_WAIT(0);
        }
        __syncthreads();

        const uint32_t buf = sb + (it & 1) * OBUF;
#pragma unroll
        for (int ks = 0; ks < 2; ++ks) {
            const uint32_t koff = ks * 32;
            uint32_t ah[2][4], al[2][4];
#pragma unroll
            for (int mt = 0; mt < 2; mt++) {
                const uint32_t aa = buf + a_off + koff + (uint32_t)mt * 16 * OSA;
                LDSM_X4(ah[mt][0], ah[mt][1], ah[mt][2], ah[mt][3], aa);
                LDSM_X4(al[mt][0], al[mt][1], al[mt][2], al[mt][3], aa + OA_TB);
            }
#pragma unroll
            for (int g4 = 0; g4 < 2; g4++) {
                uint32_t bh4[4], bl4[4];
                const uint32_t ba = buf + b_off + koff + (uint32_t)g4 * 16 * OSA;
                LDSM_X4(bh4[0], bh4[1], bh4[2], bh4[3], ba);
                LDSM_X4(bl4[0], bl4[1], bl4[2], bl4[3], ba + OB_TB);
#pragma unroll
                for (int mt = 0; mt < 2; mt++) {
#pragma unroll
                    for (int sub = 0; sub < 2; sub++) {
                        const int nt = g4 * 2 + sub, h = sub * 2;
                        MMA_BF16(c[mt][nt], ah[mt], bh4[h], bh4[h + 1]);
                        MMA_BF16(c[mt][nt], ah[mt], bl4[h], bl4[h + 1]);
                        MMA_BF16(c[mt][nt], al[mt], bh4[h], bh4[h + 1]);
                    }
                }
            }
        }
        __syncthreads();
    }

    float* pbase = part + (size_t)ksp * S_LEN * 64;
    const int rbase = m0 + wm + (lane >> 2);
    const int cbase = wn + (lane & 3) * 2;
#pragma unroll
    for (int mt = 0; mt < 2; mt++) {
#pragma unroll
        for (int nt = 0; nt < 4; nt++) {
            const int col = cbase + nt * 8;
            float* p0 = pbase + (size_t)(rbase + mt * 16) * 64 + col;
            float* p1 = pbase + (size_t)(rbase + mt * 16 + 8) * 64 + col;
            p0[0] = c[mt][nt][0];
            p0[1] = c[mt][nt][1];
            p1[0] = c[mt][nt][2];
            p1[1] = c[mt][nt][3];
        }
    }
}

__global__ __launch_bounds__(256) void gemm_out_reduce(
    const float* __restrict__ part, const float* __restrict__ bias,
    float* __restrict__ out)
{
    const size_t i = (size_t)blockIdx.x * 256 + threadIdx.x;
    float s = bias[i & 63];
#pragma unroll
    for (int k = 0; k < 8; k++) s += part[i + (size_t)k * S_LEN * 64];
    out[i] = s;
}

// ---------------------------------------------------------------------------
// Launch
// ---------------------------------------------------------------------------
extern "C" void kernel_launch(void* const* d_in, const int* in_sizes, int n_in,
                              void* d_out, int out_size)
{
    const float* query  = (const float*)d_in[0];
    const float* key_in = (const float*)d_in[1];
    const float* value  = (const float*)d_in[2];
    const float* mask_u = (const float*)d_in[3];
    const float* Wq = (const float*)d_in[4];
    const float* bq = (const float*)d_in[5];
    const float* Wk = (const float*)d_in[6];
    const float* bk = (const float*)d_in[7];
    const float* Wv = (const float*)d_in[8];
    const float* bv = (const float*)d_in[9];
    const float* Wo = (const float*)d_in[10];
    const float* bo = (const float*)d_in[11];
    float* out = (float*)d_out;

    float *gq, *gk, *gv;
    __nv_bfloat16 *ah, *al, *bh, *bl, *xh, *xl, *wh, *wl, *woh, *wol;
    cudaGetSymbolAddress((void**)&gq, g_q);
    cudaGetSymbolAddress((void**)&gk, g_k);
    cudaGetSymbolAddress((void**)&gv, g_v);
    cudaGetSymbolAddress((void**)&ah, g_Ah);
    cudaGetSymbolAddress((void**)&al, g_Al);
    cudaGetSymbolAddress((void**)&bh, g_Bh);
    cudaGetSymbolAddress((void**)&bl, g_Bl);
    cudaGetSymbolAddress((void**)&xh, g_xh);
    cudaGetSymbolAddress((void**)&xl, g_xl);
    cudaGetSymbolAddress((void**)&wh, g_wh);
    cudaGetSymbolAddress((void**)&wl, g_wl);
    cudaGetSymbolAddress((void**)&woh, g_woh);
    cudaGetSymbolAddress((void**)&wol, g_wol);

    cudaFuncSetAttribute(mma_gemm_q, cudaFuncAttributeMaxDynamicSharedMemorySize, GQ_SMEM);
    cudaFuncSetAttribute(mma_proj, cudaFuncAttributeMaxDynamicSharedMemorySize, PROJ_SMEM);
    cudaFuncSetAttribute(gemm_out_mma, cudaFuncAttributeMaxDynamicSharedMemorySize, GO_SMEM);

    // Q projection
    convert_split<<<(S_LEN * (size_t)D4096) / 2048, 256>>>(query, ah, al);
    transpose_split<<<dim3(64, 64), 256>>>(Wq, bh, bl);
    mma_gemm_q<<<1024, 256, GQ_SMEM>>>(ah, al, bh, bl, bq, gq);

    // K projection
    convert_split<<<(S_LEN * 64) / 2048, 256>>>(key_in, xh, xl);
    transpose_w64<<<64, 256>>>(Wk, wh, wl);
    mma_proj<<<dim3(D4096 / 128, S_LEN / 128), 256, PROJ_SMEM>>>(xh, xl, wh, wl, bk, gk);

    // V projection
    convert_split<<<(S_LEN * 64) / 2048, 256>>>(value, xh, xl);
    transpose_w64<<<64, 256>>>(Wv, wh, wl);
    mma_proj<<<dim3(D4096 / 128, S_LEN / 128), 256, PROJ_SMEM>>>(xh, xl, wh, wl, bv, gv);

    // Wo transpose/split
    transpose_wo<<<64, 256>>>(Wo, woh, wol);

    // attention: emits bf16 hi/lo into g_Ah/g_Al (free after mma_gemm_q)
    attn_kernel<<<S_LEN, 256>>>(mask_u, ah, al);

    // output GEMM: HMMA split-K=8, fp32 partials in g_Bh scratch
    float* part = (float*)bh;
    gemm_out_mma<<<dim3(S_LEN / 128, 8), 256, GO_SMEM>>>(ah, al, woh, wol, part);
    gemm_out_reduce<<<(S_LEN * 64) / 256, 256>>>(part, bo, out);
}

// round 9
// speedup vs baseline: 3.4686x; 1.3031x over previous
#include <cuda_runtime.h>
#include <cuda_bf16.h>
#include <cuda_fp16.h>
#include <cstdint>

#define S_LEN 8192
#define D4096 4096

__device__ float g_q[(size_t)S_LEN * D4096];
__device__ float g_k[(size_t)S_LEN * D4096];
__device__ float g_v[(size_t)S_LEN * D4096];
__device__ __nv_bfloat16 g_Ah[(size_t)S_LEN * D4096];   // query hi (fp16); later attn-out hi (bf16)
__device__ __nv_bfloat16 g_Al[(size_t)S_LEN * D4096];   // query lo (fp16); later attn-out lo (bf16)
__device__ __nv_bfloat16 g_Bh[(size_t)D4096 * D4096];   // Wq^T fp16; later fp32 split-K partials
__device__ __nv_bfloat16 g_xh[(size_t)S_LEN * 64];
__device__ __nv_bfloat16 g_xl[(size_t)S_LEN * 64];
__device__ __nv_bfloat16 g_wh[(size_t)D4096 * 64];
__device__ __nv_bfloat16 g_wl[(size_t)D4096 * 64];
__device__ __nv_bfloat16 g_woh[(size_t)64 * D4096];     // Wo^T hi  [n][k]
__device__ __nv_bfloat16 g_wol[(size_t)64 * D4096];     // Wo^T lo

__device__ __forceinline__ uint32_t smem_u32(const void* p) {
    uint32_t a;
    asm("{ .reg .u64 t; cvta.to.shared.u64 t, %1; cvt.u32.u64 %0, t; }"
        : "=r"(a) : "l"(p));
    return a;
}

#define CP_ASYNC16(saddr, gptr) \
    asm volatile("cp.async.cg.shared.global [%0], [%1], 16;" \
                 :: "r"(saddr), "l"(gptr) : "memory")
#define CP_COMMIT() asm volatile("cp.async.commit_group;" ::: "memory")
#define CP_WAIT(n)  asm volatile("cp.async.wait_group %0;" :: "n"(n) : "memory")

#define LDSM_X4(r0, r1, r2, r3, addr) \
    asm volatile("ldmatrix.sync.aligned.m8n8.x4.shared.b16 {%0,%1,%2,%3}, [%4];" \
                 : "=r"(r0), "=r"(r1), "=r"(r2), "=r"(r3) : "r"(addr))

#define MMA_BF16(c, a, b0, b1) \
    asm volatile( \
        "mma.sync.aligned.m16n8k16.row.col.f32.bf16.bf16.f32 " \
        "{%0,%1,%2,%3}, {%4,%5,%6,%7}, {%8,%9}, {%0,%1,%2,%3};" \
        : "+f"((c)[0]), "+f"((c)[1]), "+f"((c)[2]), "+f"((c)[3]) \
        : "r"((a)[0]), "r"((a)[1]), "r"((a)[2]), "r"((a)[3]), "r"(b0), "r"(b1))

#define MMA_F16(c, a, b0, b1) \
    asm volatile( \
        "mma.sync.aligned.m16n8k16.row.col.f32.f16.f16.f32 " \
        "{%0,%1,%2,%3}, {%4,%5,%6,%7}, {%8,%9}, {%0,%1,%2,%3};" \
        : "+f"((c)[0]), "+f"((c)[1]), "+f"((c)[2]), "+f"((c)[3]) \
        : "r"((a)[0]), "r"((a)[1]), "r"((a)[2]), "r"((a)[3]), "r"(b0), "r"(b1))

// ---------------------------------------------------------------------------
// fp32 -> bf16 hi/lo split
// ---------------------------------------------------------------------------
__global__ __launch_bounds__(256) void convert_split(
    const float* __restrict__ in, __nv_bfloat16* __restrict__ hi,
    __nv_bfloat16* __restrict__ lo)
{
    const size_t base = ((size_t)blockIdx.x * 256 + threadIdx.x) * 8;
    float4 a = *reinterpret_cast<const float4*>(in + base);
    float4 b = *reinterpret_cast<const float4*>(in + base + 4);
    float f[8] = {a.x, a.y, a.z, a.w, b.x, b.y, b.z, b.w};
    __nv_bfloat16 h[8], l[8];
#pragma unroll
    for (int i = 0; i < 8; i++) {
        h[i] = __float2bfloat16(f[i]);
        l[i] = __float2bfloat16(f[i] - __bfloat162float(h[i]));
    }
    *reinterpret_cast<uint4*>(hi + base) = *reinterpret_cast<uint4*>(h);
    *reinterpret_cast<uint4*>(lo + base) = *reinterpret_cast<uint4*>(l);
}

// ---------------------------------------------------------------------------
// fp32 -> fp16 hi/lo split (for query)
// ---------------------------------------------------------------------------
__global__ __launch_bounds__(256) void convert_split_h(
    const float* __restrict__ in, __half* __restrict__ hi,
    __half* __restrict__ lo)
{
    const size_t base = ((size_t)blockIdx.x * 256 + threadIdx.x) * 8;
    float4 a = *reinterpret_cast<const float4*>(in + base);
    float4 b = *reinterpret_cast<const float4*>(in + base + 4);
    float f[8] = {a.x, a.y, a.z, a.w, b.x, b.y, b.z, b.w};
    __half h[8], l[8];
#pragma unroll
    for (int i = 0; i < 8; i++) {
        h[i] = __float2half_rn(f[i]);
        l[i] = __float2half_rn(f[i] - __half2float(h[i]));
    }
    *reinterpret_cast<uint4*>(hi + base) = *reinterpret_cast<uint4*>(h);
    *reinterpret_cast<uint4*>(lo + base) = *reinterpret_cast<uint4*>(l);
}

// ---------------------------------------------------------------------------
// Wq (4096,4096) -> Wq^T (n,k) single fp16
// ---------------------------------------------------------------------------
__global__ __launch_bounds__(256) void transpose_h(
    const float* __restrict__ W, __half* __restrict__ out)
{
    __shared__ float ts[64][65];
    const int n0 = blockIdx.x * 64;
    const int k0 = blockIdx.y * 64;
    const int tid = threadIdx.x;
#pragma unroll
    for (int i = 0; i < 16; i++) {
        int idx = tid + i * 256;
        int r = idx >> 6, c = idx & 63;
        ts[r][c] = W[(size_t)(k0 + r) * D4096 + n0 + c];
    }
    __syncthreads();
#pragma unroll
    for (int i = 0; i < 8; i++) {
        int idx = tid + i * 256;
        int nl = idx >> 5, kl = (idx & 31) * 2;
        __half2 p;
        p.x = __float2half_rn(ts[kl][nl]);
        p.y = __float2half_rn(ts[kl + 1][nl]);
        *reinterpret_cast<__half2*>(out + (size_t)(n0 + nl) * D4096 + k0 + kl) = p;
    }
}

// ---------------------------------------------------------------------------
// W (64,4096) -> W^T (4096,64) bf16 hi/lo
// ---------------------------------------------------------------------------
__global__ __launch_bounds__(256) void transpose_w64(
    const float* __restrict__ W, __nv_bfloat16* __restrict__ hi,
    __nv_bfloat16* __restrict__ lo)
{
    __shared__ float ts[64][65];
    const int n0 = blockIdx.x * 64;
    const int tid = threadIdx.x;
    for (int t = tid; t < 4096; t += 256)
        ts[t >> 6][t & 63] = W[(size_t)(t >> 6) * D4096 + n0 + (t & 63)];
    __syncthreads();
    for (int t = tid; t < 4096; t += 256) {
        int nl = t >> 6, kl = t & 63;
        float f = ts[kl][nl];
        __nv_bfloat16 h = __float2bfloat16(f);
        hi[(size_t)(n0 + nl) * 64 + kl] = h;
        lo[(size_t)(n0 + nl) * 64 + kl] = __float2bfloat16(f - __bfloat162float(h));
    }
}

// ---------------------------------------------------------------------------
// Wo (4096,64) -> Wo^T (64,4096) bf16 hi/lo
// ---------------------------------------------------------------------------
__global__ __launch_bounds__(256) void transpose_wo(
    const float* __restrict__ W, __nv_bfloat16* __restrict__ hi,
    __nv_bfloat16* __restrict__ lo)
{
    __shared__ float ts[64][65];
    const int k0 = blockIdx.x * 64;
    const int tid = threadIdx.x;
    for (int t = tid; t < 4096; t += 256)
        ts[t >> 6][t & 63] = W[(size_t)(k0 + (t >> 6)) * 64 + (t & 63)];
    __syncthreads();
    for (int t = tid; t < 4096; t += 256) {
        int n = t >> 6, k = t & 63;
        float f = ts[k][n];
        __nv_bfloat16 h = __float2bfloat16(f);
        hi[(size_t)n * D4096 + k0 + k] = h;
        lo[(size_t)n * D4096 + k0 + k] = __float2bfloat16(f - __bfloat162float(h));
    }
}

// ---------------------------------------------------------------------------
// Main HMMA GEMM (fp16, 2 products): CTA 128x256, 256 thr (8 warps, 64x64),
// K-chunk 32, 3-stage. Buffers: Ah(10240) Al(10240) B(20480) = 40960 x3.
// ---------------------------------------------------------------------------
#define SA 80
#define A_TB 10240
#define B_TB 20480
#define BUF_B 40960
#define GQ_SMEM 122880

__global__ __launch_bounds__(256) void mma_gemm_q(
    const __half* __restrict__ Ah, const __half* __restrict__ Al,
    const __half* __restrict__ B,
    const float* __restrict__ bias, float* __restrict__ C)
{
    extern __shared__ char smem[];
    const uint32_t sb = smem_u32(smem);
    const int tid = threadIdx.x;
    const int warp = tid >> 5, lane = tid & 31;

    const int m0 = (blockIdx.x >> 4) * 128;
    const int n0 = (blockIdx.x & 15) * 256;

    const int wm = (warp & 1) * 64;
    const int wn = (warp >> 1) * 64;

    float c[4][8][4];
#pragma unroll
    for (int mt = 0; mt < 4; mt++)
#pragma unroll
        for (int nt = 0; nt < 8; nt++)
#pragma unroll
            for (int r = 0; r < 4; r++) c[mt][nt][r] = 0.0f;

    const int g = lane >> 3, r8 = lane & 7;
    const uint32_t a_off = (uint32_t)(wm + (g & 1) * 8 + r8) * SA + (g >> 1) * 16;
    const uint32_t b_off = 2 * A_TB + (uint32_t)(wn + (g >> 1) * 8 + r8) * SA + (g & 1) * 16;

    auto stage = [&](int chunk, int buf) {
        const int k0 = chunk * 32;
        const uint32_t base = sb + buf * BUF_B;
#pragma unroll
        for (int j = 0; j < 2; j++) {           // A: 128 rows x 4 chunks (hi+lo)
            const int idx = tid + j * 256;
            const int row = idx >> 2, kc = (idx & 3) * 16;
            const uint32_t sa = base + (uint32_t)row * SA + kc;
            const size_t ga = (size_t)(m0 + row) * D4096 + k0 + kc / 2;
            CP_ASYNC16(sa, Ah + ga);
            CP_ASYNC16(sa + A_TB, Al + ga);
        }
#pragma unroll
        for (int j = 0; j < 4; j++) {           // B: 256 rows x 4 chunks (single)
            const int idx = tid + j * 256;
            const int row = idx >> 2, kc = (idx & 3) * 16;
            const uint32_t sa = base + 2 * A_TB + (uint32_t)row * SA + kc;
            const size_t gb = (size_t)(n0 + row) * D4096 + k0 + kc / 2;
            CP_ASYNC16(sa, B + gb);
        }
        CP_COMMIT();
    };

    stage(0, 0);
    stage(1, 1);

    const int NIT = D4096 / 32;  // 128
    for (int it = 0; it < NIT; ++it) {
        if (it == NIT - 1) { CP_WAIT(0); } else { CP_WAIT(1); }
        __syncthreads();
        if (it + 2 < NIT) stage(it + 2, (it + 2) % 3);

        const uint32_t buf = sb + (it % 3) * BUF_B;
#pragma unroll
        for (int ks = 0; ks < 2; ++ks) {
            const uint32_t koff = ks * 32;
            uint32_t ah[4][4], al[4][4];
#pragma unroll
            for (int mt = 0; mt < 4; mt++) {
                const uint32_t aa = buf + a_off + koff + (uint32_t)mt * 16 * SA;
                LDSM_X4(ah[mt][0], ah[mt][1], ah[mt][2], ah[mt][3], aa);
                LDSM_X4(al[mt][0], al[mt][1], al[mt][2], al[mt][3], aa + A_TB);
            }
#pragma unroll
            for (int g4 = 0; g4 < 4; g4++) {
                uint32_t b4[4];
                const uint32_t ba = buf + b_off + koff + (uint32_t)g4 * 16 * SA;
                LDSM_X4(b4[0], b4[1], b4[2], b4[3], ba);
#pragma unroll
                for (int mt = 0; mt < 4; mt++) {
#pragma unroll
                    for (int sub = 0; sub < 2; sub++) {
                        const int nt = g4 * 2 + sub, h = sub * 2;
                        MMA_F16(c[mt][nt], ah[mt], b4[h], b4[h + 1]);
                        MMA_F16(c[mt][nt], al[mt], b4[h], b4[h + 1]);
                    }
                }
            }
        }
    }

    const int rbase = m0 + wm + (lane >> 2);
    const int cbase = n0 + wn + (lane & 3) * 2;
#pragma unroll
    for (int mt = 0; mt < 4; mt++) {
#pragma unroll
        for (int nt = 0; nt < 8; nt++) {
            const int col = cbase + nt * 8;
            const float b0 = bias[col], b1 = bias[col + 1];
            float* p0 = C + (size_t)(rbase + mt * 16) * D4096 + col;
            float* p1 = C + (size_t)(rbase + mt * 16 + 8) * D4096 + col;
            p0[0] = c[mt][nt][0] + b0;
            p0[1] = c[mt][nt][1] + b1;
            p1[0] = c[mt][nt][2] + b0;
            p1[1] = c[mt][nt][3] + b1;
        }
    }
}

// ---------------------------------------------------------------------------
// HMMA projection (K=64), bf16 3-product — unchanged
// ---------------------------------------------------------------------------
#define PSA 144
#define P_TB 18432
#define PROJ_SMEM 73728

__global__ __launch_bounds__(256) void mma_proj(
    const __nv_bfloat16* __restrict__ Xh, const __nv_bfloat16* __restrict__ Xl,
    const __nv_bfloat16* __restrict__ Wh, const __nv_bfloat16* __restrict__ Wl,
    const float* __restrict__ bias, float* __restrict__ out)
{
    extern __shared__ char smem[];
    const uint32_t sb = smem_u32(smem);
    const int tid = threadIdx.x;
    const int warp = tid >> 5, lane = tid & 31;
    const int m0 = blockIdx.y * 128;
    const int n0 = blockIdx.x * 128;
    const int wm = (warp & 3) * 32;
    const int wn = (warp >> 2) * 64;

#pragma unroll
    for (int j = 0; j < 4; j++) {
        const int idx = tid + j * 256;
        const int row = idx >> 3, kc = (idx & 7) * 16;
        const uint32_t sa = sb + (uint32_t)row * PSA + kc;
        const size_t gx = (size_t)(m0 + row) * 64 + kc / 2;
        const size_t gw = (size_t)(n0 + row) * 64 + kc / 2;
        CP_ASYNC16(sa, Xh + gx);
        CP_ASYNC16(sa + P_TB, Xl + gx);
        CP_ASYNC16(sa + 2 * P_TB, Wh + gw);
        CP_ASYNC16(sa + 3 * P_TB, Wl + gw);
    }
    CP_COMMIT();

    float c[2][8][4];
#pragma unroll
    for (int mt = 0; mt < 2; mt++)
#pragma unroll
        for (int nt = 0; nt < 8; nt++)
#pragma unroll
            for (int r = 0; r < 4; r++) c[mt][nt][r] = 0.0f;

    const int g = lane >> 3, r8 = lane & 7;
    const uint32_t a_off = (uint32_t)(wm + (g & 1) * 8 + r8) * PSA + (g >> 1) * 16;
    const uint32_t b_off = 2 * P_TB + (uint32_t)(wn + (g >> 1) * 8 + r8) * PSA + (g & 1) * 16;

    CP_WAIT(0);
    __syncthreads();

#pragma unroll
    for (int ks = 0; ks < 4; ++ks) {
        const uint32_t koff = ks * 32;
        uint32_t ah[2][4], al[2][4];
#pragma unroll
        for (int mt = 0; mt < 2; mt++) {
            const uint32_t aa = sb + a_off + koff + (uint32_t)mt * 16 * PSA;
            LDSM_X4(ah[mt][0], ah[mt][1], ah[mt][2], ah[mt][3], aa);
            LDSM_X4(al[mt][0], al[mt][1], al[mt][2], al[mt][3], aa + P_TB);
        }
#pragma unroll
        for (int g4 = 0; g4 < 4; g4++) {
            uint32_t bh4[4], bl4[4];
            const uint32_t ba = sb + b_off + koff + (uint32_t)g4 * 16 * PSA;
            LDSM_X4(bh4[0], bh4[1], bh4[2], bh4[3], ba);
            LDSM_X4(bl4[0], bl4[1], bl4[2], bl4[3], ba + P_TB);
#pragma unroll
            for (int mt = 0; mt < 2; mt++) {
#pragma unroll
                for (int sub = 0; sub < 2; sub++) {
                    const int nt = g4 * 2 + sub, h = sub * 2;
                    MMA_BF16(c[mt][nt], ah[mt], bh4[h], bh4[h + 1]);
                    MMA_BF16(c[mt][nt], ah[mt], bl4[h], bl4[h + 1]);
                    MMA_BF16(c[mt][nt], al[mt], bh4[h], bh4[h + 1]);
                }
            }
        }
    }

    const int rbase = m0 + wm + (lane >> 2);
    const int cbase = n0 + wn + (lane & 3) * 2;
#pragma unroll
    for (int mt = 0; mt < 2; mt++) {
#pragma unroll
        for (int nt = 0; nt < 8; nt++) {
            const int col = cbase + nt * 8;
            const float b0 = bias[col], b1 = bias[col + 1];
            float* p0 = out + (size_t)(rbase + mt * 16) * D4096 + col;
            float* p1 = out + (size_t)(rbase + mt * 16 + 8) * D4096 + col;
            p0[0] = c[mt][nt][0] + b0;
            p0[1] = c[mt][nt][1] + b1;
            p1[0] = c[mt][nt][2] + b0;
            p1[1] = c[mt][nt][3] + b1;
        }
    }
}

// ---------------------------------------------------------------------------
// per-token attention; emits bf16 hi/lo for the HMMA output GEMM
// ---------------------------------------------------------------------------
__global__ __launch_bounds__(256, 4) void attn_kernel(
    const float* __restrict__ mask_u,
    __nv_bfloat16* __restrict__ oh, __nv_bfloat16* __restrict__ ol)
{
    __shared__ float smA[4352];
    __shared__ float smB[4352];

    const int s = blockIdx.x;
    const int tid = threadIdx.x;
    const int tr = tid >> 4;
    const int tc = tid & 15;
    const float* qrow = g_q + (size_t)s * 4096;
    const float* krow = g_k + (size_t)s * 4096;
    const float* vrow = g_v + (size_t)s * 4096;

    for (int t = tid; t < 1024; t += 256)
        reinterpret_cast<float4*>(smA)[t] = reinterpret_cast<const float4*>(qrow)[t];
    for (int t = tid; t < 4096; t += 256)
        smB[(t & 63) * 68 + (t >> 6)] = krow[t];
    __syncthreads();

    float lg[4][4];
#pragma unroll
    for (int a = 0; a < 4; a++)
#pragma unroll
        for (int b = 0; b < 4; b++) lg[a][b] = 0.0f;
#pragma unroll 8
    for (int h = 0; h < 64; h++) {
        const float4 qv = *reinterpret_cast<const float4*>(smA + h * 64 + tr * 4);
        const float4 kv = *reinterpret_cast<const float4*>(smB + h * 68 + tc * 4);
        const float qa[4] = {qv.x, qv.y, qv.z, qv.w};
        const float kb[4] = {kv.x, kv.y, kv.z, kv.w};
#pragma unroll
        for (int a = 0; a < 4; a++)
#pragma unroll
            for (int b = 0; b < 4; b++) lg[a][b] += qa[a] * kb[b];
    }

    float lse[4];
#pragma unroll
    for (int a = 0; a < 4; a++) {
        float mx = fmaxf(fmaxf(lg[a][0], lg[a][1]), fmaxf(lg[a][2], lg[a][3]));
        mx = fmaxf(mx, __shfl_xor_sync(0xffffffffu, mx, 1));
        mx = fmaxf(mx, __shfl_xor_sync(0xffffffffu, mx, 2));
        mx = fmaxf(mx, __shfl_xor_sync(0xffffffffu, mx, 4));
        mx = fmaxf(mx, __shfl_xor_sync(0xffffffffu, mx, 8));
        float se = __expf(lg[a][0] - mx) + __expf(lg[a][1] - mx) +
                   __expf(lg[a][2] - mx) + __expf(lg[a][3] - mx);
        se += __shfl_xor_sync(0xffffffffu, se, 1);
        se += __shfl_xor_sync(0xffffffffu, se, 2);
        se += __shfl_xor_sync(0xffffffffu, se, 4);
        se += __shfl_xor_sync(0xffffffffu, se, 8);
        lse[a] = mx + __logf(se);
    }

#pragma unroll
    for (int a = 0; a < 4; a++) {
        const float4 mv = *reinterpret_cast<const float4*>(
            mask_u + ((size_t)s * 64 + tr * 4 + a) * 64 + tc * 4);
        const float mm[4] = {mv.x, mv.y, mv.z, mv.w};
#pragma unroll
        for (int b = 0; b < 4; b++) {
            const float keep = (mm[b] > 0.25f) ? (1.0f / 0.75f) : 0.0f;
            lg[a][b] = (lg[a][b] - lse[a]) * keep;
        }
    }

    __syncthreads();

#pragma unroll
    for (int a = 0; a < 4; a++) {
        float4 w;
        w.x = lg[a][0]; w.y = lg[a][1]; w.z = lg[a][2]; w.w = lg[a][3];
        *reinterpret_cast<float4*>(smB + (tr * 4 + a) * 68 + tc * 4) = w;
    }
    for (int t = tid; t < 4096; t += 256)
        smA[(t & 63) * 68 + (t >> 6)] = vrow[t];
    __syncthreads();

    float acc[4][4];
#pragma unroll
    for (int a = 0; a < 4; a++)
#pragma unroll
        for (int b = 0; b < 4; b++) acc[a][b] = 0.0f;
#pragma unroll 8
    for (int m = 0; m < 64; m++) {
        const float4 vv = *reinterpret_cast<const float4*>(smA + m * 68 + tc * 4);
        const float vb[4] = {vv.x, vv.y, vv.z, vv.w};
#pragma unroll
        for (int a = 0; a < 4; a++) {
            const float av = smB[(tr * 4 + a) * 68 + m];
#pragma unroll
            for (int b = 0; b < 4; b++) acc[a][b] += av * vb[b];
        }
    }

#pragma unroll
    for (int a = 0; a < 4; a++) {
        const size_t o = (size_t)s * 4096 + (tr * 4 + a) * 64 + tc * 4;
        __nv_bfloat16 h[4], l[4];
#pragma unroll
        for (int b = 0; b < 4; b++) {
            h[b] = __float2bfloat16(acc[a][b]);
            l[b] = __float2bfloat16(acc[a][b] - __bfloat162float(h[b]));
        }
        *reinterpret_cast<uint2*>(oh + o) = *reinterpret_cast<uint2*>(h);
        *reinterpret_cast<uint2*>(ol + o) = *reinterpret_cast<uint2*>(l);
    }
}

// ---------------------------------------------------------------------------
// output GEMM via HMMA, split-K=8 — unchanged
// ---------------------------------------------------------------------------
#define OSA 80
#define OA_TB 10240
#define OB_TB 5120
#define OBUF 30720
#define GO_SMEM 61440

__global__ __launch_bounds__(256) void gemm_out_mma(
    const __nv_bfloat16* __restrict__ Ahp, const __nv_bfloat16* __restrict__ Alp,
    const __nv_bfloat16* __restrict__ Wh, const __nv_bfloat16* __restrict__ Wl,
    float* __restrict__ part)
{
    extern __shared__ char smem[];
    const uint32_t sb = smem_u32(smem);
    const int tid = threadIdx.x;
    const int warp = tid >> 5, lane = tid & 31;
    const int m0 = blockIdx.x * 128;
    const int ksp = blockIdx.y;
    const int kbase = ksp * 512;
    const int wm = (warp & 3) * 32;
    const int wn = (warp >> 2) * 32;

    float c[2][4][4];
#pragma unroll
    for (int mt = 0; mt < 2; mt++)
#pragma unroll
        for (int nt = 0; nt < 4; nt++)
#pragma unroll
            for (int r = 0; r < 4; r++) c[mt][nt][r] = 0.0f;

    const int g = lane >> 3, r8 = lane & 7;
    const uint32_t a_off = (uint32_t)(wm + (g & 1) * 8 + r8) * OSA + (g >> 1) * 16;
    const uint32_t b_off = 2 * OA_TB + (uint32_t)(wn + (g >> 1) * 8 + r8) * OSA + (g & 1) * 16;

    auto stage = [&](int chunk, int buf) {
        const int k0 = kbase + chunk * 32;
        const uint32_t base = sb + buf * OBUF;
#pragma unroll
        for (int j = 0; j < 2; j++) {
            const int idx = tid + j * 256;
            const int row = idx >> 2, kc = (idx & 3) * 16;
            const uint32_t sa = base + (uint32_t)row * OSA + kc;
            const size_t ga = (size_t)(m0 + row) * D4096 + k0 + kc / 2;
            CP_ASYNC16(sa, Ahp + ga);
            CP_ASYNC16(sa + OA_TB, Alp + ga);
        }
        {
            const int row = tid >> 2, kc = (tid & 3) * 16;
            const uint32_t sa = base + 2 * OA_TB + (uint32_t)row * OSA + kc;
            const size_t gb = (size_t)row * D4096 + k0 + kc / 2;
            CP_ASYNC16(sa, Wh + gb);
            CP_ASYNC16(sa + OB_TB, Wl + gb);
        }
        CP_COMMIT();
    };

    stage(0, 0);

    for (int it = 0; it < 16; ++it) {
        if (it + 1 < 16) {
            stage(it + 1, (it + 1) & 1);
            CP_WAIT(1);
        } else {
            CP_WAIT(0);
        }
        __syncthreads();

        const uint32_t buf = sb + (it & 1) * OBUF;
#pragma unroll
        for (int ks = 0; ks < 2; ++ks) {
            const uint32_t koff = ks * 32;
            uint32_t ah[2][4], al[2][4];
#pragma unroll
            for (int mt = 0; mt < 2; mt++) {
                const uint32_t aa = buf + a_off + koff + (uint32_t)mt * 16 * OSA;
                LDSM_X4(ah[mt][0], ah[mt][1], ah[mt][2], ah[mt][3], aa);
                LDSM_X4(al[mt][0], al[mt][1], al[mt][2], al[mt][3], aa + OA_TB);
            }
#pragma unroll
            for (int g4 = 0; g4 < 2; g4++) {
                uint32_t bh4[4], bl4[4];
                const uint32_t ba = buf + b_off + koff + (uint32_t)g4 * 16 * OSA;
                LDSM_X4(bh4[0], bh4[1], bh4[2], bh4[3], ba);
                LDSM_X4(bl4[0], bl4[1], bl4[2], bl4[3], ba + OB_TB);
#pragma unroll
                for (int mt = 0; mt < 2; mt++) {
#pragma unroll
                    for (int sub = 0; sub < 2; sub++) {
                        const int nt = g4 * 2 + sub, h = sub * 2;
                        MMA_BF16(c[mt][nt], ah[mt], bh4[h], bh4[h + 1]);
                        MMA_BF16(c[mt][nt], ah[mt], bl4[h], bl4[h + 1]);
                        MMA_BF16(c[mt][nt], al[mt], bh4[h], bh4[h + 1]);
                    }
                }
            }
        }
        __syncthreads();
    }

    float* pbase = part + (size_t)ksp * S_LEN * 64;
    const int rbase = m0 + wm + (lane >> 2);
    const int cbase = wn + (lane & 3) * 2;
#pragma unroll
    for (int mt = 0; mt < 2; mt++) {
#pragma unroll
        for (int nt = 0; nt < 4; nt++) {
            const int col = cbase + nt * 8;
            float* p0 = pbase + (size_t)(rbase + mt * 16) * 64 + col;
            float* p1 = pbase + (size_t)(rbase + mt * 16 + 8) * 64 + col;
            p0[0] = c[mt][nt][0];
            p0[1] = c[mt][nt][1];
            p1[0] = c[mt][nt][2];
            p1[1] = c[mt][nt][3];
        }
    }
}

__global__ __launch_bounds__(256) void gemm_out_reduce(
    const float* __restrict__ part, const float* __restrict__ bias,
    float* __restrict__ out)
{
    const size_t i = (size_t)blockIdx.x * 256 + threadIdx.x;
    float s = bias[i & 63];
#pragma unroll
    for (int k = 0; k < 8; k++) s += part[i + (size_t)k * S_LEN * 64];
    out[i] = s;
}

// ---------------------------------------------------------------------------
// Launch
// ---------------------------------------------------------------------------
extern "C" void kernel_launch(void* const* d_in, const int* in_sizes, int n_in,
                              void* d_out, int out_size)
{
    const float* query  = (const float*)d_in[0];
    const float* key_in = (const float*)d_in[1];
    const float* value  = (const float*)d_in[2];
    const float* mask_u = (const float*)d_in[3];
    const float* Wq = (const float*)d_in[4];
    const float* bq = (const float*)d_in[5];
    const float* Wk = (const float*)d_in[6];
    const float* bk = (const float*)d_in[7];
    const float* Wv = (const float*)d_in[8];
    const float* bv = (const float*)d_in[9];
    const float* Wo = (const float*)d_in[10];
    const float* bo = (const float*)d_in[11];
    float* out = (float*)d_out;

    float *gq, *gk, *gv;
    __nv_bfloat16 *ah, *al, *bh, *xh, *xl, *wh, *wl, *woh, *wol;
    cudaGetSymbolAddress((void**)&gq, g_q);
    cudaGetSymbolAddress((void**)&gk, g_k);
    cudaGetSymbolAddress((void**)&gv, g_v);
    cudaGetSymbolAddress((void**)&ah, g_Ah);
    cudaGetSymbolAddress((void**)&al, g_Al);
    cudaGetSymbolAddress((void**)&bh, g_Bh);
    cudaGetSymbolAddress((void**)&xh, g_xh);
    cudaGetSymbolAddress((void**)&xl, g_xl);
    cudaGetSymbolAddress((void**)&wh, g_wh);
    cudaGetSymbolAddress((void**)&wl, g_wl);
    cudaGetSymbolAddress((void**)&woh, g_woh);
    cudaGetSymbolAddress((void**)&wol, g_wol);

    cudaFuncSetAttribute(mma_gemm_q, cudaFuncAttributeMaxDynamicSharedMemorySize, GQ_SMEM);
    cudaFuncSetAttribute(mma_proj, cudaFuncAttributeMaxDynamicSharedMemorySize, PROJ_SMEM);
    cudaFuncSetAttribute(gemm_out_mma, cudaFuncAttributeMaxDynamicSharedMemorySize, GO_SMEM);

    // Q projection: fp16 2-product
    convert_split_h<<<(S_LEN * (size_t)D4096) / 2048, 256>>>(
        query, (__half*)ah, (__half*)al);
    transpose_h<<<dim3(64, 64), 256>>>(Wq, (__half*)bh);
    mma_gemm_q<<<1024, 256, GQ_SMEM>>>((__half*)ah, (__half*)al, (__half*)bh, bq, gq);

    // K projection (bf16 3-product)
    convert_split<<<(S_LEN * 64) / 2048, 256>>>(key_in, xh, xl);
    transpose_w64<<<64, 256>>>(Wk, wh, wl);
    mma_proj<<<dim3(D4096 / 128, S_LEN / 128), 256, PROJ_SMEM>>>(xh, xl, wh, wl, bk, gk);

    // V projection
    convert_split<<<(S_LEN * 64) / 2048, 256>>>(value, xh, xl);
    transpose_w64<<<64, 256>>>(Wv, wh, wl);
    mma_proj<<<dim3(D4096 / 128, S_LEN / 128), 256, PROJ_SMEM>>>(xh, xl, wh, wl, bv, gv);

    // Wo transpose/split
    transpose_wo<<<64, 256>>>(Wo, woh, wol);

    // attention (reuses g_Ah/g_Al as bf16 hi/lo output)
    attn_kernel<<<S_LEN, 256>>>(mask_u, ah, al);

    // output GEMM: split-K=8, partials in g_Bh scratch
    float* part = (float*)bh;
    gemm_out_mma<<<dim3(S_LEN / 128, 8), 256, GO_SMEM>>>(ah, al, woh, wol, part);
    gemm_out_reduce<<<(S_LEN * 64) / 256, 256>>>(part, bo, out);
}

// round 10
// speedup vs baseline: 3.6056x; 1.0395x over previous
#include <cuda_runtime.h>
#include <cuda_bf16.h>
#include <cuda_fp16.h>
#include <cstdint>

#define S_LEN 8192
#define D4096 4096

__device__ float g_q[(size_t)S_LEN * D4096];
__device__ float g_k[(size_t)S_LEN * D4096];
__device__ float g_v[(size_t)S_LEN * D4096];
__device__ __half g_Ah[(size_t)S_LEN * D4096];    // query hi; later attn-out hi
__device__ __half g_Al[(size_t)S_LEN * D4096];    // query lo; later attn-out lo
__device__ __half g_B[(size_t)D4096 * D4096];     // Wq^T fp16; later fp32 split-K partials
__device__ __half g_xh[(size_t)S_LEN * 64];
__device__ __half g_xl[(size_t)S_LEN * 64];
__device__ __half g_w[(size_t)D4096 * 64];        // Wk^T / Wv^T fp16 (reused)
__device__ __half g_wo[(size_t)64 * D4096];       // Wo^T fp16 [n][k]

__device__ __forceinline__ uint32_t smem_u32(const void* p) {
    uint32_t a;
    asm("{ .reg .u64 t; cvta.to.shared.u64 t, %1; cvt.u32.u64 %0, t; }"
        : "=r"(a) : "l"(p));
    return a;
}

#define CP_ASYNC16(saddr, gptr) \
    asm volatile("cp.async.cg.shared.global [%0], [%1], 16;" \
                 :: "r"(saddr), "l"(gptr) : "memory")
#define CP_COMMIT() asm volatile("cp.async.commit_group;" ::: "memory")
#define CP_WAIT(n)  asm volatile("cp.async.wait_group %0;" :: "n"(n) : "memory")

#define LDSM_X4(r0, r1, r2, r3, addr) \
    asm volatile("ldmatrix.sync.aligned.m8n8.x4.shared.b16 {%0,%1,%2,%3}, [%4];" \
                 : "=r"(r0), "=r"(r1), "=r"(r2), "=r"(r3) : "r"(addr))

#define MMA_F16(c, a, b0, b1) \
    asm volatile( \
        "mma.sync.aligned.m16n8k16.row.col.f32.f16.f16.f32 " \
        "{%0,%1,%2,%3}, {%4,%5,%6,%7}, {%8,%9}, {%0,%1,%2,%3};" \
        : "+f"((c)[0]), "+f"((c)[1]), "+f"((c)[2]), "+f"((c)[3]) \
        : "r"((a)[0]), "r"((a)[1]), "r"((a)[2]), "r"((a)[3]), "r"(b0), "r"(b1))

// ---------------------------------------------------------------------------
// fp32 -> fp16 hi/lo split
// ---------------------------------------------------------------------------
__global__ __launch_bounds__(256) void convert_split_h(
    const float* __restrict__ in, __half* __restrict__ hi,
    __half* __restrict__ lo)
{
    const size_t base = ((size_t)blockIdx.x * 256 + threadIdx.x) * 8;
    float4 a = *reinterpret_cast<const float4*>(in + base);
    float4 b = *reinterpret_cast<const float4*>(in + base + 4);
    float f[8] = {a.x, a.y, a.z, a.w, b.x, b.y, b.z, b.w};
    __half h[8], l[8];
#pragma unroll
    for (int i = 0; i < 8; i++) {
        h[i] = __float2half_rn(f[i]);
        l[i] = __float2half_rn(f[i] - __half2float(h[i]));
    }
    *reinterpret_cast<uint4*>(hi + base) = *reinterpret_cast<uint4*>(h);
    *reinterpret_cast<uint4*>(lo + base) = *reinterpret_cast<uint4*>(l);
}

// ---------------------------------------------------------------------------
// Wq (4096,4096) -> Wq^T (n,k) single fp16
// ---------------------------------------------------------------------------
__global__ __launch_bounds__(256) void transpose_h(
    const float* __restrict__ W, __half* __restrict__ out)
{
    __shared__ float ts[64][65];
    const int n0 = blockIdx.x * 64;
    const int k0 = blockIdx.y * 64;
    const int tid = threadIdx.x;
#pragma unroll
    for (int i = 0; i < 16; i++) {
        int idx = tid + i * 256;
        int r = idx >> 6, c = idx & 63;
        ts[r][c] = W[(size_t)(k0 + r) * D4096 + n0 + c];
    }
    __syncthreads();
#pragma unroll
    for (int i = 0; i < 8; i++) {
        int idx = tid + i * 256;
        int nl = idx >> 5, kl = (idx & 31) * 2;
        __half2 p;
        p.x = __float2half_rn(ts[kl][nl]);
        p.y = __float2half_rn(ts[kl + 1][nl]);
        *reinterpret_cast<__half2*>(out + (size_t)(n0 + nl) * D4096 + k0 + kl) = p;
    }
}

// ---------------------------------------------------------------------------
// W (64,4096) -> W^T (4096,64) single fp16
// ---------------------------------------------------------------------------
__global__ __launch_bounds__(256) void transpose_w64_h(
    const float* __restrict__ W, __half* __restrict__ out)
{
    __shared__ float ts[64][65];
    const int n0 = blockIdx.x * 64;
    const int tid = threadIdx.x;
    for (int t = tid; t < 4096; t += 256)
        ts[t >> 6][t & 63] = W[(size_t)(t >> 6) * D4096 + n0 + (t & 63)];
    __syncthreads();
    for (int t = tid; t < 4096; t += 256) {
        int nl = t >> 6, kl = t & 63;
        out[(size_t)(n0 + nl) * 64 + kl] = __float2half_rn(ts[kl][nl]);
    }
}

// ---------------------------------------------------------------------------
// Wo (4096,64) -> Wo^T (64,4096) single fp16
// ---------------------------------------------------------------------------
__global__ __launch_bounds__(256) void transpose_wo_h(
    const float* __restrict__ W, __half* __restrict__ out)
{
    __shared__ float ts[64][65];
    const int k0 = blockIdx.x * 64;
    const int tid = threadIdx.x;
    for (int t = tid; t < 4096; t += 256)
        ts[t >> 6][t & 63] = W[(size_t)(k0 + (t >> 6)) * 64 + (t & 63)];
    __syncthreads();
    for (int t = tid; t < 4096; t += 256) {
        int n = t >> 6, k = t & 63;
        out[(size_t)n * D4096 + k0 + k] = __float2half_rn(ts[k][n]);
    }
}

// ---------------------------------------------------------------------------
// Main HMMA GEMM (fp16, 2 products): CTA 128x256, 256 thr (8 warps, 64x64),
// K-chunk 32, 3-stage. Buffers: Ah(10240) Al(10240) B(20480) = 40960 x3.
// ---------------------------------------------------------------------------
#define SA 80
#define A_TB 10240
#define B_TB 20480
#define BUF_B 40960
#define GQ_SMEM 122880

__global__ __launch_bounds__(256) void mma_gemm_q(
    const __half* __restrict__ Ah, const __half* __restrict__ Al,
    const __half* __restrict__ B,
    const float* __restrict__ bias, float* __restrict__ C)
{
    extern __shared__ char smem[];
    const uint32_t sb = smem_u32(smem);
    const int tid = threadIdx.x;
    const int warp = tid >> 5, lane = tid & 31;

    const int m0 = (blockIdx.x >> 4) * 128;
    const int n0 = (blockIdx.x & 15) * 256;

    const int wm = (warp & 1) * 64;
    const int wn = (warp >> 1) * 64;

    float c[4][8][4];
#pragma unroll
    for (int mt = 0; mt < 4; mt++)
#pragma unroll
        for (int nt = 0; nt < 8; nt++)
#pragma unroll
            for (int r = 0; r < 4; r++) c[mt][nt][r] = 0.0f;

    const int g = lane >> 3, r8 = lane & 7;
    const uint32_t a_off = (uint32_t)(wm + (g & 1) * 8 + r8) * SA + (g >> 1) * 16;
    const uint32_t b_off = 2 * A_TB + (uint32_t)(wn + (g >> 1) * 8 + r8) * SA + (g & 1) * 16;

    auto stage = [&](int chunk, int buf) {
        const int k0 = chunk * 32;
        const uint32_t base = sb + buf * BUF_B;
#pragma unroll
        for (int j = 0; j < 2; j++) {           // A: 128 rows x 4 chunks (hi+lo)
            const int idx = tid + j * 256;
            const int row = idx >> 2, kc = (idx & 3) * 16;
            const uint32_t sa = base + (uint32_t)row * SA + kc;
            const size_t ga = (size_t)(m0 + row) * D4096 + k0 + kc / 2;
            CP_ASYNC16(sa, Ah + ga);
            CP_ASYNC16(sa + A_TB, Al + ga);
        }
#pragma unroll
        for (int j = 0; j < 4; j++) {           // B: 256 rows x 4 chunks (single)
            const int idx = tid + j * 256;
            const int row = idx >> 2, kc = (idx & 3) * 16;
            const uint32_t sa = base + 2 * A_TB + (uint32_t)row * SA + kc;
            const size_t gb = (size_t)(n0 + row) * D4096 + k0 + kc / 2;
            CP_ASYNC16(sa, B + gb);
        }
        CP_COMMIT();
    };

    stage(0, 0);
    stage(1, 1);

    const int NIT = D4096 / 32;  // 128
    for (int it = 0; it < NIT; ++it) {
        if (it == NIT - 1) { CP_WAIT(0); } else { CP_WAIT(1); }
        __syncthreads();
        if (it + 2 < NIT) stage(it + 2, (it + 2) % 3);

        const uint32_t buf = sb + (it % 3) * BUF_B;
#pragma unroll
        for (int ks = 0; ks < 2; ++ks) {
            const uint32_t koff = ks * 32;
            uint32_t ah[4][4], al[4][4];
#pragma unroll
            for (int mt = 0; mt < 4; mt++) {
                const uint32_t aa = buf + a_off + koff + (uint32_t)mt * 16 * SA;
                LDSM_X4(ah[mt][0], ah[mt][1], ah[mt][2], ah[mt][3], aa);
                LDSM_X4(al[mt][0], al[mt][1], al[mt][2], al[mt][3], aa + A_TB);
            }
#pragma unroll
            for (int g4 = 0; g4 < 4; g4++) {
                uint32_t b4[4];
                const uint32_t ba = buf + b_off + koff + (uint32_t)g4 * 16 * SA;
                LDSM_X4(b4[0], b4[1], b4[2], b4[3], ba);
#pragma unroll
                for (int mt = 0; mt < 4; mt++) {
#pragma unroll
                    for (int sub = 0; sub < 2; sub++) {
                        const int nt = g4 * 2 + sub, h = sub * 2;
                        MMA_F16(c[mt][nt], ah[mt], b4[h], b4[h + 1]);
                        MMA_F16(c[mt][nt], al[mt], b4[h], b4[h + 1]);
                    }
                }
            }
        }
    }

    const int rbase = m0 + wm + (lane >> 2);
    const int cbase = n0 + wn + (lane & 3) * 2;
#pragma unroll
    for (int mt = 0; mt < 4; mt++) {
#pragma unroll
        for (int nt = 0; nt < 8; nt++) {
            const int col = cbase + nt * 8;
            const float b0 = bias[col], b1 = bias[col + 1];
            float* p0 = C + (size_t)(rbase + mt * 16) * D4096 + col;
            float* p1 = C + (size_t)(rbase + mt * 16 + 8) * D4096 + col;
            p0[0] = c[mt][nt][0] + b0;
            p0[1] = c[mt][nt][1] + b1;
            p1[0] = c[mt][nt][2] + b0;
            p1[1] = c[mt][nt][3] + b1;
        }
    }
}

// ---------------------------------------------------------------------------
// HMMA projection (K=64), fp16 2-product: X hi/lo, W single.
// CTA 128x128, 256 thr (8 warps: 4m x 2n, warp 32x64).
// SMEM: Xh, Xl, W tiles, each 128 rows x 144B = 18432; total 55296.
// ---------------------------------------------------------------------------
#define PSA 144
#define P_TB 18432
#define PROJ_SMEM 55296

__global__ __launch_bounds__(256) void mma_proj_h(
    const __half* __restrict__ Xh, const __half* __restrict__ Xl,
    const __half* __restrict__ W,
    const float* __restrict__ bias, float* __restrict__ out)
{
    extern __shared__ char smem[];
    const uint32_t sb = smem_u32(smem);
    const int tid = threadIdx.x;
    const int warp = tid >> 5, lane = tid & 31;
    const int m0 = blockIdx.y * 128;
    const int n0 = blockIdx.x * 128;
    const int wm = (warp & 3) * 32;
    const int wn = (warp >> 2) * 64;

#pragma unroll
    for (int j = 0; j < 4; j++) {
        const int idx = tid + j * 256;
        const int row = idx >> 3, kc = (idx & 7) * 16;
        const uint32_t sa = sb + (uint32_t)row * PSA + kc;
        const size_t gx = (size_t)(m0 + row) * 64 + kc / 2;
        const size_t gw = (size_t)(n0 + row) * 64 + kc / 2;
        CP_ASYNC16(sa, Xh + gx);
        CP_ASYNC16(sa + P_TB, Xl + gx);
        CP_ASYNC16(sa + 2 * P_TB, W + gw);
    }
    CP_COMMIT();

    float c[2][8][4];
#pragma unroll
    for (int mt = 0; mt < 2; mt++)
#pragma unroll
        for (int nt = 0; nt < 8; nt++)
#pragma unroll
            for (int r = 0; r < 4; r++) c[mt][nt][r] = 0.0f;

    const int g = lane >> 3, r8 = lane & 7;
    const uint32_t a_off = (uint32_t)(wm + (g & 1) * 8 + r8) * PSA + (g >> 1) * 16;
    const uint32_t b_off = 2 * P_TB + (uint32_t)(wn + (g >> 1) * 8 + r8) * PSA + (g & 1) * 16;

    CP_WAIT(0);
    __syncthreads();

#pragma unroll
    for (int ks = 0; ks < 4; ++ks) {
        const uint32_t koff = ks * 32;
        uint32_t ah[2][4], al[2][4];
#pragma unroll
        for (int mt = 0; mt < 2; mt++) {
            const uint32_t aa = sb + a_off + koff + (uint32_t)mt * 16 * PSA;
            LDSM_X4(ah[mt][0], ah[mt][1], ah[mt][2], ah[mt][3], aa);
            LDSM_X4(al[mt][0], al[mt][1], al[mt][2], al[mt][3], aa + P_TB);
        }
#pragma unroll
        for (int g4 = 0; g4 < 4; g4++) {
            uint32_t b4[4];
            const uint32_t ba = sb + b_off + koff + (uint32_t)g4 * 16 * PSA;
            LDSM_X4(b4[0], b4[1], b4[2], b4[3], ba);
#pragma unroll
            for (int mt = 0; mt < 2; mt++) {
#pragma unroll
                for (int sub = 0; sub < 2; sub++) {
                    const int nt = g4 * 2 + sub, h = sub * 2;
                    MMA_F16(c[mt][nt], ah[mt], b4[h], b4[h + 1]);
                    MMA_F16(c[mt][nt], al[mt], b4[h], b4[h + 1]);
                }
            }
        }
    }

    const int rbase = m0 + wm + (lane >> 2);
    const int cbase = n0 + wn + (lane & 3) * 2;
#pragma unroll
    for (int mt = 0; mt < 2; mt++) {
#pragma unroll
        for (int nt = 0; nt < 8; nt++) {
            const int col = cbase + nt * 8;
            const float b0 = bias[col], b1 = bias[col + 1];
            float* p0 = out + (size_t)(rbase + mt * 16) * D4096 + col;
            float* p1 = out + (size_t)(rbase + mt * 16 + 8) * D4096 + col;
            p0[0] = c[mt][nt][0] + b0;
            p0[1] = c[mt][nt][1] + b1;
            p1[0] = c[mt][nt][2] + b0;
            p1[1] = c[mt][nt][3] + b1;
        }
    }
}

// ---------------------------------------------------------------------------
// per-token attention; emits fp16 hi/lo for the output GEMM
// ---------------------------------------------------------------------------
__global__ __launch_bounds__(256, 6) void attn_kernel(
    const float* __restrict__ mask_u,
    __half* __restrict__ oh, __half* __restrict__ ol)
{
    __shared__ float smA[4352];
    __shared__ float smB[4352];

    const int s = blockIdx.x;
    const int tid = threadIdx.x;
    const int tr = tid >> 4;
    const int tc = tid & 15;
    const float* qrow = g_q + (size_t)s * 4096;
    const float* krow = g_k + (size_t)s * 4096;
    const float* vrow = g_v + (size_t)s * 4096;

    for (int t = tid; t < 1024; t += 256)
        reinterpret_cast<float4*>(smA)[t] = reinterpret_cast<const float4*>(qrow)[t];
    for (int t = tid; t < 4096; t += 256)
        smB[(t & 63) * 68 + (t >> 6)] = krow[t];
    __syncthreads();

    float lg[4][4];
#pragma unroll
    for (int a = 0; a < 4; a++)
#pragma unroll
        for (int b = 0; b < 4; b++) lg[a][b] = 0.0f;
#pragma unroll 8
    for (int h = 0; h < 64; h++) {
        const float4 qv = *reinterpret_cast<const float4*>(smA + h * 64 + tr * 4);
        const float4 kv = *reinterpret_cast<const float4*>(smB + h * 68 + tc * 4);
        const float qa[4] = {qv.x, qv.y, qv.z, qv.w};
        const float kb[4] = {kv.x, kv.y, kv.z, kv.w};
#pragma unroll
        for (int a = 0; a < 4; a++)
#pragma unroll
            for (int b = 0; b < 4; b++) lg[a][b] += qa[a] * kb[b];
    }

    float lse[4];
#pragma unroll
    for (int a = 0; a < 4; a++) {
        float mx = fmaxf(fmaxf(lg[a][0], lg[a][1]), fmaxf(lg[a][2], lg[a][3]));
        mx = fmaxf(mx, __shfl_xor_sync(0xffffffffu, mx, 1));
        mx = fmaxf(mx, __shfl_xor_sync(0xffffffffu, mx, 2));
        mx = fmaxf(mx, __shfl_xor_sync(0xffffffffu, mx, 4));
        mx = fmaxf(mx, __shfl_xor_sync(0xffffffffu, mx, 8));
        float se = __expf(lg[a][0] - mx) + __expf(lg[a][1] - mx) +
                   __expf(lg[a][2] - mx) + __expf(lg[a][3] - mx);
        se += __shfl_xor_sync(0xffffffffu, se, 1);
        se += __shfl_xor_sync(0xffffffffu, se, 2);
        se += __shfl_xor_sync(0xffffffffu, se, 4);
        se += __shfl_xor_sync(0xffffffffu, se, 8);
        lse[a] = mx + __logf(se);
    }

#pragma unroll
    for (int a = 0; a < 4; a++) {
        const float4 mv = *reinterpret_cast<const float4*>(
            mask_u + ((size_t)s * 64 + tr * 4 + a) * 64 + tc * 4);
        const float mm[4] = {mv.x, mv.y, mv.z, mv.w};
#pragma unroll
        for (int b = 0; b < 4; b++) {
            const float keep = (mm[b] > 0.25f) ? (1.0f / 0.75f) : 0.0f;
            lg[a][b] = (lg[a][b] - lse[a]) * keep;
        }
    }

    __syncthreads();

#pragma unroll
    for (int a = 0; a < 4; a++) {
        float4 w;
        w.x = lg[a][0]; w.y = lg[a][1]; w.z = lg[a][2]; w.w = lg[a][3];
        *reinterpret_cast<float4*>(smB + (tr * 4 + a) * 68 + tc * 4) = w;
    }
    for (int t = tid; t < 4096; t += 256)
        smA[(t & 63) * 68 + (t >> 6)] = vrow[t];
    __syncthreads();

    float acc[4][4];
#pragma unroll
    for (int a = 0; a < 4; a++)
#pragma unroll
        for (int b = 0; b < 4; b++) acc[a][b] = 0.0f;
#pragma unroll 8
    for (int m = 0; m < 64; m++) {
        const float4 vv = *reinterpret_cast<const float4*>(smA + m * 68 + tc * 4);
        const float vb[4] = {vv.x, vv.y, vv.z, vv.w};
#pragma unroll
        for (int a = 0; a < 4; a++) {
            const float av = smB[(tr * 4 + a) * 68 + m];
#pragma unroll
            for (int b = 0; b < 4; b++) acc[a][b] += av * vb[b];
        }
    }

#pragma unroll
    for (int a = 0; a < 4; a++) {
        const size_t o = (size_t)s * 4096 + (tr * 4 + a) * 64 + tc * 4;
        __half h[4], l[4];
#pragma unroll
        for (int b = 0; b < 4; b++) {
            h[b] = __float2half_rn(acc[a][b]);
            l[b] = __float2half_rn(acc[a][b] - __half2float(h[b]));
        }
        *reinterpret_cast<uint2*>(oh + o) = *reinterpret_cast<uint2*>(h);
        *reinterpret_cast<uint2*>(ol + o) = *reinterpret_cast<uint2*>(l);
    }
}

// ---------------------------------------------------------------------------
// output GEMM via HMMA fp16 2-product, split-K=8
// ---------------------------------------------------------------------------
#define OSA 80
#define OA_TB 10240
#define OB_TB 5120
#define OBUF 25600
#define GO_SMEM 51200

__global__ __launch_bounds__(256) void gemm_out_mma(
    const __half* __restrict__ Ahp, const __half* __restrict__ Alp,
    const __half* __restrict__ W,
    float* __restrict__ part)
{
    extern __shared__ char smem[];
    const uint32_t sb = smem_u32(smem);
    const int tid = threadIdx.x;
    const int warp = tid >> 5, lane = tid & 31;
    const int m0 = blockIdx.x * 128;
    const int ksp = blockIdx.y;
    const int kbase = ksp * 512;
    const int wm = (warp & 3) * 32;
    const int wn = (warp >> 2) * 32;

    float c[2][4][4];
#pragma unroll
    for (int mt = 0; mt < 2; mt++)
#pragma unroll
        for (int nt = 0; nt < 4; nt++)
#pragma unroll
            for (int r = 0; r < 4; r++) c[mt][nt][r] = 0.0f;

    const int g = lane >> 3, r8 = lane & 7;
    const uint32_t a_off = (uint32_t)(wm + (g & 1) * 8 + r8) * OSA + (g >> 1) * 16;
    const uint32_t b_off = 2 * OA_TB + (uint32_t)(wn + (g >> 1) * 8 + r8) * OSA + (g & 1) * 16;

    auto stage = [&](int chunk, int buf) {
        const int k0 = kbase + chunk * 32;
        const uint32_t base = sb + buf * OBUF;
#pragma unroll
        for (int j = 0; j < 2; j++) {
            const int idx = tid + j * 256;
            const int row = idx >> 2, kc = (idx & 3) * 16;
            const uint32_t sa = base + (uint32_t)row * OSA + kc;
            const size_t ga = (size_t)(m0 + row) * D4096 + k0 + kc / 2;
            CP_ASYNC16(sa, Ahp + ga);
            CP_ASYNC16(sa + OA_TB, Alp + ga);
        }
        {
            const int row = tid >> 2, kc = (tid & 3) * 16;
            const uint32_t sa = base + 2 * OA_TB + (uint32_t)row * OSA + kc;
            const size_t gb = (size_t)row * D4096 + k0 + kc / 2;
            CP_ASYNC16(sa, W + gb);
        }
        CP_COMMIT();
    };

    stage(0, 0);

    for (int it = 0; it < 16; ++it) {
        if (it + 1 < 16) {
            stage(it + 1, (it + 1) & 1);
            CP_WAIT(1);
        } else {
            CP_WAIT(0);
        }
        __syncthreads();

        const uint32_t buf = sb + (it & 1) * OBUF;
#pragma unroll
        for (int ks = 0; ks < 2; ++ks) {
            const uint32_t koff = ks * 32;
            uint32_t ah[2][4], al[2][4];
#pragma unroll
            for (int mt = 0; mt < 2; mt++) {
                const uint32_t aa = buf + a_off + koff + (uint32_t)mt * 16 * OSA;
                LDSM_X4(ah[mt][0], ah[mt][1], ah[mt][2], ah[mt][3], aa);
                LDSM_X4(al[mt][0], al[mt][1], al[mt][2], al[mt][3], aa + OA_TB);
            }
#pragma unroll
            for (int g4 = 0; g4 < 2; g4++) {
                uint32_t b4[4];
                const uint32_t ba = buf + b_off + koff + (uint32_t)g4 * 16 * OSA;
                LDSM_X4(b4[0], b4[1], b4[2], b4[3], ba);
#pragma unroll
                for (int mt = 0; mt < 2; mt++) {
#pragma unroll
                    for (int sub = 0; sub < 2; sub++) {
                        const int nt = g4 * 2 + sub, h = sub * 2;
                        MMA_F16(c[mt][nt], ah[mt], b4[h], b4[h + 1]);
                        MMA_F16(c[mt][nt], al[mt], b4[h], b4[h + 1]);
                    }
                }
            }
        }
        __syncthreads();
    }

    float* pbase = part + (size_t)ksp * S_LEN * 64;
    const int rbase = m0 + wm + (lane >> 2);
    const int cbase = wn + (lane & 3) * 2;
#pragma unroll
    for (int mt = 0; mt < 2; mt++) {
#pragma unroll
        for (int nt = 0; nt < 4; nt++) {
            const int col = cbase + nt * 8;
            float* p0 = pbase + (size_t)(rbase + mt * 16) * 64 + col;
            float* p1 = pbase + (size_t)(rbase + mt * 16 + 8) * 64 + col;
            p0[0] = c[mt][nt][0];
            p0[1] = c[mt][nt][1];
            p1[0] = c[mt][nt][2];
            p1[1] = c[mt][nt][3];
        }
    }
}

__global__ __launch_bounds__(256) void gemm_out_reduce(
    const float* __restrict__ part, const float* __restrict__ bias,
    float* __restrict__ out)
{
    const size_t i = (size_t)blockIdx.x * 256 + threadIdx.x;
    float s = bias[i & 63];
#pragma unroll
    for (int k = 0; k < 8; k++) s += part[i + (size_t)k * S_LEN * 64];
    out[i] = s;
}

// ---------------------------------------------------------------------------
// Launch
// ---------------------------------------------------------------------------
extern "C" void kernel_launch(void* const* d_in, const int* in_sizes, int n_in,
                              void* d_out, int out_size)
{
    const float* query  = (const float*)d_in[0];
    const float* key_in = (const float*)d_in[1];
    const float* value  = (const float*)d_in[2];
    const float* mask_u = (const float*)d_in[3];
    const float* Wq = (const float*)d_in[4];
    const float* bq = (const float*)d_in[5];
    const float* Wk = (const float*)d_in[6];
    const float* bk = (const float*)d_in[7];
    const float* Wv = (const float*)d_in[8];
    const float* bv = (const float*)d_in[9];
    const float* Wo = (const float*)d_in[10];
    const float* bo = (const float*)d_in[11];
    float* out = (float*)d_out;

    float *gq, *gk, *gv;
    __half *ah, *al, *b, *xh, *xl, *w, *wo;
    cudaGetSymbolAddress((void**)&gq, g_q);
    cudaGetSymbolAddress((void**)&gk, g_k);
    cudaGetSymbolAddress((void**)&gv, g_v);
    cudaGetSymbolAddress((void**)&ah, g_Ah);
    cudaGetSymbolAddress((void**)&al, g_Al);
    cudaGetSymbolAddress((void**)&b, g_B);
    cudaGetSymbolAddress((void**)&xh, g_xh);
    cudaGetSymbolAddress((void**)&xl, g_xl);
    cudaGetSymbolAddress((void**)&w, g_w);
    cudaGetSymbolAddress((void**)&wo, g_wo);

    cudaFuncSetAttribute(mma_gemm_q, cudaFuncAttributeMaxDynamicSharedMemorySize, GQ_SMEM);
    cudaFuncSetAttribute(mma_proj_h, cudaFuncAttributeMaxDynamicSharedMemorySize, PROJ_SMEM);
    cudaFuncSetAttribute(gemm_out_mma, cudaFuncAttributeMaxDynamicSharedMemorySize, GO_SMEM);

    // Q projection: fp16 2-product
    convert_split_h<<<(S_LEN * (size_t)D4096) / 2048, 256>>>(query, ah, al);
    transpose_h<<<dim3(64, 64), 256>>>(Wq, b);
    mma_gemm_q<<<1024, 256, GQ_SMEM>>>(ah, al, b, bq, gq);

    // K projection: fp16 2-product
    convert_split_h<<<(S_LEN * 64) / 2048, 256>>>(key_in, xh, xl);
    transpose_w64_h<<<64, 256>>>(Wk, w);
    mma_proj_h<<<dim3(D4096 / 128, S_LEN / 128), 256, PROJ_SMEM>>>(xh, xl, w, bk, gk);

    // V projection: fp16 2-product
    convert_split_h<<<(S_LEN * 64) / 2048, 256>>>(value, xh, xl);
    transpose_w64_h<<<64, 256>>>(Wv, w);
    mma_proj_h<<<dim3(D4096 / 128, S_LEN / 128), 256, PROJ_SMEM>>>(xh, xl, w, bv, gv);

    // Wo transpose
    transpose_wo_h<<<64, 256>>>(Wo, wo);

    // attention (emits fp16 hi/lo into g_Ah/g_Al, free after mma_gemm_q)
    attn_kernel<<<S_LEN, 256>>>(mask_u, ah, al);

    // output GEMM: fp16 2-product split-K=8, partials in g_B scratch
    float* part = (float*)b;
    gemm_out_mma<<<dim3(S_LEN / 128, 8), 256, GO_SMEM>>>(ah, al, wo, part);
    gemm_out_reduce<<<(S_LEN * 64) / 256, 256>>>(part, bo, out);
}

// round 11
// speedup vs baseline: 3.7775x; 1.0477x over previous
#include <cuda_runtime.h>
#include <cuda_bf16.h>
#include <cuda_fp16.h>
#include <cstdint>

#define S_LEN 8192
#define D4096 4096

__device__ float g_q[(size_t)S_LEN * D4096];
__device__ float g_k[(size_t)S_LEN * D4096];
__device__ float g_v[(size_t)S_LEN * D4096];
__device__ __half g_Ah[(size_t)S_LEN * D4096];    // query hi; later attn-out hi
__device__ __half g_Al[(size_t)S_LEN * D4096];    // query lo; later attn-out lo
__device__ __half g_B[(size_t)D4096 * D4096];     // Wq^T fp16; later fp32 split-K partials
__device__ __half g_xh[(size_t)S_LEN * 64];
__device__ __half g_xl[(size_t)S_LEN * 64];
__device__ __half g_w[(size_t)D4096 * 64];
__device__ __half g_wo[(size_t)64 * D4096];

__device__ __forceinline__ uint32_t smem_u32(const void* p) {
    uint32_t a;
    asm("{ .reg .u64 t; cvta.to.shared.u64 t, %1; cvt.u32.u64 %0, t; }"
        : "=r"(a) : "l"(p));
    return a;
}

#define CP_ASYNC16(saddr, gptr) \
    asm volatile("cp.async.cg.shared.global [%0], [%1], 16;" \
                 :: "r"(saddr), "l"(gptr) : "memory")
#define CP_COMMIT() asm volatile("cp.async.commit_group;" ::: "memory")
#define CP_WAIT(n)  asm volatile("cp.async.wait_group %0;" :: "n"(n) : "memory")

#define LDSM_X4(r0, r1, r2, r3, addr) \
    asm volatile("ldmatrix.sync.aligned.m8n8.x4.shared.b16 {%0,%1,%2,%3}, [%4];" \
                 : "=r"(r0), "=r"(r1), "=r"(r2), "=r"(r3) : "r"(addr))

#define LDSM_X4_T(r0, r1, r2, r3, addr) \
    asm volatile("ldmatrix.sync.aligned.m8n8.x4.trans.shared.b16 {%0,%1,%2,%3}, [%4];" \
                 : "=r"(r0), "=r"(r1), "=r"(r2), "=r"(r3) : "r"(addr))

#define MMA_F16(c, a, b0, b1) \
    asm volatile( \
        "mma.sync.aligned.m16n8k16.row.col.f32.f16.f16.f32 " \
        "{%0,%1,%2,%3}, {%4,%5,%6,%7}, {%8,%9}, {%0,%1,%2,%3};" \
        : "+f"((c)[0]), "+f"((c)[1]), "+f"((c)[2]), "+f"((c)[3]) \
        : "r"((a)[0]), "r"((a)[1]), "r"((a)[2]), "r"((a)[3]), "r"(b0), "r"(b1))

// fast exp on FFMA pipe (rel err ~4e-5); avoids the MUFU rt=8 floor
__device__ __forceinline__ float fexpf(float x) {
    x = fmaxf(x, -87.0f);
    float y = x * 1.4426950408889634f;
    float n = rintf(y);
    float f = y - n;
    float p = 1.3337294e-3f;
    p = fmaf(p, f, 9.6181291e-3f);
    p = fmaf(p, f, 5.5504109e-2f);
    p = fmaf(p, f, 2.4022651e-1f);
    p = fmaf(p, f, 6.9314718e-1f);
    p = fmaf(p, f, 1.0f);
    return p * __int_as_float((__float2int_rn(n) + 127) << 23);
}

__device__ __forceinline__ uint32_t pack2h(float a, float b) {
    __half2 h = __floats2half2_rn(a, b);
    return *reinterpret_cast<uint32_t*>(&h);
}

// ---------------------------------------------------------------------------
// fp32 -> fp16 hi/lo split
// ---------------------------------------------------------------------------
__global__ __launch_bounds__(256) void convert_split_h(
    const float* __restrict__ in, __half* __restrict__ hi,
    __half* __restrict__ lo)
{
    const size_t base = ((size_t)blockIdx.x * 256 + threadIdx.x) * 8;
    float4 a = *reinterpret_cast<const float4*>(in + base);
    float4 b = *reinterpret_cast<const float4*>(in + base + 4);
    float f[8] = {a.x, a.y, a.z, a.w, b.x, b.y, b.z, b.w};
    __half h[8], l[8];
#pragma unroll
    for (int i = 0; i < 8; i++) {
        h[i] = __float2half_rn(f[i]);
        l[i] = __float2half_rn(f[i] - __half2float(h[i]));
    }
    *reinterpret_cast<uint4*>(hi + base) = *reinterpret_cast<uint4*>(h);
    *reinterpret_cast<uint4*>(lo + base) = *reinterpret_cast<uint4*>(l);
}

// ---------------------------------------------------------------------------
// Wq -> Wq^T fp16
// ---------------------------------------------------------------------------
__global__ __launch_bounds__(256) void transpose_h(
    const float* __restrict__ W, __half* __restrict__ out)
{
    __shared__ float ts[64][65];
    const int n0 = blockIdx.x * 64;
    const int k0 = blockIdx.y * 64;
    const int tid = threadIdx.x;
#pragma unroll
    for (int i = 0; i < 16; i++) {
        int idx = tid + i * 256;
        int r = idx >> 6, c = idx & 63;
        ts[r][c] = W[(size_t)(k0 + r) * D4096 + n0 + c];
    }
    __syncthreads();
#pragma unroll
    for (int i = 0; i < 8; i++) {
        int idx = tid + i * 256;
        int nl = idx >> 5, kl = (idx & 31) * 2;
        __half2 p;
        p.x = __float2half_rn(ts[kl][nl]);
        p.y = __float2half_rn(ts[kl + 1][nl]);
        *reinterpret_cast<__half2*>(out + (size_t)(n0 + nl) * D4096 + k0 + kl) = p;
    }
}

__global__ __launch_bounds__(256) void transpose_w64_h(
    const float* __restrict__ W, __half* __restrict__ out)
{
    __shared__ float ts[64][65];
    const int n0 = blockIdx.x * 64;
    const int tid = threadIdx.x;
    for (int t = tid; t < 4096; t += 256)
        ts[t >> 6][t & 63] = W[(size_t)(t >> 6) * D4096 + n0 + (t & 63)];
    __syncthreads();
    for (int t = tid; t < 4096; t += 256) {
        int nl = t >> 6, kl = t & 63;
        out[(size_t)(n0 + nl) * 64 + kl] = __float2half_rn(ts[kl][nl]);
    }
}

__global__ __launch_bounds__(256) void transpose_wo_h(
    const float* __restrict__ W, __half* __restrict__ out)
{
    __shared__ float ts[64][65];
    const int k0 = blockIdx.x * 64;
    const int tid = threadIdx.x;
    for (int t = tid; t < 4096; t += 256)
        ts[t >> 6][t & 63] = W[(size_t)(k0 + (t >> 6)) * 64 + (t & 63)];
    __syncthreads();
    for (int t = tid; t < 4096; t += 256) {
        int n = t >> 6, k = t & 63;
        out[(size_t)n * D4096 + k0 + k] = __float2half_rn(ts[k][n]);
    }
}

// ---------------------------------------------------------------------------
// Main HMMA GEMM (fp16, 2 products) — unchanged from R10
// ---------------------------------------------------------------------------
#define SA 80
#define A_TB 10240
#define B_TB 20480
#define BUF_B 40960
#define GQ_SMEM 122880

__global__ __launch_bounds__(256) void mma_gemm_q(
    const __half* __restrict__ Ah, const __half* __restrict__ Al,
    const __half* __restrict__ B,
    const float* __restrict__ bias, float* __restrict__ C)
{
    extern __shared__ char smem[];
    const uint32_t sb = smem_u32(smem);
    const int tid = threadIdx.x;
    const int warp = tid >> 5, lane = tid & 31;

    const int m0 = (blockIdx.x >> 4) * 128;
    const int n0 = (blockIdx.x & 15) * 256;

    const int wm = (warp & 1) * 64;
    const int wn = (warp >> 1) * 64;

    float c[4][8][4];
#pragma unroll
    for (int mt = 0; mt < 4; mt++)
#pragma unroll
        for (int nt = 0; nt < 8; nt++)
#pragma unroll
            for (int r = 0; r < 4; r++) c[mt][nt][r] = 0.0f;

    const int g = lane >> 3, r8 = lane & 7;
    const uint32_t a_off = (uint32_t)(wm + (g & 1) * 8 + r8) * SA + (g >> 1) * 16;
    const uint32_t b_off = 2 * A_TB + (uint32_t)(wn + (g >> 1) * 8 + r8) * SA + (g & 1) * 16;

    auto stage = [&](int chunk, int buf) {
        const int k0 = chunk * 32;
        const uint32_t base = sb + buf * BUF_B;
#pragma unroll
        for (int j = 0; j < 2; j++) {
            const int idx = tid + j * 256;
            const int row = idx >> 2, kc = (idx & 3) * 16;
            const uint32_t sa = base + (uint32_t)row * SA + kc;
            const size_t ga = (size_t)(m0 + row) * D4096 + k0 + kc / 2;
            CP_ASYNC16(sa, Ah + ga);
            CP_ASYNC16(sa + A_TB, Al + ga);
        }
#pragma unroll
        for (int j = 0; j < 4; j++) {
            const int idx = tid + j * 256;
            const int row = idx >> 2, kc = (idx & 3) * 16;
            const uint32_t sa = base + 2 * A_TB + (uint32_t)row * SA + kc;
            const size_t gb = (size_t)(n0 + row) * D4096 + k0 + kc / 2;
            CP_ASYNC16(sa, B + gb);
        }
        CP_COMMIT();
    };

    stage(0, 0);
    stage(1, 1);

    const int NIT = D4096 / 32;
    for (int it = 0; it < NIT; ++it) {
        if (it == NIT - 1) { CP_WAIT(0); } else { CP_WAIT(1); }
        __syncthreads();
        if (it + 2 < NIT) stage(it + 2, (it + 2) % 3);

        const uint32_t buf = sb + (it % 3) * BUF_B;
#pragma unroll
        for (int ks = 0; ks < 2; ++ks) {
            const uint32_t koff = ks * 32;
            uint32_t ah[4][4], al[4][4];
#pragma unroll
            for (int mt = 0; mt < 4; mt++) {
                const uint32_t aa = buf + a_off + koff + (uint32_t)mt * 16 * SA;
                LDSM_X4(ah[mt][0], ah[mt][1], ah[mt][2], ah[mt][3], aa);
                LDSM_X4(al[mt][0], al[mt][1], al[mt][2], al[mt][3], aa + A_TB);
            }
#pragma unroll
            for (int g4 = 0; g4 < 4; g4++) {
                uint32_t b4[4];
                const uint32_t ba = buf + b_off + koff + (uint32_t)g4 * 16 * SA;
                LDSM_X4(b4[0], b4[1], b4[2], b4[3], ba);
#pragma unroll
                for (int mt = 0; mt < 4; mt++) {
#pragma unroll
                    for (int sub = 0; sub < 2; sub++) {
                        const int nt = g4 * 2 + sub, h = sub * 2;
                        MMA_F16(c[mt][nt], ah[mt], b4[h], b4[h + 1]);
                        MMA_F16(c[mt][nt], al[mt], b4[h], b4[h + 1]);
                    }
                }
            }
        }
    }

    const int rbase = m0 + wm + (lane >> 2);
    const int cbase = n0 + wn + (lane & 3) * 2;
#pragma unroll
    for (int mt = 0; mt < 4; mt++) {
#pragma unroll
        for (int nt = 0; nt < 8; nt++) {
            const int col = cbase + nt * 8;
            const float b0 = bias[col], b1 = bias[col + 1];
            float* p0 = C + (size_t)(rbase + mt * 16) * D4096 + col;
            float* p1 = C + (size_t)(rbase + mt * 16 + 8) * D4096 + col;
            p0[0] = c[mt][nt][0] + b0;
            p0[1] = c[mt][nt][1] + b1;
            p1[0] = c[mt][nt][2] + b0;
            p1[1] = c[mt][nt][3] + b1;
        }
    }
}

// ---------------------------------------------------------------------------
// HMMA projection (K=64), fp16 2-product — unchanged from R10
// ---------------------------------------------------------------------------
#define PSA 144
#define P_TB 18432
#define PROJ_SMEM 55296

__global__ __launch_bounds__(256) void mma_proj_h(
    const __half* __restrict__ Xh, const __half* __restrict__ Xl,
    const __half* __restrict__ W,
    const float* __restrict__ bias, float* __restrict__ out)
{
    extern __shared__ char smem[];
    const uint32_t sb = smem_u32(smem);
    const int tid = threadIdx.x;
    const int warp = tid >> 5, lane = tid & 31;
    const int m0 = blockIdx.y * 128;
    const int n0 = blockIdx.x * 128;
    const int wm = (warp & 3) * 32;
    const int wn = (warp >> 2) * 64;

#pragma unroll
    for (int j = 0; j < 4; j++) {
        const int idx = tid + j * 256;
        const int row = idx >> 3, kc = (idx & 7) * 16;
        const uint32_t sa = sb + (uint32_t)row * PSA + kc;
        const size_t gx = (size_t)(m0 + row) * 64 + kc / 2;
        const size_t gw = (size_t)(n0 + row) * 64 + kc / 2;
        CP_ASYNC16(sa, Xh + gx);
        CP_ASYNC16(sa + P_TB, Xl + gx);
        CP_ASYNC16(sa + 2 * P_TB, W + gw);
    }
    CP_COMMIT();

    float c[2][8][4];
#pragma unroll
    for (int mt = 0; mt < 2; mt++)
#pragma unroll
        for (int nt = 0; nt < 8; nt++)
#pragma unroll
            for (int r = 0; r < 4; r++) c[mt][nt][r] = 0.0f;

    const int g = lane >> 3, r8 = lane & 7;
    const uint32_t a_off = (uint32_t)(wm + (g & 1) * 8 + r8) * PSA + (g >> 1) * 16;
    const uint32_t b_off = 2 * P_TB + (uint32_t)(wn + (g >> 1) * 8 + r8) * PSA + (g & 1) * 16;

    CP_WAIT(0);
    __syncthreads();

#pragma unroll
    for (int ks = 0; ks < 4; ++ks) {
        const uint32_t koff = ks * 32;
        uint32_t ah[2][4], al[2][4];
#pragma unroll
        for (int mt = 0; mt < 2; mt++) {
            const uint32_t aa = sb + a_off + koff + (uint32_t)mt * 16 * PSA;
            LDSM_X4(ah[mt][0], ah[mt][1], ah[mt][2], ah[mt][3], aa);
            LDSM_X4(al[mt][0], al[mt][1], al[mt][2], al[mt][3], aa + P_TB);
        }
#pragma unroll
        for (int g4 = 0; g4 < 4; g4++) {
            uint32_t b4[4];
            const uint32_t ba = sb + b_off + koff + (uint32_t)g4 * 16 * PSA;
            LDSM_X4(b4[0], b4[1], b4[2], b4[3], ba);
#pragma unroll
            for (int mt = 0; mt < 2; mt++) {
#pragma unroll
                for (int sub = 0; sub < 2; sub++) {
                    const int nt = g4 * 2 + sub, h = sub * 2;
                    MMA_F16(c[mt][nt], ah[mt], b4[h], b4[h + 1]);
                    MMA_F16(c[mt][nt], al[mt], b4[h], b4[h + 1]);
                }
            }
        }
    }

    const int rbase = m0 + wm + (lane >> 2);
    const int cbase = n0 + wn + (lane & 3) * 2;
#pragma unroll
    for (int mt = 0; mt < 2; mt++) {
#pragma unroll
        for (int nt = 0; nt < 8; nt++) {
            const int col = cbase + nt * 8;
            const float b0 = bias[col], b1 = bias[col + 1];
            float* p0 = out + (size_t)(rbase + mt * 16) * D4096 + col;
            float* p1 = out + (size_t)(rbase + mt * 16 + 8) * D4096 + col;
            p0[0] = c[mt][nt][0] + b0;
            p0[1] = c[mt][nt][1] + b1;
            p1[0] = c[mt][nt][2] + b0;
            p1[1] = c[mt][nt][3] + b1;
        }
    }
}

// ---------------------------------------------------------------------------
// Tensorized per-token attention. One token per 128-thr CTA (4 warps x 16 rows).
//   QK: A = q^T via ldmatrix.trans on q stored [h][i]; B = k stored [j][h].
//   3-product fp16 (qh*kh + ql*kh + qh*kl).
//   log-softmax on fragments with polynomial exp; dropout scale.
//   PV: A = at fragments in-register (hi/lo); B = v stored [j][m] (hi/lo).
//   Emits fp16 hi/lo to g_Ah/g_Al.
// smem: sm[0]=qh->vh, sm[1]=ql->vl, sm[2]=kh, sm[3]=kl; row stride 72 halves.
// ---------------------------------------------------------------------------
#define AST 144   // bytes per smem row (72 halves)

__global__ __launch_bounds__(128, 4) void attn_mma(
    const float* __restrict__ mask_u,
    __half* __restrict__ oh, __half* __restrict__ ol)
{
    __shared__ __half sm[4][64 * 72];

    const int s = blockIdx.x;
    const int tid = threadIdx.x;
    const int w = tid >> 5, lane = tid & 31;
    const int gid = lane >> 2, tig = lane & 3;

    const uint32_t sq = smem_u32(sm[0]);
    const uint32_t sk = smem_u32(sm[2]);
    const uint32_t HB = 64 * 72 * 2;  // bytes per buffer (9216)

    // ---- stage q (as stored: row h, col i) and k (row j, col h), hi/lo ----
    {
        const float4* qf = reinterpret_cast<const float4*>(g_q + (size_t)s * 4096);
        const float4* kf = reinterpret_cast<const float4*>(g_k + (size_t)s * 4096);
        for (int t = tid; t < 1024; t += 128) {
            const int row = t >> 4, col = (t & 15) * 4;
            const int off = row * 72 + col;
            float4 qv = qf[t];
            float fq[4] = {qv.x, qv.y, qv.z, qv.w};
            __half h[4], l[4];
#pragma unroll
            for (int i = 0; i < 4; i++) {
                h[i] = __float2half_rn(fq[i]);
                l[i] = __float2half_rn(fq[i] - __half2float(h[i]));
            }
            *reinterpret_cast<uint2*>(&sm[0][off]) = *reinterpret_cast<uint2*>(h);
            *reinterpret_cast<uint2*>(&sm[1][off]) = *reinterpret_cast<uint2*>(l);
            float4 kv = kf[t];
            float fk[4] = {kv.x, kv.y, kv.z, kv.w};
#pragma unroll
            for (int i = 0; i < 4; i++) {
                h[i] = __float2half_rn(fk[i]);
                l[i] = __float2half_rn(fk[i] - __half2float(h[i]));
            }
            *reinterpret_cast<uint2*>(&sm[2][off]) = *reinterpret_cast<uint2*>(h);
            *reinterpret_cast<uint2*>(&sm[3][off]) = *reinterpret_cast<uint2*>(l);
        }
    }
    __syncthreads();

    // ldmatrix lane offsets
    const int lg = lane >> 3, lr = lane & 7;
    // A (trans): storage row = h, col = i
    const uint32_t atoff = (uint32_t)((lg >> 1) * 8 + lr) * AST +
                           (uint32_t)(w * 16 + (lg & 1) * 8) * 2;
    // B (direct): storage row = n (j or m), col = k
    const uint32_t boff = (uint32_t)((lg >> 1) * 8 + lr) * AST + (uint32_t)(lg & 1) * 16;

    // ---- QK: logits fragments c[nt][4], warp rows i = w*16..w*16+15, cols 64 ----
    float c[8][4];
#pragma unroll
    for (int nt = 0; nt < 8; nt++)
#pragma unroll
        for (int r = 0; r < 4; r++) c[nt][r] = 0.0f;

#pragma unroll
    for (int kc = 0; kc < 4; kc++) {
        uint32_t aq = sq + (uint32_t)kc * 16 * AST + atoff;
        uint32_t ah[4], al[4];
        LDSM_X4_T(ah[0], ah[1], ah[2], ah[3], aq);
        LDSM_X4_T(al[0], al[1], al[2], al[3], aq + HB);
#pragma unroll
        for (int g4 = 0; g4 < 4; g4++) {
            uint32_t bh4[4], bl4[4];
            uint32_t bk = sk + (uint32_t)g4 * 16 * AST + boff + kc * 32;
            LDSM_X4(bh4[0], bh4[1], bh4[2], bh4[3], bk);
            LDSM_X4(bl4[0], bl4[1], bl4[2], bl4[3], bk + HB);
#pragma unroll
            for (int sub = 0; sub < 2; sub++) {
                const int nt = g4 * 2 + sub, h = sub * 2;
                MMA_F16(c[nt], ah, bh4[h], bh4[h + 1]);
                MMA_F16(c[nt], al, bh4[h], bh4[h + 1]);
                MMA_F16(c[nt], ah, bl4[h], bl4[h + 1]);
            }
        }
    }

    // ---- row-wise log-softmax (rows r0 = w*16+gid, r1 = r0+8) ----
    float mx0 = -1e30f, mx1 = -1e30f;
#pragma unroll
    for (int nt = 0; nt < 8; nt++) {
        mx0 = fmaxf(mx0, fmaxf(c[nt][0], c[nt][1]));
        mx1 = fmaxf(mx1, fmaxf(c[nt][2], c[nt][3]));
    }
    mx0 = fmaxf(mx0, __shfl_xor_sync(0xffffffffu, mx0, 1));
    mx0 = fmaxf(mx0, __shfl_xor_sync(0xffffffffu, mx0, 2));
    mx1 = fmaxf(mx1, __shfl_xor_sync(0xffffffffu, mx1, 1));
    mx1 = fmaxf(mx1, __shfl_xor_sync(0xffffffffu, mx1, 2));
    float se0 = 0.0f, se1 = 0.0f;
#pragma unroll
    for (int nt = 0; nt < 8; nt++) {
        se0 += fexpf(c[nt][0] - mx0) + fexpf(c[nt][1] - mx0);
        se1 += fexpf(c[nt][2] - mx1) + fexpf(c[nt][3] - mx1);
    }
    se0 += __shfl_xor_sync(0xffffffffu, se0, 1);
    se0 += __shfl_xor_sync(0xffffffffu, se0, 2);
    se1 += __shfl_xor_sync(0xffffffffu, se1, 1);
    se1 += __shfl_xor_sync(0xffffffffu, se1, 2);
    const float lse0 = mx0 + __logf(se0);
    const float lse1 = mx1 + __logf(se1);

    // ---- dropout + convert to fp16 hi/lo A-fragments ----
    const int r0 = w * 16 + gid;
    const float* m0p = mask_u + ((size_t)s * 64 + r0) * 64 + tig * 2;
    const float* m1p = m0p + 8 * 64;
    uint32_t ath0[8], atl0[8], ath1[8], atl1[8];
#pragma unroll
    for (int nt = 0; nt < 8; nt++) {
        const float2 mv0 = *reinterpret_cast<const float2*>(m0p + nt * 8);
        const float2 mv1 = *reinterpret_cast<const float2*>(m1p + nt * 8);
        float v0 = (c[nt][0] - lse0) * ((mv0.x > 0.25f) ? (1.0f / 0.75f) : 0.0f);
        float v1 = (c[nt][1] - lse0) * ((mv0.y > 0.25f) ? (1.0f / 0.75f) : 0.0f);
        float v2 = (c[nt][2] - lse1) * ((mv1.x > 0.25f) ? (1.0f / 0.75f) : 0.0f);
        float v3 = (c[nt][3] - lse1) * ((mv1.y > 0.25f) ? (1.0f / 0.75f) : 0.0f);
        __half h0 = __float2half_rn(v0), h1 = __float2half_rn(v1);
        __half h2 = __float2half_rn(v2), h3 = __float2half_rn(v3);
        ath0[nt] = ((uint32_t)__half_as_ushort(h1) << 16) | __half_as_ushort(h0);
        ath1[nt] = ((uint32_t)__half_as_ushort(h3) << 16) | __half_as_ushort(h2);
        atl0[nt] = pack2h(v0 - __half2float(h0), v1 - __half2float(h1));
        atl1[nt] = pack2h(v2 - __half2float(h2), v3 - __half2float(h3));
    }

    // ---- stage v over q buffers ----
    __syncthreads();
    {
        const float4* vf = reinterpret_cast<const float4*>(g_v + (size_t)s * 4096);
        for (int t = tid; t < 1024; t += 128) {
            const int row = t >> 4, col = (t & 15) * 4;
            const int off = row * 72 + col;
            float4 vv = vf[t];
            float fv[4] = {vv.x, vv.y, vv.z, vv.w};
            __half h[4], l[4];
#pragma unroll
            for (int i = 0; i < 4; i++) {
                h[i] = __float2half_rn(fv[i]);
                l[i] = __float2half_rn(fv[i] - __half2float(h[i]));
            }
            *reinterpret_cast<uint2*>(&sm[0][off]) = *reinterpret_cast<uint2*>(h);
            *reinterpret_cast<uint2*>(&sm[1][off]) = *reinterpret_cast<uint2*>(l);
        }
    }
    __syncthreads();

    // ---- PV: out[i][j] = sum_m at[i][m] * v[j][m]; 3 products ----
    float o[8][4];
#pragma unroll
    for (int nt = 0; nt < 8; nt++)
#pragma unroll
        for (int r = 0; r < 4; r++) o[nt][r] = 0.0f;

#pragma unroll
    for (int mc = 0; mc < 4; mc++) {
        uint32_t Ah2[4] = {ath0[2 * mc], ath1[2 * mc], ath0[2 * mc + 1], ath1[2 * mc + 1]};
        uint32_t Al2[4] = {atl0[2 * mc], atl1[2 * mc], atl0[2 * mc + 1], atl1[2 * mc + 1]};
#pragma unroll
        for (int g4 = 0; g4 < 4; g4++) {
            uint32_t vh4[4], vl4[4];
            uint32_t bv = sq + (uint32_t)g4 * 16 * AST + boff + mc * 32;
            LDSM_X4(vh4[0], vh4[1], vh4[2], vh4[3], bv);
            LDSM_X4(vl4[0], vl4[1], vl4[2], vl4[3], bv + HB);
#pragma unroll
            for (int sub = 0; sub < 2; sub++) {
                const int nt = g4 * 2 + sub, h = sub * 2;
                MMA_F16(o[nt], Ah2, vh4[h], vh4[h + 1]);
                MMA_F16(o[nt], Al2, vh4[h], vh4[h + 1]);
                MMA_F16(o[nt], Ah2, vl4[h], vl4[h + 1]);
            }
        }
    }

    // ---- emit fp16 hi/lo: out index s*4096 + i*64 + j ----
    __half* ohp = oh + (size_t)s * 4096;
    __half* olp = ol + (size_t)s * 4096;
#pragma unroll
    for (int nt = 0; nt < 8; nt++) {
        const int j = nt * 8 + tig * 2;
        __half h0 = __float2half_rn(o[nt][0]), h1 = __float2half_rn(o[nt][1]);
        __half h2 = __float2half_rn(o[nt][2]), h3 = __float2half_rn(o[nt][3]);
        uint32_t hi0 = ((uint32_t)__half_as_ushort(h1) << 16) | __half_as_ushort(h0);
        uint32_t hi1 = ((uint32_t)__half_as_ushort(h3) << 16) | __half_as_ushort(h2);
        uint32_t lo0 = pack2h(o[nt][0] - __half2float(h0), o[nt][1] - __half2float(h1));
        uint32_t lo1 = pack2h(o[nt][2] - __half2float(h2), o[nt][3] - __half2float(h3));
        *reinterpret_cast<uint32_t*>(ohp + r0 * 64 + j) = hi0;
        *reinterpret_cast<uint32_t*>(ohp + (r0 + 8) * 64 + j) = hi1;
        *reinterpret_cast<uint32_t*>(olp + r0 * 64 + j) = lo0;
        *reinterpret_cast<uint32_t*>(olp + (r0 + 8) * 64 + j) = lo1;
    }
}

// ---------------------------------------------------------------------------
// output GEMM via HMMA fp16 2-product, split-K=8 — unchanged from R10
// ---------------------------------------------------------------------------
#define OSA 80
#define OA_TB 10240
#define OB_TB 5120
#define OBUF 25600
#define GO_SMEM 51200

__global__ __launch_bounds__(256) void gemm_out_mma(
    const __half* __restrict__ Ahp, const __half* __restrict__ Alp,
    const __half* __restrict__ W,
    float* __restrict__ part)
{
    extern __shared__ char smem[];
    const uint32_t sb = smem_u32(smem);
    const int tid = threadIdx.x;
    const int warp = tid >> 5, lane = tid & 31;
    const int m0 = blockIdx.x * 128;
    const int ksp = blockIdx.y;
    const int kbase = ksp * 512;
    const int wm = (warp & 3) * 32;
    const int wn = (warp >> 2) * 32;

    float c[2][4][4];
#pragma unroll
    for (int mt = 0; mt < 2; mt++)
#pragma unroll
        for (int nt = 0; nt < 4; nt++)
#pragma unroll
            for (int r = 0; r < 4; r++) c[mt][nt][r] = 0.0f;

    const int g = lane >> 3, r8 = lane & 7;
    const uint32_t a_off = (uint32_t)(wm + (g & 1) * 8 + r8) * OSA + (g >> 1) * 16;
    const uint32_t b_off = 2 * OA_TB + (uint32_t)(wn + (g >> 1) * 8 + r8) * OSA + (g & 1) * 16;

    auto stage = [&](int chunk, int buf) {
        const int k0 = kbase + chunk * 32;
        const uint32_t base = sb + buf * OBUF;
#pragma unroll
        for (int j = 0; j < 2; j++) {
            const int idx = tid + j * 256;
            const int row = idx >> 2, kc = (idx & 3) * 16;
            const uint32_t sa = base + (uint32_t)row * OSA + kc;
            const size_t ga = (size_t)(m0 + row) * D4096 + k0 + kc / 2;
            CP_ASYNC16(sa, Ahp + ga);
            CP_ASYNC16(sa + OA_TB, Alp + ga);
        }
        {
            const int row = tid >> 2, kc = (tid & 3) * 16;
            const uint32_t sa = base + 2 * OA_TB + (uint32_t)row * OSA + kc;
            const size_t gb = (size_t)row * D4096 + k0 + kc / 2;
            CP_ASYNC16(sa, W + gb);
        }
        CP_COMMIT();
    };

    stage(0, 0);

    for (int it = 0; it < 16; ++it) {
        if (it + 1 < 16) {
            stage(it + 1, (it + 1) & 1);
            CP_WAIT(1);
        } else {
            CP_WAIT(0);
        }
        __syncthreads();

        const uint32_t buf = sb + (it & 1) * OBUF;
#pragma unroll
        for (int ks = 0; ks < 2; ++ks) {
            const uint32_t koff = ks * 32;
            uint32_t ah[2][4], al[2][4];
#pragma unroll
            for (int mt = 0; mt < 2; mt++) {
                const uint32_t aa = buf + a_off + koff + (uint32_t)mt * 16 * OSA;
                LDSM_X4(ah[mt][0], ah[mt][1], ah[mt][2], ah[mt][3], aa);
                LDSM_X4(al[mt][0], al[mt][1], al[mt][2], al[mt][3], aa + OA_TB);
            }
#pragma unroll
            for (int g4 = 0; g4 < 2; g4++) {
                uint32_t b4[4];
                const uint32_t ba = buf + b_off + koff + (uint32_t)g4 * 16 * OSA;
                LDSM_X4(b4[0], b4[1], b4[2], b4[3], ba);
#pragma unroll
                for (int mt = 0; mt < 2; mt++) {
#pragma unroll
                    for (int sub = 0; sub < 2; sub++) {
                        const int nt = g4 * 2 + sub, h = sub * 2;
                        MMA_F16(c[mt][nt], ah[mt], b4[h], b4[h + 1]);
                        MMA_F16(c[mt][nt], al[mt], b4[h], b4[h + 1]);
                    }
                }
            }
        }
        __syncthreads();
    }

    float* pbase = part + (size_t)ksp * S_LEN * 64;
    const int rbase = m0 + wm + (lane >> 2);
    const int cbase = wn + (lane & 3) * 2;
#pragma unroll
    for (int mt = 0; mt < 2; mt++) {
#pragma unroll
        for (int nt = 0; nt < 4; nt++) {
            const int col = cbase + nt * 8;
            float* p0 = pbase + (size_t)(rbase + mt * 16) * 64 + col;
            float* p1 = pbase + (size_t)(rbase + mt * 16 + 8) * 64 + col;
            p0[0] = c[mt][nt][0];
            p0[1] = c[mt][nt][1];
            p1[0] = c[mt][nt][2];
            p1[1] = c[mt][nt][3];
        }
    }
}

__global__ __launch_bounds__(256) void gemm_out_reduce(
    const float* __restrict__ part, const float* __restrict__ bias,
    float* __restrict__ out)
{
    const size_t i = (size_t)blockIdx.x * 256 + threadIdx.x;
    float s = bias[i & 63];
#pragma unroll
    for (int k = 0; k < 8; k++) s += part[i + (size_t)k * S_LEN * 64];
    out[i] = s;
}

// ---------------------------------------------------------------------------
// Launch
// ---------------------------------------------------------------------------
extern "C" void kernel_launch(void* const* d_in, const int* in_sizes, int n_in,
                              void* d_out, int out_size)
{
    const float* query  = (const float*)d_in[0];
    const float* key_in = (const float*)d_in[1];
    const float* value  = (const float*)d_in[2];
    const float* mask_u = (const float*)d_in[3];
    const float* Wq = (const float*)d_in[4];
    const float* bq = (const float*)d_in[5];
    const float* Wk = (const float*)d_in[6];
    const float* bk = (const float*)d_in[7];
    const float* Wv = (const float*)d_in[8];
    const float* bv = (const float*)d_in[9];
    const float* Wo = (const float*)d_in[10];
    const float* bo = (const float*)d_in[11];
    float* out = (float*)d_out;

    float *gq, *gk, *gv;
    __half *ah, *al, *b, *xh, *xl, *w, *wo;
    cudaGetSymbolAddress((void**)&gq, g_q);
    cudaGetSymbolAddress((void**)&gk, g_k);
    cudaGetSymbolAddress((void**)&gv, g_v);
    cudaGetSymbolAddress((void**)&ah, g_Ah);
    cudaGetSymbolAddress((void**)&al, g_Al);
    cudaGetSymbolAddress((void**)&b, g_B);
    cudaGetSymbolAddress((void**)&xh, g_xh);
    cudaGetSymbolAddress((void**)&xl, g_xl);
    cudaGetSymbolAddress((void**)&w, g_w);
    cudaGetSymbolAddress((void**)&wo, g_wo);

    cudaFuncSetAttribute(mma_gemm_q, cudaFuncAttributeMaxDynamicSharedMemorySize, GQ_SMEM);
    cudaFuncSetAttribute(mma_proj_h, cudaFuncAttributeMaxDynamicSharedMemorySize, PROJ_SMEM);
    cudaFuncSetAttribute(gemm_out_mma, cudaFuncAttributeMaxDynamicSharedMemorySize, GO_SMEM);

    // Q projection: fp16 2-product
    convert_split_h<<<(S_LEN * (size_t)D4096) / 2048, 256>>>(query, ah, al);
    transpose_h<<<dim3(64, 64), 256>>>(Wq, b);
    mma_gemm_q<<<1024, 256, GQ_SMEM>>>(ah, al, b, bq, gq);

    // K projection
    convert_split_h<<<(S_LEN * 64) / 2048, 256>>>(key_in, xh, xl);
    transpose_w64_h<<<64, 256>>>(Wk, w);
    mma_proj_h<<<dim3(D4096 / 128, S_LEN / 128), 256, PROJ_SMEM>>>(xh, xl, w, bk, gk);

    // V projection
    convert_split_h<<<(S_LEN * 64) / 2048, 256>>>(value, xh, xl);
    transpose_w64_h<<<64, 256>>>(Wv, w);
    mma_proj_h<<<dim3(D4096 / 128, S_LEN / 128), 256, PROJ_SMEM>>>(xh, xl, w, bv, gv);

    // Wo transpose
    transpose_wo_h<<<64, 256>>>(Wo, wo);

    // tensorized attention (emits fp16 hi/lo into g_Ah/g_Al)
    attn_mma<<<S_LEN, 128>>>(mask_u, ah, al);

    // output GEMM: fp16 2-product split-K=8, partials in g_B scratch
    float* part = (float*)b;
    gemm_out_mma<<<dim3(S_LEN / 128, 8), 256, GO_SMEM>>>(ah, al, wo, part);
    gemm_out_reduce<<<(S_LEN * 64) / 256, 256>>>(part, bo, out);
}

// round 12
// speedup vs baseline: 5.5233x; 1.4621x over previous
#include <cuda_runtime.h>
#include <cuda_bf16.h>
#include <cuda_fp16.h>
#include <cstdint>

#define S_LEN 8192
#define D4096 4096

__device__ float g_q[(size_t)S_LEN * D4096];
__device__ float g_k[(size_t)S_LEN * D4096];
__device__ float g_v[(size_t)S_LEN * D4096];
__device__ __half g_Ah[(size_t)S_LEN * D4096];    // query fp16; later attn-out fp16
__device__ __half g_B[(size_t)D4096 * D4096];     // Wq^T fp16; later fp32 split-K partials
__device__ __half g_xh[(size_t)S_LEN * 64];
__device__ __half g_xl[(size_t)S_LEN * 64];
__device__ __half g_w[(size_t)D4096 * 64];
__device__ __half g_wo[(size_t)64 * D4096];

__device__ __forceinline__ uint32_t smem_u32(const void* p) {
    uint32_t a;
    asm("{ .reg .u64 t; cvta.to.shared.u64 t, %1; cvt.u32.u64 %0, t; }"
        : "=r"(a) : "l"(p));
    return a;
}

#define CP_ASYNC16(saddr, gptr) \
    asm volatile("cp.async.cg.shared.global [%0], [%1], 16;" \
                 :: "r"(saddr), "l"(gptr) : "memory")
#define CP_COMMIT() asm volatile("cp.async.commit_group;" ::: "memory")
#define CP_WAIT(n)  asm volatile("cp.async.wait_group %0;" :: "n"(n) : "memory")

#define LDSM_X4(r0, r1, r2, r3, addr) \
    asm volatile("ldmatrix.sync.aligned.m8n8.x4.shared.b16 {%0,%1,%2,%3}, [%4];" \
                 : "=r"(r0), "=r"(r1), "=r"(r2), "=r"(r3) : "r"(addr))

#define LDSM_X4_T(r0, r1, r2, r3, addr) \
    asm volatile("ldmatrix.sync.aligned.m8n8.x4.trans.shared.b16 {%0,%1,%2,%3}, [%4];" \
                 : "=r"(r0), "=r"(r1), "=r"(r2), "=r"(r3) : "r"(addr))

#define MMA_F16(c, a, b0, b1) \
    asm volatile( \
        "mma.sync.aligned.m16n8k16.row.col.f32.f16.f16.f32 " \
        "{%0,%1,%2,%3}, {%4,%5,%6,%7}, {%8,%9}, {%0,%1,%2,%3};" \
        : "+f"((c)[0]), "+f"((c)[1]), "+f"((c)[2]), "+f"((c)[3]) \
        : "r"((a)[0]), "r"((a)[1]), "r"((a)[2]), "r"((a)[3]), "r"(b0), "r"(b1))

// fast exp on FFMA pipe (rel err ~4e-5)
__device__ __forceinline__ float fexpf(float x) {
    x = fmaxf(x, -87.0f);
    float y = x * 1.4426950408889634f;
    float n = rintf(y);
    float f = y - n;
    float p = 1.3337294e-3f;
    p = fmaf(p, f, 9.6181291e-3f);
    p = fmaf(p, f, 5.5504109e-2f);
    p = fmaf(p, f, 2.4022651e-1f);
    p = fmaf(p, f, 6.9314718e-1f);
    p = fmaf(p, f, 1.0f);
    return p * __int_as_float((__float2int_rn(n) + 127) << 23);
}

__device__ __forceinline__ uint32_t pack2h(float a, float b) {
    __half2 h = __floats2half2_rn(a, b);
    return *reinterpret_cast<uint32_t*>(&h);
}

// ---------------------------------------------------------------------------
// fp32 -> fp16 (single)
// ---------------------------------------------------------------------------
__global__ __launch_bounds__(256) void convert_h(
    const float* __restrict__ in, __half* __restrict__ out)
{
    const size_t base = ((size_t)blockIdx.x * 256 + threadIdx.x) * 8;
    float4 a = *reinterpret_cast<const float4*>(in + base);
    float4 b = *reinterpret_cast<const float4*>(in + base + 4);
    float f[8] = {a.x, a.y, a.z, a.w, b.x, b.y, b.z, b.w};
    __half h[8];
#pragma unroll
    for (int i = 0; i < 8; i++) h[i] = __float2half_rn(f[i]);
    *reinterpret_cast<uint4*>(out + base) = *reinterpret_cast<uint4*>(h);
}

// ---------------------------------------------------------------------------
// fp32 -> fp16 hi/lo split (k/v inputs)
// ---------------------------------------------------------------------------
__global__ __launch_bounds__(256) void convert_split_h(
    const float* __restrict__ in, __half* __restrict__ hi,
    __half* __restrict__ lo)
{
    const size_t base = ((size_t)blockIdx.x * 256 + threadIdx.x) * 8;
    float4 a = *reinterpret_cast<const float4*>(in + base);
    float4 b = *reinterpret_cast<const float4*>(in + base + 4);
    float f[8] = {a.x, a.y, a.z, a.w, b.x, b.y, b.z, b.w};
    __half h[8], l[8];
#pragma unroll
    for (int i = 0; i < 8; i++) {
        h[i] = __float2half_rn(f[i]);
        l[i] = __float2half_rn(f[i] - __half2float(h[i]));
    }
    *reinterpret_cast<uint4*>(hi + base) = *reinterpret_cast<uint4*>(h);
    *reinterpret_cast<uint4*>(lo + base) = *reinterpret_cast<uint4*>(l);
}

// ---------------------------------------------------------------------------
// Wq -> Wq^T fp16
// ---------------------------------------------------------------------------
__global__ __launch_bounds__(256) void transpose_h(
    const float* __restrict__ W, __half* __restrict__ out)
{
    __shared__ float ts[64][65];
    const int n0 = blockIdx.x * 64;
    const int k0 = blockIdx.y * 64;
    const int tid = threadIdx.x;
#pragma unroll
    for (int i = 0; i < 16; i++) {
        int idx = tid + i * 256;
        int r = idx >> 6, c = idx & 63;
        ts[r][c] = W[(size_t)(k0 + r) * D4096 + n0 + c];
    }
    __syncthreads();
#pragma unroll
    for (int i = 0; i < 8; i++) {
        int idx = tid + i * 256;
        int nl = idx >> 5, kl = (idx & 31) * 2;
        __half2 p;
        p.x = __float2half_rn(ts[kl][nl]);
        p.y = __float2half_rn(ts[kl + 1][nl]);
        *reinterpret_cast<__half2*>(out + (size_t)(n0 + nl) * D4096 + k0 + kl) = p;
    }
}

__global__ __launch_bounds__(256) void transpose_w64_h(
    const float* __restrict__ W, __half* __restrict__ out)
{
    __shared__ float ts[64][65];
    const int n0 = blockIdx.x * 64;
    const int tid = threadIdx.x;
    for (int t = tid; t < 4096; t += 256)
        ts[t >> 6][t & 63] = W[(size_t)(t >> 6) * D4096 + n0 + (t & 63)];
    __syncthreads();
    for (int t = tid; t < 4096; t += 256) {
        int nl = t >> 6, kl = t & 63;
        out[(size_t)(n0 + nl) * 64 + kl] = __float2half_rn(ts[kl][nl]);
    }
}

__global__ __launch_bounds__(256) void transpose_wo_h(
    const float* __restrict__ W, __half* __restrict__ out)
{
    __shared__ float ts[64][65];
    const int k0 = blockIdx.x * 64;
    const int tid = threadIdx.x;
    for (int t = tid; t < 4096; t += 256)
        ts[t >> 6][t & 63] = W[(size_t)(k0 + (t >> 6)) * 64 + (t & 63)];
    __syncthreads();
    for (int t = tid; t < 4096; t += 256) {
        int n = t >> 6, k = t & 63;
        out[(size_t)n * D4096 + k0 + k] = __float2half_rn(ts[k][n]);
    }
}

// ---------------------------------------------------------------------------
// Main HMMA GEMM, SINGLE-product fp16: CTA 128x256, 8 warps (64x64 tiles),
// K-chunk 32, 3-stage. Buffers: A(10240) B(20480) = 30720 x3 = 92160.
// ---------------------------------------------------------------------------
#define SA 80
#define A_TB 10240
#define B_TB 20480
#define BUF_B 30720
#define GQ_SMEM 92160

__global__ __launch_bounds__(256) void mma_gemm_q(
    const __half* __restrict__ A, const __half* __restrict__ B,
    const float* __restrict__ bias, float* __restrict__ C)
{
    extern __shared__ char smem[];
    const uint32_t sb = smem_u32(smem);
    const int tid = threadIdx.x;
    const int warp = tid >> 5, lane = tid & 31;

    const int m0 = (blockIdx.x >> 4) * 128;
    const int n0 = (blockIdx.x & 15) * 256;

    const int wm = (warp & 1) * 64;
    const int wn = (warp >> 1) * 64;

    float c[4][8][4];
#pragma unroll
    for (int mt = 0; mt < 4; mt++)
#pragma unroll
        for (int nt = 0; nt < 8; nt++)
#pragma unroll
            for (int r = 0; r < 4; r++) c[mt][nt][r] = 0.0f;

    const int g = lane >> 3, r8 = lane & 7;
    const uint32_t a_off = (uint32_t)(wm + (g & 1) * 8 + r8) * SA + (g >> 1) * 16;
    const uint32_t b_off = A_TB + (uint32_t)(wn + (g >> 1) * 8 + r8) * SA + (g & 1) * 16;

    auto stage = [&](int chunk, int buf) {
        const int k0 = chunk * 32;
        const uint32_t base = sb + buf * BUF_B;
#pragma unroll
        for (int j = 0; j < 2; j++) {           // A: 128 rows x 4 chunks
            const int idx = tid + j * 256;
            const int row = idx >> 2, kc = (idx & 3) * 16;
            const uint32_t sa = base + (uint32_t)row * SA + kc;
            const size_t ga = (size_t)(m0 + row) * D4096 + k0 + kc / 2;
            CP_ASYNC16(sa, A + ga);
        }
#pragma unroll
        for (int j = 0; j < 4; j++) {           // B: 256 rows x 4 chunks
            const int idx = tid + j * 256;
            const int row = idx >> 2, kc = (idx & 3) * 16;
            const uint32_t sa = base + A_TB + (uint32_t)row * SA + kc;
            const size_t gb = (size_t)(n0 + row) * D4096 + k0 + kc / 2;
            CP_ASYNC16(sa, B + gb);
        }
        CP_COMMIT();
    };

    stage(0, 0);
    stage(1, 1);

    const int NIT = D4096 / 32;
    for (int it = 0; it < NIT; ++it) {
        if (it == NIT - 1) { CP_WAIT(0); } else { CP_WAIT(1); }
        __syncthreads();
        if (it + 2 < NIT) stage(it + 2, (it + 2) % 3);

        const uint32_t buf = sb + (it % 3) * BUF_B;
#pragma unroll
        for (int ks = 0; ks < 2; ++ks) {
            const uint32_t koff = ks * 32;
            uint32_t ah[4][4];
#pragma unroll
            for (int mt = 0; mt < 4; mt++) {
                const uint32_t aa = buf + a_off + koff + (uint32_t)mt * 16 * SA;
                LDSM_X4(ah[mt][0], ah[mt][1], ah[mt][2], ah[mt][3], aa);
            }
#pragma unroll
            for (int g4 = 0; g4 < 4; g4++) {
                uint32_t b4[4];
                const uint32_t ba = buf + b_off + koff + (uint32_t)g4 * 16 * SA;
                LDSM_X4(b4[0], b4[1], b4[2], b4[3], ba);
#pragma unroll
                for (int mt = 0; mt < 4; mt++) {
#pragma unroll
                    for (int sub = 0; sub < 2; sub++) {
                        const int nt = g4 * 2 + sub, h = sub * 2;
                        MMA_F16(c[mt][nt], ah[mt], b4[h], b4[h + 1]);
                    }
                }
            }
        }
    }

    const int rbase = m0 + wm + (lane >> 2);
    const int cbase = n0 + wn + (lane & 3) * 2;
#pragma unroll
    for (int mt = 0; mt < 4; mt++) {
#pragma unroll
        for (int nt = 0; nt < 8; nt++) {
            const int col = cbase + nt * 8;
            const float b0 = bias[col], b1 = bias[col + 1];
            float* p0 = C + (size_t)(rbase + mt * 16) * D4096 + col;
            float* p1 = C + (size_t)(rbase + mt * 16 + 8) * D4096 + col;
            p0[0] = c[mt][nt][0] + b0;
            p0[1] = c[mt][nt][1] + b1;
            p1[0] = c[mt][nt][2] + b0;
            p1[1] = c[mt][nt][3] + b1;
        }
    }
}

// ---------------------------------------------------------------------------
// HMMA projection (K=64), fp16 2-product (kept for error margin)
// ---------------------------------------------------------------------------
#define PSA 144
#define P_TB 18432
#define PROJ_SMEM 55296

__global__ __launch_bounds__(256) void mma_proj_h(
    const __half* __restrict__ Xh, const __half* __restrict__ Xl,
    const __half* __restrict__ W,
    const float* __restrict__ bias, float* __restrict__ out)
{
    extern __shared__ char smem[];
    const uint32_t sb = smem_u32(smem);
    const int tid = threadIdx.x;
    const int warp = tid >> 5, lane = tid & 31;
    const int m0 = blockIdx.y * 128;
    const int n0 = blockIdx.x * 128;
    const int wm = (warp & 3) * 32;
    const int wn = (warp >> 2) * 64;

#pragma unroll
    for (int j = 0; j < 4; j++) {
        const int idx = tid + j * 256;
        const int row = idx >> 3, kc = (idx & 7) * 16;
        const uint32_t sa = sb + (uint32_t)row * PSA + kc;
        const size_t gx = (size_t)(m0 + row) * 64 + kc / 2;
        const size_t gw = (size_t)(n0 + row) * 64 + kc / 2;
        CP_ASYNC16(sa, Xh + gx);
        CP_ASYNC16(sa + P_TB, Xl + gx);
        CP_ASYNC16(sa + 2 * P_TB, W + gw);
    }
    CP_COMMIT();

    float c[2][8][4];
#pragma unroll
    for (int mt = 0; mt < 2; mt++)
#pragma unroll
        for (int nt = 0; nt < 8; nt++)
#pragma unroll
            for (int r = 0; r < 4; r++) c[mt][nt][r] = 0.0f;

    const int g = lane >> 3, r8 = lane & 7;
    const uint32_t a_off = (uint32_t)(wm + (g & 1) * 8 + r8) * PSA + (g >> 1) * 16;
    const uint32_t b_off = 2 * P_TB + (uint32_t)(wn + (g >> 1) * 8 + r8) * PSA + (g & 1) * 16;

    CP_WAIT(0);
    __syncthreads();

#pragma unroll
    for (int ks = 0; ks < 4; ++ks) {
        const uint32_t koff = ks * 32;
        uint32_t ah[2][4], al[2][4];
#pragma unroll
        for (int mt = 0; mt < 2; mt++) {
            const uint32_t aa = sb + a_off + koff + (uint32_t)mt * 16 * PSA;
            LDSM_X4(ah[mt][0], ah[mt][1], ah[mt][2], ah[mt][3], aa);
            LDSM_X4(al[mt][0], al[mt][1], al[mt][2], al[mt][3], aa + P_TB);
        }
#pragma unroll
        for (int g4 = 0; g4 < 4; g4++) {
            uint32_t b4[4];
            const uint32_t ba = sb + b_off + koff + (uint32_t)g4 * 16 * PSA;
            LDSM_X4(b4[0], b4[1], b4[2], b4[3], ba);
#pragma unroll
            for (int mt = 0; mt < 2; mt++) {
#pragma unroll
                for (int sub = 0; sub < 2; sub++) {
                    const int nt = g4 * 2 + sub, h = sub * 2;
                    MMA_F16(c[mt][nt], ah[mt], b4[h], b4[h + 1]);
                    MMA_F16(c[mt][nt], al[mt], b4[h], b4[h + 1]);
                }
            }
        }
    }

    const int rbase = m0 + wm + (lane >> 2);
    const int cbase = n0 + wn + (lane & 3) * 2;
#pragma unroll
    for (int mt = 0; mt < 2; mt++) {
#pragma unroll
        for (int nt = 0; nt < 8; nt++) {
            const int col = cbase + nt * 8;
            const float b0 = bias[col], b1 = bias[col + 1];
            float* p0 = out + (size_t)(rbase + mt * 16) * D4096 + col;
            float* p1 = out + (size_t)(rbase + mt * 16 + 8) * D4096 + col;
            p0[0] = c[mt][nt][0] + b0;
            p0[1] = c[mt][nt][1] + b1;
            p1[0] = c[mt][nt][2] + b0;
            p1[1] = c[mt][nt][3] + b1;
        }
    }
}

// ---------------------------------------------------------------------------
// Tensorized per-token attention; emits fp16 (single) for the output GEMM
// ---------------------------------------------------------------------------
#define AST 144

__global__ __launch_bounds__(128, 4) void attn_mma(
    const float* __restrict__ mask_u, __half* __restrict__ oh)
{
    __shared__ __half sm[4][64 * 72];

    const int s = blockIdx.x;
    const int tid = threadIdx.x;
    const int w = tid >> 5, lane = tid & 31;
    const int gid = lane >> 2, tig = lane & 3;

    const uint32_t sq = smem_u32(sm[0]);
    const uint32_t sk = smem_u32(sm[2]);
    const uint32_t HB = 64 * 72 * 2;

    {
        const float4* qf = reinterpret_cast<const float4*>(g_q + (size_t)s * 4096);
        const float4* kf = reinterpret_cast<const float4*>(g_k + (size_t)s * 4096);
        for (int t = tid; t < 1024; t += 128) {
            const int row = t >> 4, col = (t & 15) * 4;
            const int off = row * 72 + col;
            float4 qv = qf[t];
            float fq[4] = {qv.x, qv.y, qv.z, qv.w};
            __half h[4], l[4];
#pragma unroll
            for (int i = 0; i < 4; i++) {
                h[i] = __float2half_rn(fq[i]);
                l[i] = __float2half_rn(fq[i] - __half2float(h[i]));
            }
            *reinterpret_cast<uint2*>(&sm[0][off]) = *reinterpret_cast<uint2*>(h);
            *reinterpret_cast<uint2*>(&sm[1][off]) = *reinterpret_cast<uint2*>(l);
            float4 kv = kf[t];
            float fk[4] = {kv.x, kv.y, kv.z, kv.w};
#pragma unroll
            for (int i = 0; i < 4; i++) {
                h[i] = __float2half_rn(fk[i]);
                l[i] = __float2half_rn(fk[i] - __half2float(h[i]));
            }
            *reinterpret_cast<uint2*>(&sm[2][off]) = *reinterpret_cast<uint2*>(h);
            *reinterpret_cast<uint2*>(&sm[3][off]) = *reinterpret_cast<uint2*>(l);
        }
    }
    __syncthreads();

    const int lg = lane >> 3, lr = lane & 7;
    const uint32_t atoff = (uint32_t)((lg >> 1) * 8 + lr) * AST +
                           (uint32_t)(w * 16 + (lg & 1) * 8) * 2;
    const uint32_t boff = (uint32_t)((lg >> 1) * 8 + lr) * AST + (uint32_t)(lg & 1) * 16;

    float c[8][4];
#pragma unroll
    for (int nt = 0; nt < 8; nt++)
#pragma unroll
        for (int r = 0; r < 4; r++) c[nt][r] = 0.0f;

#pragma unroll
    for (int kc = 0; kc < 4; kc++) {
        uint32_t aq = sq + (uint32_t)kc * 16 * AST + atoff;
        uint32_t ah[4], al[4];
        LDSM_X4_T(ah[0], ah[1], ah[2], ah[3], aq);
        LDSM_X4_T(al[0], al[1], al[2], al[3], aq + HB);
#pragma unroll
        for (int g4 = 0; g4 < 4; g4++) {
            uint32_t bh4[4], bl4[4];
            uint32_t bk = sk + (uint32_t)g4 * 16 * AST + boff + kc * 32;
            LDSM_X4(bh4[0], bh4[1], bh4[2], bh4[3], bk);
            LDSM_X4(bl4[0], bl4[1], bl4[2], bl4[3], bk + HB);
#pragma unroll
            for (int sub = 0; sub < 2; sub++) {
                const int nt = g4 * 2 + sub, h = sub * 2;
                MMA_F16(c[nt], ah, bh4[h], bh4[h + 1]);
                MMA_F16(c[nt], al, bh4[h], bh4[h + 1]);
                MMA_F16(c[nt], ah, bl4[h], bl4[h + 1]);
            }
        }
    }

    float mx0 = -1e30f, mx1 = -1e30f;
#pragma unroll
    for (int nt = 0; nt < 8; nt++) {
        mx0 = fmaxf(mx0, fmaxf(c[nt][0], c[nt][1]));
        mx1 = fmaxf(mx1, fmaxf(c[nt][2], c[nt][3]));
    }
    mx0 = fmaxf(mx0, __shfl_xor_sync(0xffffffffu, mx0, 1));
    mx0 = fmaxf(mx0, __shfl_xor_sync(0xffffffffu, mx0, 2));
    mx1 = fmaxf(mx1, __shfl_xor_sync(0xffffffffu, mx1, 1));
    mx1 = fmaxf(mx1, __shfl_xor_sync(0xffffffffu, mx1, 2));
    float se0 = 0.0f, se1 = 0.0f;
#pragma unroll
    for (int nt = 0; nt < 8; nt++) {
        se0 += fexpf(c[nt][0] - mx0) + fexpf(c[nt][1] - mx0);
        se1 += fexpf(c[nt][2] - mx1) + fexpf(c[nt][3] - mx1);
    }
    se0 += __shfl_xor_sync(0xffffffffu, se0, 1);
    se0 += __shfl_xor_sync(0xffffffffu, se0, 2);
    se1 += __shfl_xor_sync(0xffffffffu, se1, 1);
    se1 += __shfl_xor_sync(0xffffffffu, se1, 2);
    const float lse0 = mx0 + __logf(se0);
    const float lse1 = mx1 + __logf(se1);

    const int r0 = w * 16 + gid;
    const float* m0p = mask_u + ((size_t)s * 64 + r0) * 64 + tig * 2;
    const float* m1p = m0p + 8 * 64;
    uint32_t ath0[8], atl0[8], ath1[8], atl1[8];
#pragma unroll
    for (int nt = 0; nt < 8; nt++) {
        const float2 mv0 = *reinterpret_cast<const float2*>(m0p + nt * 8);
        const float2 mv1 = *reinterpret_cast<const float2*>(m1p + nt * 8);
        float v0 = (c[nt][0] - lse0) * ((mv0.x > 0.25f) ? (1.0f / 0.75f) : 0.0f);
        float v1 = (c[nt][1] - lse0) * ((mv0.y > 0.25f) ? (1.0f / 0.75f) : 0.0f);
        float v2 = (c[nt][2] - lse1) * ((mv1.x > 0.25f) ? (1.0f / 0.75f) : 0.0f);
        float v3 = (c[nt][3] - lse1) * ((mv1.y > 0.25f) ? (1.0f / 0.75f) : 0.0f);
        __half h0 = __float2half_rn(v0), h1 = __float2half_rn(v1);
        __half h2 = __float2half_rn(v2), h3 = __float2half_rn(v3);
        ath0[nt] = ((uint32_t)__half_as_ushort(h1) << 16) | __half_as_ushort(h0);
        ath1[nt] = ((uint32_t)__half_as_ushort(h3) << 16) | __half_as_ushort(h2);
        atl0[nt] = pack2h(v0 - __half2float(h0), v1 - __half2float(h1));
        atl1[nt] = pack2h(v2 - __half2float(h2), v3 - __half2float(h3));
    }

    __syncthreads();
    {
        const float4* vf = reinterpret_cast<const float4*>(g_v + (size_t)s * 4096);
        for (int t = tid; t < 1024; t += 128) {
            const int row = t >> 4, col = (t & 15) * 4;
            const int off = row * 72 + col;
            float4 vv = vf[t];
            float fv[4] = {vv.x, vv.y, vv.z, vv.w};
            __half h[4], l[4];
#pragma unroll
            for (int i = 0; i < 4; i++) {
                h[i] = __float2half_rn(fv[i]);
                l[i] = __float2half_rn(fv[i] - __half2float(h[i]));
            }
            *reinterpret_cast<uint2*>(&sm[0][off]) = *reinterpret_cast<uint2*>(h);
            *reinterpret_cast<uint2*>(&sm[1][off]) = *reinterpret_cast<uint2*>(l);
        }
    }
    __syncthreads();

    float o[8][4];
#pragma unroll
    for (int nt = 0; nt < 8; nt++)
#pragma unroll
        for (int r = 0; r < 4; r++) o[nt][r] = 0.0f;

#pragma unroll
    for (int mc = 0; mc < 4; mc++) {
        uint32_t Ah2[4] = {ath0[2 * mc], ath1[2 * mc], ath0[2 * mc + 1], ath1[2 * mc + 1]};
        uint32_t Al2[4] = {atl0[2 * mc], atl1[2 * mc], atl0[2 * mc + 1], atl1[2 * mc + 1]};
#pragma unroll
        for (int g4 = 0; g4 < 4; g4++) {
            uint32_t vh4[4], vl4[4];
            uint32_t bv = sq + (uint32_t)g4 * 16 * AST + boff + mc * 32;
            LDSM_X4(vh4[0], vh4[1], vh4[2], vh4[3], bv);
            LDSM_X4(vl4[0], vl4[1], vl4[2], vl4[3], bv + HB);
#pragma unroll
            for (int sub = 0; sub < 2; sub++) {
                const int nt = g4 * 2 + sub, h = sub * 2;
                MMA_F16(o[nt], Ah2, vh4[h], vh4[h + 1]);
                MMA_F16(o[nt], Al2, vh4[h], vh4[h + 1]);
                MMA_F16(o[nt], Ah2, vl4[h], vl4[h + 1]);
            }
        }
    }

    __half* ohp = oh + (size_t)s * 4096;
#pragma unroll
    for (int nt = 0; nt < 8; nt++) {
        const int j = nt * 8 + tig * 2;
        *reinterpret_cast<uint32_t*>(ohp + r0 * 64 + j) = pack2h(o[nt][0], o[nt][1]);
        *reinterpret_cast<uint32_t*>(ohp + (r0 + 8) * 64 + j) = pack2h(o[nt][2], o[nt][3]);
    }
}

// ---------------------------------------------------------------------------
// output GEMM via HMMA fp16 SINGLE-product, split-K=8
// ---------------------------------------------------------------------------
#define OSA 80
#define OA_TB 10240
#define OB_TB 5120
#define OBUF 15360
#define GO_SMEM 30720

__global__ __launch_bounds__(256) void gemm_out_mma(
    const __half* __restrict__ A, const __half* __restrict__ W,
    float* __restrict__ part)
{
    extern __shared__ char smem[];
    const uint32_t sb = smem_u32(smem);
    const int tid = threadIdx.x;
    const int warp = tid >> 5, lane = tid & 31;
    const int m0 = blockIdx.x * 128;
    const int ksp = blockIdx.y;
    const int kbase = ksp * 512;
    const int wm = (warp & 3) * 32;
    const int wn = (warp >> 2) * 32;

    float c[2][4][4];
#pragma unroll
    for (int mt = 0; mt < 2; mt++)
#pragma unroll
        for (int nt = 0; nt < 4; nt++)
#pragma unroll
            for (int r = 0; r < 4; r++) c[mt][nt][r] = 0.0f;

    const int g = lane >> 3, r8 = lane & 7;
    const uint32_t a_off = (uint32_t)(wm + (g & 1) * 8 + r8) * OSA + (g >> 1) * 16;
    const uint32_t b_off = OA_TB + (uint32_t)(wn + (g >> 1) * 8 + r8) * OSA + (g & 1) * 16;

    auto stage = [&](int chunk, int buf) {
        const int k0 = kbase + chunk * 32;
        const uint32_t base = sb + buf * OBUF;
#pragma unroll
        for (int j = 0; j < 2; j++) {
            const int idx = tid + j * 256;
            const int row = idx >> 2, kc = (idx & 3) * 16;
            const uint32_t sa = base + (uint32_t)row * OSA + kc;
            const size_t ga = (size_t)(m0 + row) * D4096 + k0 + kc / 2;
            CP_ASYNC16(sa, A + ga);
        }
        {
            const int row = tid >> 2, kc = (tid & 3) * 16;
            const uint32_t sa = base + OA_TB + (uint32_t)row * OSA + kc;
            const size_t gb = (size_t)row * D4096 + k0 + kc / 2;
            CP_ASYNC16(sa, W + gb);
        }
        CP_COMMIT();
    };

    stage(0, 0);

    for (int it = 0; it < 16; ++it) {
        if (it + 1 < 16) {
            stage(it + 1, (it + 1) & 1);
            CP_WAIT(1);
        } else {
            CP_WAIT(0);
        }
        __syncthreads();

        const uint32_t buf = sb + (it & 1) * OBUF;
#pragma unroll
        for (int ks = 0; ks < 2; ++ks) {
            const uint32_t koff = ks * 32;
            uint32_t ah[2][4];
#pragma unroll
            for (int mt = 0; mt < 2; mt++) {
                const uint32_t aa = buf + a_off + koff + (uint32_t)mt * 16 * OSA;
                LDSM_X4(ah[mt][0], ah[mt][1], ah[mt][2], ah[mt][3], aa);
            }
#pragma unroll
            for (int g4 = 0; g4 < 2; g4++) {
                uint32_t b4[4];
                const uint32_t ba = buf + b_off + koff + (uint32_t)g4 * 16 * OSA;
                LDSM_X4(b4[0], b4[1], b4[2], b4[3], ba);
#pragma unroll
                for (int mt = 0; mt < 2; mt++) {
#pragma unroll
                    for (int sub = 0; sub < 2; sub++) {
                        const int nt = g4 * 2 + sub, h = sub * 2;
                        MMA_F16(c[mt][nt], ah[mt], b4[h], b4[h + 1]);
                    }
                }
            }
        }
        __syncthreads();
    }

    float* pbase = part + (size_t)ksp * S_LEN * 64;
    const int rbase = m0 + wm + (lane >> 2);
    const int cbase = wn + (lane & 3) * 2;
#pragma unroll
    for (int mt = 0; mt < 2; mt++) {
#pragma unroll
        for (int nt = 0; nt < 4; nt++) {
            const int col = cbase + nt * 8;
            float* p0 = pbase + (size_t)(rbase + mt * 16) * 64 + col;
            float* p1 = pbase + (size_t)(rbase + mt * 16 + 8) * 64 + col;
            p0[0] = c[mt][nt][0];
            p0[1] = c[mt][nt][1];
            p1[0] = c[mt][nt][2];
            p1[1] = c[mt][nt][3];
        }
    }
}

__global__ __launch_bounds__(256) void gemm_out_reduce(
    const float* __restrict__ part, const float* __restrict__ bias,
    float* __restrict__ out)
{
    const size_t i = (size_t)blockIdx.x * 256 + threadIdx.x;
    float s = bias[i & 63];
#pragma unroll
    for (int k = 0; k < 8; k++) s += part[i + (size_t)k * S_LEN * 64];
    out[i] = s;
}

// ---------------------------------------------------------------------------
// Launch
// ---------------------------------------------------------------------------
extern "C" void kernel_launch(void* const* d_in, const int* in_sizes, int n_in,
                              void* d_out, int out_size)
{
    const float* query  = (const float*)d_in[0];
    const float* key_in = (const float*)d_in[1];
    const float* value  = (const float*)d_in[2];
    const float* mask_u = (const float*)d_in[3];
    const float* Wq = (const float*)d_in[4];
    const float* bq = (const float*)d_in[5];
    const float* Wk = (const float*)d_in[6];
    const float* bk = (const float*)d_in[7];
    const float* Wv = (const float*)d_in[8];
    const float* bv = (const float*)d_in[9];
    const float* Wo = (const float*)d_in[10];
    const float* bo = (const float*)d_in[11];
    float* out = (float*)d_out;

    float *gq, *gk, *gv;
    __half *ah, *b, *xh, *xl, *w, *wo;
    cudaGetSymbolAddress((void**)&gq, g_q);
    cudaGetSymbolAddress((void**)&gk, g_k);
    cudaGetSymbolAddress((void**)&gv, g_v);
    cudaGetSymbolAddress((void**)&ah, g_Ah);
    cudaGetSymbolAddress((void**)&b, g_B);
    cudaGetSymbolAddress((void**)&xh, g_xh);
    cudaGetSymbolAddress((void**)&xl, g_xl);
    cudaGetSymbolAddress((void**)&w, g_w);
    cudaGetSymbolAddress((void**)&wo, g_wo);

    cudaFuncSetAttribute(mma_gemm_q, cudaFuncAttributeMaxDynamicSharedMemorySize, GQ_SMEM);
    cudaFuncSetAttribute(mma_proj_h, cudaFuncAttributeMaxDynamicSharedMemorySize, PROJ_SMEM);
    cudaFuncSetAttribute(gemm_out_mma, cudaFuncAttributeMaxDynamicSharedMemorySize, GO_SMEM);

    // Q projection: fp16 single-product
    convert_h<<<(S_LEN * (size_t)D4096) / 2048, 256>>>(query, ah);
    transpose_h<<<dim3(64, 64), 256>>>(Wq, b);
    mma_gemm_q<<<1024, 256, GQ_SMEM>>>(ah, b, bq, gq);

    // K projection (2-product)
    convert_split_h<<<(S_LEN * 64) / 2048, 256>>>(key_in, xh, xl);
    transpose_w64_h<<<64, 256>>>(Wk, w);
    mma_proj_h<<<dim3(D4096 / 128, S_LEN / 128), 256, PROJ_SMEM>>>(xh, xl, w, bk, gk);

    // V projection (2-product)
    convert_split_h<<<(S_LEN * 64) / 2048, 256>>>(value, xh, xl);
    transpose_w64_h<<<64, 256>>>(Wv, w);
    mma_proj_h<<<dim3(D4096 / 128, S_LEN / 128), 256, PROJ_SMEM>>>(xh, xl, w, bv, gv);

    // Wo transpose
    transpose_wo_h<<<64, 256>>>(Wo, wo);

    // tensorized attention (emits fp16 into g_Ah)
    attn_mma<<<S_LEN, 128>>>(mask_u, ah);

    // output GEMM: fp16 single-product split-K=8, partials in g_B scratch
    float* part = (float*)b;
    gemm_out_mma<<<dim3(S_LEN / 128, 8), 256, GO_SMEM>>>(ah, wo, part);
    gemm_out_reduce<<<(S_LEN * 64) / 256, 256>>>(part, bo, out);
}

// round 13
// speedup vs baseline: 5.8982x; 1.0679x over previous
#include <cuda_runtime.h>
#include <cuda_bf16.h>
#include <cuda_fp16.h>
#include <cstdint>

#define S_LEN 8192
#define D4096 4096

__device__ float g_q[(size_t)S_LEN * D4096];
__device__ float g_k[(size_t)S_LEN * D4096];
__device__ float g_v[(size_t)S_LEN * D4096];
__device__ __half g_Ah[(size_t)S_LEN * D4096];    // query fp16; later attn-out fp16
__device__ __half g_B[(size_t)D4096 * D4096];     // Wq^T fp16; later fp32 split-K partials
__device__ __half g_xh[(size_t)S_LEN * 64];
__device__ __half g_xl[(size_t)S_LEN * 64];
__device__ __half g_w[(size_t)D4096 * 64];
__device__ __half g_wo[(size_t)64 * D4096];

__device__ __forceinline__ uint32_t smem_u32(const void* p) {
    uint32_t a;
    asm("{ .reg .u64 t; cvta.to.shared.u64 t, %1; cvt.u32.u64 %0, t; }"
        : "=r"(a) : "l"(p));
    return a;
}

#define CP_ASYNC16(saddr, gptr) \
    asm volatile("cp.async.cg.shared.global [%0], [%1], 16;" \
                 :: "r"(saddr), "l"(gptr) : "memory")
#define CP_COMMIT() asm volatile("cp.async.commit_group;" ::: "memory")
#define CP_WAIT(n)  asm volatile("cp.async.wait_group %0;" :: "n"(n) : "memory")

#define LDSM_X4(r0, r1, r2, r3, addr) \
    asm volatile("ldmatrix.sync.aligned.m8n8.x4.shared.b16 {%0,%1,%2,%3}, [%4];" \
                 : "=r"(r0), "=r"(r1), "=r"(r2), "=r"(r3) : "r"(addr))

#define LDSM_X4_T(r0, r1, r2, r3, addr) \
    asm volatile("ldmatrix.sync.aligned.m8n8.x4.trans.shared.b16 {%0,%1,%2,%3}, [%4];" \
                 : "=r"(r0), "=r"(r1), "=r"(r2), "=r"(r3) : "r"(addr))

#define MMA_F16(c, a, b0, b1) \
    asm volatile( \
        "mma.sync.aligned.m16n8k16.row.col.f32.f16.f16.f32 " \
        "{%0,%1,%2,%3}, {%4,%5,%6,%7}, {%8,%9}, {%0,%1,%2,%3};" \
        : "+f"((c)[0]), "+f"((c)[1]), "+f"((c)[2]), "+f"((c)[3]) \
        : "r"((a)[0]), "r"((a)[1]), "r"((a)[2]), "r"((a)[3]), "r"(b0), "r"(b1))

// fast exp on FFMA pipe (rel err ~4e-5)
__device__ __forceinline__ float fexpf(float x) {
    x = fmaxf(x, -87.0f);
    float y = x * 1.4426950408889634f;
    float n = rintf(y);
    float f = y - n;
    float p = 1.3337294e-3f;
    p = fmaf(p, f, 9.6181291e-3f);
    p = fmaf(p, f, 5.5504109e-2f);
    p = fmaf(p, f, 2.4022651e-1f);
    p = fmaf(p, f, 6.9314718e-1f);
    p = fmaf(p, f, 1.0f);
    return p * __int_as_float((__float2int_rn(n) + 127) << 23);
}

__device__ __forceinline__ uint32_t pack2h(float a, float b) {
    __half2 h = __floats2half2_rn(a, b);
    return *reinterpret_cast<uint32_t*>(&h);
}

// ---------------------------------------------------------------------------
// fp32 -> fp16 (single)
// ---------------------------------------------------------------------------
__global__ __launch_bounds__(256) void convert_h(
    const float* __restrict__ in, __half* __restrict__ out)
{
    const size_t base = ((size_t)blockIdx.x * 256 + threadIdx.x) * 8;
    float4 a = *reinterpret_cast<const float4*>(in + base);
    float4 b = *reinterpret_cast<const float4*>(in + base + 4);
    float f[8] = {a.x, a.y, a.z, a.w, b.x, b.y, b.z, b.w};
    __half h[8];
#pragma unroll
    for (int i = 0; i < 8; i++) h[i] = __float2half_rn(f[i]);
    *reinterpret_cast<uint4*>(out + base) = *reinterpret_cast<uint4*>(h);
}

// ---------------------------------------------------------------------------
// fp32 -> fp16 hi/lo split (k/v inputs)
// ---------------------------------------------------------------------------
__global__ __launch_bounds__(256) void convert_split_h(
    const float* __restrict__ in, __half* __restrict__ hi,
    __half* __restrict__ lo)
{
    const size_t base = ((size_t)blockIdx.x * 256 + threadIdx.x) * 8;
    float4 a = *reinterpret_cast<const float4*>(in + base);
    float4 b = *reinterpret_cast<const float4*>(in + base + 4);
    float f[8] = {a.x, a.y, a.z, a.w, b.x, b.y, b.z, b.w};
    __half h[8], l[8];
#pragma unroll
    for (int i = 0; i < 8; i++) {
        h[i] = __float2half_rn(f[i]);
        l[i] = __float2half_rn(f[i] - __half2float(h[i]));
    }
    *reinterpret_cast<uint4*>(hi + base) = *reinterpret_cast<uint4*>(h);
    *reinterpret_cast<uint4*>(lo + base) = *reinterpret_cast<uint4*>(l);
}

// ---------------------------------------------------------------------------
// Wq -> Wq^T fp16
// ---------------------------------------------------------------------------
__global__ __launch_bounds__(256) void transpose_h(
    const float* __restrict__ W, __half* __restrict__ out)
{
    __shared__ float ts[64][65];
    const int n0 = blockIdx.x * 64;
    const int k0 = blockIdx.y * 64;
    const int tid = threadIdx.x;
#pragma unroll
    for (int i = 0; i < 16; i++) {
        int idx = tid + i * 256;
        int r = idx >> 6, c = idx & 63;
        ts[r][c] = W[(size_t)(k0 + r) * D4096 + n0 + c];
    }
    __syncthreads();
#pragma unroll
    for (int i = 0; i < 8; i++) {
        int idx = tid + i * 256;
        int nl = idx >> 5, kl = (idx & 31) * 2;
        __half2 p;
        p.x = __float2half_rn(ts[kl][nl]);
        p.y = __float2half_rn(ts[kl + 1][nl]);
        *reinterpret_cast<__half2*>(out + (size_t)(n0 + nl) * D4096 + k0 + kl) = p;
    }
}

__global__ __launch_bounds__(256) void transpose_w64_h(
    const float* __restrict__ W, __half* __restrict__ out)
{
    __shared__ float ts[64][65];
    const int n0 = blockIdx.x * 64;
    const int tid = threadIdx.x;
    for (int t = tid; t < 4096; t += 256)
        ts[t >> 6][t & 63] = W[(size_t)(t >> 6) * D4096 + n0 + (t & 63)];
    __syncthreads();
    for (int t = tid; t < 4096; t += 256) {
        int nl = t >> 6, kl = t & 63;
        out[(size_t)(n0 + nl) * 64 + kl] = __float2half_rn(ts[kl][nl]);
    }
}

__global__ __launch_bounds__(256) void transpose_wo_h(
    const float* __restrict__ W, __half* __restrict__ out)
{
    __shared__ float ts[64][65];
    const int k0 = blockIdx.x * 64;
    const int tid = threadIdx.x;
    for (int t = tid; t < 4096; t += 256)
        ts[t >> 6][t & 63] = W[(size_t)(k0 + (t >> 6)) * 64 + (t & 63)];
    __syncthreads();
    for (int t = tid; t < 4096; t += 256) {
        int n = t >> 6, k = t & 63;
        out[(size_t)n * D4096 + k0 + k] = __float2half_rn(ts[k][n]);
    }
}

// ---------------------------------------------------------------------------
// Main HMMA GEMM, single-product fp16: CTA 128x256, 512 thr (16 warps,
// 4m x 4n, warp 32x64), K-chunk 32, 3-stage.
// ---------------------------------------------------------------------------
#define SA 80
#define A_TB 10240
#define B_TB 20480
#define BUF_B 30720
#define GQ_SMEM 92160

__global__ __launch_bounds__(512) void mma_gemm_q(
    const __half* __restrict__ A, const __half* __restrict__ B,
    const float* __restrict__ bias, float* __restrict__ C)
{
    extern __shared__ char smem[];
    const uint32_t sb = smem_u32(smem);
    const int tid = threadIdx.x;
    const int warp = tid >> 5, lane = tid & 31;

    const int m0 = (blockIdx.x >> 4) * 128;
    const int n0 = (blockIdx.x & 15) * 256;

    const int wm = (warp & 3) * 32;
    const int wn = (warp >> 2) * 64;

    float c[2][8][4];
#pragma unroll
    for (int mt = 0; mt < 2; mt++)
#pragma unroll
        for (int nt = 0; nt < 8; nt++)
#pragma unroll
            for (int r = 0; r < 4; r++) c[mt][nt][r] = 0.0f;

    const int g = lane >> 3, r8 = lane & 7;
    const uint32_t a_off = (uint32_t)(wm + (g & 1) * 8 + r8) * SA + (g >> 1) * 16;
    const uint32_t b_off = A_TB + (uint32_t)(wn + (g >> 1) * 8 + r8) * SA + (g & 1) * 16;

    auto stage = [&](int chunk, int buf) {
        const int k0 = chunk * 32;
        const uint32_t base = sb + buf * BUF_B;
        {   // A: 128 rows x 4 chunks, one per thread
            const int row = tid >> 2, kc = (tid & 3) * 16;
            CP_ASYNC16(base + (uint32_t)row * SA + kc,
                       A + (size_t)(m0 + row) * D4096 + k0 + kc / 2);
        }
#pragma unroll
        for (int j = 0; j < 2; j++) {   // B: 256 rows x 4 chunks
            const int idx = tid + j * 512;
            const int row = idx >> 2, kc = (idx & 3) * 16;
            CP_ASYNC16(base + A_TB + (uint32_t)row * SA + kc,
                       B + (size_t)(n0 + row) * D4096 + k0 + kc / 2);
        }
        CP_COMMIT();
    };

    stage(0, 0);
    stage(1, 1);

    const int NIT = D4096 / 32;
    for (int it = 0; it < NIT; ++it) {
        if (it == NIT - 1) { CP_WAIT(0); } else { CP_WAIT(1); }
        __syncthreads();
        if (it + 2 < NIT) stage(it + 2, (it + 2) % 3);

        const uint32_t buf = sb + (it % 3) * BUF_B;
#pragma unroll
        for (int ks = 0; ks < 2; ++ks) {
            const uint32_t koff = ks * 32;
            uint32_t ah[2][4];
#pragma unroll
            for (int mt = 0; mt < 2; mt++) {
                const uint32_t aa = buf + a_off + koff + (uint32_t)mt * 16 * SA;
                LDSM_X4(ah[mt][0], ah[mt][1], ah[mt][2], ah[mt][3], aa);
            }
#pragma unroll
            for (int g4 = 0; g4 < 4; g4++) {
                uint32_t b4[4];
                const uint32_t ba = buf + b_off + koff + (uint32_t)g4 * 16 * SA;
                LDSM_X4(b4[0], b4[1], b4[2], b4[3], ba);
#pragma unroll
                for (int mt = 0; mt < 2; mt++) {
#pragma unroll
                    for (int sub = 0; sub < 2; sub++) {
                        const int nt = g4 * 2 + sub, h = sub * 2;
                        MMA_F16(c[mt][nt], ah[mt], b4[h], b4[h + 1]);
                    }
                }
            }
        }
    }

    const int rbase = m0 + wm + (lane >> 2);
    const int cbase = n0 + wn + (lane & 3) * 2;
#pragma unroll
    for (int mt = 0; mt < 2; mt++) {
#pragma unroll
        for (int nt = 0; nt < 8; nt++) {
            const int col = cbase + nt * 8;
            const float b0 = bias[col], b1 = bias[col + 1];
            float* p0 = C + (size_t)(rbase + mt * 16) * D4096 + col;
            float* p1 = C + (size_t)(rbase + mt * 16 + 8) * D4096 + col;
            p0[0] = c[mt][nt][0] + b0;
            p0[1] = c[mt][nt][1] + b1;
            p1[0] = c[mt][nt][2] + b0;
            p1[1] = c[mt][nt][3] + b1;
        }
    }
}

// ---------------------------------------------------------------------------
// HMMA projection (K=64), fp16 2-product — unchanged
// ---------------------------------------------------------------------------
#define PSA 144
#define P_TB 18432
#define PROJ_SMEM 55296

__global__ __launch_bounds__(256) void mma_proj_h(
    const __half* __restrict__ Xh, const __half* __restrict__ Xl,
    const __half* __restrict__ W,
    const float* __restrict__ bias, float* __restrict__ out)
{
    extern __shared__ char smem[];
    const uint32_t sb = smem_u32(smem);
    const int tid = threadIdx.x;
    const int warp = tid >> 5, lane = tid & 31;
    const int m0 = blockIdx.y * 128;
    const int n0 = blockIdx.x * 128;
    const int wm = (warp & 3) * 32;
    const int wn = (warp >> 2) * 64;

#pragma unroll
    for (int j = 0; j < 4; j++) {
        const int idx = tid + j * 256;
        const int row = idx >> 3, kc = (idx & 7) * 16;
        const uint32_t sa = sb + (uint32_t)row * PSA + kc;
        const size_t gx = (size_t)(m0 + row) * 64 + kc / 2;
        const size_t gw = (size_t)(n0 + row) * 64 + kc / 2;
        CP_ASYNC16(sa, Xh + gx);
        CP_ASYNC16(sa + P_TB, Xl + gx);
        CP_ASYNC16(sa + 2 * P_TB, W + gw);
    }
    CP_COMMIT();

    float c[2][8][4];
#pragma unroll
    for (int mt = 0; mt < 2; mt++)
#pragma unroll
        for (int nt = 0; nt < 8; nt++)
#pragma unroll
            for (int r = 0; r < 4; r++) c[mt][nt][r] = 0.0f;

    const int g = lane >> 3, r8 = lane & 7;
    const uint32_t a_off = (uint32_t)(wm + (g & 1) * 8 + r8) * PSA + (g >> 1) * 16;
    const uint32_t b_off = 2 * P_TB + (uint32_t)(wn + (g >> 1) * 8 + r8) * PSA + (g & 1) * 16;

    CP_WAIT(0);
    __syncthreads();

#pragma unroll
    for (int ks = 0; ks < 4; ++ks) {
        const uint32_t koff = ks * 32;
        uint32_t ah[2][4], al[2][4];
#pragma unroll
        for (int mt = 0; mt < 2; mt++) {
            const uint32_t aa = sb + a_off + koff + (uint32_t)mt * 16 * PSA;
            LDSM_X4(ah[mt][0], ah[mt][1], ah[mt][2], ah[mt][3], aa);
            LDSM_X4(al[mt][0], al[mt][1], al[mt][2], al[mt][3], aa + P_TB);
        }
#pragma unroll
        for (int g4 = 0; g4 < 4; g4++) {
            uint32_t b4[4];
            const uint32_t ba = sb + b_off + koff + (uint32_t)g4 * 16 * PSA;
            LDSM_X4(b4[0], b4[1], b4[2], b4[3], ba);
#pragma unroll
            for (int mt = 0; mt < 2; mt++) {
#pragma unroll
                for (int sub = 0; sub < 2; sub++) {
                    const int nt = g4 * 2 + sub, h = sub * 2;
                    MMA_F16(c[mt][nt], ah[mt], b4[h], b4[h + 1]);
                    MMA_F16(c[mt][nt], al[mt], b4[h], b4[h + 1]);
                }
            }
        }
    }

    const int rbase = m0 + wm + (lane >> 2);
    const int cbase = n0 + wn + (lane & 3) * 2;
#pragma unroll
    for (int mt = 0; mt < 2; mt++) {
#pragma unroll
        for (int nt = 0; nt < 8; nt++) {
            const int col = cbase + nt * 8;
            const float b0 = bias[col], b1 = bias[col + 1];
            float* p0 = out + (size_t)(rbase + mt * 16) * D4096 + col;
            float* p1 = out + (size_t)(rbase + mt * 16 + 8) * D4096 + col;
            p0[0] = c[mt][nt][0] + b0;
            p0[1] = c[mt][nt][1] + b1;
            p1[0] = c[mt][nt][2] + b0;
            p1[1] = c[mt][nt][3] + b1;
        }
    }
}

// ---------------------------------------------------------------------------
// Tensorized per-token attention — unchanged from R12
// ---------------------------------------------------------------------------
#define AST 144

__global__ __launch_bounds__(128, 4) void attn_mma(
    const float* __restrict__ mask_u, __half* __restrict__ oh)
{
    __shared__ __half sm[4][64 * 72];

    const int s = blockIdx.x;
    const int tid = threadIdx.x;
    const int w = tid >> 5, lane = tid & 31;
    const int gid = lane >> 2, tig = lane & 3;

    const uint32_t sq = smem_u32(sm[0]);
    const uint32_t sk = smem_u32(sm[2]);
    const uint32_t HB = 64 * 72 * 2;

    {
        const float4* qf = reinterpret_cast<const float4*>(g_q + (size_t)s * 4096);
        const float4* kf = reinterpret_cast<const float4*>(g_k + (size_t)s * 4096);
        for (int t = tid; t < 1024; t += 128) {
            const int row = t >> 4, col = (t & 15) * 4;
            const int off = row * 72 + col;
            float4 qv = qf[t];
            float fq[4] = {qv.x, qv.y, qv.z, qv.w};
            __half h[4], l[4];
#pragma unroll
            for (int i = 0; i < 4; i++) {
                h[i] = __float2half_rn(fq[i]);
                l[i] = __float2half_rn(fq[i] - __half2float(h[i]));
            }
            *reinterpret_cast<uint2*>(&sm[0][off]) = *reinterpret_cast<uint2*>(h);
            *reinterpret_cast<uint2*>(&sm[1][off]) = *reinterpret_cast<uint2*>(l);
            float4 kv = kf[t];
            float fk[4] = {kv.x, kv.y, kv.z, kv.w};
#pragma unroll
            for (int i = 0; i < 4; i++) {
                h[i] = __float2half_rn(fk[i]);
                l[i] = __float2half_rn(fk[i] - __half2float(h[i]));
            }
            *reinterpret_cast<uint2*>(&sm[2][off]) = *reinterpret_cast<uint2*>(h);
            *reinterpret_cast<uint2*>(&sm[3][off]) = *reinterpret_cast<uint2*>(l);
        }
    }
    __syncthreads();

    const int lg = lane >> 3, lr = lane & 7;
    const uint32_t atoff = (uint32_t)((lg >> 1) * 8 + lr) * AST +
                           (uint32_t)(w * 16 + (lg & 1) * 8) * 2;
    const uint32_t boff = (uint32_t)((lg >> 1) * 8 + lr) * AST + (uint32_t)(lg & 1) * 16;

    float c[8][4];
#pragma unroll
    for (int nt = 0; nt < 8; nt++)
#pragma unroll
        for (int r = 0; r < 4; r++) c[nt][r] = 0.0f;

#pragma unroll
    for (int kc = 0; kc < 4; kc++) {
        uint32_t aq = sq + (uint32_t)kc * 16 * AST + atoff;
        uint32_t ah[4], al[4];
        LDSM_X4_T(ah[0], ah[1], ah[2], ah[3], aq);
        LDSM_X4_T(al[0], al[1], al[2], al[3], aq + HB);
#pragma unroll
        for (int g4 = 0; g4 < 4; g4++) {
            uint32_t bh4[4], bl4[4];
            uint32_t bk = sk + (uint32_t)g4 * 16 * AST + boff + kc * 32;
            LDSM_X4(bh4[0], bh4[1], bh4[2], bh4[3], bk);
            LDSM_X4(bl4[0], bl4[1], bl4[2], bl4[3], bk + HB);
#pragma unroll
            for (int sub = 0; sub < 2; sub++) {
                const int nt = g4 * 2 + sub, h = sub * 2;
                MMA_F16(c[nt], ah, bh4[h], bh4[h + 1]);
                MMA_F16(c[nt], al, bh4[h], bh4[h + 1]);
                MMA_F16(c[nt], ah, bl4[h], bl4[h + 1]);
            }
        }
    }

    float mx0 = -1e30f, mx1 = -1e30f;
#pragma unroll
    for (int nt = 0; nt < 8; nt++) {
        mx0 = fmaxf(mx0, fmaxf(c[nt][0], c[nt][1]));
        mx1 = fmaxf(mx1, fmaxf(c[nt][2], c[nt][3]));
    }
    mx0 = fmaxf(mx0, __shfl_xor_sync(0xffffffffu, mx0, 1));
    mx0 = fmaxf(mx0, __shfl_xor_sync(0xffffffffu, mx0, 2));
    mx1 = fmaxf(mx1, __shfl_xor_sync(0xffffffffu, mx1, 1));
    mx1 = fmaxf(mx1, __shfl_xor_sync(0xffffffffu, mx1, 2));
    float se0 = 0.0f, se1 = 0.0f;
#pragma unroll
    for (int nt = 0; nt < 8; nt++) {
        se0 += fexpf(c[nt][0] - mx0) + fexpf(c[nt][1] - mx0);
        se1 += fexpf(c[nt][2] - mx1) + fexpf(c[nt][3] - mx1);
    }
    se0 += __shfl_xor_sync(0xffffffffu, se0, 1);
    se0 += __shfl_xor_sync(0xffffffffu, se0, 2);
    se1 += __shfl_xor_sync(0xffffffffu, se1, 1);
    se1 += __shfl_xor_sync(0xffffffffu, se1, 2);
    const float lse0 = mx0 + __logf(se0);
    const float lse1 = mx1 + __logf(se1);

    const int r0 = w * 16 + gid;
    const float* m0p = mask_u + ((size_t)s * 64 + r0) * 64 + tig * 2;
    const float* m1p = m0p + 8 * 64;
    uint32_t ath0[8], atl0[8], ath1[8], atl1[8];
#pragma unroll
    for (int nt = 0; nt < 8; nt++) {
        const float2 mv0 = *reinterpret_cast<const float2*>(m0p + nt * 8);
        const float2 mv1 = *reinterpret_cast<const float2*>(m1p + nt * 8);
        float v0 = (c[nt][0] - lse0) * ((mv0.x > 0.25f) ? (1.0f / 0.75f) : 0.0f);
        float v1 = (c[nt][1] - lse0) * ((mv0.y > 0.25f) ? (1.0f / 0.75f) : 0.0f);
        float v2 = (c[nt][2] - lse1) * ((mv1.x > 0.25f) ? (1.0f / 0.75f) : 0.0f);
        float v3 = (c[nt][3] - lse1) * ((mv1.y > 0.25f) ? (1.0f / 0.75f) : 0.0f);
        __half h0 = __float2half_rn(v0), h1 = __float2half_rn(v1);
        __half h2 = __float2half_rn(v2), h3 = __float2half_rn(v3);
        ath0[nt] = ((uint32_t)__half_as_ushort(h1) << 16) | __half_as_ushort(h0);
        ath1[nt] = ((uint32_t)__half_as_ushort(h3) << 16) | __half_as_ushort(h2);
        atl0[nt] = pack2h(v0 - __half2float(h0), v1 - __half2float(h1));
        atl1[nt] = pack2h(v2 - __half2float(h2), v3 - __half2float(h3));
    }

    __syncthreads();
    {
        const float4* vf = reinterpret_cast<const float4*>(g_v + (size_t)s * 4096);
        for (int t = tid; t < 1024; t += 128) {
            const int row = t >> 4, col = (t & 15) * 4;
            const int off = row * 72 + col;
            float4 vv = vf[t];
            float fv[4] = {vv.x, vv.y, vv.z, vv.w};
            __half h[4], l[4];
#pragma unroll
            for (int i = 0; i < 4; i++) {
                h[i] = __float2half_rn(fv[i]);
                l[i] = __float2half_rn(fv[i] - __half2float(h[i]));
            }
            *reinterpret_cast<uint2*>(&sm[0][off]) = *reinterpret_cast<uint2*>(h);
            *reinterpret_cast<uint2*>(&sm[1][off]) = *reinterpret_cast<uint2*>(l);
        }
    }
    __syncthreads();

    float o[8][4];
#pragma unroll
    for (int nt = 0; nt < 8; nt++)
#pragma unroll
        for (int r = 0; r < 4; r++) o[nt][r] = 0.0f;

#pragma unroll
    for (int mc = 0; mc < 4; mc++) {
        uint32_t Ah2[4] = {ath0[2 * mc], ath1[2 * mc], ath0[2 * mc + 1], ath1[2 * mc + 1]};
        uint32_t Al2[4] = {atl0[2 * mc], atl1[2 * mc], atl0[2 * mc + 1], atl1[2 * mc + 1]};
#pragma unroll
        for (int g4 = 0; g4 < 4; g4++) {
            uint32_t vh4[4], vl4[4];
            uint32_t bv = sq + (uint32_t)g4 * 16 * AST + boff + mc * 32;
            LDSM_X4(vh4[0], vh4[1], vh4[2], vh4[3], bv);
            LDSM_X4(vl4[0], vl4[1], vl4[2], vl4[3], bv + HB);
#pragma unroll
            for (int sub = 0; sub < 2; sub++) {
                const int nt = g4 * 2 + sub, h = sub * 2;
                MMA_F16(o[nt], Ah2, vh4[h], vh4[h + 1]);
                MMA_F16(o[nt], Al2, vh4[h], vh4[h + 1]);
                MMA_F16(o[nt], Ah2, vl4[h], vl4[h + 1]);
            }
        }
    }

    __half* ohp = oh + (size_t)s * 4096;
#pragma unroll
    for (int nt = 0; nt < 8; nt++) {
        const int j = nt * 8 + tig * 2;
        *reinterpret_cast<uint32_t*>(ohp + r0 * 64 + j) = pack2h(o[nt][0], o[nt][1]);
        *reinterpret_cast<uint32_t*>(ohp + (r0 + 8) * 64 + j) = pack2h(o[nt][2], o[nt][3]);
    }
}

// ---------------------------------------------------------------------------
// output GEMM via HMMA fp16 single-product, split-K=8 — unchanged
// ---------------------------------------------------------------------------
#define OSA 80
#define OA_TB 10240
#define OB_TB 5120
#define OBUF 15360
#define GO_SMEM 30720

__global__ __launch_bounds__(256) void gemm_out_mma(
    const __half* __restrict__ A, const __half* __restrict__ W,
    float* __restrict__ part)
{
    extern __shared__ char smem[];
    const uint32_t sb = smem_u32(smem);
    const int tid = threadIdx.x;
    const int warp = tid >> 5, lane = tid & 31;
    const int m0 = blockIdx.x * 128;
    const int ksp = blockIdx.y;
    const int kbase = ksp * 512;
    const int wm = (warp & 3) * 32;
    const int wn = (warp >> 2) * 32;

    float c[2][4][4];
#pragma unroll
    for (int mt = 0; mt < 2; mt++)
#pragma unroll
        for (int nt = 0; nt < 4; nt++)
#pragma unroll
            for (int r = 0; r < 4; r++) c[mt][nt][r] = 0.0f;

    const int g = lane >> 3, r8 = lane & 7;
    const uint32_t a_off = (uint32_t)(wm + (g & 1) * 8 + r8) * OSA + (g >> 1) * 16;
    const uint32_t b_off = OA_TB + (uint32_t)(wn + (g >> 1) * 8 + r8) * OSA + (g & 1) * 16;

    auto stage = [&](int chunk, int buf) {
        const int k0 = kbase + chunk * 32;
        const uint32_t base = sb + buf * OBUF;
#pragma unroll
        for (int j = 0; j < 2; j++) {
            const int idx = tid + j * 256;
            const int row = idx >> 2, kc = (idx & 3) * 16;
            const uint32_t sa = base + (uint32_t)row * OSA + kc;
            const size_t ga = (size_t)(m0 + row) * D4096 + k0 + kc / 2;
            CP_ASYNC16(sa, A + ga);
        }
        {
            const int row = tid >> 2, kc = (tid & 3) * 16;
            const uint32_t sa = base + OA_TB + (uint32_t)row * OSA + kc;
            const size_t gb = (size_t)row * D4096 + k0 + kc / 2;
            CP_ASYNC16(sa, W + gb);
        }
        CP_COMMIT();
    };

    stage(0, 0);

    for (int it = 0; it < 16; ++it) {
        if (it + 1 < 16) {
            stage(it + 1, (it + 1) & 1);
            CP_WAIT(1);
        } else {
            CP_WAIT(0);
        }
        __syncthreads();

        const uint32_t buf = sb + (it & 1) * OBUF;
#pragma unroll
        for (int ks = 0; ks < 2; ++ks) {
            const uint32_t koff = ks * 32;
            uint32_t ah[2][4];
#pragma unroll
            for (int mt = 0; mt < 2; mt++) {
                const uint32_t aa = buf + a_off + koff + (uint32_t)mt * 16 * OSA;
                LDSM_X4(ah[mt][0], ah[mt][1], ah[mt][2], ah[mt][3], aa);
            }
#pragma unroll
            for (int g4 = 0; g4 < 2; g4++) {
                uint32_t b4[4];
                const uint32_t ba = buf + b_off + koff + (uint32_t)g4 * 16 * OSA;
                LDSM_X4(b4[0], b4[1], b4[2], b4[3], ba);
#pragma unroll
                for (int mt = 0; mt < 2; mt++) {
#pragma unroll
                    for (int sub = 0; sub < 2; sub++) {
                        const int nt = g4 * 2 + sub, h = sub * 2;
                        MMA_F16(c[mt][nt], ah[mt], b4[h], b4[h + 1]);
                    }
                }
            }
        }
        __syncthreads();
    }

    float* pbase = part + (size_t)ksp * S_LEN * 64;
    const int rbase = m0 + wm + (lane >> 2);
    const int cbase = wn + (lane & 3) * 2;
#pragma unroll
    for (int mt = 0; mt < 2; mt++) {
#pragma unroll
        for (int nt = 0; nt < 4; nt++) {
            const int col = cbase + nt * 8;
            float* p0 = pbase + (size_t)(rbase + mt * 16) * 64 + col;
            float* p1 = pbase + (size_t)(rbase + mt * 16 + 8) * 64 + col;
            p0[0] = c[mt][nt][0];
            p0[1] = c[mt][nt][1];
            p1[0] = c[mt][nt][2];
            p1[1] = c[mt][nt][3];
        }
    }
}

__global__ __launch_bounds__(256) void gemm_out_reduce(
    const float* __restrict__ part, const float* __restrict__ bias,
    float* __restrict__ out)
{
    const size_t i = (size_t)blockIdx.x * 256 + threadIdx.x;
    float s = bias[i & 63];
#pragma unroll
    for (int k = 0; k < 8; k++) s += part[i + (size_t)k * S_LEN * 64];
    out[i] = s;
}

// ---------------------------------------------------------------------------
// Launch: fork/join side stream overlaps k/v/Wo prep with the Q GEMM
// ---------------------------------------------------------------------------
extern "C" void kernel_launch(void* const* d_in, const int* in_sizes, int n_in,
                              void* d_out, int out_size)
{
    const float* query  = (const float*)d_in[0];
    const float* key_in = (const float*)d_in[1];
    const float* value  = (const float*)d_in[2];
    const float* mask_u = (const float*)d_in[3];
    const float* Wq = (const float*)d_in[4];
    const float* bq = (const float*)d_in[5];
    const float* Wk = (const float*)d_in[6];
    const float* bk = (const float*)d_in[7];
    const float* Wv = (const float*)d_in[8];
    const float* bv = (const float*)d_in[9];
    const float* Wo = (const float*)d_in[10];
    const float* bo = (const float*)d_in[11];
    float* out = (float*)d_out;

    float *gq, *gk, *gv;
    __half *ah, *b, *xh, *xl, *w, *wo;
    cudaGetSymbolAddress((void**)&gq, g_q);
    cudaGetSymbolAddress((void**)&gk, g_k);
    cudaGetSymbolAddress((void**)&gv, g_v);
    cudaGetSymbolAddress((void**)&ah, g_Ah);
    cudaGetSymbolAddress((void**)&b, g_B);
    cudaGetSymbolAddress((void**)&xh, g_xh);
    cudaGetSymbolAddress((void**)&xl, g_xl);
    cudaGetSymbolAddress((void**)&w, g_w);
    cudaGetSymbolAddress((void**)&wo, g_wo);

    cudaFuncSetAttribute(mma_gemm_q, cudaFuncAttributeMaxDynamicSharedMemorySize, GQ_SMEM);
    cudaFuncSetAttribute(mma_proj_h, cudaFuncAttributeMaxDynamicSharedMemorySize, PROJ_SMEM);
    cudaFuncSetAttribute(gemm_out_mma, cudaFuncAttributeMaxDynamicSharedMemorySize, GO_SMEM);

    cudaStream_t s1;
    cudaStreamCreateWithFlags(&s1, cudaStreamNonBlocking);
    cudaEvent_t e0, e1;
    cudaEventCreateWithFlags(&e0, cudaEventDisableTiming);
    cudaEventCreateWithFlags(&e1, cudaEventDisableTiming);

    // fork side stream off the capture (default) stream
    cudaEventRecord(e0, 0);
    cudaStreamWaitEvent(s1, e0, 0);

    // main stream: Q projection chain (the long pole)
    convert_h<<<(S_LEN * (size_t)D4096) / 2048, 256>>>(query, ah);
    transpose_h<<<dim3(64, 64), 256>>>(Wq, b);
    mma_gemm_q<<<1024, 512, GQ_SMEM>>>(ah, b, bq, gq);

    // side stream: K/V projections + Wo transpose (independent of Q chain)
    convert_split_h<<<(S_LEN * 64) / 2048, 256, 0, s1>>>(key_in, xh, xl);
    transpose_w64_h<<<64, 256, 0, s1>>>(Wk, w);
    mma_proj_h<<<dim3(D4096 / 128, S_LEN / 128), 256, PROJ_SMEM, s1>>>(xh, xl, w, bk, gk);
    convert_split_h<<<(S_LEN * 64) / 2048, 256, 0, s1>>>(value, xh, xl);
    transpose_w64_h<<<64, 256, 0, s1>>>(Wv, w);
    mma_proj_h<<<dim3(D4096 / 128, S_LEN / 128), 256, PROJ_SMEM, s1>>>(xh, xl, w, bv, gv);
    transpose_wo_h<<<64, 256, 0, s1>>>(Wo, wo);

    // join
    cudaEventRecord(e1, s1);
    cudaStreamWaitEvent(0, e1, 0);

    // attention (emits fp16 into g_Ah), then output GEMM
    attn_mma<<<S_LEN, 128>>>(mask_u, ah);
    float* part = (float*)b;
    gemm_out_mma<<<dim3(S_LEN / 128, 8), 256, GO_SMEM>>>(ah, wo, part);
    gemm_out_reduce<<<(S_LEN * 64) / 256, 256>>>(part, bo, out);

    cudaEventDestroy(e0);
    cudaEventDestroy(e1);
    cudaStreamDestroy(s1);
}

// round 14
// speedup vs baseline: 6.5438x; 1.1095x over previous
#include <cuda_runtime.h>
#include <cuda_bf16.h>
#include <cuda_fp16.h>
#include <cstdint>

#define S_LEN 8192
#define D4096 4096

__device__ float g_q[(size_t)S_LEN * D4096];
__device__ float g_k[(size_t)S_LEN * D4096];
__device__ float g_v[(size_t)S_LEN * D4096];
__device__ __half g_Ah[(size_t)S_LEN * D4096];    // query fp16; later attn-out fp16
__device__ __half g_B[(size_t)D4096 * D4096];     // Wq^T fp16; later fp32 split-K partials
__device__ __half g_xh[(size_t)S_LEN * 64];
__device__ __half g_xl[(size_t)S_LEN * 64];
__device__ __half g_w[(size_t)D4096 * 64];
__device__ __half g_wo[(size_t)64 * D4096];

__device__ __forceinline__ uint32_t smem_u32(const void* p) {
    uint32_t a;
    asm("{ .reg .u64 t; cvta.to.shared.u64 t, %1; cvt.u32.u64 %0, t; }"
        : "=r"(a) : "l"(p));
    return a;
}

#define CP_ASYNC16(saddr, gptr) \
    asm volatile("cp.async.cg.shared.global [%0], [%1], 16;" \
                 :: "r"(saddr), "l"(gptr) : "memory")
#define CP_COMMIT() asm volatile("cp.async.commit_group;" ::: "memory")
#define CP_WAIT(n)  asm volatile("cp.async.wait_group %0;" :: "n"(n) : "memory")

#define LDSM_X4(r0, r1, r2, r3, addr) \
    asm volatile("ldmatrix.sync.aligned.m8n8.x4.shared.b16 {%0,%1,%2,%3}, [%4];" \
                 : "=r"(r0), "=r"(r1), "=r"(r2), "=r"(r3) : "r"(addr))

#define LDSM_X4_T(r0, r1, r2, r3, addr) \
    asm volatile("ldmatrix.sync.aligned.m8n8.x4.trans.shared.b16 {%0,%1,%2,%3}, [%4];" \
                 : "=r"(r0), "=r"(r1), "=r"(r2), "=r"(r3) : "r"(addr))

#define MMA_F16(c, a, b0, b1) \
    asm volatile( \
        "mma.sync.aligned.m16n8k16.row.col.f32.f16.f16.f32 " \
        "{%0,%1,%2,%3}, {%4,%5,%6,%7}, {%8,%9}, {%0,%1,%2,%3};" \
        : "+f"((c)[0]), "+f"((c)[1]), "+f"((c)[2]), "+f"((c)[3]) \
        : "r"((a)[0]), "r"((a)[1]), "r"((a)[2]), "r"((a)[3]), "r"(b0), "r"(b1))

// fast exp on FFMA pipe (rel err ~4e-5)
__device__ __forceinline__ float fexpf(float x) {
    x = fmaxf(x, -87.0f);
    float y = x * 1.4426950408889634f;
    float n = rintf(y);
    float f = y - n;
    float p = 1.3337294e-3f;
    p = fmaf(p, f, 9.6181291e-3f);
    p = fmaf(p, f, 5.5504109e-2f);
    p = fmaf(p, f, 2.4022651e-1f);
    p = fmaf(p, f, 6.9314718e-1f);
    p = fmaf(p, f, 1.0f);
    return p * __int_as_float((__float2int_rn(n) + 127) << 23);
}

__device__ __forceinline__ uint32_t pack2h(float a, float b) {
    __half2 h = __floats2half2_rn(a, b);
    return *reinterpret_cast<uint32_t*>(&h);
}

// ---------------------------------------------------------------------------
__global__ __launch_bounds__(256) void convert_h(
    const float* __restrict__ in, __half* __restrict__ out)
{
    const size_t base = ((size_t)blockIdx.x * 256 + threadIdx.x) * 8;
    float4 a = *reinterpret_cast<const float4*>(in + base);
    float4 b = *reinterpret_cast<const float4*>(in + base + 4);
    float f[8] = {a.x, a.y, a.z, a.w, b.x, b.y, b.z, b.w};
    __half h[8];
#pragma unroll
    for (int i = 0; i < 8; i++) h[i] = __float2half_rn(f[i]);
    *reinterpret_cast<uint4*>(out + base) = *reinterpret_cast<uint4*>(h);
}

__global__ __launch_bounds__(256) void convert_split_h(
    const float* __restrict__ in, __half* __restrict__ hi,
    __half* __restrict__ lo)
{
    const size_t base = ((size_t)blockIdx.x * 256 + threadIdx.x) * 8;
    float4 a = *reinterpret_cast<const float4*>(in + base);
    float4 b = *reinterpret_cast<const float4*>(in + base + 4);
    float f[8] = {a.x, a.y, a.z, a.w, b.x, b.y, b.z, b.w};
    __half h[8], l[8];
#pragma unroll
    for (int i = 0; i < 8; i++) {
        h[i] = __float2half_rn(f[i]);
        l[i] = __float2half_rn(f[i] - __half2float(h[i]));
    }
    *reinterpret_cast<uint4*>(hi + base) = *reinterpret_cast<uint4*>(h);
    *reinterpret_cast<uint4*>(lo + base) = *reinterpret_cast<uint4*>(l);
}

__global__ __launch_bounds__(256) void transpose_h(
    const float* __restrict__ W, __half* __restrict__ out)
{
    __shared__ float ts[64][65];
    const int n0 = blockIdx.x * 64;
    const int k0 = blockIdx.y * 64;
    const int tid = threadIdx.x;
#pragma unroll
    for (int i = 0; i < 16; i++) {
        int idx = tid + i * 256;
        int r = idx >> 6, c = idx & 63;
        ts[r][c] = W[(size_t)(k0 + r) * D4096 + n0 + c];
    }
    __syncthreads();
#pragma unroll
    for (int i = 0; i < 8; i++) {
        int idx = tid + i * 256;
        int nl = idx >> 5, kl = (idx & 31) * 2;
        __half2 p;
        p.x = __float2half_rn(ts[kl][nl]);
        p.y = __float2half_rn(ts[kl + 1][nl]);
        *reinterpret_cast<__half2*>(out + (size_t)(n0 + nl) * D4096 + k0 + kl) = p;
    }
}

__global__ __launch_bounds__(256) void transpose_w64_h(
    const float* __restrict__ W, __half* __restrict__ out)
{
    __shared__ float ts[64][65];
    const int n0 = blockIdx.x * 64;
    const int tid = threadIdx.x;
    for (int t = tid; t < 4096; t += 256)
        ts[t >> 6][t & 63] = W[(size_t)(t >> 6) * D4096 + n0 + (t & 63)];
    __syncthreads();
    for (int t = tid; t < 4096; t += 256) {
        int nl = t >> 6, kl = t & 63;
        out[(size_t)(n0 + nl) * 64 + kl] = __float2half_rn(ts[kl][nl]);
    }
}

__global__ __launch_bounds__(256) void transpose_wo_h(
    const float* __restrict__ W, __half* __restrict__ out)
{
    __shared__ float ts[64][65];
    const int k0 = blockIdx.x * 64;
    const int tid = threadIdx.x;
    for (int t = tid; t < 4096; t += 256)
        ts[t >> 6][t & 63] = W[(size_t)(k0 + (t >> 6)) * 64 + (t & 63)];
    __syncthreads();
    for (int t = tid; t < 4096; t += 256) {
        int n = t >> 6, k = t & 63;
        out[(size_t)n * D4096 + k0 + k] = __float2half_rn(ts[k][n]);
    }
}

// ---------------------------------------------------------------------------
// Main HMMA GEMM, single-product fp16: CTA 128x256, 512 thr (16 warps,
// 4m x 4n, warp 32x64), K-chunk 64 (half the barriers), 3-stage.
// Buffer: A 128x144B (18432) + B 256x144B (36864) = 55296; x3 = 165888.
// ---------------------------------------------------------------------------
#define SA 144
#define A_TB 18432
#define BUF_B 55296
#define GQ_SMEM 165888

__global__ __launch_bounds__(512) void mma_gemm_q(
    const __half* __restrict__ A, const __half* __restrict__ B,
    const float* __restrict__ bias, float* __restrict__ C)
{
    extern __shared__ char smem[];
    const uint32_t sb = smem_u32(smem);
    const int tid = threadIdx.x;
    const int warp = tid >> 5, lane = tid & 31;

    const int m0 = (blockIdx.x >> 4) * 128;
    const int n0 = (blockIdx.x & 15) * 256;

    const int wm = (warp & 3) * 32;
    const int wn = (warp >> 2) * 64;

    float c[2][8][4];
#pragma unroll
    for (int mt = 0; mt < 2; mt++)
#pragma unroll
        for (int nt = 0; nt < 8; nt++)
#pragma unroll
            for (int r = 0; r < 4; r++) c[mt][nt][r] = 0.0f;

    const int g = lane >> 3, r8 = lane & 7;
    const uint32_t a_off = (uint32_t)(wm + (g & 1) * 8 + r8) * SA + (g >> 1) * 16;
    const uint32_t b_off = A_TB + (uint32_t)(wn + (g >> 1) * 8 + r8) * SA + (g & 1) * 16;

    auto stage = [&](int chunk, int buf) {
        const int k0 = chunk * 64;
        const uint32_t base = sb + buf * BUF_B;
#pragma unroll
        for (int j = 0; j < 2; j++) {   // A: 128 rows x 8 chunks
            const int idx = tid + j * 512;
            const int row = idx >> 3, kc = (idx & 7) * 16;
            CP_ASYNC16(base + (uint32_t)row * SA + kc,
                       A + (size_t)(m0 + row) * D4096 + k0 + kc / 2);
        }
#pragma unroll
        for (int j = 0; j < 4; j++) {   // B: 256 rows x 8 chunks
            const int idx = tid + j * 512;
            const int row = idx >> 3, kc = (idx & 7) * 16;
            CP_ASYNC16(base + A_TB + (uint32_t)row * SA + kc,
                       B + (size_t)(n0 + row) * D4096 + k0 + kc / 2);
        }
        CP_COMMIT();
    };

    stage(0, 0);
    stage(1, 1);

    const int NIT = D4096 / 64;  // 64
    for (int it = 0; it < NIT; ++it) {
        if (it == NIT - 1) { CP_WAIT(0); } else { CP_WAIT(1); }
        __syncthreads();
        if (it + 2 < NIT) stage(it + 2, (it + 2) % 3);

        const uint32_t buf = sb + (it % 3) * BUF_B;
#pragma unroll
        for (int ks = 0; ks < 4; ++ks) {
            const uint32_t koff = ks * 32;
            uint32_t ah[2][4];
#pragma unroll
            for (int mt = 0; mt < 2; mt++) {
                const uint32_t aa = buf + a_off + koff + (uint32_t)mt * 16 * SA;
                LDSM_X4(ah[mt][0], ah[mt][1], ah[mt][2], ah[mt][3], aa);
            }
#pragma unroll
            for (int g4 = 0; g4 < 4; g4++) {
                uint32_t b4[4];
                const uint32_t ba = buf + b_off + koff + (uint32_t)g4 * 16 * SA;
                LDSM_X4(b4[0], b4[1], b4[2], b4[3], ba);
#pragma unroll
                for (int mt = 0; mt < 2; mt++) {
#pragma unroll
                    for (int sub = 0; sub < 2; sub++) {
                        const int nt = g4 * 2 + sub, h = sub * 2;
                        MMA_F16(c[mt][nt], ah[mt], b4[h], b4[h + 1]);
                    }
                }
            }
        }
    }

    const int rbase = m0 + wm + (lane >> 2);
    const int cbase = n0 + wn + (lane & 3) * 2;
#pragma unroll
    for (int mt = 0; mt < 2; mt++) {
#pragma unroll
        for (int nt = 0; nt < 8; nt++) {
            const int col = cbase + nt * 8;
            const float b0 = bias[col], b1 = bias[col + 1];
            float* p0 = C + (size_t)(rbase + mt * 16) * D4096 + col;
            float* p1 = C + (size_t)(rbase + mt * 16 + 8) * D4096 + col;
            p0[0] = c[mt][nt][0] + b0;
            p0[1] = c[mt][nt][1] + b1;
            p1[0] = c[mt][nt][2] + b0;
            p1[1] = c[mt][nt][3] + b1;
        }
    }
}

// ---------------------------------------------------------------------------
// HMMA projection (K=64), fp16 2-product — unchanged
// ---------------------------------------------------------------------------
#define PSA 144
#define P_TB 18432
#define PROJ_SMEM 55296

__global__ __launch_bounds__(256) void mma_proj_h(
    const __half* __restrict__ Xh, const __half* __restrict__ Xl,
    const __half* __restrict__ W,
    const float* __restrict__ bias, float* __restrict__ out)
{
    extern __shared__ char smem[];
    const uint32_t sb = smem_u32(smem);
    const int tid = threadIdx.x;
    const int warp = tid >> 5, lane = tid & 31;
    const int m0 = blockIdx.y * 128;
    const int n0 = blockIdx.x * 128;
    const int wm = (warp & 3) * 32;
    const int wn = (warp >> 2) * 64;

#pragma unroll
    for (int j = 0; j < 4; j++) {
        const int idx = tid + j * 256;
        const int row = idx >> 3, kc = (idx & 7) * 16;
        const uint32_t sa = sb + (uint32_t)row * PSA + kc;
        const size_t gx = (size_t)(m0 + row) * 64 + kc / 2;
        const size_t gw = (size_t)(n0 + row) * 64 + kc / 2;
        CP_ASYNC16(sa, Xh + gx);
        CP_ASYNC16(sa + P_TB, Xl + gx);
        CP_ASYNC16(sa + 2 * P_TB, W + gw);
    }
    CP_COMMIT();

    float c[2][8][4];
#pragma unroll
    for (int mt = 0; mt < 2; mt++)
#pragma unroll
        for (int nt = 0; nt < 8; nt++)
#pragma unroll
            for (int r = 0; r < 4; r++) c[mt][nt][r] = 0.0f;

    const int g = lane >> 3, r8 = lane & 7;
    const uint32_t a_off = (uint32_t)(wm + (g & 1) * 8 + r8) * PSA + (g >> 1) * 16;
    const uint32_t b_off = 2 * P_TB + (uint32_t)(wn + (g >> 1) * 8 + r8) * PSA + (g & 1) * 16;

    CP_WAIT(0);
    __syncthreads();

#pragma unroll
    for (int ks = 0; ks < 4; ++ks) {
        const uint32_t koff = ks * 32;
        uint32_t ah[2][4], al[2][4];
#pragma unroll
        for (int mt = 0; mt < 2; mt++) {
            const uint32_t aa = sb + a_off + koff + (uint32_t)mt * 16 * PSA;
            LDSM_X4(ah[mt][0], ah[mt][1], ah[mt][2], ah[mt][3], aa);
            LDSM_X4(al[mt][0], al[mt][1], al[mt][2], al[mt][3], aa + P_TB);
        }
#pragma unroll
        for (int g4 = 0; g4 < 4; g4++) {
            uint32_t b4[4];
            const uint32_t ba = sb + b_off + koff + (uint32_t)g4 * 16 * PSA;
            LDSM_X4(b4[0], b4[1], b4[2], b4[3], ba);
#pragma unroll
            for (int mt = 0; mt < 2; mt++) {
#pragma unroll
                for (int sub = 0; sub < 2; sub++) {
                    const int nt = g4 * 2 + sub, h = sub * 2;
                    MMA_F16(c[mt][nt], ah[mt], b4[h], b4[h + 1]);
                    MMA_F16(c[mt][nt], al[mt], b4[h], b4[h + 1]);
                }
            }
        }
    }

    const int rbase = m0 + wm + (lane >> 2);
    const int cbase = n0 + wn + (lane & 3) * 2;
#pragma unroll
    for (int mt = 0; mt < 2; mt++) {
#pragma unroll
        for (int nt = 0; nt < 8; nt++) {
            const int col = cbase + nt * 8;
            const float b0 = bias[col], b1 = bias[col + 1];
            float* p0 = out + (size_t)(rbase + mt * 16) * D4096 + col;
            float* p1 = out + (size_t)(rbase + mt * 16 + 8) * D4096 + col;
            p0[0] = c[mt][nt][0] + b0;
            p0[1] = c[mt][nt][1] + b1;
            p1[0] = c[mt][nt][2] + b0;
            p1[1] = c[mt][nt][3] + b1;
        }
    }
}

// ---------------------------------------------------------------------------
// Tensorized per-token attention. QK 2-product (q fp16 single, k hi/lo);
// PV 3-product (at hi/lo, v hi/lo partial).
// smem: sm[0]=qh->vh, sm[1]=(spare)->vl, sm[2]=kh, sm[3]=kl.
// ---------------------------------------------------------------------------
#define AST 144

__global__ __launch_bounds__(128, 4) void attn_mma(
    const float* __restrict__ mask_u, __half* __restrict__ oh)
{
    __shared__ __half sm[4][64 * 72];

    const int s = blockIdx.x;
    const int tid = threadIdx.x;
    const int w = tid >> 5, lane = tid & 31;
    const int gid = lane >> 2, tig = lane & 3;

    const uint32_t sq = smem_u32(sm[0]);
    const uint32_t sk = smem_u32(sm[2]);
    const uint32_t HB = 64 * 72 * 2;

    {
        const float4* qf = reinterpret_cast<const float4*>(g_q + (size_t)s * 4096);
        const float4* kf = reinterpret_cast<const float4*>(g_k + (size_t)s * 4096);
        for (int t = tid; t < 1024; t += 128) {
            const int row = t >> 4, col = (t & 15) * 4;
            const int off = row * 72 + col;
            float4 qv = qf[t];
            __half h[4], l[4];
            h[0] = __float2half_rn(qv.x);
            h[1] = __float2half_rn(qv.y);
            h[2] = __float2half_rn(qv.z);
            h[3] = __float2half_rn(qv.w);
            *reinterpret_cast<uint2*>(&sm[0][off]) = *reinterpret_cast<uint2*>(h);
            float4 kv = kf[t];
            float fk[4] = {kv.x, kv.y, kv.z, kv.w};
#pragma unroll
            for (int i = 0; i < 4; i++) {
                h[i] = __float2half_rn(fk[i]);
                l[i] = __float2half_rn(fk[i] - __half2float(h[i]));
            }
            *reinterpret_cast<uint2*>(&sm[2][off]) = *reinterpret_cast<uint2*>(h);
            *reinterpret_cast<uint2*>(&sm[3][off]) = *reinterpret_cast<uint2*>(l);
        }
    }
    __syncthreads();

    const int lg = lane >> 3, lr = lane & 7;
    const uint32_t atoff = (uint32_t)((lg >> 1) * 8 + lr) * AST +
                           (uint32_t)(w * 16 + (lg & 1) * 8) * 2;
    const uint32_t boff = (uint32_t)((lg >> 1) * 8 + lr) * AST + (uint32_t)(lg & 1) * 16;

    float c[8][4];
#pragma unroll
    for (int nt = 0; nt < 8; nt++)
#pragma unroll
        for (int r = 0; r < 4; r++) c[nt][r] = 0.0f;

#pragma unroll
    for (int kc = 0; kc < 4; kc++) {
        uint32_t aq = sq + (uint32_t)kc * 16 * AST + atoff;
        uint32_t ah[4];
        LDSM_X4_T(ah[0], ah[1], ah[2], ah[3], aq);
#pragma unroll
        for (int g4 = 0; g4 < 4; g4++) {
            uint32_t bh4[4], bl4[4];
            uint32_t bk = sk + (uint32_t)g4 * 16 * AST + boff + kc * 32;
            LDSM_X4(bh4[0], bh4[1], bh4[2], bh4[3], bk);
            LDSM_X4(bl4[0], bl4[1], bl4[2], bl4[3], bk + HB);
#pragma unroll
            for (int sub = 0; sub < 2; sub++) {
                const int nt = g4 * 2 + sub, h = sub * 2;
                MMA_F16(c[nt], ah, bh4[h], bh4[h + 1]);
                MMA_F16(c[nt], ah, bl4[h], bl4[h + 1]);
            }
        }
    }

    float mx0 = -1e30f, mx1 = -1e30f;
#pragma unroll
    for (int nt = 0; nt < 8; nt++) {
        mx0 = fmaxf(mx0, fmaxf(c[nt][0], c[nt][1]));
        mx1 = fmaxf(mx1, fmaxf(c[nt][2], c[nt][3]));
    }
    mx0 = fmaxf(mx0, __shfl_xor_sync(0xffffffffu, mx0, 1));
    mx0 = fmaxf(mx0, __shfl_xor_sync(0xffffffffu, mx0, 2));
    mx1 = fmaxf(mx1, __shfl_xor_sync(0xffffffffu, mx1, 1));
    mx1 = fmaxf(mx1, __shfl_xor_sync(0xffffffffu, mx1, 2));
    float se0 = 0.0f, se1 = 0.0f;
#pragma unroll
    for (int nt = 0; nt < 8; nt++) {
        se0 += fexpf(c[nt][0] - mx0) + fexpf(c[nt][1] - mx0);
        se1 += fexpf(c[nt][2] - mx1) + fexpf(c[nt][3] - mx1);
    }
    se0 += __shfl_xor_sync(0xffffffffu, se0, 1);
    se0 += __shfl_xor_sync(0xffffffffu, se0, 2);
    se1 += __shfl_xor_sync(0xffffffffu, se1, 1);
    se1 += __shfl_xor_sync(0xffffffffu, se1, 2);
    const float lse0 = mx0 + __logf(se0);
    const float lse1 = mx1 + __logf(se1);

    const int r0 = w * 16 + gid;
    const float* m0p = mask_u + ((size_t)s * 64 + r0) * 64 + tig * 2;
    const float* m1p = m0p + 8 * 64;
    uint32_t ath0[8], atl0[8], ath1[8], atl1[8];
#pragma unroll
    for (int nt = 0; nt < 8; nt++) {
        const float2 mv0 = *reinterpret_cast<const float2*>(m0p + nt * 8);
        const float2 mv1 = *reinterpret_cast<const float2*>(m1p + nt * 8);
        float v0 = (c[nt][0] - lse0) * ((mv0.x > 0.25f) ? (1.0f / 0.75f) : 0.0f);
        float v1 = (c[nt][1] - lse0) * ((mv0.y > 0.25f) ? (1.0f / 0.75f) : 0.0f);
        float v2 = (c[nt][2] - lse1) * ((mv1.x > 0.25f) ? (1.0f / 0.75f) : 0.0f);
        float v3 = (c[nt][3] - lse1) * ((mv1.y > 0.25f) ? (1.0f / 0.75f) : 0.0f);
        __half h0 = __float2half_rn(v0), h1 = __float2half_rn(v1);
        __half h2 = __float2half_rn(v2), h3 = __float2half_rn(v3);
        ath0[nt] = ((uint32_t)__half_as_ushort(h1) << 16) | __half_as_ushort(h0);
        ath1[nt] = ((uint32_t)__half_as_ushort(h3) << 16) | __half_as_ushort(h2);
        atl0[nt] = pack2h(v0 - __half2float(h0), v1 - __half2float(h1));
        atl1[nt] = pack2h(v2 - __half2float(h2), v3 - __half2float(h3));
    }

    __syncthreads();
    {
        const float4* vf = reinterpret_cast<const float4*>(g_v + (size_t)s * 4096);
        for (int t = tid; t < 1024; t += 128) {
            const int row = t >> 4, col = (t & 15) * 4;
            const int off = row * 72 + col;
            float4 vv = vf[t];
            float fv[4] = {vv.x, vv.y, vv.z, vv.w};
            __half h[4], l[4];
#pragma unroll
            for (int i = 0; i < 4; i++) {
                h[i] = __float2half_rn(fv[i]);
                l[i] = __float2half_rn(fv[i] - __half2float(h[i]));
            }
            *reinterpret_cast<uint2*>(&sm[0][off]) = *reinterpret_cast<uint2*>(h);
            *reinterpret_cast<uint2*>(&sm[1][off]) = *reinterpret_cast<uint2*>(l);
        }
    }
    __syncthreads();

    float o[8][4];
#pragma unroll
    for (int nt = 0; nt < 8; nt++)
#pragma unroll
        for (int r = 0; r < 4; r++) o[nt][r] = 0.0f;

#pragma unroll
    for (int mc = 0; mc < 4; mc++) {
        uint32_t Ah2[4] = {ath0[2 * mc], ath1[2 * mc], ath0[2 * mc + 1], ath1[2 * mc + 1]};
        uint32_t Al2[4] = {atl0[2 * mc], atl1[2 * mc], atl0[2 * mc + 1], atl1[2 * mc + 1]};
#pragma unroll
        for (int g4 = 0; g4 < 4; g4++) {
            uint32_t vh4[4], vl4[4];
            uint32_t bv = sq + (uint32_t)g4 * 16 * AST + boff + mc * 32;
            LDSM_X4(vh4[0], vh4[1], vh4[2], vh4[3], bv);
            LDSM_X4(vl4[0], vl4[1], vl4[2], vl4[3], bv + HB);
#pragma unroll
            for (int sub = 0; sub < 2; sub++) {
                const int nt = g4 * 2 + sub, h = sub * 2;
                MMA_F16(o[nt], Ah2, vh4[h], vh4[h + 1]);
                MMA_F16(o[nt], Al2, vh4[h], vh4[h + 1]);
                MMA_F16(o[nt], Ah2, vl4[h], vl4[h + 1]);
            }
        }
    }

    __half* ohp = oh + (size_t)s * 4096;
#pragma unroll
    for (int nt = 0; nt < 8; nt++) {
        const int j = nt * 8 + tig * 2;
        *reinterpret_cast<uint32_t*>(ohp + r0 * 64 + j) = pack2h(o[nt][0], o[nt][1]);
        *reinterpret_cast<uint32_t*>(ohp + (r0 + 8) * 64 + j) = pack2h(o[nt][2], o[nt][3]);
    }
}

// ---------------------------------------------------------------------------
// output GEMM via HMMA fp16 single-product, split-K=8 — unchanged
// ---------------------------------------------------------------------------
#define OSA 80
#define OA_TB 10240
#define OB_TB 5120
#define OBUF 15360
#define GO_SMEM 30720

__global__ __launch_bounds__(256) void gemm_out_mma(
    const __half* __restrict__ A, const __half* __restrict__ W,
    float* __restrict__ part)
{
    extern __shared__ char smem[];
    const uint32_t sb = smem_u32(smem);
    const int tid = threadIdx.x;
    const int warp = tid >> 5, lane = tid & 31;
    const int m0 = blockIdx.x * 128;
    const int ksp = blockIdx.y;
    const int kbase = ksp * 512;
    const int wm = (warp & 3) * 32;
    const int wn = (warp >> 2) * 32;

    float c[2][4][4];
#pragma unroll
    for (int mt = 0; mt < 2; mt++)
#pragma unroll
        for (int nt = 0; nt < 4; nt++)
#pragma unroll
            for (int r = 0; r < 4; r++) c[mt][nt][r] = 0.0f;

    const int g = lane >> 3, r8 = lane & 7;
    const uint32_t a_off = (uint32_t)(wm + (g & 1) * 8 + r8) * OSA + (g >> 1) * 16;
    const uint32_t b_off = OA_TB + (uint32_t)(wn + (g >> 1) * 8 + r8) * OSA + (g & 1) * 16;

    auto stage = [&](int chunk, int buf) {
        const int k0 = kbase + chunk * 32;
        const uint32_t base = sb + buf * OBUF;
#pragma unroll
        for (int j = 0; j < 2; j++) {
            const int idx = tid + j * 256;
            const int row = idx >> 2, kc = (idx & 3) * 16;
            const uint32_t sa = base + (uint32_t)row * OSA + kc;
            const size_t ga = (size_t)(m0 + row) * D4096 + k0 + kc / 2;
            CP_ASYNC16(sa, A + ga);
        }
        {
            const int row = tid >> 2, kc = (tid & 3) * 16;
            const uint32_t sa = base + OA_TB + (uint32_t)row * OSA + kc;
            const size_t gb = (size_t)row * D4096 + k0 + kc / 2;
            CP_ASYNC16(sa, W + gb);
        }
        CP_COMMIT();
    };

    stage(0, 0);

    for (int it = 0; it < 16; ++it) {
        if (it + 1 < 16) {
            stage(it + 1, (it + 1) & 1);
            CP_WAIT(1);
        } else {
            CP_WAIT(0);
        }
        __syncthreads();

        const uint32_t buf = sb + (it & 1) * OBUF;
#pragma unroll
        for (int ks = 0; ks < 2; ++ks) {
            const uint32_t koff = ks * 32;
            uint32_t ah[2][4];
#pragma unroll
            for (int mt = 0; mt < 2; mt++) {
                const uint32_t aa = buf + a_off + koff + (uint32_t)mt * 16 * OSA;
                LDSM_X4(ah[mt][0], ah[mt][1], ah[mt][2], ah[mt][3], aa);
            }
#pragma unroll
            for (int g4 = 0; g4 < 2; g4++) {
                uint32_t b4[4];
                const uint32_t ba = buf + b_off + koff + (uint32_t)g4 * 16 * OSA;
                LDSM_X4(b4[0], b4[1], b4[2], b4[3], ba);
#pragma unroll
                for (int mt = 0; mt < 2; mt++) {
#pragma unroll
                    for (int sub = 0; sub < 2; sub++) {
                        const int nt = g4 * 2 + sub, h = sub * 2;
                        MMA_F16(c[mt][nt], ah[mt], b4[h], b4[h + 1]);
                    }
                }
            }
        }
        __syncthreads();
    }

    float* pbase = part + (size_t)ksp * S_LEN * 64;
    const int rbase = m0 + wm + (lane >> 2);
    const int cbase = wn + (lane & 3) * 2;
#pragma unroll
    for (int mt = 0; mt < 2; mt++) {
#pragma unroll
        for (int nt = 0; nt < 4; nt++) {
            const int col = cbase + nt * 8;
            float* p0 = pbase + (size_t)(rbase + mt * 16) * 64 + col;
            float* p1 = pbase + (size_t)(rbase + mt * 16 + 8) * 64 + col;
            p0[0] = c[mt][nt][0];
            p0[1] = c[mt][nt][1];
            p1[0] = c[mt][nt][2];
            p1[1] = c[mt][nt][3];
        }
    }
}

__global__ __launch_bounds__(256) void gemm_out_reduce(
    const float* __restrict__ part, const float* __restrict__ bias,
    float* __restrict__ out)
{
    const size_t i = (size_t)blockIdx.x * 256 + threadIdx.x;
    float s = bias[i & 63];
#pragma unroll
    for (int k = 0; k < 8; k++) s += part[i + (size_t)k * S_LEN * 64];
    out[i] = s;
}

// ---------------------------------------------------------------------------
// Launch: side stream carries Wq transpose (joined before GEMM1) + k/v/Wo prep
// ---------------------------------------------------------------------------
extern "C" void kernel_launch(void* const* d_in, const int* in_sizes, int n_in,
                              void* d_out, int out_size)
{
    const float* query  = (const float*)d_in[0];
    const float* key_in = (const float*)d_in[1];
    const float* value  = (const float*)d_in[2];
    const float* mask_u = (const float*)d_in[3];
    const float* Wq = (const float*)d_in[4];
    const float* bq = (const float*)d_in[5];
    const float* Wk = (const float*)d_in[6];
    const float* bk = (const float*)d_in[7];
    const float* Wv = (const float*)d_in[8];
    const float* bv = (const float*)d_in[9];
    const float* Wo = (const float*)d_in[10];
    const float* bo = (const float*)d_in[11];
    float* out = (float*)d_out;

    float *gq, *gk, *gv;
    __half *ah, *b, *xh, *xl, *w, *wo;
    cudaGetSymbolAddress((void**)&gq, g_q);
    cudaGetSymbolAddress((void**)&gk, g_k);
    cudaGetSymbolAddress((void**)&gv, g_v);
    cudaGetSymbolAddress((void**)&ah, g_Ah);
    cudaGetSymbolAddress((void**)&b, g_B);
    cudaGetSymbolAddress((void**)&xh, g_xh);
    cudaGetSymbolAddress((void**)&xl, g_xl);
    cudaGetSymbolAddress((void**)&w, g_w);
    cudaGetSymbolAddress((void**)&wo, g_wo);

    cudaFuncSetAttribute(mma_gemm_q, cudaFuncAttributeMaxDynamicSharedMemorySize, GQ_SMEM);
    cudaFuncSetAttribute(mma_proj_h, cudaFuncAttributeMaxDynamicSharedMemorySize, PROJ_SMEM);
    cudaFuncSetAttribute(gemm_out_mma, cudaFuncAttributeMaxDynamicSharedMemorySize, GO_SMEM);

    cudaStream_t s1;
    cudaStreamCreateWithFlags(&s1, cudaStreamNonBlocking);
    cudaEvent_t e0, e1, e2;
    cudaEventCreateWithFlags(&e0, cudaEventDisableTiming);
    cudaEventCreateWithFlags(&e1, cudaEventDisableTiming);
    cudaEventCreateWithFlags(&e2, cudaEventDisableTiming);

    // fork
    cudaEventRecord(e0, 0);
    cudaStreamWaitEvent(s1, e0, 0);

    // side stream: Wq transpose first (GEMM1 dependency), then k/v/Wo prep
    transpose_h<<<dim3(64, 64), 256, 0, s1>>>(Wq, b);
    cudaEventRecord(e2, s1);
    convert_split_h<<<(S_LEN * 64) / 2048, 256, 0, s1>>>(key_in, xh, xl);
    transpose_w64_h<<<64, 256, 0, s1>>>(Wk, w);
    mma_proj_h<<<dim3(D4096 / 128, S_LEN / 128), 256, PROJ_SMEM, s1>>>(xh, xl, w, bk, gk);
    convert_split_h<<<(S_LEN * 64) / 2048, 256, 0, s1>>>(value, xh, xl);
    transpose_w64_h<<<64, 256, 0, s1>>>(Wv, w);
    mma_proj_h<<<dim3(D4096 / 128, S_LEN / 128), 256, PROJ_SMEM, s1>>>(xh, xl, w, bv, gv);
    transpose_wo_h<<<64, 256, 0, s1>>>(Wo, wo);

    // main stream: query convert, then (after Wq^T ready) the big GEMM
    convert_h<<<(S_LEN * (size_t)D4096) / 2048, 256>>>(query, ah);
    cudaStreamWaitEvent(0, e2, 0);
    mma_gemm_q<<<1024, 512, GQ_SMEM>>>(ah, b, bq, gq);

    // join side stream
    cudaEventRecord(e1, s1);
    cudaStreamWaitEvent(0, e1, 0);

    // attention (emits fp16 into g_Ah), then output GEMM
    attn_mma<<<S_LEN, 128>>>(mask_u, ah);
    float* part = (float*)b;
    gemm_out_mma<<<dim3(S_LEN / 128, 8), 256, GO_SMEM>>>(ah, wo, part);
    gemm_out_reduce<<<(S_LEN * 64) / 256, 256>>>(part, bo, out);

    cudaEventDestroy(e0);
    cudaEventDestroy(e1);
    cudaEventDestroy(e2);
    cudaStreamDestroy(s1);
}

// round 15
// speedup vs baseline: 7.1789x; 1.0971x over previous
#include <cuda_runtime.h>
#include <cuda_bf16.h>
#include <cuda_fp16.h>
#include <cstdint>

#define S_LEN 8192
#define D4096 4096

__device__ float g_q[(size_t)S_LEN * D4096];      // aliased: GEMM1 fp16 output (q)
__device__ float g_k[(size_t)S_LEN * D4096];      // aliased: k fp16 hi | lo
__device__ float g_v[(size_t)S_LEN * D4096];      // aliased: v fp16 hi | lo
__device__ __half g_Ah[(size_t)S_LEN * D4096];    // query fp16; later attn-out fp16
__device__ __half g_B[(size_t)D4096 * D4096];     // Wq^T fp16; later fp32 split-K partials
__device__ __half g_xh[(size_t)S_LEN * 64];
__device__ __half g_xl[(size_t)S_LEN * 64];
__device__ __half g_w[(size_t)D4096 * 64];
__device__ __half g_wo[(size_t)64 * D4096];

__device__ __forceinline__ uint32_t smem_u32(const void* p) {
    uint32_t a;
    asm("{ .reg .u64 t; cvta.to.shared.u64 t, %1; cvt.u32.u64 %0, t; }"
        : "=r"(a) : "l"(p));
    return a;
}

#define CP_ASYNC16(saddr, gptr) \
    asm volatile("cp.async.cg.shared.global [%0], [%1], 16;" \
                 :: "r"(saddr), "l"(gptr) : "memory")
#define CP_COMMIT() asm volatile("cp.async.commit_group;" ::: "memory")
#define CP_WAIT(n)  asm volatile("cp.async.wait_group %0;" :: "n"(n) : "memory")

#define LDSM_X4(r0, r1, r2, r3, addr) \
    asm volatile("ldmatrix.sync.aligned.m8n8.x4.shared.b16 {%0,%1,%2,%3}, [%4];" \
                 : "=r"(r0), "=r"(r1), "=r"(r2), "=r"(r3) : "r"(addr))

#define LDSM_X4_T(r0, r1, r2, r3, addr) \
    asm volatile("ldmatrix.sync.aligned.m8n8.x4.trans.shared.b16 {%0,%1,%2,%3}, [%4];" \
                 : "=r"(r0), "=r"(r1), "=r"(r2), "=r"(r3) : "r"(addr))

#define MMA_F16(c, a, b0, b1) \
    asm volatile( \
        "mma.sync.aligned.m16n8k16.row.col.f32.f16.f16.f32 " \
        "{%0,%1,%2,%3}, {%4,%5,%6,%7}, {%8,%9}, {%0,%1,%2,%3};" \
        : "+f"((c)[0]), "+f"((c)[1]), "+f"((c)[2]), "+f"((c)[3]) \
        : "r"((a)[0]), "r"((a)[1]), "r"((a)[2]), "r"((a)[3]), "r"(b0), "r"(b1))

// fast exp on FFMA pipe (rel err ~4e-5)
__device__ __forceinline__ float fexpf(float x) {
    x = fmaxf(x, -87.0f);
    float y = x * 1.4426950408889634f;
    float n = rintf(y);
    float f = y - n;
    float p = 1.3337294e-3f;
    p = fmaf(p, f, 9.6181291e-3f);
    p = fmaf(p, f, 5.5504109e-2f);
    p = fmaf(p, f, 2.4022651e-1f);
    p = fmaf(p, f, 6.9314718e-1f);
    p = fmaf(p, f, 1.0f);
    return p * __int_as_float((__float2int_rn(n) + 127) << 23);
}

__device__ __forceinline__ uint32_t pack2h(float a, float b) {
    __half2 h = __floats2half2_rn(a, b);
    return *reinterpret_cast<uint32_t*>(&h);
}

// ---------------------------------------------------------------------------
__global__ __launch_bounds__(256) void convert_h(
    const float* __restrict__ in, __half* __restrict__ out)
{
    const size_t base = ((size_t)blockIdx.x * 256 + threadIdx.x) * 8;
    float4 a = *reinterpret_cast<const float4*>(in + base);
    float4 b = *reinterpret_cast<const float4*>(in + base + 4);
    float f[8] = {a.x, a.y, a.z, a.w, b.x, b.y, b.z, b.w};
    __half h[8];
#pragma unroll
    for (int i = 0; i < 8; i++) h[i] = __float2half_rn(f[i]);
    *reinterpret_cast<uint4*>(out + base) = *reinterpret_cast<uint4*>(h);
}

__global__ __launch_bounds__(256) void convert_split_h(
    const float* __restrict__ in, __half* __restrict__ hi,
    __half* __restrict__ lo)
{
    const size_t base = ((size_t)blockIdx.x * 256 + threadIdx.x) * 8;
    float4 a = *reinterpret_cast<const float4*>(in + base);
    float4 b = *reinterpret_cast<const float4*>(in + base + 4);
    float f[8] = {a.x, a.y, a.z, a.w, b.x, b.y, b.z, b.w};
    __half h[8], l[8];
#pragma unroll
    for (int i = 0; i < 8; i++) {
        h[i] = __float2half_rn(f[i]);
        l[i] = __float2half_rn(f[i] - __half2float(h[i]));
    }
    *reinterpret_cast<uint4*>(hi + base) = *reinterpret_cast<uint4*>(h);
    *reinterpret_cast<uint4*>(lo + base) = *reinterpret_cast<uint4*>(l);
}

__global__ __launch_bounds__(256) void transpose_h(
    const float* __restrict__ W, __half* __restrict__ out)
{
    __shared__ float ts[64][65];
    const int n0 = blockIdx.x * 64;
    const int k0 = blockIdx.y * 64;
    const int tid = threadIdx.x;
#pragma unroll
    for (int i = 0; i < 16; i++) {
        int idx = tid + i * 256;
        int r = idx >> 6, c = idx & 63;
        ts[r][c] = W[(size_t)(k0 + r) * D4096 + n0 + c];
    }
    __syncthreads();
#pragma unroll
    for (int i = 0; i < 8; i++) {
        int idx = tid + i * 256;
        int nl = idx >> 5, kl = (idx & 31) * 2;
        __half2 p;
        p.x = __float2half_rn(ts[kl][nl]);
        p.y = __float2half_rn(ts[kl + 1][nl]);
        *reinterpret_cast<__half2*>(out + (size_t)(n0 + nl) * D4096 + k0 + kl) = p;
    }
}

__global__ __launch_bounds__(256) void transpose_w64_h(
    const float* __restrict__ W, __half* __restrict__ out)
{
    __shared__ float ts[64][65];
    const int n0 = blockIdx.x * 64;
    const int tid = threadIdx.x;
    for (int t = tid; t < 4096; t += 256)
        ts[t >> 6][t & 63] = W[(size_t)(t >> 6) * D4096 + n0 + (t & 63)];
    __syncthreads();
    for (int t = tid; t < 4096; t += 256) {
        int nl = t >> 6, kl = t & 63;
        out[(size_t)(n0 + nl) * 64 + kl] = __float2half_rn(ts[kl][nl]);
    }
}

__global__ __launch_bounds__(256) void transpose_wo_h(
    const float* __restrict__ W, __half* __restrict__ out)
{
    __shared__ float ts[64][65];
    const int k0 = blockIdx.x * 64;
    const int tid = threadIdx.x;
    for (int t = tid; t < 4096; t += 256)
        ts[t >> 6][t & 63] = W[(size_t)(k0 + (t >> 6)) * 64 + (t & 63)];
    __syncthreads();
    for (int t = tid; t < 4096; t += 256) {
        int n = t >> 6, k = t & 63;
        out[(size_t)n * D4096 + k0 + k] = __float2half_rn(ts[k][n]);
    }
}

// ---------------------------------------------------------------------------
// Main HMMA GEMM, single-product fp16, fp16 output.
// CTA 128x256, 512 thr (16 warps, 4m x 4n), K-chunk 64, 3-stage.
// ---------------------------------------------------------------------------
#define SA 144
#define A_TB 18432
#define BUF_B 55296
#define GQ_SMEM 165888

__global__ __launch_bounds__(512) void mma_gemm_q(
    const __half* __restrict__ A, const __half* __restrict__ B,
    const float* __restrict__ bias, __half* __restrict__ C)
{
    extern __shared__ char smem[];
    const uint32_t sb = smem_u32(smem);
    const int tid = threadIdx.x;
    const int warp = tid >> 5, lane = tid & 31;

    const int m0 = (blockIdx.x >> 4) * 128;
    const int n0 = (blockIdx.x & 15) * 256;

    const int wm = (warp & 3) * 32;
    const int wn = (warp >> 2) * 64;

    float c[2][8][4];
#pragma unroll
    for (int mt = 0; mt < 2; mt++)
#pragma unroll
        for (int nt = 0; nt < 8; nt++)
#pragma unroll
            for (int r = 0; r < 4; r++) c[mt][nt][r] = 0.0f;

    const int g = lane >> 3, r8 = lane & 7;
    const uint32_t a_off = (uint32_t)(wm + (g & 1) * 8 + r8) * SA + (g >> 1) * 16;
    const uint32_t b_off = A_TB + (uint32_t)(wn + (g >> 1) * 8 + r8) * SA + (g & 1) * 16;

    auto stage = [&](int chunk, int buf) {
        const int k0 = chunk * 64;
        const uint32_t base = sb + buf * BUF_B;
#pragma unroll
        for (int j = 0; j < 2; j++) {
            const int idx = tid + j * 512;
            const int row = idx >> 3, kc = (idx & 7) * 16;
            CP_ASYNC16(base + (uint32_t)row * SA + kc,
                       A + (size_t)(m0 + row) * D4096 + k0 + kc / 2);
        }
#pragma unroll
        for (int j = 0; j < 4; j++) {
            const int idx = tid + j * 512;
            const int row = idx >> 3, kc = (idx & 7) * 16;
            CP_ASYNC16(base + A_TB + (uint32_t)row * SA + kc,
                       B + (size_t)(n0 + row) * D4096 + k0 + kc / 2);
        }
        CP_COMMIT();
    };

    stage(0, 0);
    stage(1, 1);

    const int NIT = D4096 / 64;
    for (int it = 0; it < NIT; ++it) {
        if (it == NIT - 1) { CP_WAIT(0); } else { CP_WAIT(1); }
        __syncthreads();
        if (it + 2 < NIT) stage(it + 2, (it + 2) % 3);

        const uint32_t buf = sb + (it % 3) * BUF_B;
#pragma unroll
        for (int ks = 0; ks < 4; ++ks) {
            const uint32_t koff = ks * 32;
            uint32_t ah[2][4];
#pragma unroll
            for (int mt = 0; mt < 2; mt++) {
                const uint32_t aa = buf + a_off + koff + (uint32_t)mt * 16 * SA;
                LDSM_X4(ah[mt][0], ah[mt][1], ah[mt][2], ah[mt][3], aa);
            }
#pragma unroll
            for (int g4 = 0; g4 < 4; g4++) {
                uint32_t b4[4];
                const uint32_t ba = buf + b_off + koff + (uint32_t)g4 * 16 * SA;
                LDSM_X4(b4[0], b4[1], b4[2], b4[3], ba);
#pragma unroll
                for (int mt = 0; mt < 2; mt++) {
#pragma unroll
                    for (int sub = 0; sub < 2; sub++) {
                        const int nt = g4 * 2 + sub, h = sub * 2;
                        MMA_F16(c[mt][nt], ah[mt], b4[h], b4[h + 1]);
                    }
                }
            }
        }
    }

    const int rbase = m0 + wm + (lane >> 2);
    const int cbase = n0 + wn + (lane & 3) * 2;
#pragma unroll
    for (int mt = 0; mt < 2; mt++) {
#pragma unroll
        for (int nt = 0; nt < 8; nt++) {
            const int col = cbase + nt * 8;
            const float b0 = bias[col], b1 = bias[col + 1];
            *reinterpret_cast<uint32_t*>(C + (size_t)(rbase + mt * 16) * D4096 + col) =
                pack2h(c[mt][nt][0] + b0, c[mt][nt][1] + b1);
            *reinterpret_cast<uint32_t*>(C + (size_t)(rbase + mt * 16 + 8) * D4096 + col) =
                pack2h(c[mt][nt][2] + b0, c[mt][nt][3] + b1);
        }
    }
}

// ---------------------------------------------------------------------------
// HMMA projection (K=64), fp16 2-product; emits fp16 hi/lo.
// ---------------------------------------------------------------------------
#define PSA 144
#define P_TB 18432
#define PROJ_SMEM 55296

__global__ __launch_bounds__(256) void mma_proj_h(
    const __half* __restrict__ Xh, const __half* __restrict__ Xl,
    const __half* __restrict__ W, const float* __restrict__ bias,
    __half* __restrict__ outh, __half* __restrict__ outl)
{
    extern __shared__ char smem[];
    const uint32_t sb = smem_u32(smem);
    const int tid = threadIdx.x;
    const int warp = tid >> 5, lane = tid & 31;
    const int m0 = blockIdx.y * 128;
    const int n0 = blockIdx.x * 128;
    const int wm = (warp & 3) * 32;
    const int wn = (warp >> 2) * 64;

#pragma unroll
    for (int j = 0; j < 4; j++) {
        const int idx = tid + j * 256;
        const int row = idx >> 3, kc = (idx & 7) * 16;
        const uint32_t sa = sb + (uint32_t)row * PSA + kc;
        const size_t gx = (size_t)(m0 + row) * 64 + kc / 2;
        const size_t gw = (size_t)(n0 + row) * 64 + kc / 2;
        CP_ASYNC16(sa, Xh + gx);
        CP_ASYNC16(sa + P_TB, Xl + gx);
        CP_ASYNC16(sa + 2 * P_TB, W + gw);
    }
    CP_COMMIT();

    float c[2][8][4];
#pragma unroll
    for (int mt = 0; mt < 2; mt++)
#pragma unroll
        for (int nt = 0; nt < 8; nt++)
#pragma unroll
            for (int r = 0; r < 4; r++) c[mt][nt][r] = 0.0f;

    const int g = lane >> 3, r8 = lane & 7;
    const uint32_t a_off = (uint32_t)(wm + (g & 1) * 8 + r8) * PSA + (g >> 1) * 16;
    const uint32_t b_off = 2 * P_TB + (uint32_t)(wn + (g >> 1) * 8 + r8) * PSA + (g & 1) * 16;

    CP_WAIT(0);
    __syncthreads();

#pragma unroll
    for (int ks = 0; ks < 4; ++ks) {
        const uint32_t koff = ks * 32;
        uint32_t ah[2][4], al[2][4];
#pragma unroll
        for (int mt = 0; mt < 2; mt++) {
            const uint32_t aa = sb + a_off + koff + (uint32_t)mt * 16 * PSA;
            LDSM_X4(ah[mt][0], ah[mt][1], ah[mt][2], ah[mt][3], aa);
            LDSM_X4(al[mt][0], al[mt][1], al[mt][2], al[mt][3], aa + P_TB);
        }
#pragma unroll
        for (int g4 = 0; g4 < 4; g4++) {
            uint32_t b4[4];
            const uint32_t ba = sb + b_off + koff + (uint32_t)g4 * 16 * PSA;
            LDSM_X4(b4[0], b4[1], b4[2], b4[3], ba);
#pragma unroll
            for (int mt = 0; mt < 2; mt++) {
#pragma unroll
                for (int sub = 0; sub < 2; sub++) {
                    const int nt = g4 * 2 + sub, h = sub * 2;
                    MMA_F16(c[mt][nt], ah[mt], b4[h], b4[h + 1]);
                    MMA_F16(c[mt][nt], al[mt], b4[h], b4[h + 1]);
                }
            }
        }
    }

    const int rbase = m0 + wm + (lane >> 2);
    const int cbase = n0 + wn + (lane & 3) * 2;
#pragma unroll
    for (int mt = 0; mt < 2; mt++) {
#pragma unroll
        for (int nt = 0; nt < 8; nt++) {
            const int col = cbase + nt * 8;
            const float b0 = bias[col], b1 = bias[col + 1];
#pragma unroll
            for (int half_ = 0; half_ < 2; half_++) {
                const float s0 = c[mt][nt][half_ * 2 + 0] + b0;
                const float s1 = c[mt][nt][half_ * 2 + 1] + b1;
                const __half h0 = __float2half_rn(s0), h1 = __float2half_rn(s1);
                const size_t off = (size_t)(rbase + mt * 16 + half_ * 8) * D4096 + col;
                *reinterpret_cast<uint32_t*>(outh + off) =
                    ((uint32_t)__half_as_ushort(h1) << 16) | __half_as_ushort(h0);
                *reinterpret_cast<uint32_t*>(outl + off) =
                    pack2h(s0 - __half2float(h0), s1 - __half2float(h1));
            }
        }
    }
}

// ---------------------------------------------------------------------------
// Tensorized per-token attention, all-fp16 inputs, fully async staging.
// smem: q, kh, kl, vh, vl — five 64x72-half buffers (46080 B).
// ---------------------------------------------------------------------------
#define AST 144

__global__ __launch_bounds__(128, 4) void attn_mma(
    const float* __restrict__ mask_u,
    const __half* __restrict__ qh, const __half* __restrict__ kh,
    const __half* __restrict__ kl, const __half* __restrict__ vh,
    const __half* __restrict__ vl, __half* __restrict__ oh, int s_base)
{
    __shared__ __half smq[64 * 72];
    __shared__ __half smkh[64 * 72];
    __shared__ __half smkl[64 * 72];
    __shared__ __half smvh[64 * 72];
    __shared__ __half smvl[64 * 72];

    const int s = blockIdx.x + s_base;
    const int tid = threadIdx.x;
    const int w = tid >> 5, lane = tid & 31;
    const int gid = lane >> 2, tig = lane & 3;

    const uint32_t sq = smem_u32(smq);
    const uint32_t skh = smem_u32(smkh);
    const uint32_t skl = smem_u32(smkl);
    const uint32_t svh = smem_u32(smvh);
    const uint32_t svl = smem_u32(smvl);

    // group 1: q, k hi/lo ; group 2: v hi/lo (prefetched under QK/softmax)
    const size_t gbase = (size_t)s * 4096;
#pragma unroll
    for (int j = 0; j < 4; j++) {
        const int t = tid + j * 128;             // 512 chunks of 8 halves
        const int row = t >> 3, kc = (t & 7) * 16;
        const uint32_t so = (uint32_t)row * AST + kc;
        const size_t go = gbase + (size_t)row * 64 + kc / 2;
        CP_ASYNC16(sq + so, qh + go);
        CP_ASYNC16(skh + so, kh + go);
        CP_ASYNC16(skl + so, kl + go);
    }
    CP_COMMIT();
#pragma unroll
    for (int j = 0; j < 4; j++) {
        const int t = tid + j * 128;
        const int row = t >> 3, kc = (t & 7) * 16;
        const uint32_t so = (uint32_t)row * AST + kc;
        const size_t go = gbase + (size_t)row * 64 + kc / 2;
        CP_ASYNC16(svh + so, vh + go);
        CP_ASYNC16(svl + so, vl + go);
    }
    CP_COMMIT();

    CP_WAIT(1);
    __syncthreads();

    const int lg = lane >> 3, lr = lane & 7;
    const uint32_t atoff = (uint32_t)((lg >> 1) * 8 + lr) * AST +
                           (uint32_t)(w * 16 + (lg & 1) * 8) * 2;
    const uint32_t boff = (uint32_t)((lg >> 1) * 8 + lr) * AST + (uint32_t)(lg & 1) * 16;

    // ---- QK (2-product: q single, k hi/lo) ----
    float c[8][4];
#pragma unroll
    for (int nt = 0; nt < 8; nt++)
#pragma unroll
        for (int r = 0; r < 4; r++) c[nt][r] = 0.0f;

#pragma unroll
    for (int kc = 0; kc < 4; kc++) {
        uint32_t aq = sq + (uint32_t)kc * 16 * AST + atoff;
        uint32_t ah[4];
        LDSM_X4_T(ah[0], ah[1], ah[2], ah[3], aq);
#pragma unroll
        for (int g4 = 0; g4 < 4; g4++) {
            uint32_t bh4[4], bl4[4];
            uint32_t bko = (uint32_t)g4 * 16 * AST + boff + kc * 32;
            LDSM_X4(bh4[0], bh4[1], bh4[2], bh4[3], skh + bko);
            LDSM_X4(bl4[0], bl4[1], bl4[2], bl4[3], skl + bko);
#pragma unroll
            for (int sub = 0; sub < 2; sub++) {
                const int nt = g4 * 2 + sub, h = sub * 2;
                MMA_F16(c[nt], ah, bh4[h], bh4[h + 1]);
                MMA_F16(c[nt], ah, bl4[h], bl4[h + 1]);
            }
        }
    }

    // ---- log-softmax ----
    float mx0 = -1e30f, mx1 = -1e30f;
#pragma unroll
    for (int nt = 0; nt < 8; nt++) {
        mx0 = fmaxf(mx0, fmaxf(c[nt][0], c[nt][1]));
        mx1 = fmaxf(mx1, fmaxf(c[nt][2], c[nt][3]));
    }
    mx0 = fmaxf(mx0, __shfl_xor_sync(0xffffffffu, mx0, 1));
    mx0 = fmaxf(mx0, __shfl_xor_sync(0xffffffffu, mx0, 2));
    mx1 = fmaxf(mx1, __shfl_xor_sync(0xffffffffu, mx1, 1));
    mx1 = fmaxf(mx1, __shfl_xor_sync(0xffffffffu, mx1, 2));
    float se0 = 0.0f, se1 = 0.0f;
#pragma unroll
    for (int nt = 0; nt < 8; nt++) {
        se0 += fexpf(c[nt][0] - mx0) + fexpf(c[nt][1] - mx0);
        se1 += fexpf(c[nt][2] - mx1) + fexpf(c[nt][3] - mx1);
    }
    se0 += __shfl_xor_sync(0xffffffffu, se0, 1);
    se0 += __shfl_xor_sync(0xffffffffu, se0, 2);
    se1 += __shfl_xor_sync(0xffffffffu, se1, 1);
    se1 += __shfl_xor_sync(0xffffffffu, se1, 2);
    const float lse0 = mx0 + __logf(se0);
    const float lse1 = mx1 + __logf(se1);

    // ---- dropout + at hi/lo fragments ----
    const int r0 = w * 16 + gid;
    const float* m0p = mask_u + ((size_t)s * 64 + r0) * 64 + tig * 2;
    const float* m1p = m0p + 8 * 64;
    uint32_t ath0[8], atl0[8], ath1[8], atl1[8];
#pragma unroll
    for (int nt = 0; nt < 8; nt++) {
        const float2 mv0 = *reinterpret_cast<const float2*>(m0p + nt * 8);
        const float2 mv1 = *reinterpret_cast<const float2*>(m1p + nt * 8);
        float v0 = (c[nt][0] - lse0) * ((mv0.x > 0.25f) ? (1.0f / 0.75f) : 0.0f);
        float v1 = (c[nt][1] - lse0) * ((mv0.y > 0.25f) ? (1.0f / 0.75f) : 0.0f);
        float v2 = (c[nt][2] - lse1) * ((mv1.x > 0.25f) ? (1.0f / 0.75f) : 0.0f);
        float v3 = (c[nt][3] - lse1) * ((mv1.y > 0.25f) ? (1.0f / 0.75f) : 0.0f);
        __half h0 = __float2half_rn(v0), h1 = __float2half_rn(v1);
        __half h2 = __float2half_rn(v2), h3 = __float2half_rn(v3);
        ath0[nt] = ((uint32_t)__half_as_ushort(h1) << 16) | __half_as_ushort(h0);
        ath1[nt] = ((uint32_t)__half_as_ushort(h3) << 16) | __half_as_ushort(h2);
        atl0[nt] = pack2h(v0 - __half2float(h0), v1 - __half2float(h1));
        atl1[nt] = pack2h(v2 - __half2float(h2), v3 - __half2float(h3));
    }

    // ---- v ready? (prefetched during QK) ----
    CP_WAIT(0);
    __syncthreads();

    float o[8][4];
#pragma unroll
    for (int nt = 0; nt < 8; nt++)
#pragma unroll
        for (int r = 0; r < 4; r++) o[nt][r] = 0.0f;

#pragma unroll
    for (int mc = 0; mc < 4; mc++) {
        uint32_t Ah2[4] = {ath0[2 * mc], ath1[2 * mc], ath0[2 * mc + 1], ath1[2 * mc + 1]};
        uint32_t Al2[4] = {atl0[2 * mc], atl1[2 * mc], atl0[2 * mc + 1], atl1[2 * mc + 1]};
#pragma unroll
        for (int g4 = 0; g4 < 4; g4++) {
            uint32_t vh4[4], vl4[4];
            uint32_t bvo = (uint32_t)g4 * 16 * AST + boff + mc * 32;
            LDSM_X4(vh4[0], vh4[1], vh4[2], vh4[3], svh + bvo);
            LDSM_X4(vl4[0], vl4[1], vl4[2], vl4[3], svl + bvo);
#pragma unroll
            for (int sub = 0; sub < 2; sub++) {
                const int nt = g4 * 2 + sub, h = sub * 2;
                MMA_F16(o[nt], Ah2, vh4[h], vh4[h + 1]);
                MMA_F16(o[nt], Al2, vh4[h], vh4[h + 1]);
                MMA_F16(o[nt], Ah2, vl4[h], vl4[h + 1]);
            }
        }
    }

    __half* ohp = oh + (size_t)s * 4096;
#pragma unroll
    for (int nt = 0; nt < 8; nt++) {
        const int j = nt * 8 + tig * 2;
        *reinterpret_cast<uint32_t*>(ohp + r0 * 64 + j) = pack2h(o[nt][0], o[nt][1]);
        *reinterpret_cast<uint32_t*>(ohp + (r0 + 8) * 64 + j) = pack2h(o[nt][2], o[nt][3]);
    }
}

// ---------------------------------------------------------------------------
// output GEMM via HMMA fp16 single-product, split-K=8; m_base for half-split
// ---------------------------------------------------------------------------
#define OSA 80
#define OA_TB 10240
#define OBUF 15360
#define GO_SMEM 30720

__global__ __launch_bounds__(256) void gemm_out_mma(
    const __half* __restrict__ A, const __half* __restrict__ W,
    float* __restrict__ part, int m_base)
{
    extern __shared__ char smem[];
    const uint32_t sb = smem_u32(smem);
    const int tid = threadIdx.x;
    const int warp = tid >> 5, lane = tid & 31;
    const int m0 = (blockIdx.x + m_base) * 128;
    const int ksp = blockIdx.y;
    const int kbase = ksp * 512;
    const int wm = (warp & 3) * 32;
    const int wn = (warp >> 2) * 32;

    float c[2][4][4];
#pragma unroll
    for (int mt = 0; mt < 2; mt++)
#pragma unroll
        for (int nt = 0; nt < 4; nt++)
#pragma unroll
            for (int r = 0; r < 4; r++) c[mt][nt][r] = 0.0f;

    const int g = lane >> 3, r8 = lane & 7;
    const uint32_t a_off = (uint32_t)(wm + (g & 1) * 8 + r8) * OSA + (g >> 1) * 16;
    const uint32_t b_off = OA_TB + (uint32_t)(wn + (g >> 1) * 8 + r8) * OSA + (g & 1) * 16;

    auto stage = [&](int chunk, int buf) {
        const int k0 = kbase + chunk * 32;
        const uint32_t base = sb + buf * OBUF;
#pragma unroll
        for (int j = 0; j < 2; j++) {
            const int idx = tid + j * 256;
            const int row = idx >> 2, kc = (idx & 3) * 16;
            CP_ASYNC16(base + (uint32_t)row * OSA + kc,
                       A + (size_t)(m0 + row) * D4096 + k0 + kc / 2);
        }
        {
            const int row = tid >> 2, kc = (tid & 3) * 16;
            CP_ASYNC16(base + OA_TB + (uint32_t)row * OSA + kc,
                       W + (size_t)row * D4096 + k0 + kc / 2);
        }
        CP_COMMIT();
    };

    stage(0, 0);

    for (int it = 0; it < 16; ++it) {
        if (it + 1 < 16) {
            stage(it + 1, (it + 1) & 1);
            CP_WAIT(1);
        } else {
            CP_WAIT(0);
        }
        __syncthreads();

        const uint32_t buf = sb + (it & 1) * OBUF;
#pragma unroll
        for (int ks = 0; ks < 2; ++ks) {
            const uint32_t koff = ks * 32;
            uint32_t ah[2][4];
#pragma unroll
            for (int mt = 0; mt < 2; mt++) {
                const uint32_t aa = buf + a_off + koff + (uint32_t)mt * 16 * OSA;
                LDSM_X4(ah[mt][0], ah[mt][1], ah[mt][2], ah[mt][3], aa);
            }
#pragma unroll
            for (int g4 = 0; g4 < 2; g4++) {
                uint32_t b4[4];
                const uint32_t ba = buf + b_off + koff + (uint32_t)g4 * 16 * OSA;
                LDSM_X4(b4[0], b4[1], b4[2], b4[3], ba);
#pragma unroll
                for (int mt = 0; mt < 2; mt++) {
#pragma unroll
                    for (int sub = 0; sub < 2; sub++) {
                        const int nt = g4 * 2 + sub, h = sub * 2;
                        MMA_F16(c[mt][nt], ah[mt], b4[h], b4[h + 1]);
                    }
                }
            }
        }
        __syncthreads();
    }

    float* pbase = part + (size_t)ksp * S_LEN * 64;
    const int rbase = m0 + wm + (lane >> 2);
    const int cbase = wn + (lane & 3) * 2;
#pragma unroll
    for (int mt = 0; mt < 2; mt++) {
#pragma unroll
        for (int nt = 0; nt < 4; nt++) {
            const int col = cbase + nt * 8;
            float* p0 = pbase + (size_t)(rbase + mt * 16) * 64 + col;
            float* p1 = pbase + (size_t)(rbase + mt * 16 + 8) * 64 + col;
            p0[0] = c[mt][nt][0];
            p0[1] = c[mt][nt][1];
            p1[0] = c[mt][nt][2];
            p1[1] = c[mt][nt][3];
        }
    }
}

__global__ __launch_bounds__(256) void gemm_out_reduce(
    const float* __restrict__ part, const float* __restrict__ bias,
    float* __restrict__ out)
{
    const size_t i = (size_t)blockIdx.x * 256 + threadIdx.x;
    float s = bias[i & 63];
#pragma unroll
    for (int k = 0; k < 8; k++) s += part[i + (size_t)k * S_LEN * 64];
    out[i] = s;
}

// ---------------------------------------------------------------------------
// Launch: side stream for weight prep + k/v proj; tail pipelined in halves.
// ---------------------------------------------------------------------------
extern "C" void kernel_launch(void* const* d_in, const int* in_sizes, int n_in,
                              void* d_out, int out_size)
{
    const float* query  = (const float*)d_in[0];
    const float* key_in = (const float*)d_in[1];
    const float* value  = (const float*)d_in[2];
    const float* mask_u = (const float*)d_in[3];
    const float* Wq = (const float*)d_in[4];
    const float* bq = (const float*)d_in[5];
    const float* Wk = (const float*)d_in[6];
    const float* bk = (const float*)d_in[7];
    const float* Wv = (const float*)d_in[8];
    const float* bv = (const float*)d_in[9];
    const float* Wo = (const float*)d_in[10];
    const float* bo = (const float*)d_in[11];
    float* out = (float*)d_out;

    float *gq, *gk, *gv;
    __half *ah, *b, *xh, *xl, *w, *wo;
    cudaGetSymbolAddress((void**)&gq, g_q);
    cudaGetSymbolAddress((void**)&gk, g_k);
    cudaGetSymbolAddress((void**)&gv, g_v);
    cudaGetSymbolAddress((void**)&ah, g_Ah);
    cudaGetSymbolAddress((void**)&b, g_B);
    cudaGetSymbolAddress((void**)&xh, g_xh);
    cudaGetSymbolAddress((void**)&xl, g_xl);
    cudaGetSymbolAddress((void**)&w, g_w);
    cudaGetSymbolAddress((void**)&wo, g_wo);

    __half* qh = (__half*)gq;                       // GEMM1 fp16 output
    __half* kh = (__half*)gk;
    __half* kl = kh + (size_t)S_LEN * D4096;
    __half* vh = (__half*)gv;
    __half* vl = vh + (size_t)S_LEN * D4096;

    cudaFuncSetAttribute(mma_gemm_q, cudaFuncAttributeMaxDynamicSharedMemorySize, GQ_SMEM);
    cudaFuncSetAttribute(mma_proj_h, cudaFuncAttributeMaxDynamicSharedMemorySize, PROJ_SMEM);
    cudaFuncSetAttribute(gemm_out_mma, cudaFuncAttributeMaxDynamicSharedMemorySize, GO_SMEM);

    cudaStream_t s1;
    cudaStreamCreateWithFlags(&s1, cudaStreamNonBlocking);
    cudaEvent_t e0, e1, e2, eA, e3;
    cudaEventCreateWithFlags(&e0, cudaEventDisableTiming);
    cudaEventCreateWithFlags(&e1, cudaEventDisableTiming);
    cudaEventCreateWithFlags(&e2, cudaEventDisableTiming);
    cudaEventCreateWithFlags(&eA, cudaEventDisableTiming);
    cudaEventCreateWithFlags(&e3, cudaEventDisableTiming);

    cudaEventRecord(e0, 0);
    cudaStreamWaitEvent(s1, e0, 0);

    // side stream: Wq transpose first, then k/v projections + Wo transpose
    transpose_h<<<dim3(64, 64), 256, 0, s1>>>(Wq, b);
    cudaEventRecord(e2, s1);
    convert_split_h<<<(S_LEN * 64) / 2048, 256, 0, s1>>>(key_in, xh, xl);
    transpose_w64_h<<<64, 256, 0, s1>>>(Wk, w);
    mma_proj_h<<<dim3(D4096 / 128, S_LEN / 128), 256, PROJ_SMEM, s1>>>(xh, xl, w, bk, kh, kl);
    convert_split_h<<<(S_LEN * 64) / 2048, 256, 0, s1>>>(value, xh, xl);
    transpose_w64_h<<<64, 256, 0, s1>>>(Wv, w);
    mma_proj_h<<<dim3(D4096 / 128, S_LEN / 128), 256, PROJ_SMEM, s1>>>(xh, xl, w, bv, vh, vl);
    transpose_wo_h<<<64, 256, 0, s1>>>(Wo, wo);

    // main stream: query convert + big GEMM (fp16 output)
    convert_h<<<(S_LEN * (size_t)D4096) / 2048, 256>>>(query, ah);
    cudaStreamWaitEvent(0, e2, 0);
    mma_gemm_q<<<1024, 512, GQ_SMEM>>>(ah, b, bq, qh);

    // join side stream (k/v/Wo ready)
    cudaEventRecord(e1, s1);
    cudaStreamWaitEvent(0, e1, 0);

    // attention in two halves; gemm_out half-1 overlaps attn half-2
    float* part = (float*)b;
    attn_mma<<<S_LEN / 2, 128>>>(mask_u, qh, kh, kl, vh, vl, ah, 0);
    cudaEventRecord(eA, 0);
    cudaStreamWaitEvent(s1, eA, 0);
    gemm_out_mma<<<dim3(32, 8), 256, GO_SMEM, s1>>>(ah, wo, part, 0);
    attn_mma<<<S_LEN / 2, 128>>>(mask_u, qh, kh, kl, vh, vl, ah, S_LEN / 2);
    gemm_out_mma<<<dim3(32, 8), 256, GO_SMEM>>>(ah, wo, part, 32);
    cudaEventRecord(e3, s1);
    cudaStreamWaitEvent(0, e3, 0);
    gemm_out_reduce<<<(S_LEN * 64) / 256, 256>>>(part, bo, out);

    cudaEventDestroy(e0);
    cudaEventDestroy(e1);
    cudaEventDestroy(e2);
    cudaEventDestroy(eA);
    cudaEventDestroy(e3);
    cudaStreamDestroy(s1);
}

// round 16
// speedup vs baseline: 7.3221x; 1.0199x over previous
#include <cuda_runtime.h>
#include <cuda_bf16.h>
#include <cuda_fp16.h>
#include <cstdint>

#define S_LEN 8192
#define D4096 4096

__device__ float g_q[(size_t)S_LEN * D4096];      // aliased: GEMM1 fp16 output (q)
__device__ float g_k[(size_t)S_LEN * D4096];      // aliased: k fp16 hi | lo
__device__ float g_v[(size_t)S_LEN * D4096];      // aliased: v fp16 hi | lo
__device__ __half g_Ah[(size_t)S_LEN * D4096];    // query fp16; later attn-out fp16
__device__ __half g_B[(size_t)D4096 * D4096];     // Wq^T fp16
__device__ float g_part[(size_t)8 * S_LEN * 64];  // split-K partials (dedicated)
__device__ __half g_xh[(size_t)S_LEN * 64];
__device__ __half g_xl[(size_t)S_LEN * 64];
__device__ __half g_w[(size_t)D4096 * 64];
__device__ __half g_wo[(size_t)64 * D4096];

__device__ __forceinline__ uint32_t smem_u32(const void* p) {
    uint32_t a;
    asm("{ .reg .u64 t; cvta.to.shared.u64 t, %1; cvt.u32.u64 %0, t; }"
        : "=r"(a) : "l"(p));
    return a;
}

#define CP_ASYNC16(saddr, gptr) \
    asm volatile("cp.async.cg.shared.global [%0], [%1], 16;" \
                 :: "r"(saddr), "l"(gptr) : "memory")
#define CP_COMMIT() asm volatile("cp.async.commit_group;" ::: "memory")
#define CP_WAIT(n)  asm volatile("cp.async.wait_group %0;" :: "n"(n) : "memory")

#define LDSM_X4(r0, r1, r2, r3, addr) \
    asm volatile("ldmatrix.sync.aligned.m8n8.x4.shared.b16 {%0,%1,%2,%3}, [%4];" \
                 : "=r"(r0), "=r"(r1), "=r"(r2), "=r"(r3) : "r"(addr))

#define LDSM_X4_T(r0, r1, r2, r3, addr) \
    asm volatile("ldmatrix.sync.aligned.m8n8.x4.trans.shared.b16 {%0,%1,%2,%3}, [%4];" \
                 : "=r"(r0), "=r"(r1), "=r"(r2), "=r"(r3) : "r"(addr))

#define MMA_F16(c, a, b0, b1) \
    asm volatile( \
        "mma.sync.aligned.m16n8k16.row.col.f32.f16.f16.f32 " \
        "{%0,%1,%2,%3}, {%4,%5,%6,%7}, {%8,%9}, {%0,%1,%2,%3};" \
        : "+f"((c)[0]), "+f"((c)[1]), "+f"((c)[2]), "+f"((c)[3]) \
        : "r"((a)[0]), "r"((a)[1]), "r"((a)[2]), "r"((a)[3]), "r"(b0), "r"(b1))

// fast exp on FFMA pipe (rel err ~4e-5)
__device__ __forceinline__ float fexpf(float x) {
    x = fmaxf(x, -87.0f);
    float y = x * 1.4426950408889634f;
    float n = rintf(y);
    float f = y - n;
    float p = 1.3337294e-3f;
    p = fmaf(p, f, 9.6181291e-3f);
    p = fmaf(p, f, 5.5504109e-2f);
    p = fmaf(p, f, 2.4022651e-1f);
    p = fmaf(p, f, 6.9314718e-1f);
    p = fmaf(p, f, 1.0f);
    return p * __int_as_float((__float2int_rn(n) + 127) << 23);
}

__device__ __forceinline__ uint32_t pack2h(float a, float b) {
    __half2 h = __floats2half2_rn(a, b);
    return *reinterpret_cast<uint32_t*>(&h);
}

// ---------------------------------------------------------------------------
__global__ __launch_bounds__(256) void convert_h(
    const float* __restrict__ in, __half* __restrict__ out)
{
    const size_t base = ((size_t)blockIdx.x * 256 + threadIdx.x) * 8;
    float4 a = *reinterpret_cast<const float4*>(in + base);
    float4 b = *reinterpret_cast<const float4*>(in + base + 4);
    float f[8] = {a.x, a.y, a.z, a.w, b.x, b.y, b.z, b.w};
    __half h[8];
#pragma unroll
    for (int i = 0; i < 8; i++) h[i] = __float2half_rn(f[i]);
    *reinterpret_cast<uint4*>(out + base) = *reinterpret_cast<uint4*>(h);
}

__global__ __launch_bounds__(256) void convert_split_h(
    const float* __restrict__ in, __half* __restrict__ hi,
    __half* __restrict__ lo)
{
    const size_t base = ((size_t)blockIdx.x * 256 + threadIdx.x) * 8;
    float4 a = *reinterpret_cast<const float4*>(in + base);
    float4 b = *reinterpret_cast<const float4*>(in + base + 4);
    float f[8] = {a.x, a.y, a.z, a.w, b.x, b.y, b.z, b.w};
    __half h[8], l[8];
#pragma unroll
    for (int i = 0; i < 8; i++) {
        h[i] = __float2half_rn(f[i]);
        l[i] = __float2half_rn(f[i] - __half2float(h[i]));
    }
    *reinterpret_cast<uint4*>(hi + base) = *reinterpret_cast<uint4*>(h);
    *reinterpret_cast<uint4*>(lo + base) = *reinterpret_cast<uint4*>(l);
}

__global__ __launch_bounds__(256) void transpose_h(
    const float* __restrict__ W, __half* __restrict__ out)
{
    __shared__ float ts[64][65];
    const int n0 = blockIdx.x * 64;
    const int k0 = blockIdx.y * 64;
    const int tid = threadIdx.x;
#pragma unroll
    for (int i = 0; i < 16; i++) {
        int idx = tid + i * 256;
        int r = idx >> 6, c = idx & 63;
        ts[r][c] = W[(size_t)(k0 + r) * D4096 + n0 + c];
    }
    __syncthreads();
#pragma unroll
    for (int i = 0; i < 8; i++) {
        int idx = tid + i * 256;
        int nl = idx >> 5, kl = (idx & 31) * 2;
        __half2 p;
        p.x = __float2half_rn(ts[kl][nl]);
        p.y = __float2half_rn(ts[kl + 1][nl]);
        *reinterpret_cast<__half2*>(out + (size_t)(n0 + nl) * D4096 + k0 + kl) = p;
    }
}

__global__ __launch_bounds__(256) void transpose_w64_h(
    const float* __restrict__ W, __half* __restrict__ out)
{
    __shared__ float ts[64][65];
    const int n0 = blockIdx.x * 64;
    const int tid = threadIdx.x;
    for (int t = tid; t < 4096; t += 256)
        ts[t >> 6][t & 63] = W[(size_t)(t >> 6) * D4096 + n0 + (t & 63)];
    __syncthreads();
    for (int t = tid; t < 4096; t += 256) {
        int nl = t >> 6, kl = t & 63;
        out[(size_t)(n0 + nl) * 64 + kl] = __float2half_rn(ts[kl][nl]);
    }
}

__global__ __launch_bounds__(256) void transpose_wo_h(
    const float* __restrict__ W, __half* __restrict__ out)
{
    __shared__ float ts[64][65];
    const int k0 = blockIdx.x * 64;
    const int tid = threadIdx.x;
    for (int t = tid; t < 4096; t += 256)
        ts[t >> 6][t & 63] = W[(size_t)(k0 + (t >> 6)) * 64 + (t & 63)];
    __syncthreads();
    for (int t = tid; t < 4096; t += 256) {
        int n = t >> 6, k = t & 63;
        out[(size_t)n * D4096 + k0 + k] = __float2half_rn(ts[k][n]);
    }
}

// ---------------------------------------------------------------------------
// Main HMMA GEMM, single-product fp16, fp16 output, m-half split.
// CTA 128x256, 512 thr (16 warps, 4m x 4n), K-chunk 64, 3-stage.
// ---------------------------------------------------------------------------
#define SA 144
#define A_TB 18432
#define BUF_B 55296
#define GQ_SMEM 165888

__global__ __launch_bounds__(512) void mma_gemm_q(
    const __half* __restrict__ A, const __half* __restrict__ B,
    const float* __restrict__ bias, __half* __restrict__ C, int m_base)
{
    extern __shared__ char smem[];
    const uint32_t sb = smem_u32(smem);
    const int tid = threadIdx.x;
    const int warp = tid >> 5, lane = tid & 31;

    const int m0 = ((blockIdx.x >> 4) + m_base) * 128;
    const int n0 = (blockIdx.x & 15) * 256;

    const int wm = (warp & 3) * 32;
    const int wn = (warp >> 2) * 64;

    float c[2][8][4];
#pragma unroll
    for (int mt = 0; mt < 2; mt++)
#pragma unroll
        for (int nt = 0; nt < 8; nt++)
#pragma unroll
            for (int r = 0; r < 4; r++) c[mt][nt][r] = 0.0f;

    const int g = lane >> 3, r8 = lane & 7;
    const uint32_t a_off = (uint32_t)(wm + (g & 1) * 8 + r8) * SA + (g >> 1) * 16;
    const uint32_t b_off = A_TB + (uint32_t)(wn + (g >> 1) * 8 + r8) * SA + (g & 1) * 16;

    auto stage = [&](int chunk, int buf) {
        const int k0 = chunk * 64;
        const uint32_t base = sb + buf * BUF_B;
#pragma unroll
        for (int j = 0; j < 2; j++) {
            const int idx = tid + j * 512;
            const int row = idx >> 3, kc = (idx & 7) * 16;
            CP_ASYNC16(base + (uint32_t)row * SA + kc,
                       A + (size_t)(m0 + row) * D4096 + k0 + kc / 2);
        }
#pragma unroll
        for (int j = 0; j < 4; j++) {
            const int idx = tid + j * 512;
            const int row = idx >> 3, kc = (idx & 7) * 16;
            CP_ASYNC16(base + A_TB + (uint32_t)row * SA + kc,
                       B + (size_t)(n0 + row) * D4096 + k0 + kc / 2);
        }
        CP_COMMIT();
    };

    stage(0, 0);
    stage(1, 1);

    const int NIT = D4096 / 64;
    for (int it = 0; it < NIT; ++it) {
        if (it == NIT - 1) { CP_WAIT(0); } else { CP_WAIT(1); }
        __syncthreads();
        if (it + 2 < NIT) stage(it + 2, (it + 2) % 3);

        const uint32_t buf = sb + (it % 3) * BUF_B;
#pragma unroll
        for (int ks = 0; ks < 4; ++ks) {
            const uint32_t koff = ks * 32;
            uint32_t ah[2][4];
#pragma unroll
            for (int mt = 0; mt < 2; mt++) {
                const uint32_t aa = buf + a_off + koff + (uint32_t)mt * 16 * SA;
                LDSM_X4(ah[mt][0], ah[mt][1], ah[mt][2], ah[mt][3], aa);
            }
#pragma unroll
            for (int g4 = 0; g4 < 4; g4++) {
                uint32_t b4[4];
                const uint32_t ba = buf + b_off + koff + (uint32_t)g4 * 16 * SA;
                LDSM_X4(b4[0], b4[1], b4[2], b4[3], ba);
#pragma unroll
                for (int mt = 0; mt < 2; mt++) {
#pragma unroll
                    for (int sub = 0; sub < 2; sub++) {
                        const int nt = g4 * 2 + sub, h = sub * 2;
                        MMA_F16(c[mt][nt], ah[mt], b4[h], b4[h + 1]);
                    }
                }
            }
        }
    }

    const int rbase = m0 + wm + (lane >> 2);
    const int cbase = n0 + wn + (lane & 3) * 2;
#pragma unroll
    for (int mt = 0; mt < 2; mt++) {
#pragma unroll
        for (int nt = 0; nt < 8; nt++) {
            const int col = cbase + nt * 8;
            const float b0 = bias[col], b1 = bias[col + 1];
            *reinterpret_cast<uint32_t*>(C + (size_t)(rbase + mt * 16) * D4096 + col) =
                pack2h(c[mt][nt][0] + b0, c[mt][nt][1] + b1);
            *reinterpret_cast<uint32_t*>(C + (size_t)(rbase + mt * 16 + 8) * D4096 + col) =
                pack2h(c[mt][nt][2] + b0, c[mt][nt][3] + b1);
        }
    }
}

// ---------------------------------------------------------------------------
// HMMA projection (K=64), fp16 2-product; emits fp16 hi/lo.
// ---------------------------------------------------------------------------
#define PSA 144
#define P_TB 18432
#define PROJ_SMEM 55296

__global__ __launch_bounds__(256) void mma_proj_h(
    const __half* __restrict__ Xh, const __half* __restrict__ Xl,
    const __half* __restrict__ W, const float* __restrict__ bias,
    __half* __restrict__ outh, __half* __restrict__ outl)
{
    extern __shared__ char smem[];
    const uint32_t sb = smem_u32(smem);
    const int tid = threadIdx.x;
    const int warp = tid >> 5, lane = tid & 31;
    const int m0 = blockIdx.y * 128;
    const int n0 = blockIdx.x * 128;
    const int wm = (warp & 3) * 32;
    const int wn = (warp >> 2) * 64;

#pragma unroll
    for (int j = 0; j < 4; j++) {
        const int idx = tid + j * 256;
        const int row = idx >> 3, kc = (idx & 7) * 16;
        const uint32_t sa = sb + (uint32_t)row * PSA + kc;
        const size_t gx = (size_t)(m0 + row) * 64 + kc / 2;
        const size_t gw = (size_t)(n0 + row) * 64 + kc / 2;
        CP_ASYNC16(sa, Xh + gx);
        CP_ASYNC16(sa + P_TB, Xl + gx);
        CP_ASYNC16(sa + 2 * P_TB, W + gw);
    }
    CP_COMMIT();

    float c[2][8][4];
#pragma unroll
    for (int mt = 0; mt < 2; mt++)
#pragma unroll
        for (int nt = 0; nt < 8; nt++)
#pragma unroll
            for (int r = 0; r < 4; r++) c[mt][nt][r] = 0.0f;

    const int g = lane >> 3, r8 = lane & 7;
    const uint32_t a_off = (uint32_t)(wm + (g & 1) * 8 + r8) * PSA + (g >> 1) * 16;
    const uint32_t b_off = 2 * P_TB + (uint32_t)(wn + (g >> 1) * 8 + r8) * PSA + (g & 1) * 16;

    CP_WAIT(0);
    __syncthreads();

#pragma unroll
    for (int ks = 0; ks < 4; ++ks) {
        const uint32_t koff = ks * 32;
        uint32_t ah[2][4], al[2][4];
#pragma unroll
        for (int mt = 0; mt < 2; mt++) {
            const uint32_t aa = sb + a_off + koff + (uint32_t)mt * 16 * PSA;
            LDSM_X4(ah[mt][0], ah[mt][1], ah[mt][2], ah[mt][3], aa);
            LDSM_X4(al[mt][0], al[mt][1], al[mt][2], al[mt][3], aa + P_TB);
        }
#pragma unroll
        for (int g4 = 0; g4 < 4; g4++) {
            uint32_t b4[4];
            const uint32_t ba = sb + b_off + koff + (uint32_t)g4 * 16 * PSA;
            LDSM_X4(b4[0], b4[1], b4[2], b4[3], ba);
#pragma unroll
            for (int mt = 0; mt < 2; mt++) {
#pragma unroll
                for (int sub = 0; sub < 2; sub++) {
                    const int nt = g4 * 2 + sub, h = sub * 2;
                    MMA_F16(c[mt][nt], ah[mt], b4[h], b4[h + 1]);
                    MMA_F16(c[mt][nt], al[mt], b4[h], b4[h + 1]);
                }
            }
        }
    }

    const int rbase = m0 + wm + (lane >> 2);
    const int cbase = n0 + wn + (lane & 3) * 2;
#pragma unroll
    for (int mt = 0; mt < 2; mt++) {
#pragma unroll
        for (int nt = 0; nt < 8; nt++) {
            const int col = cbase + nt * 8;
            const float b0 = bias[col], b1 = bias[col + 1];
#pragma unroll
            for (int half_ = 0; half_ < 2; half_++) {
                const float s0 = c[mt][nt][half_ * 2 + 0] + b0;
                const float s1 = c[mt][nt][half_ * 2 + 1] + b1;
                const __half h0 = __float2half_rn(s0), h1 = __float2half_rn(s1);
                const size_t off = (size_t)(rbase + mt * 16 + half_ * 8) * D4096 + col;
                *reinterpret_cast<uint32_t*>(outh + off) =
                    ((uint32_t)__half_as_ushort(h1) << 16) | __half_as_ushort(h0);
                *reinterpret_cast<uint32_t*>(outl + off) =
                    pack2h(s0 - __half2float(h0), s1 - __half2float(h1));
            }
        }
    }
}

// ---------------------------------------------------------------------------
// Tensorized per-token attention. QK 2-product (q, k hi/lo);
// PV 2-product (at hi/lo, v single). smem: q, kh, kl, vh (36864 B).
// ---------------------------------------------------------------------------
#define AST 144

__global__ __launch_bounds__(128, 4) void attn_mma(
    const float* __restrict__ mask_u,
    const __half* __restrict__ qh, const __half* __restrict__ kh,
    const __half* __restrict__ kl, const __half* __restrict__ vh,
    __half* __restrict__ oh, int s_base)
{
    __shared__ __half smq[64 * 72];
    __shared__ __half smkh[64 * 72];
    __shared__ __half smkl[64 * 72];
    __shared__ __half smvh[64 * 72];

    const int s = blockIdx.x + s_base;
    const int tid = threadIdx.x;
    const int w = tid >> 5, lane = tid & 31;
    const int gid = lane >> 2, tig = lane & 3;

    const uint32_t sq = smem_u32(smq);
    const uint32_t skh = smem_u32(smkh);
    const uint32_t skl = smem_u32(smkl);
    const uint32_t svh = smem_u32(smvh);

    const size_t gbase = (size_t)s * 4096;
#pragma unroll
    for (int j = 0; j < 4; j++) {
        const int t = tid + j * 128;
        const int row = t >> 3, kc = (t & 7) * 16;
        const uint32_t so = (uint32_t)row * AST + kc;
        const size_t go = gbase + (size_t)row * 64 + kc / 2;
        CP_ASYNC16(sq + so, qh + go);
        CP_ASYNC16(skh + so, kh + go);
        CP_ASYNC16(skl + so, kl + go);
    }
    CP_COMMIT();
#pragma unroll
    for (int j = 0; j < 4; j++) {
        const int t = tid + j * 128;
        const int row = t >> 3, kc = (t & 7) * 16;
        CP_ASYNC16(svh + (uint32_t)row * AST + kc,
                   vh + gbase + (size_t)row * 64 + kc / 2);
    }
    CP_COMMIT();

    CP_WAIT(1);
    __syncthreads();

    const int lg = lane >> 3, lr = lane & 7;
    const uint32_t atoff = (uint32_t)((lg >> 1) * 8 + lr) * AST +
                           (uint32_t)(w * 16 + (lg & 1) * 8) * 2;
    const uint32_t boff = (uint32_t)((lg >> 1) * 8 + lr) * AST + (uint32_t)(lg & 1) * 16;

    float c[8][4];
#pragma unroll
    for (int nt = 0; nt < 8; nt++)
#pragma unroll
        for (int r = 0; r < 4; r++) c[nt][r] = 0.0f;

#pragma unroll
    for (int kc = 0; kc < 4; kc++) {
        uint32_t aq = sq + (uint32_t)kc * 16 * AST + atoff;
        uint32_t ah[4];
        LDSM_X4_T(ah[0], ah[1], ah[2], ah[3], aq);
#pragma unroll
        for (int g4 = 0; g4 < 4; g4++) {
            uint32_t bh4[4], bl4[4];
            uint32_t bko = (uint32_t)g4 * 16 * AST + boff + kc * 32;
            LDSM_X4(bh4[0], bh4[1], bh4[2], bh4[3], skh + bko);
            LDSM_X4(bl4[0], bl4[1], bl4[2], bl4[3], skl + bko);
#pragma unroll
            for (int sub = 0; sub < 2; sub++) {
                const int nt = g4 * 2 + sub, h = sub * 2;
                MMA_F16(c[nt], ah, bh4[h], bh4[h + 1]);
                MMA_F16(c[nt], ah, bl4[h], bl4[h + 1]);
            }
        }
    }

    float mx0 = -1e30f, mx1 = -1e30f;
#pragma unroll
    for (int nt = 0; nt < 8; nt++) {
        mx0 = fmaxf(mx0, fmaxf(c[nt][0], c[nt][1]));
        mx1 = fmaxf(mx1, fmaxf(c[nt][2], c[nt][3]));
    }
    mx0 = fmaxf(mx0, __shfl_xor_sync(0xffffffffu, mx0, 1));
    mx0 = fmaxf(mx0, __shfl_xor_sync(0xffffffffu, mx0, 2));
    mx1 = fmaxf(mx1, __shfl_xor_sync(0xffffffffu, mx1, 1));
    mx1 = fmaxf(mx1, __shfl_xor_sync(0xffffffffu, mx1, 2));
    float se0 = 0.0f, se1 = 0.0f;
#pragma unroll
    for (int nt = 0; nt < 8; nt++) {
        se0 += fexpf(c[nt][0] - mx0) + fexpf(c[nt][1] - mx0);
        se1 += fexpf(c[nt][2] - mx1) + fexpf(c[nt][3] - mx1);
    }
    se0 += __shfl_xor_sync(0xffffffffu, se0, 1);
    se0 += __shfl_xor_sync(0xffffffffu, se0, 2);
    se1 += __shfl_xor_sync(0xffffffffu, se1, 1);
    se1 += __shfl_xor_sync(0xffffffffu, se1, 2);
    const float lse0 = mx0 + __logf(se0);
    const float lse1 = mx1 + __logf(se1);

    const int r0 = w * 16 + gid;
    const float* m0p = mask_u + ((size_t)s * 64 + r0) * 64 + tig * 2;
    const float* m1p = m0p + 8 * 64;
    uint32_t ath0[8], atl0[8], ath1[8], atl1[8];
#pragma unroll
    for (int nt = 0; nt < 8; nt++) {
        const float2 mv0 = *reinterpret_cast<const float2*>(m0p + nt * 8);
        const float2 mv1 = *reinterpret_cast<const float2*>(m1p + nt * 8);
        float v0 = (c[nt][0] - lse0) * ((mv0.x > 0.25f) ? (1.0f / 0.75f) : 0.0f);
        float v1 = (c[nt][1] - lse0) * ((mv0.y > 0.25f) ? (1.0f / 0.75f) : 0.0f);
        float v2 = (c[nt][2] - lse1) * ((mv1.x > 0.25f) ? (1.0f / 0.75f) : 0.0f);
        float v3 = (c[nt][3] - lse1) * ((mv1.y > 0.25f) ? (1.0f / 0.75f) : 0.0f);
        __half h0 = __float2half_rn(v0), h1 = __float2half_rn(v1);
        __half h2 = __float2half_rn(v2), h3 = __float2half_rn(v3);
        ath0[nt] = ((uint32_t)__half_as_ushort(h1) << 16) | __half_as_ushort(h0);
        ath1[nt] = ((uint32_t)__half_as_ushort(h3) << 16) | __half_as_ushort(h2);
        atl0[nt] = pack2h(v0 - __half2float(h0), v1 - __half2float(h1));
        atl1[nt] = pack2h(v2 - __half2float(h2), v3 - __half2float(h3));
    }

    CP_WAIT(0);
    __syncthreads();

    float o[8][4];
#pragma unroll
    for (int nt = 0; nt < 8; nt++)
#pragma unroll
        for (int r = 0; r < 4; r++) o[nt][r] = 0.0f;

#pragma unroll
    for (int mc = 0; mc < 4; mc++) {
        uint32_t Ah2[4] = {ath0[2 * mc], ath1[2 * mc], ath0[2 * mc + 1], ath1[2 * mc + 1]};
        uint32_t Al2[4] = {atl0[2 * mc], atl1[2 * mc], atl0[2 * mc + 1], atl1[2 * mc + 1]};
#pragma unroll
        for (int g4 = 0; g4 < 4; g4++) {
            uint32_t vh4[4];
            uint32_t bvo = (uint32_t)g4 * 16 * AST + boff + mc * 32;
            LDSM_X4(vh4[0], vh4[1], vh4[2], vh4[3], svh + bvo);
#pragma unroll
            for (int sub = 0; sub < 2; sub++) {
                const int nt = g4 * 2 + sub, h = sub * 2;
                MMA_F16(o[nt], Ah2, vh4[h], vh4[h + 1]);
                MMA_F16(o[nt], Al2, vh4[h], vh4[h + 1]);
            }
        }
    }

    __half* ohp = oh + (size_t)s * 4096;
#pragma unroll
    for (int nt = 0; nt < 8; nt++) {
        const int j = nt * 8 + tig * 2;
        *reinterpret_cast<uint32_t*>(ohp + r0 * 64 + j) = pack2h(o[nt][0], o[nt][1]);
        *reinterpret_cast<uint32_t*>(ohp + (r0 + 8) * 64 + j) = pack2h(o[nt][2], o[nt][3]);
    }
}

// ---------------------------------------------------------------------------
// output GEMM via HMMA fp16 single-product, split-K=8; m_base for half-split
// ---------------------------------------------------------------------------
#define OSA 80
#define OA_TB 10240
#define OBUF 15360
#define GO_SMEM 30720

__global__ __launch_bounds__(256) void gemm_out_mma(
    const __half* __restrict__ A, const __half* __restrict__ W,
    float* __restrict__ part, int m_base)
{
    extern __shared__ char smem[];
    const uint32_t sb = smem_u32(smem);
    const int tid = threadIdx.x;
    const int warp = tid >> 5, lane = tid & 31;
    const int m0 = (blockIdx.x + m_base) * 128;
    const int ksp = blockIdx.y;
    const int kbase = ksp * 512;
    const int wm = (warp & 3) * 32;
    const int wn = (warp >> 2) * 32;

    float c[2][4][4];
#pragma unroll
    for (int mt = 0; mt < 2; mt++)
#pragma unroll
        for (int nt = 0; nt < 4; nt++)
#pragma unroll
            for (int r = 0; r < 4; r++) c[mt][nt][r] = 0.0f;

    const int g = lane >> 3, r8 = lane & 7;
    const uint32_t a_off = (uint32_t)(wm + (g & 1) * 8 + r8) * OSA + (g >> 1) * 16;
    const uint32_t b_off = OA_TB + (uint32_t)(wn + (g >> 1) * 8 + r8) * OSA + (g & 1) * 16;

    auto stage = [&](int chunk, int buf) {
        const int k0 = kbase + chunk * 32;
        const uint32_t base = sb + buf * OBUF;
#pragma unroll
        for (int j = 0; j < 2; j++) {
            const int idx = tid + j * 256;
            const int row = idx >> 2, kc = (idx & 3) * 16;
            CP_ASYNC16(base + (uint32_t)row * OSA + kc,
                       A + (size_t)(m0 + row) * D4096 + k0 + kc / 2);
        }
        {
            const int row = tid >> 2, kc = (tid & 3) * 16;
            CP_ASYNC16(base + OA_TB + (uint32_t)row * OSA + kc,
                       W + (size_t)row * D4096 + k0 + kc / 2);
        }
        CP_COMMIT();
    };

    stage(0, 0);

    for (int it = 0; it < 16; ++it) {
        if (it + 1 < 16) {
            stage(it + 1, (it + 1) & 1);
            CP_WAIT(1);
        } else {
            CP_WAIT(0);
        }
        __syncthreads();

        const uint32_t buf = sb + (it & 1) * OBUF;
#pragma unroll
        for (int ks = 0; ks < 2; ++ks) {
            const uint32_t koff = ks * 32;
            uint32_t ah[2][4];
#pragma unroll
            for (int mt = 0; mt < 2; mt++) {
                const uint32_t aa = buf + a_off + koff + (uint32_t)mt * 16 * OSA;
                LDSM_X4(ah[mt][0], ah[mt][1], ah[mt][2], ah[mt][3], aa);
            }
#pragma unroll
            for (int g4 = 0; g4 < 2; g4++) {
                uint32_t b4[4];
                const uint32_t ba = buf + b_off + koff + (uint32_t)g4 * 16 * OSA;
                LDSM_X4(b4[0], b4[1], b4[2], b4[3], ba);
#pragma unroll
                for (int mt = 0; mt < 2; mt++) {
#pragma unroll
                    for (int sub = 0; sub < 2; sub++) {
                        const int nt = g4 * 2 + sub, h = sub * 2;
                        MMA_F16(c[mt][nt], ah[mt], b4[h], b4[h + 1]);
                    }
                }
            }
        }
        __syncthreads();
    }

    float* pbase = part + (size_t)ksp * S_LEN * 64;
    const int rbase = m0 + wm + (lane >> 2);
    const int cbase = wn + (lane & 3) * 2;
#pragma unroll
    for (int mt = 0; mt < 2; mt++) {
#pragma unroll
        for (int nt = 0; nt < 4; nt++) {
            const int col = cbase + nt * 8;
            float* p0 = pbase + (size_t)(rbase + mt * 16) * 64 + col;
            float* p1 = pbase + (size_t)(rbase + mt * 16 + 8) * 64 + col;
            p0[0] = c[mt][nt][0];
            p0[1] = c[mt][nt][1];
            p1[0] = c[mt][nt][2];
            p1[1] = c[mt][nt][3];
        }
    }
}

__global__ __launch_bounds__(256) void gemm_out_reduce(
    const float* __restrict__ part, const float* __restrict__ bias,
    float* __restrict__ out)
{
    const size_t i = (size_t)blockIdx.x * 256 + threadIdx.x;
    float s = bias[i & 63];
#pragma unroll
    for (int k = 0; k < 8; k++) s += part[i + (size_t)k * S_LEN * 64];
    out[i] = s;
}

// ---------------------------------------------------------------------------
// Launch: GEMM1 halves pipelined with attention + output GEMM halves.
// ---------------------------------------------------------------------------
extern "C" void kernel_launch(void* const* d_in, const int* in_sizes, int n_in,
                              void* d_out, int out_size)
{
    const float* query  = (const float*)d_in[0];
    const float* key_in = (const float*)d_in[1];
    const float* value  = (const float*)d_in[2];
    const float* mask_u = (const float*)d_in[3];
    const float* Wq = (const float*)d_in[4];
    const float* bq = (const float*)d_in[5];
    const float* Wk = (const float*)d_in[6];
    const float* bk = (const float*)d_in[7];
    const float* Wv = (const float*)d_in[8];
    const float* bv = (const float*)d_in[9];
    const float* Wo = (const float*)d_in[10];
    const float* bo = (const float*)d_in[11];
    float* out = (float*)d_out;

    float *gq, *gk, *gv, *part;
    __half *ah, *b, *xh, *xl, *w, *wo;
    cudaGetSymbolAddress((void**)&gq, g_q);
    cudaGetSymbolAddress((void**)&gk, g_k);
    cudaGetSymbolAddress((void**)&gv, g_v);
    cudaGetSymbolAddress((void**)&part, g_part);
    cudaGetSymbolAddress((void**)&ah, g_Ah);
    cudaGetSymbolAddress((void**)&b, g_B);
    cudaGetSymbolAddress((void**)&xh, g_xh);
    cudaGetSymbolAddress((void**)&xl, g_xl);
    cudaGetSymbolAddress((void**)&w, g_w);
    cudaGetSymbolAddress((void**)&wo, g_wo);

    __half* qh = (__half*)gq;
    __half* kh = (__half*)gk;
    __half* kl = kh + (size_t)S_LEN * D4096;
    __half* vh = (__half*)gv;
    __half* vl = vh + (size_t)S_LEN * D4096;   // written by proj, unused by attn

    cudaFuncSetAttribute(mma_gemm_q, cudaFuncAttributeMaxDynamicSharedMemorySize, GQ_SMEM);
    cudaFuncSetAttribute(mma_proj_h, cudaFuncAttributeMaxDynamicSharedMemorySize, PROJ_SMEM);
    cudaFuncSetAttribute(gemm_out_mma, cudaFuncAttributeMaxDynamicSharedMemorySize, GO_SMEM);

    cudaStream_t s1;
    cudaStreamCreateWithFlags(&s1, cudaStreamNonBlocking);
    cudaEvent_t e0, e1, e2, eG0, eS;
    cudaEventCreateWithFlags(&e0, cudaEventDisableTiming);
    cudaEventCreateWithFlags(&e1, cudaEventDisableTiming);
    cudaEventCreateWithFlags(&e2, cudaEventDisableTiming);
    cudaEventCreateWithFlags(&eG0, cudaEventDisableTiming);
    cudaEventCreateWithFlags(&eS, cudaEventDisableTiming);

    cudaEventRecord(e0, 0);
    cudaStreamWaitEvent(s1, e0, 0);

    // side stream: Wq^T first, then k/v projections + Wo^T
    transpose_h<<<dim3(64, 64), 256, 0, s1>>>(Wq, b);
    cudaEventRecord(e2, s1);
    convert_split_h<<<(S_LEN * 64) / 2048, 256, 0, s1>>>(key_in, xh, xl);
    transpose_w64_h<<<64, 256, 0, s1>>>(Wk, w);
    mma_proj_h<<<dim3(D4096 / 128, S_LEN / 128), 256, PROJ_SMEM, s1>>>(xh, xl, w, bk, kh, kl);
    convert_split_h<<<(S_LEN * 64) / 2048, 256, 0, s1>>>(value, xh, xl);
    transpose_w64_h<<<64, 256, 0, s1>>>(Wv, w);
    mma_proj_h<<<dim3(D4096 / 128, S_LEN / 128), 256, PROJ_SMEM, s1>>>(xh, xl, w, bv, vh, vl);
    transpose_wo_h<<<64, 256, 0, s1>>>(Wo, wo);
    cudaEventRecord(e1, s1);

    // main: query convert + GEMM1 half 0
    convert_h<<<(S_LEN * (size_t)D4096) / 2048, 256>>>(query, ah);
    cudaStreamWaitEvent(0, e2, 0);
    mma_gemm_q<<<512, 512, GQ_SMEM>>>(ah, b, bq, qh, 0);
    cudaEventRecord(eG0, 0);

    // side: attn half 0 + gemm_out half 0 overlap GEMM1 half 1
    cudaStreamWaitEvent(s1, eG0, 0);   // q rows 0..4095 ready; k/v ready (same stream)
    attn_mma<<<S_LEN / 2, 128, 0, s1>>>(mask_u, qh, kh, kl, vh, ah, 0);
    gemm_out_mma<<<dim3(32, 8), 256, GO_SMEM, s1>>>(ah, wo, part, 0);
    cudaEventRecord(eS, s1);

    // main: GEMM1 half 1, then attn half 1 + gemm_out half 1
    mma_gemm_q<<<512, 512, GQ_SMEM>>>(ah, b, bq, qh, 32);
    cudaStreamWaitEvent(0, e1, 0);     // k/v/Wo ready
    attn_mma<<<S_LEN / 2, 128>>>(mask_u, qh, kh, kl, vh, ah, S_LEN / 2);
    gemm_out_mma<<<dim3(32, 8), 256, GO_SMEM>>>(ah, wo, part, 32);
    cudaStreamWaitEvent(0, eS, 0);
    gemm_out_reduce<<<(S_LEN * 64) / 256, 256>>>(part, bo, out);

    cudaEventDestroy(e0);
    cudaEventDestroy(e1);
    cudaEventDestroy(e2);
    cudaEventDestroy(eG0);
    cudaEventDestroy(eS);
    cudaStreamDestroy(s1);
}

// round 17
// speedup vs baseline: 7.6344x; 1.0427x over previous
#include <cuda_runtime.h>
#include <cuda_bf16.h>
#include <cuda_fp16.h>
#include <cstdint>

#define S_LEN 8192
#define D4096 4096

__device__ float g_q[(size_t)S_LEN * D4096];      // aliased: GEMM1 fp16 output (q)
__device__ float g_k[(size_t)S_LEN * D4096];      // aliased: k fp16 hi | lo
__device__ float g_v[(size_t)S_LEN * D4096];      // aliased: v fp16 hi | lo
__device__ __half g_Ah[(size_t)S_LEN * D4096];    // query fp16; later attn-out fp16
__device__ __half g_B[(size_t)D4096 * D4096];     // Wq^T fp16
__device__ float g_part[(size_t)8 * S_LEN * 64];  // split-K partials
__device__ __half g_xh[(size_t)S_LEN * 64];
__device__ __half g_xl[(size_t)S_LEN * 64];
__device__ __half g_w[(size_t)D4096 * 64];
__device__ __half g_wo[(size_t)64 * D4096];

__device__ __forceinline__ uint32_t smem_u32(const void* p) {
    uint32_t a;
    asm("{ .reg .u64 t; cvta.to.shared.u64 t, %1; cvt.u32.u64 %0, t; }"
        : "=r"(a) : "l"(p));
    return a;
}

#define CP_ASYNC16(saddr, gptr) \
    asm volatile("cp.async.cg.shared.global [%0], [%1], 16;" \
                 :: "r"(saddr), "l"(gptr) : "memory")
#define CP_COMMIT() asm volatile("cp.async.commit_group;" ::: "memory")
#define CP_WAIT(n)  asm volatile("cp.async.wait_group %0;" :: "n"(n) : "memory")

#define LDSM_X4(r0, r1, r2, r3, addr) \
    asm volatile("ldmatrix.sync.aligned.m8n8.x4.shared.b16 {%0,%1,%2,%3}, [%4];" \
                 : "=r"(r0), "=r"(r1), "=r"(r2), "=r"(r3) : "r"(addr))

#define LDSM_X4_T(r0, r1, r2, r3, addr) \
    asm volatile("ldmatrix.sync.aligned.m8n8.x4.trans.shared.b16 {%0,%1,%2,%3}, [%4];" \
                 : "=r"(r0), "=r"(r1), "=r"(r2), "=r"(r3) : "r"(addr))

#define MMA_F16(c, a, b0, b1) \
    asm volatile( \
        "mma.sync.aligned.m16n8k16.row.col.f32.f16.f16.f32 " \
        "{%0,%1,%2,%3}, {%4,%5,%6,%7}, {%8,%9}, {%0,%1,%2,%3};" \
        : "+f"((c)[0]), "+f"((c)[1]), "+f"((c)[2]), "+f"((c)[3]) \
        : "r"((a)[0]), "r"((a)[1]), "r"((a)[2]), "r"((a)[3]), "r"(b0), "r"(b1))

// fast exp on FFMA pipe (rel err ~4e-5)
__device__ __forceinline__ float fexpf(float x) {
    x = fmaxf(x, -87.0f);
    float y = x * 1.4426950408889634f;
    float n = rintf(y);
    float f = y - n;
    float p = 1.3337294e-3f;
    p = fmaf(p, f, 9.6181291e-3f);
    p = fmaf(p, f, 5.5504109e-2f);
    p = fmaf(p, f, 2.4022651e-1f);
    p = fmaf(p, f, 6.9314718e-1f);
    p = fmaf(p, f, 1.0f);
    return p * __int_as_float((__float2int_rn(n) + 127) << 23);
}

__device__ __forceinline__ uint32_t pack2h(float a, float b) {
    __half2 h = __floats2half2_rn(a, b);
    return *reinterpret_cast<uint32_t*>(&h);
}

// ---------------------------------------------------------------------------
__global__ __launch_bounds__(256) void convert_h(
    const float* __restrict__ in, __half* __restrict__ out)
{
    const size_t base = ((size_t)blockIdx.x * 256 + threadIdx.x) * 8;
    float4 a = *reinterpret_cast<const float4*>(in + base);
    float4 b = *reinterpret_cast<const float4*>(in + base + 4);
    float f[8] = {a.x, a.y, a.z, a.w, b.x, b.y, b.z, b.w};
    __half h[8];
#pragma unroll
    for (int i = 0; i < 8; i++) h[i] = __float2half_rn(f[i]);
    *reinterpret_cast<uint4*>(out + base) = *reinterpret_cast<uint4*>(h);
}

__global__ __launch_bounds__(256) void convert_split_h(
    const float* __restrict__ in, __half* __restrict__ hi,
    __half* __restrict__ lo)
{
    const size_t base = ((size_t)blockIdx.x * 256 + threadIdx.x) * 8;
    float4 a = *reinterpret_cast<const float4*>(in + base);
    float4 b = *reinterpret_cast<const float4*>(in + base + 4);
    float f[8] = {a.x, a.y, a.z, a.w, b.x, b.y, b.z, b.w};
    __half h[8], l[8];
#pragma unroll
    for (int i = 0; i < 8; i++) {
        h[i] = __float2half_rn(f[i]);
        l[i] = __float2half_rn(f[i] - __half2float(h[i]));
    }
    *reinterpret_cast<uint4*>(hi + base) = *reinterpret_cast<uint4*>(h);
    *reinterpret_cast<uint4*>(lo + base) = *reinterpret_cast<uint4*>(l);
}

__global__ __launch_bounds__(256) void transpose_h(
    const float* __restrict__ W, __half* __restrict__ out)
{
    __shared__ float ts[64][65];
    const int n0 = blockIdx.x * 64;
    const int k0 = blockIdx.y * 64;
    const int tid = threadIdx.x;
#pragma unroll
    for (int i = 0; i < 16; i++) {
        int idx = tid + i * 256;
        int r = idx >> 6, c = idx & 63;
        ts[r][c] = W[(size_t)(k0 + r) * D4096 + n0 + c];
    }
    __syncthreads();
#pragma unroll
    for (int i = 0; i < 8; i++) {
        int idx = tid + i * 256;
        int nl = idx >> 5, kl = (idx & 31) * 2;
        __half2 p;
        p.x = __float2half_rn(ts[kl][nl]);
        p.y = __float2half_rn(ts[kl + 1][nl]);
        *reinterpret_cast<__half2*>(out + (size_t)(n0 + nl) * D4096 + k0 + kl) = p;
    }
}

__global__ __launch_bounds__(256) void transpose_w64_h(
    const float* __restrict__ W, __half* __restrict__ out)
{
    __shared__ float ts[64][65];
    const int n0 = blockIdx.x * 64;
    const int tid = threadIdx.x;
    for (int t = tid; t < 4096; t += 256)
        ts[t >> 6][t & 63] = W[(size_t)(t >> 6) * D4096 + n0 + (t & 63)];
    __syncthreads();
    for (int t = tid; t < 4096; t += 256) {
        int nl = t >> 6, kl = t & 63;
        out[(size_t)(n0 + nl) * 64 + kl] = __float2half_rn(ts[kl][nl]);
    }
}

__global__ __launch_bounds__(256) void transpose_wo_h(
    const float* __restrict__ W, __half* __restrict__ out)
{
    __shared__ float ts[64][65];
    const int k0 = blockIdx.x * 64;
    const int tid = threadIdx.x;
    for (int t = tid; t < 4096; t += 256)
        ts[t >> 6][t & 63] = W[(size_t)(k0 + (t >> 6)) * 64 + (t & 63)];
    __syncthreads();
    for (int t = tid; t < 4096; t += 256) {
        int n = t >> 6, k = t & 63;
        out[(size_t)n * D4096 + k0 + k] = __float2half_rn(ts[k][n]);
    }
}

// ---------------------------------------------------------------------------
// Main HMMA GEMM: CTA 128x256, 512 thr (16 warps, 4m x 4n, warp 32x64),
// K-chunk 128, 2-stage (wait -> bar -> issue-next -> compute).
// Buffer: A 128x272B (34816) + B 256x272B (69632) = 104448; x2 = 208896.
// ---------------------------------------------------------------------------
#define SA 272
#define A_TB 34816
#define BUF_B 104448
#define GQ_SMEM 208896

__global__ __launch_bounds__(512) void mma_gemm_q(
    const __half* __restrict__ A, const __half* __restrict__ B,
    const float* __restrict__ bias, __half* __restrict__ C, int m_base)
{
    extern __shared__ char smem[];
    const uint32_t sb = smem_u32(smem);
    const int tid = threadIdx.x;
    const int warp = tid >> 5, lane = tid & 31;

    const int m0 = ((blockIdx.x >> 4) + m_base) * 128;
    const int n0 = (blockIdx.x & 15) * 256;

    const int wm = (warp & 3) * 32;
    const int wn = (warp >> 2) * 64;

    float c[2][8][4];
#pragma unroll
    for (int mt = 0; mt < 2; mt++)
#pragma unroll
        for (int nt = 0; nt < 8; nt++)
#pragma unroll
            for (int r = 0; r < 4; r++) c[mt][nt][r] = 0.0f;

    const int g = lane >> 3, r8 = lane & 7;
    const uint32_t a_off = (uint32_t)(wm + (g & 1) * 8 + r8) * SA + (g >> 1) * 16;
    const uint32_t b_off = A_TB + (uint32_t)(wn + (g >> 1) * 8 + r8) * SA + (g & 1) * 16;

    auto stage = [&](int chunk, int buf) {
        const int k0 = chunk * 128;
        const uint32_t base = sb + buf * BUF_B;
#pragma unroll
        for (int j = 0; j < 4; j++) {   // A: 128 rows x 16 chunks (2048)
            const int idx = tid + j * 512;
            const int row = idx >> 4, kc = (idx & 15) * 16;
            CP_ASYNC16(base + (uint32_t)row * SA + kc,
                       A + (size_t)(m0 + row) * D4096 + k0 + kc / 2);
        }
#pragma unroll
        for (int j = 0; j < 8; j++) {   // B: 256 rows x 16 chunks (4096)
            const int idx = tid + j * 512;
            const int row = idx >> 4, kc = (idx & 15) * 16;
            CP_ASYNC16(base + A_TB + (uint32_t)row * SA + kc,
                       B + (size_t)(n0 + row) * D4096 + k0 + kc / 2);
        }
        CP_COMMIT();
    };

    stage(0, 0);

    const int NIT = D4096 / 128;  // 32
    for (int it = 0; it < NIT; ++it) {
        CP_WAIT(0);
        __syncthreads();
        if (it + 1 < NIT) stage(it + 1, (it + 1) & 1);

        const uint32_t buf = sb + (it & 1) * BUF_B;
#pragma unroll
        for (int ks = 0; ks < 8; ++ks) {
            const uint32_t koff = ks * 32;
            uint32_t ah[2][4];
#pragma unroll
            for (int mt = 0; mt < 2; mt++) {
                const uint32_t aa = buf + a_off + koff + (uint32_t)mt * 16 * SA;
                LDSM_X4(ah[mt][0], ah[mt][1], ah[mt][2], ah[mt][3], aa);
            }
#pragma unroll
            for (int g4 = 0; g4 < 4; g4++) {
                uint32_t b4[4];
                const uint32_t ba = buf + b_off + koff + (uint32_t)g4 * 16 * SA;
                LDSM_X4(b4[0], b4[1], b4[2], b4[3], ba);
#pragma unroll
                for (int mt = 0; mt < 2; mt++) {
#pragma unroll
                    for (int sub = 0; sub < 2; sub++) {
                        const int nt = g4 * 2 + sub, h = sub * 2;
                        MMA_F16(c[mt][nt], ah[mt], b4[h], b4[h + 1]);
                    }
                }
            }
        }
    }

    const int rbase = m0 + wm + (lane >> 2);
    const int cbase = n0 + wn + (lane & 3) * 2;
#pragma unroll
    for (int mt = 0; mt < 2; mt++) {
#pragma unroll
        for (int nt = 0; nt < 8; nt++) {
            const int col = cbase + nt * 8;
            const float b0 = bias[col], b1 = bias[col + 1];
            *reinterpret_cast<uint32_t*>(C + (size_t)(rbase + mt * 16) * D4096 + col) =
                pack2h(c[mt][nt][0] + b0, c[mt][nt][1] + b1);
            *reinterpret_cast<uint32_t*>(C + (size_t)(rbase + mt * 16 + 8) * D4096 + col) =
                pack2h(c[mt][nt][2] + b0, c[mt][nt][3] + b1);
        }
    }
}

// ---------------------------------------------------------------------------
// HMMA projection (K=64), fp16 2-product; emits fp16 hi/lo.
// ---------------------------------------------------------------------------
#define PSA 144
#define P_TB 18432
#define PROJ_SMEM 55296

__global__ __launch_bounds__(256) void mma_proj_h(
    const __half* __restrict__ Xh, const __half* __restrict__ Xl,
    const __half* __restrict__ W, const float* __restrict__ bias,
    __half* __restrict__ outh, __half* __restrict__ outl)
{
    extern __shared__ char smem[];
    const uint32_t sb = smem_u32(smem);
    const int tid = threadIdx.x;
    const int warp = tid >> 5, lane = tid & 31;
    const int m0 = blockIdx.y * 128;
    const int n0 = blockIdx.x * 128;
    const int wm = (warp & 3) * 32;
    const int wn = (warp >> 2) * 64;

#pragma unroll
    for (int j = 0; j < 4; j++) {
        const int idx = tid + j * 256;
        const int row = idx >> 3, kc = (idx & 7) * 16;
        const uint32_t sa = sb + (uint32_t)row * PSA + kc;
        const size_t gx = (size_t)(m0 + row) * 64 + kc / 2;
        const size_t gw = (size_t)(n0 + row) * 64 + kc / 2;
        CP_ASYNC16(sa, Xh + gx);
        CP_ASYNC16(sa + P_TB, Xl + gx);
        CP_ASYNC16(sa + 2 * P_TB, W + gw);
    }
    CP_COMMIT();

    float c[2][8][4];
#pragma unroll
    for (int mt = 0; mt < 2; mt++)
#pragma unroll
        for (int nt = 0; nt < 8; nt++)
#pragma unroll
            for (int r = 0; r < 4; r++) c[mt][nt][r] = 0.0f;

    const int g = lane >> 3, r8 = lane & 7;
    const uint32_t a_off = (uint32_t)(wm + (g & 1) * 8 + r8) * PSA + (g >> 1) * 16;
    const uint32_t b_off = 2 * P_TB + (uint32_t)(wn + (g >> 1) * 8 + r8) * PSA + (g & 1) * 16;

    CP_WAIT(0);
    __syncthreads();

#pragma unroll
    for (int ks = 0; ks < 4; ++ks) {
        const uint32_t koff = ks * 32;
        uint32_t ah[2][4], al[2][4];
#pragma unroll
        for (int mt = 0; mt < 2; mt++) {
            const uint32_t aa = sb + a_off + koff + (uint32_t)mt * 16 * PSA;
            LDSM_X4(ah[mt][0], ah[mt][1], ah[mt][2], ah[mt][3], aa);
            LDSM_X4(al[mt][0], al[mt][1], al[mt][2], al[mt][3], aa + P_TB);
        }
#pragma unroll
        for (int g4 = 0; g4 < 4; g4++) {
            uint32_t b4[4];
            const uint32_t ba = sb + b_off + koff + (uint32_t)g4 * 16 * PSA;
            LDSM_X4(b4[0], b4[1], b4[2], b4[3], ba);
#pragma unroll
            for (int mt = 0; mt < 2; mt++) {
#pragma unroll
                for (int sub = 0; sub < 2; sub++) {
                    const int nt = g4 * 2 + sub, h = sub * 2;
                    MMA_F16(c[mt][nt], ah[mt], b4[h], b4[h + 1]);
                    MMA_F16(c[mt][nt], al[mt], b4[h], b4[h + 1]);
                }
            }
        }
    }

    const int rbase = m0 + wm + (lane >> 2);
    const int cbase = n0 + wn + (lane & 3) * 2;
#pragma unroll
    for (int mt = 0; mt < 2; mt++) {
#pragma unroll
        for (int nt = 0; nt < 8; nt++) {
            const int col = cbase + nt * 8;
            const float b0 = bias[col], b1 = bias[col + 1];
#pragma unroll
            for (int half_ = 0; half_ < 2; half_++) {
                const float s0 = c[mt][nt][half_ * 2 + 0] + b0;
                const float s1 = c[mt][nt][half_ * 2 + 1] + b1;
                const __half h0 = __float2half_rn(s0), h1 = __float2half_rn(s1);
                const size_t off = (size_t)(rbase + mt * 16 + half_ * 8) * D4096 + col;
                *reinterpret_cast<uint32_t*>(outh + off) =
                    ((uint32_t)__half_as_ushort(h1) << 16) | __half_as_ushort(h0);
                *reinterpret_cast<uint32_t*>(outl + off) =
                    pack2h(s0 - __half2float(h0), s1 - __half2float(h1));
            }
        }
    }
}

// ---------------------------------------------------------------------------
// Tensorized per-token attention. QK 1-product (q, k both single fp16);
// PV 2-product (at hi/lo, v single). smem: q, kh, vh (27648 B).
// ---------------------------------------------------------------------------
#define AST 144

__global__ __launch_bounds__(128, 4) void attn_mma(
    const float* __restrict__ mask_u,
    const __half* __restrict__ qh, const __half* __restrict__ kh,
    const __half* __restrict__ vh, __half* __restrict__ oh, int s_base)
{
    __shared__ __half smq[64 * 72];
    __shared__ __half smkh[64 * 72];
    __shared__ __half smvh[64 * 72];

    const int s = blockIdx.x + s_base;
    const int tid = threadIdx.x;
    const int w = tid >> 5, lane = tid & 31;
    const int gid = lane >> 2, tig = lane & 3;

    const uint32_t sq = smem_u32(smq);
    const uint32_t skh = smem_u32(smkh);
    const uint32_t svh = smem_u32(smvh);

    const size_t gbase = (size_t)s * 4096;
#pragma unroll
    for (int j = 0; j < 4; j++) {
        const int t = tid + j * 128;
        const int row = t >> 3, kc = (t & 7) * 16;
        const uint32_t so = (uint32_t)row * AST + kc;
        const size_t go = gbase + (size_t)row * 64 + kc / 2;
        CP_ASYNC16(sq + so, qh + go);
        CP_ASYNC16(skh + so, kh + go);
    }
    CP_COMMIT();
#pragma unroll
    for (int j = 0; j < 4; j++) {
        const int t = tid + j * 128;
        const int row = t >> 3, kc = (t & 7) * 16;
        CP_ASYNC16(svh + (uint32_t)row * AST + kc,
                   vh + gbase + (size_t)row * 64 + kc / 2);
    }
    CP_COMMIT();

    CP_WAIT(1);
    __syncthreads();

    const int lg = lane >> 3, lr = lane & 7;
    const uint32_t atoff = (uint32_t)((lg >> 1) * 8 + lr) * AST +
                           (uint32_t)(w * 16 + (lg & 1) * 8) * 2;
    const uint32_t boff = (uint32_t)((lg >> 1) * 8 + lr) * AST + (uint32_t)(lg & 1) * 16;

    float c[8][4];
#pragma unroll
    for (int nt = 0; nt < 8; nt++)
#pragma unroll
        for (int r = 0; r < 4; r++) c[nt][r] = 0.0f;

#pragma unroll
    for (int kc = 0; kc < 4; kc++) {
        uint32_t aq = sq + (uint32_t)kc * 16 * AST + atoff;
        uint32_t ah[4];
        LDSM_X4_T(ah[0], ah[1], ah[2], ah[3], aq);
#pragma unroll
        for (int g4 = 0; g4 < 4; g4++) {
            uint32_t bh4[4];
            uint32_t bko = (uint32_t)g4 * 16 * AST + boff + kc * 32;
            LDSM_X4(bh4[0], bh4[1], bh4[2], bh4[3], skh + bko);
#pragma unroll
            for (int sub = 0; sub < 2; sub++) {
                const int nt = g4 * 2 + sub, h = sub * 2;
                MMA_F16(c[nt], ah, bh4[h], bh4[h + 1]);
            }
        }
    }

    float mx0 = -1e30f, mx1 = -1e30f;
#pragma unroll
    for (int nt = 0; nt < 8; nt++) {
        mx0 = fmaxf(mx0, fmaxf(c[nt][0], c[nt][1]));
        mx1 = fmaxf(mx1, fmaxf(c[nt][2], c[nt][3]));
    }
    mx0 = fmaxf(mx0, __shfl_xor_sync(0xffffffffu, mx0, 1));
    mx0 = fmaxf(mx0, __shfl_xor_sync(0xffffffffu, mx0, 2));
    mx1 = fmaxf(mx1, __shfl_xor_sync(0xffffffffu, mx1, 1));
    mx1 = fmaxf(mx1, __shfl_xor_sync(0xffffffffu, mx1, 2));
    float se0 = 0.0f, se1 = 0.0f;
#pragma unroll
    for (int nt = 0; nt < 8; nt++) {
        se0 += fexpf(c[nt][0] - mx0) + fexpf(c[nt][1] - mx0);
        se1 += fexpf(c[nt][2] - mx1) + fexpf(c[nt][3] - mx1);
    }
    se0 += __shfl_xor_sync(0xffffffffu, se0, 1);
    se0 += __shfl_xor_sync(0xffffffffu, se0, 2);
    se1 += __shfl_xor_sync(0xffffffffu, se1, 1);
    se1 += __shfl_xor_sync(0xffffffffu, se1, 2);
    const float lse0 = mx0 + __logf(se0);
    const float lse1 = mx1 + __logf(se1);

    const int r0 = w * 16 + gid;
    const float* m0p = mask_u + ((size_t)s * 64 + r0) * 64 + tig * 2;
    const float* m1p = m0p + 8 * 64;
    uint32_t ath0[8], atl0[8], ath1[8], atl1[8];
#pragma unroll
    for (int nt = 0; nt < 8; nt++) {
        const float2 mv0 = *reinterpret_cast<const float2*>(m0p + nt * 8);
        const float2 mv1 = *reinterpret_cast<const float2*>(m1p + nt * 8);
        float v0 = (c[nt][0] - lse0) * ((mv0.x > 0.25f) ? (1.0f / 0.75f) : 0.0f);
        float v1 = (c[nt][1] - lse0) * ((mv0.y > 0.25f) ? (1.0f / 0.75f) : 0.0f);
        float v2 = (c[nt][2] - lse1) * ((mv1.x > 0.25f) ? (1.0f / 0.75f) : 0.0f);
        float v3 = (c[nt][3] - lse1) * ((mv1.y > 0.25f) ? (1.0f / 0.75f) : 0.0f);
        __half h0 = __float2half_rn(v0), h1 = __float2half_rn(v1);
        __half h2 = __float2half_rn(v2), h3 = __float2half_rn(v3);
        ath0[nt] = ((uint32_t)__half_as_ushort(h1) << 16) | __half_as_ushort(h0);
        ath1[nt] = ((uint32_t)__half_as_ushort(h3) << 16) | __half_as_ushort(h2);
        atl0[nt] = pack2h(v0 - __half2float(h0), v1 - __half2float(h1));
        atl1[nt] = pack2h(v2 - __half2float(h2), v3 - __half2float(h3));
    }

    CP_WAIT(0);
    __syncthreads();

    float o[8][4];
#pragma unroll
    for (int nt = 0; nt < 8; nt++)
#pragma unroll
        for (int r = 0; r < 4; r++) o[nt][r] = 0.0f;

#pragma unroll
    for (int mc = 0; mc < 4; mc++) {
        uint32_t Ah2[4] = {ath0[2 * mc], ath1[2 * mc], ath0[2 * mc + 1], ath1[2 * mc + 1]};
        uint32_t Al2[4] = {atl0[2 * mc], atl1[2 * mc], atl0[2 * mc + 1], atl1[2 * mc + 1]};
#pragma unroll
        for (int g4 = 0; g4 < 4; g4++) {
            uint32_t vh4[4];
            uint32_t bvo = (uint32_t)g4 * 16 * AST + boff + mc * 32;
            LDSM_X4(vh4[0], vh4[1], vh4[2], vh4[3], svh + bvo);
#pragma unroll
            for (int sub = 0; sub < 2; sub++) {
                const int nt = g4 * 2 + sub, h = sub * 2;
                MMA_F16(o[nt], Ah2, vh4[h], vh4[h + 1]);
                MMA_F16(o[nt], Al2, vh4[h], vh4[h + 1]);
            }
        }
    }

    __half* ohp = oh + (size_t)s * 4096;
#pragma unroll
    for (int nt = 0; nt < 8; nt++) {
        const int j = nt * 8 + tig * 2;
        *reinterpret_cast<uint32_t*>(ohp + r0 * 64 + j) = pack2h(o[nt][0], o[nt][1]);
        *reinterpret_cast<uint32_t*>(ohp + (r0 + 8) * 64 + j) = pack2h(o[nt][2], o[nt][3]);
    }
}

// ---------------------------------------------------------------------------
// output GEMM via HMMA fp16 single-product, split-K=8; m_base for half-split
// ---------------------------------------------------------------------------
#define OSA 80
#define OA_TB 10240
#define OBUF 15360
#define GO_SMEM 30720

__global__ __launch_bounds__(256) void gemm_out_mma(
    const __half* __restrict__ A, const __half* __restrict__ W,
    float* __restrict__ part, int m_base)
{
    extern __shared__ char smem[];
    const uint32_t sb = smem_u32(smem);
    const int tid = threadIdx.x;
    const int warp = tid >> 5, lane = tid & 31;
    const int m0 = (blockIdx.x + m_base) * 128;
    const int ksp = blockIdx.y;
    const int kbase = ksp * 512;
    const int wm = (warp & 3) * 32;
    const int wn = (warp >> 2) * 32;

    float c[2][4][4];
#pragma unroll
    for (int mt = 0; mt < 2; mt++)
#pragma unroll
        for (int nt = 0; nt < 4; nt++)
#pragma unroll
            for (int r = 0; r < 4; r++) c[mt][nt][r] = 0.0f;

    const int g = lane >> 3, r8 = lane & 7;
    const uint32_t a_off = (uint32_t)(wm + (g & 1) * 8 + r8) * OSA + (g >> 1) * 16;
    const uint32_t b_off = OA_TB + (uint32_t)(wn + (g >> 1) * 8 + r8) * OSA + (g & 1) * 16;

    auto stage = [&](int chunk, int buf) {
        const int k0 = kbase + chunk * 32;
        const uint32_t base = sb + buf * OBUF;
#pragma unroll
        for (int j = 0; j < 2; j++) {
            const int idx = tid + j * 256;
            const int row = idx >> 2, kc = (idx & 3) * 16;
            CP_ASYNC16(base + (uint32_t)row * OSA + kc,
                       A + (size_t)(m0 + row) * D4096 + k0 + kc / 2);
        }
        {
            const int row = tid >> 2, kc = (tid & 3) * 16;
            CP_ASYNC16(base + OA_TB + (uint32_t)row * OSA + kc,
                       W + (size_t)row * D4096 + k0 + kc / 2);
        }
        CP_COMMIT();
    };

    stage(0, 0);

    for (int it = 0; it < 16; ++it) {
        if (it + 1 < 16) {
            stage(it + 1, (it + 1) & 1);
            CP_WAIT(1);
        } else {
            CP_WAIT(0);
        }
        __syncthreads();

        const uint32_t buf = sb + (it & 1) * OBUF;
#pragma unroll
        for (int ks = 0; ks < 2; ++ks) {
            const uint32_t koff = ks * 32;
            uint32_t ah[2][4];
#pragma unroll
            for (int mt = 0; mt < 2; mt++) {
                const uint32_t aa = buf + a_off + koff + (uint32_t)mt * 16 * OSA;
                LDSM_X4(ah[mt][0], ah[mt][1], ah[mt][2], ah[mt][3], aa);
            }
#pragma unroll
            for (int g4 = 0; g4 < 2; g4++) {
                uint32_t b4[4];
                const uint32_t ba = buf + b_off + koff + (uint32_t)g4 * 16 * OSA;
                LDSM_X4(b4[0], b4[1], b4[2], b4[3], ba);
#pragma unroll
                for (int mt = 0; mt < 2; mt++) {
#pragma unroll
                    for (int sub = 0; sub < 2; sub++) {
                        const int nt = g4 * 2 + sub, h = sub * 2;
                        MMA_F16(c[mt][nt], ah[mt], b4[h], b4[h + 1]);
                    }
                }
            }
        }
        __syncthreads();
    }

    float* pbase = part + (size_t)ksp * S_LEN * 64;
    const int rbase = m0 + wm + (lane >> 2);
    const int cbase = wn + (lane & 3) * 2;
#pragma unroll
    for (int mt = 0; mt < 2; mt++) {
#pragma unroll
        for (int nt = 0; nt < 4; nt++) {
            const int col = cbase + nt * 8;
            float* p0 = pbase + (size_t)(rbase + mt * 16) * 64 + col;
            float* p1 = pbase + (size_t)(rbase + mt * 16 + 8) * 64 + col;
            p0[0] = c[mt][nt][0];
            p0[1] = c[mt][nt][1];
            p1[0] = c[mt][nt][2];
            p1[1] = c[mt][nt][3];
        }
    }
}

__global__ __launch_bounds__(256) void gemm_out_reduce(
    const float* __restrict__ part, const float* __restrict__ bias,
    float* __restrict__ out)
{
    const size_t i = (size_t)blockIdx.x * 256 + threadIdx.x;
    float s = bias[i & 63];
#pragma unroll
    for (int k = 0; k < 8; k++) s += part[i + (size_t)k * S_LEN * 64];
    out[i] = s;
}

// ---------------------------------------------------------------------------
// Launch
// ---------------------------------------------------------------------------
extern "C" void kernel_launch(void* const* d_in, const int* in_sizes, int n_in,
                              void* d_out, int out_size)
{
    const float* query  = (const float*)d_in[0];
    const float* key_in = (const float*)d_in[1];
    const float* value  = (const float*)d_in[2];
    const float* mask_u = (const float*)d_in[3];
    const float* Wq = (const float*)d_in[4];
    const float* bq = (const float*)d_in[5];
    const float* Wk = (const float*)d_in[6];
    const float* bk = (const float*)d_in[7];
    const float* Wv = (const float*)d_in[8];
    const float* bv = (const float*)d_in[9];
    const float* Wo = (const float*)d_in[10];
    const float* bo = (const float*)d_in[11];
    float* out = (float*)d_out;

    float *gq, *gk, *gv, *part;
    __half *ah, *b, *xh, *xl, *w, *wo;
    cudaGetSymbolAddress((void**)&gq, g_q);
    cudaGetSymbolAddress((void**)&gk, g_k);
    cudaGetSymbolAddress((void**)&gv, g_v);
    cudaGetSymbolAddress((void**)&part, g_part);
    cudaGetSymbolAddress((void**)&ah, g_Ah);
    cudaGetSymbolAddress((void**)&b, g_B);
    cudaGetSymbolAddress((void**)&xh, g_xh);
    cudaGetSymbolAddress((void**)&xl, g_xl);
    cudaGetSymbolAddress((void**)&w, g_w);
    cudaGetSymbolAddress((void**)&wo, g_wo);

    __half* qh = (__half*)gq;
    __half* kh = (__half*)gk;
    __half* kl = kh + (size_t)S_LEN * D4096;   // proj writes it; attn no longer reads
    __half* vh = (__half*)gv;
    __half* vl = vh + (size_t)S_LEN * D4096;

    cudaFuncSetAttribute(mma_gemm_q, cudaFuncAttributeMaxDynamicSharedMemorySize, GQ_SMEM);
    cudaFuncSetAttribute(mma_proj_h, cudaFuncAttributeMaxDynamicSharedMemorySize, PROJ_SMEM);
    cudaFuncSetAttribute(gemm_out_mma, cudaFuncAttributeMaxDynamicSharedMemorySize, GO_SMEM);

    cudaStream_t s1;
    cudaStreamCreateWithFlags(&s1, cudaStreamNonBlocking);
    cudaEvent_t e0, e1, e2, eG0, eS;
    cudaEventCreateWithFlags(&e0, cudaEventDisableTiming);
    cudaEventCreateWithFlags(&e1, cudaEventDisableTiming);
    cudaEventCreateWithFlags(&e2, cudaEventDisableTiming);
    cudaEventCreateWithFlags(&eG0, cudaEventDisableTiming);
    cudaEventCreateWithFlags(&eS, cudaEventDisableTiming);

    cudaEventRecord(e0, 0);
    cudaStreamWaitEvent(s1, e0, 0);

    // side stream: Wq^T first, then k/v projections + Wo^T
    transpose_h<<<dim3(64, 64), 256, 0, s1>>>(Wq, b);
    cudaEventRecord(e2, s1);
    convert_split_h<<<(S_LEN * 64) / 2048, 256, 0, s1>>>(key_in, xh, xl);
    transpose_w64_h<<<64, 256, 0, s1>>>(Wk, w);
    mma_proj_h<<<dim3(D4096 / 128, S_LEN / 128), 256, PROJ_SMEM, s1>>>(xh, xl, w, bk, kh, kl);
    convert_split_h<<<(S_LEN * 64) / 2048, 256, 0, s1>>>(value, xh, xl);
    transpose_w64_h<<<64, 256, 0, s1>>>(Wv, w);
    mma_proj_h<<<dim3(D4096 / 128, S_LEN / 128), 256, PROJ_SMEM, s1>>>(xh, xl, w, bv, vh, vl);
    transpose_wo_h<<<64, 256, 0, s1>>>(Wo, wo);
    cudaEventRecord(e1, s1);

    // main: query convert + GEMM1 half 0
    convert_h<<<(S_LEN * (size_t)D4096) / 2048, 256>>>(query, ah);
    cudaStreamWaitEvent(0, e2, 0);
    mma_gemm_q<<<512, 512, GQ_SMEM>>>(ah, b, bq, qh, 0);
    cudaEventRecord(eG0, 0);

    // side: attn half 0 + gemm_out half 0 (fills GEMM1 half-1 wave-tail gaps)
    cudaStreamWaitEvent(s1, eG0, 0);
    attn_mma<<<S_LEN / 2, 128, 0, s1>>>(mask_u, qh, kh, vh, ah, 0);
    gemm_out_mma<<<dim3(32, 8), 256, GO_SMEM, s1>>>(ah, wo, part, 0);
    cudaEventRecord(eS, s1);

    // main: GEMM1 half 1, then attn half 1 + gemm_out half 1
    mma_gemm_q<<<512, 512, GQ_SMEM>>>(ah, b, bq, qh, 32);
    cudaStreamWaitEvent(0, e1, 0);
    attn_mma<<<S_LEN / 2, 128>>>(mask_u, qh, kh, vh, ah, S_LEN / 2);
    gemm_out_mma<<<dim3(32, 8), 256, GO_SMEM>>>(ah, wo, part, 32);
    cudaStreamWaitEvent(0, eS, 0);
    gemm_out_reduce<<<(S_LEN * 64) / 256, 256>>>(part, bo, out);

    cudaEventDestroy(e0);
    cudaEventDestroy(e1);
    cudaEventDestroy(e2);
    cudaEventDestroy(eG0);
    cudaEventDestroy(eS);
    cudaStreamDestroy(s1);
}